// round 3
// baseline (speedup 1.0000x reference)
#include <cuda_runtime.h>
#include <math.h>

#define B_ 16
#define D_ 128
#define N_ 8192
#define NW_ 64
#define QT 64          // n-positions per qkv block
#define XC 68          // x tile cols (QT + 4 pad)

typedef unsigned long long ull;

// ---------------- device scratch ----------------
__device__ ull g_wq2[D_*5*D_];   // [(i*5+t)*D + d] = (w,w) packed broadcast
__device__ ull g_wk2[D_*5*D_];
__device__ ull g_wv2[D_*5*D_];
__device__ float g_cs[N_*64];
__device__ float g_sn[N_*64];
__device__ float g_q[B_*N_*D_];  // (B,N,D) rotary+scaled
__device__ float g_k[B_*N_*D_];
__device__ float g_v[B_*N_*D_];
__device__ float g_a[B_*N_*D_];
__device__ float g_scale[D_];
__device__ float g_shift[D_];

// ---------------- f32x2 helpers ----------------
__device__ __forceinline__ void fma2(ull& acc, ull a, ull b) {
    asm("fma.rn.f32x2 %0, %1, %2, %0;" : "+l"(acc) : "l"(a), "l"(b));
}
__device__ __forceinline__ ull bcast2(float v) {
    ull r; asm("mov.b64 %0, {%1, %1};" : "=l"(r) : "f"(v)); return r;
}
__device__ __forceinline__ ull pack2(float a, float b) {
    ull r; asm("mov.b64 %0, {%1, %2};" : "=l"(r) : "f"(a), "f"(b)); return r;
}
__device__ __forceinline__ float2 unpack2(ull p) {
    float2 r; asm("mov.b64 {%0, %1}, %2;" : "=f"(r.x), "=f"(r.y) : "l"(p)); return r;
}

// ---------------- prep ----------------
__global__ void prep_weights(const float* __restrict__ qw, const float* __restrict__ kw,
                             const float* __restrict__ vw) {
    int e = blockIdx.x * blockDim.x + threadIdx.x;
    if (e >= D_*5*D_) return;
    int o = e % D_, r = e / D_;           // r = i*5 + t
    int src = o * (D_*5) + r;
    unsigned bq = __float_as_uint(qw[src]);
    unsigned bk = __float_as_uint(kw[src]);
    unsigned bv = __float_as_uint(vw[src]);
    g_wq2[e] = ((ull)bq << 32) | bq;
    g_wk2[e] = ((ull)bk << 32) | bk;
    g_wv2[e] = ((ull)bv << 32) | bv;
}

__global__ void prep_trig() {
    int e = blockIdx.x * blockDim.x + threadIdx.x;
    if (e >= N_*64) return;
    int n = e >> 6, f = e & 63;
    double invf = pow(10000.0, -((double)(2*f)) / 128.0);
    float ang = (float)n * (float)invf;    // match JAX fp32 angle rounding
    double a = (double)ang;
    g_cs[e] = (float)cos(a);
    g_sn[e] = (float)sin(a);
}

// ---------- fused QKV causal conv + bias + rotary + scale ----------
#define QKV_SMEM (128*XC*4 + 128*XC*8)   // raw floats + packed pairs

__global__ __launch_bounds__(256) void qkv_conv(const float* __restrict__ x,
                                                const float* __restrict__ qb,
                                                const float* __restrict__ kb,
                                                const float* __restrict__ vb) {
    extern __shared__ char smraw[];
    float* xs = (float*)smraw;                    // [128][XC]
    ull*   xp = (ull*)(smraw + 128*XC*4);         // [128][XC] pairs
    const int b = blockIdx.y, n0 = blockIdx.x * QT;
    const int t = threadIdx.x;
    const int d = t & 127, h = t >> 7;

    // load raw x tile (coalesced)
    {
        int warp = t >> 5, lane = t & 31;
        for (int r = warp; r < 128; r += 8) {
            const float* xr = x + (size_t)(b*D_ + r) * N_;
            for (int c = lane; c < XC; c += 32) {
                int n = n0 - 4 + c;
                xs[r*XC + c] = (n >= 0) ? xr[n] : 0.0f;
            }
        }
    }
    __syncthreads();
    // build overlapping pairs (x[c], x[c+1]) once per block
    {
        int r = t >> 1;
        int c0 = (t & 1) * 34;
        int ce = (c0 + 34 < 67) ? c0 + 34 : 67;
        for (int c = c0; c < ce; c++)
            xp[r*XC + c] = pack2(xs[r*XC + c], xs[r*XC + c + 1]);
    }
    __syncthreads();

    ull aq[16], ak[16], av[16];
#pragma unroll
    for (int j = 0; j < 16; j++) { aq[j] = 0ULL; ak[j] = 0ULL; av[j] = 0ULL; }

    for (int i = 0; i < 128; i++) {
        ull wq[5], wk[5], wv[5];
#pragma unroll
        for (int tt = 0; tt < 5; tt++) {
            int wi = (i*5 + tt)*D_ + d;
            wq[tt] = __ldg(&g_wq2[wi]);
            wk[tt] = __ldg(&g_wk2[wi]);
            wv[tt] = __ldg(&g_wv2[wi]);
        }
        const ull* prow = xp + i*XC + h*32;
#pragma unroll
        for (int tt = 0; tt < 5; tt++) {
#pragma unroll
            for (int jp = 0; jp < 16; jp++) {
                ull px = prow[2*jp + tt];     // broadcast LDS.64
                fma2(aq[jp], wq[tt], px);
                fma2(ak[jp], wk[tt], px);
                fma2(av[jp], wv[tt], px);
            }
        }
    }
    __syncthreads();

    // exchange q,k through smem for rotary pairing
    float* qsm = (float*)smraw;            // [QT][128]
    float* ksm = qsm + QT*128;             // [QT][128]
    float bqv = qb[d], bkv = kb[d];
#pragma unroll
    for (int jp = 0; jp < 16; jp++) {
        int j = h*32 + 2*jp;
        float2 q2 = unpack2(aq[jp]);
        float2 k2 = unpack2(ak[jp]);
        qsm[j*128 + d]     = q2.x + bqv;
        qsm[(j+1)*128 + d] = q2.y + bqv;
        ksm[j*128 + d]     = k2.x + bkv;
        ksm[(j+1)*128 + d] = k2.y + bkv;
    }
    __syncthreads();

    const float scl = 0.08838834764831845f;   // 128^-0.5
    const int dp = (d + 64) & 127;
    const float sg = (d < 64) ? -1.0f : 1.0f;
    const int f = d & 63;
    const float bvv = vb[d];
#pragma unroll
    for (int jp = 0; jp < 16; jp++) {
        float2 v2 = unpack2(av[jp]);
#pragma unroll
        for (int u = 0; u < 2; u++) {
            int j = h*32 + 2*jp + u;
            int n = n0 + j;
            float cc = g_cs[n*64 + f], ss = g_sn[n*64 + f];
            float qv = qsm[j*128 + d],      kv = ksm[j*128 + d];
            float qh = sg * qsm[j*128 + dp], kh = sg * ksm[j*128 + dp];
            size_t o = (size_t)(b*N_ + n) * 128 + d;
            g_q[o] = (qv*cc + qh*ss) * scl;
            g_k[o] = kv*cc + kh*ss;
            g_v[o] = ((u == 0) ? v2.x : v2.y) + bvv;
        }
    }
}

// ---------------- windowed causal attention ----------------
#define SS 260
#define ATTN_SMEM ((16384 + 128*SS + 8192) * 4)   // qs + S + k/v buffer = 231424 B

__global__ __launch_bounds__(256) void attn_kernel() {
    extern __shared__ float sm[];
    float* qs = sm;                  // [128][128]
    float* S  = sm + 16384;          // [128][260]
    float* kb = S + 128*SS;          // k chunk [64][128] swizzled / v chunk [32][128]

    const int wi = blockIdx.x, b = blockIdx.y;
    const int n0 = wi * 128, t = threadIdx.x;

    for (int fI = t; fI < 4096; fI += 256) {
        int r = fI >> 5, c4 = fI & 31;
        *(float4*)(qs + r*128 + c4*4) =
            *(const float4*)(g_q + (size_t)(b*N_ + n0 + r)*D_ + c4*4);
    }

    // ---- S = q @ k^T : 4 chunks of 64 key rows, f32x2 over d ----
    {
        const int rg = t >> 4, cg = t & 15;
        const int r0 = rg * 8;
        for (int ch = 0; ch < 4; ch++) {
            __syncthreads();
            for (int fI = t; fI < 2048; fI += 256) {
                int r = fI >> 5, c4 = fI & 31;
                int nk = n0 - 128 + ch*64 + r;
                float4 v = make_float4(0.f, 0.f, 0.f, 0.f);
                if (nk >= 0) v = *(const float4*)(g_k + (size_t)(b*N_ + nk)*D_ + c4*4);
                *(float4*)(kb + r*128 + ((c4 ^ (r & 7)) * 4)) = v;   // XOR swizzle
            }
            __syncthreads();

            ull acc[8][4];
#pragma unroll
            for (int u0 = 0; u0 < 8; u0++)
#pragma unroll
                for (int u1 = 0; u1 < 4; u1++) acc[u0][u1] = 0ULL;

            for (int d4 = 0; d4 < 32; d4++) {
                ulonglong2 q2[8];
#pragma unroll
                for (int rr = 0; rr < 8; rr++)
                    q2[rr] = *(const ulonglong2*)(qs + (r0+rr)*128 + d4*4);
#pragma unroll
                for (int u = 0; u < 4; u++) {
                    int kr = cg + 16*u;
                    ulonglong2 k2 = *(const ulonglong2*)(kb + kr*128 + ((d4 ^ (kr & 7)) * 4));
#pragma unroll
                    for (int rr = 0; rr < 8; rr++) {
                        fma2(acc[rr][u], q2[rr].x, k2.x);
                        fma2(acc[rr][u], q2[rr].y, k2.y);
                    }
                }
            }
#pragma unroll
            for (int rr = 0; rr < 8; rr++)
#pragma unroll
                for (int u = 0; u < 4; u++) {
                    float2 p = unpack2(acc[rr][u]);
                    S[(r0+rr)*SS + ch*64 + cg + 16*u] = p.x + p.y;
                }
        }
    }
    __syncthreads();

    // ---- masked softmax: row i valid cols [jstart, 128+i] ----
    if (t < 128) {
        float* row = S + t*SS;
        int jstart = (wi == 0) ? 128 : 0;
        int jend = 128 + t + 1;
        float m = -3.402823466e38f;
        for (int j = jstart; j < jend; j++) m = fmaxf(m, row[j]);
        float s = 0.f;
        for (int j = jstart; j < jend; j++) { float e = __expf(row[j] - m); row[j] = e; s += e; }
        float inv = 1.0f / s;
        for (int j = 0; j < jstart; j++) row[j] = 0.f;
        for (int j = jstart; j < jend; j++) row[j] *= inv;
        for (int j = jend; j < 256; j++) row[j] = 0.f;
    }

    // ---- OUT = P @ V : 8 chunks of 32 rows, f32x2 over output cols ----
    {
        const int rg = t >> 4, cg = t & 15;
        const int r0 = rg*8, c0 = cg*8;
        ull acc[8][4];
#pragma unroll
        for (int u0 = 0; u0 < 8; u0++)
#pragma unroll
            for (int u1 = 0; u1 < 4; u1++) acc[u0][u1] = 0ULL;

        for (int ch = 0; ch < 8; ch++) {
            __syncthreads();
            for (int fI = t; fI < 1024; fI += 256) {
                int r = fI >> 5, c4 = fI & 31;
                int nk = n0 - 128 + ch*32 + r;
                float4 v = make_float4(0.f, 0.f, 0.f, 0.f);
                if (nk >= 0) v = *(const float4*)(g_v + (size_t)(b*N_ + nk)*D_ + c4*4);
                *(float4*)(kb + r*128 + c4*4) = v;
            }
            __syncthreads();
            for (int k4 = 0; k4 < 8; k4++) {
                float4 p4[8];
#pragma unroll
                for (int rr = 0; rr < 8; rr++)
                    p4[rr] = *(const float4*)(S + (r0+rr)*SS + ch*32 + k4*4);
#pragma unroll
                for (int j = 0; j < 4; j++) {
                    ulonglong2 va  = *(const ulonglong2*)(kb + (k4*4+j)*128 + c0);
                    ulonglong2 vb2 = *(const ulonglong2*)(kb + (k4*4+j)*128 + c0 + 4);
#pragma unroll
                    for (int rr = 0; rr < 8; rr++) {
                        float pv = (j==0)?p4[rr].x:(j==1)?p4[rr].y:(j==2)?p4[rr].z:p4[rr].w;
                        ull pb = bcast2(pv);
                        fma2(acc[rr][0], pb, va.x);
                        fma2(acc[rr][1], pb, va.y);
                        fma2(acc[rr][2], pb, vb2.x);
                        fma2(acc[rr][3], pb, vb2.y);
                    }
                }
            }
        }
#pragma unroll
        for (int rr = 0; rr < 8; rr++) {
            float2 a0 = unpack2(acc[rr][0]), a1 = unpack2(acc[rr][1]);
            float2 a2 = unpack2(acc[rr][2]), a3 = unpack2(acc[rr][3]);
            float* o = g_a + (size_t)(b*N_ + n0 + r0 + rr)*D_ + c0;
            *(float4*)(o)     = make_float4(a0.x, a0.y, a1.x, a1.y);
            *(float4*)(o + 4) = make_float4(a2.x, a2.y, a3.x, a3.y);
        }
    }
}

// ---------------- 1x1 conv -> d_out in (B,D,N) ----------------
#define C1_SMEM ((128*128 + 32*132) * 4)

__global__ __launch_bounds__(256) void conv1x1(const float* __restrict__ ow,
                                               const float* __restrict__ ob,
                                               float* __restrict__ out) {
    extern __shared__ float sm[];
    float* ws = sm;             // [128][128]
    float* as = sm + 16384;     // [32][132]
    const int b = blockIdx.y, n0 = blockIdx.x * 32, t = threadIdx.x;

    for (int f = t; f < 4096; f += 256) ((float4*)ws)[f] = ((const float4*)ow)[f];
    for (int f = t; f < 1024; f += 256) {
        int r = f >> 5, c = f & 31;
        *(float4*)(as + r*132 + c*4) =
            *(const float4*)(g_a + (size_t)(b*N_ + n0 + r)*D_ + c*4);
    }
    __syncthreads();

    const int rg = t >> 4, cg = t & 15;
    const int o0 = rg*8, nA = cg*2;
    float acc[8][2];
#pragma unroll
    for (int u = 0; u < 8; u++) { acc[u][0] = 0.f; acc[u][1] = 0.f; }

    for (int i4 = 0; i4 < 32; i4++) {
        float4 a0 = *(const float4*)(as + nA*132 + i4*4);
        float4 a1 = *(const float4*)(as + (nA+1)*132 + i4*4);
#pragma unroll
        for (int rr = 0; rr < 8; rr++) {
            float4 w = *(const float4*)(ws + (o0+rr)*128 + i4*4);
            acc[rr][0] = fmaf(w.x, a0.x, acc[rr][0]);
            acc[rr][0] = fmaf(w.y, a0.y, acc[rr][0]);
            acc[rr][0] = fmaf(w.z, a0.z, acc[rr][0]);
            acc[rr][0] = fmaf(w.w, a0.w, acc[rr][0]);
            acc[rr][1] = fmaf(w.x, a1.x, acc[rr][1]);
            acc[rr][1] = fmaf(w.y, a1.y, acc[rr][1]);
            acc[rr][1] = fmaf(w.z, a1.z, acc[rr][1]);
            acc[rr][1] = fmaf(w.w, a1.w, acc[rr][1]);
        }
    }
#pragma unroll
    for (int rr = 0; rr < 8; rr++) {
        float bo = ob[o0 + rr];
        float* p = out + (size_t)(b*D_ + o0 + rr)*N_ + n0 + nA;
        p[0] = acc[rr][0] + bo;
        p[1] = acc[rr][1] + bo;
    }
}

// ---------------- BatchNorm ----------------
__global__ void bn_stats(const float* __restrict__ y, const float* __restrict__ gamma,
                         const float* __restrict__ beta) {
    int d = blockIdx.x, t = threadIdx.x;
    double s = 0.0, s2 = 0.0;
    for (int b = 0; b < B_; b++) {
        const float* p = y + (size_t)(b*D_ + d) * N_;
        for (int n = t; n < N_; n += 256) { double v = p[n]; s += v; s2 += v*v; }
    }
    __shared__ double sh[512];
    sh[t] = s; sh[256 + t] = s2;
    __syncthreads();
    for (int o = 128; o > 0; o >>= 1) {
        if (t < o) { sh[t] += sh[t+o]; sh[256+t] += sh[256+t+o]; }
        __syncthreads();
    }
    if (t == 0) {
        double cnt = (double)B_ * (double)N_;
        double m = sh[0] / cnt;
        double var = sh[256] / cnt - m*m;
        double rs = rsqrt(var + 1e-5);
        double sc = rs * (double)gamma[d];
        g_scale[d] = (float)sc;
        g_shift[d] = (float)((double)beta[d] - m*sc);
    }
}

__global__ void bn_apply(float* __restrict__ y) {
    int i = (blockIdx.x * 256 + threadIdx.x) * 4;
    int d = (i >> 13) & 127;
    float sc = g_scale[d], sh = g_shift[d];
    float4 v = *(float4*)(y + i);
    v.x = v.x*sc + sh; v.y = v.y*sc + sh; v.z = v.z*sc + sh; v.w = v.w*sc + sh;
    *(float4*)(y + i) = v;
}

// ---------------- launch ----------------
extern "C" void kernel_launch(void* const* d_in, const int* in_sizes, int n_in,
                              void* d_out, int out_size) {
    const float* x  = (const float*)d_in[0];
    const float* qw = (const float*)d_in[1];
    const float* qb = (const float*)d_in[2];
    const float* kw = (const float*)d_in[3];
    const float* kb = (const float*)d_in[4];
    const float* vw = (const float*)d_in[5];
    const float* vb = (const float*)d_in[6];
    const float* ow = (const float*)d_in[7];
    const float* ob = (const float*)d_in[8];
    const float* gamma = (const float*)d_in[9];
    const float* beta  = (const float*)d_in[10];
    float* out = (float*)d_out;

    cudaFuncSetAttribute(qkv_conv, cudaFuncAttributeMaxDynamicSharedMemorySize, QKV_SMEM);
    cudaFuncSetAttribute(attn_kernel, cudaFuncAttributeMaxDynamicSharedMemorySize, ATTN_SMEM);
    cudaFuncSetAttribute(conv1x1, cudaFuncAttributeMaxDynamicSharedMemorySize, C1_SMEM);

    prep_weights<<<(D_*5*D_ + 255) / 256, 256>>>(qw, kw, vw);
    prep_trig<<<(N_*64 + 255) / 256, 256>>>();
    qkv_conv<<<dim3(N_/QT, B_), 256, QKV_SMEM>>>(x, qb, kb, vb);
    attn_kernel<<<dim3(NW_, B_), 256, ATTN_SMEM>>>();
    conv1x1<<<dim3(N_/32, B_), 256, C1_SMEM>>>(ow, ob, out);
    bn_stats<<<D_, 256>>>(out, gamma, beta);
    bn_apply<<<(B_*D_*N_) / 1024, 256>>>(out);
}

// round 4
// speedup vs baseline: 1.1131x; 1.1131x over previous
#include <cuda_runtime.h>
#include <math.h>

#define B_ 16
#define D_ 128
#define N_ 8192
#define NW_ 64
#define QT 32          // n-positions per qkv block
#define XC 36          // x tile cols (QT + 4)

typedef unsigned long long ull;

// ---------------- device scratch ----------------
__device__ ull g_wq2[D_*5*D_];   // [(i*5+t)*D + d] = (w,w) packed broadcast
__device__ ull g_wk2[D_*5*D_];
__device__ ull g_wv2[D_*5*D_];
__device__ float g_cs[N_*64];
__device__ float g_sn[N_*64];
__device__ float g_q[B_*N_*D_];  // (B,N,D) rotary+scaled
__device__ float g_k[B_*N_*D_];
__device__ float g_v[B_*N_*D_];
__device__ float g_a[B_*N_*D_];
__device__ float g_scale[D_];
__device__ float g_shift[D_];

// ---------------- f32x2 helpers ----------------
__device__ __forceinline__ void fma2(ull& acc, ull a, ull b) {
    asm("fma.rn.f32x2 %0, %1, %2, %0;" : "+l"(acc) : "l"(a), "l"(b));
}
__device__ __forceinline__ ull bcast2(float v) {
    ull r; asm("mov.b64 %0, {%1, %1};" : "=l"(r) : "f"(v)); return r;
}
__device__ __forceinline__ ull pack2(float a, float b) {
    ull r; asm("mov.b64 %0, {%1, %2};" : "=l"(r) : "f"(a), "f"(b)); return r;
}
__device__ __forceinline__ float2 unpack2(ull p) {
    float2 r; asm("mov.b64 {%0, %1}, %2;" : "=f"(r.x), "=f"(r.y) : "l"(p)); return r;
}

// ---------------- prep ----------------
__global__ void prep_weights(const float* __restrict__ qw, const float* __restrict__ kw,
                             const float* __restrict__ vw) {
    int e = blockIdx.x * blockDim.x + threadIdx.x;
    if (e >= D_*5*D_) return;
    int o = e % D_, r = e / D_;           // r = i*5 + t
    int src = o * (D_*5) + r;
    unsigned bq = __float_as_uint(qw[src]);
    unsigned bk = __float_as_uint(kw[src]);
    unsigned bv = __float_as_uint(vw[src]);
    g_wq2[e] = ((ull)bq << 32) | bq;
    g_wk2[e] = ((ull)bk << 32) | bk;
    g_wv2[e] = ((ull)bv << 32) | bv;
}

__global__ void prep_trig() {
    __shared__ float invf_s[64];
    int t = threadIdx.x;
    if (t < 64) {
        double invf = pow(10000.0, -((double)(2*t)) / 128.0);
        invf_s[t] = (float)invf;          // same numerics as before
    }
    __syncthreads();
    int e = blockIdx.x * 256 + t;
    int n = e >> 6, f = e & 63;
    float ang = (float)n * invf_s[f];     // match JAX fp32 angle rounding
    double s, c;
    sincos((double)ang, &s, &c);
    g_cs[e] = (float)c;
    g_sn[e] = (float)s;
}

// ---------- fused QKV causal conv + bias + rotary + scale ----------
#define QKV_SMEM (128*XC*4 + 128*XC*8)   // raw floats + packed pairs = 55296 B

__global__ __launch_bounds__(256, 2) void qkv_conv(const float* __restrict__ x,
                                                   const float* __restrict__ qb,
                                                   const float* __restrict__ kb,
                                                   const float* __restrict__ vb) {
    extern __shared__ char smraw[];
    float* xs = (float*)smraw;                    // [128][XC]
    ull*   xp = (ull*)(smraw + 128*XC*4);         // [128][XC] pairs (35 used)
    const int b = blockIdx.y, n0 = blockIdx.x * QT;
    const int t = threadIdx.x;
    const int d = t & 127, h = t >> 7;            // h = n-half (16 each)

    // load raw x tile (coalesced)
    {
        int warp = t >> 5, lane = t & 31;
        for (int r = warp; r < 128; r += 8) {
            const float* xr = x + (size_t)(b*D_ + r) * N_;
            for (int c = lane; c < XC; c += 32) {
                int n = n0 - 4 + c;
                xs[r*XC + c] = (n >= 0) ? xr[n] : 0.0f;
            }
        }
    }
    __syncthreads();
    // overlapping pairs (x[c], x[c+1]), c = 0..34
    for (int idx = t; idx < 128*35; idx += 256) {
        int r = idx / 35, c = idx % 35;
        xp[r*XC + c] = pack2(xs[r*XC + c], xs[r*XC + c + 1]);
    }
    __syncthreads();

    ull aq[8], ak[8], av[8];
#pragma unroll
    for (int j = 0; j < 8; j++) { aq[j] = 0ULL; ak[j] = 0ULL; av[j] = 0ULL; }

    const ull* prow = xp + h*16;
    for (int i = 0; i < 128; i++, prow += XC) {
        ull wq[5], wk[5], wv[5];
#pragma unroll
        for (int tt = 0; tt < 5; tt++) {
            int wi = (i*5 + tt)*D_ + d;
            wq[tt] = __ldg(&g_wq2[wi]);
            wk[tt] = __ldg(&g_wk2[wi]);
            wv[tt] = __ldg(&g_wv2[wi]);
        }
#pragma unroll
        for (int jp = 0; jp < 8; jp++) {
#pragma unroll
            for (int tt = 0; tt < 5; tt++) {
                ull px = prow[2*jp + tt];        // warp-uniform broadcast LDS.64
                fma2(aq[jp], wq[tt], px);
                fma2(ak[jp], wk[tt], px);
                fma2(av[jp], wv[tt], px);
            }
        }
    }
    __syncthreads();

    // exchange q,k via smem for rotary cross-channel pairing
    float* qsm = (float*)smraw;            // [QT][128]
    float* ksm = qsm + QT*128;             // [QT][128]
    float bqv = qb[d], bkv = kb[d];
#pragma unroll
    for (int jp = 0; jp < 8; jp++) {
        int j = h*16 + 2*jp;
        float2 q2 = unpack2(aq[jp]);
        float2 k2 = unpack2(ak[jp]);
        qsm[j*128 + d]     = q2.x + bqv;
        qsm[(j+1)*128 + d] = q2.y + bqv;
        ksm[j*128 + d]     = k2.x + bkv;
        ksm[(j+1)*128 + d] = k2.y + bkv;
    }
    __syncthreads();

    const float scl = 0.08838834764831845f;   // 128^-0.5
    const int dp = (d + 64) & 127;
    const float sg = (d < 64) ? -1.0f : 1.0f;
    const int f = d & 63;
    const float bvv = vb[d];
#pragma unroll
    for (int jp = 0; jp < 8; jp++) {
        float2 v2 = unpack2(av[jp]);
#pragma unroll
        for (int u = 0; u < 2; u++) {
            int j = h*16 + 2*jp + u;
            int n = n0 + j;
            float cc = g_cs[n*64 + f], ss = g_sn[n*64 + f];
            float qv = qsm[j*128 + d],      kv = ksm[j*128 + d];
            float qh = sg * qsm[j*128 + dp], kh = sg * ksm[j*128 + dp];
            size_t o = (size_t)(b*N_ + n) * 128 + d;
            g_q[o] = (qv*cc + qh*ss) * scl;
            g_k[o] = kv*cc + kh*ss;
            g_v[o] = ((u == 0) ? v2.x : v2.y) + bvv;
        }
    }
}

// ---------------- windowed causal attention (R3, kept) ----------------
#define SS 260
#define ATTN_SMEM ((16384 + 128*SS + 8192) * 4)

__global__ __launch_bounds__(256) void attn_kernel() {
    extern __shared__ float sm[];
    float* qs = sm;                  // [128][128]
    float* S  = sm + 16384;          // [128][260]
    float* kb = S + 128*SS;          // k chunk [64][128] swizzled / v chunk [32][128]

    const int wi = blockIdx.x, b = blockIdx.y;
    const int n0 = wi * 128, t = threadIdx.x;

    for (int fI = t; fI < 4096; fI += 256) {
        int r = fI >> 5, c4 = fI & 31;
        *(float4*)(qs + r*128 + c4*4) =
            *(const float4*)(g_q + (size_t)(b*N_ + n0 + r)*D_ + c4*4);
    }

    // ---- S = q @ k^T : 4 chunks of 64 key rows, f32x2 over d ----
    {
        const int rg = t >> 4, cg = t & 15;
        const int r0 = rg * 8;
        for (int ch = 0; ch < 4; ch++) {
            __syncthreads();
            for (int fI = t; fI < 2048; fI += 256) {
                int r = fI >> 5, c4 = fI & 31;
                int nk = n0 - 128 + ch*64 + r;
                float4 v = make_float4(0.f, 0.f, 0.f, 0.f);
                if (nk >= 0) v = *(const float4*)(g_k + (size_t)(b*N_ + nk)*D_ + c4*4);
                *(float4*)(kb + r*128 + ((c4 ^ (r & 7)) * 4)) = v;   // XOR swizzle
            }
            __syncthreads();

            ull acc[8][4];
#pragma unroll
            for (int u0 = 0; u0 < 8; u0++)
#pragma unroll
                for (int u1 = 0; u1 < 4; u1++) acc[u0][u1] = 0ULL;

            for (int d4 = 0; d4 < 32; d4++) {
                ulonglong2 q2[8];
#pragma unroll
                for (int rr = 0; rr < 8; rr++)
                    q2[rr] = *(const ulonglong2*)(qs + (r0+rr)*128 + d4*4);
#pragma unroll
                for (int u = 0; u < 4; u++) {
                    int kr = cg + 16*u;
                    ulonglong2 k2 = *(const ulonglong2*)(kb + kr*128 + ((d4 ^ (kr & 7)) * 4));
#pragma unroll
                    for (int rr = 0; rr < 8; rr++) {
                        fma2(acc[rr][u], q2[rr].x, k2.x);
                        fma2(acc[rr][u], q2[rr].y, k2.y);
                    }
                }
            }
#pragma unroll
            for (int rr = 0; rr < 8; rr++)
#pragma unroll
                for (int u = 0; u < 4; u++) {
                    float2 p = unpack2(acc[rr][u]);
                    S[(r0+rr)*SS + ch*64 + cg + 16*u] = p.x + p.y;
                }
        }
    }
    __syncthreads();

    // ---- masked softmax: row i valid cols [jstart, 128+i] ----
    if (t < 128) {
        float* row = S + t*SS;
        int jstart = (wi == 0) ? 128 : 0;
        int jend = 128 + t + 1;
        float m = -3.402823466e38f;
        for (int j = jstart; j < jend; j++) m = fmaxf(m, row[j]);
        float s = 0.f;
        for (int j = jstart; j < jend; j++) { float e = __expf(row[j] - m); row[j] = e; s += e; }
        float inv = 1.0f / s;
        for (int j = 0; j < jstart; j++) row[j] = 0.f;
        for (int j = jstart; j < jend; j++) row[j] *= inv;
        for (int j = jend; j < 256; j++) row[j] = 0.f;
    }

    // ---- OUT = P @ V : 8 chunks of 32 rows, f32x2 over output cols ----
    {
        const int rg = t >> 4, cg = t & 15;
        const int r0 = rg*8, c0 = cg*8;
        ull acc[8][4];
#pragma unroll
        for (int u0 = 0; u0 < 8; u0++)
#pragma unroll
            for (int u1 = 0; u1 < 4; u1++) acc[u0][u1] = 0ULL;

        for (int ch = 0; ch < 8; ch++) {
            __syncthreads();
            for (int fI = t; fI < 1024; fI += 256) {
                int r = fI >> 5, c4 = fI & 31;
                int nk = n0 - 128 + ch*32 + r;
                float4 v = make_float4(0.f, 0.f, 0.f, 0.f);
                if (nk >= 0) v = *(const float4*)(g_v + (size_t)(b*N_ + nk)*D_ + c4*4);
                *(float4*)(kb + r*128 + c4*4) = v;
            }
            __syncthreads();
            for (int k4 = 0; k4 < 8; k4++) {
                float4 p4[8];
#pragma unroll
                for (int rr = 0; rr < 8; rr++)
                    p4[rr] = *(const float4*)(S + (r0+rr)*SS + ch*32 + k4*4);
#pragma unroll
                for (int j = 0; j < 4; j++) {
                    ulonglong2 va  = *(const ulonglong2*)(kb + (k4*4+j)*128 + c0);
                    ulonglong2 vb2 = *(const ulonglong2*)(kb + (k4*4+j)*128 + c0 + 4);
#pragma unroll
                    for (int rr = 0; rr < 8; rr++) {
                        float pv = (j==0)?p4[rr].x:(j==1)?p4[rr].y:(j==2)?p4[rr].z:p4[rr].w;
                        ull pb = bcast2(pv);
                        fma2(acc[rr][0], pb, va.x);
                        fma2(acc[rr][1], pb, va.y);
                        fma2(acc[rr][2], pb, vb2.x);
                        fma2(acc[rr][3], pb, vb2.y);
                    }
                }
            }
        }
#pragma unroll
        for (int rr = 0; rr < 8; rr++) {
            float2 a0 = unpack2(acc[rr][0]), a1 = unpack2(acc[rr][1]);
            float2 a2 = unpack2(acc[rr][2]), a3 = unpack2(acc[rr][3]);
            float* o = g_a + (size_t)(b*N_ + n0 + r0 + rr)*D_ + c0;
            *(float4*)(o)     = make_float4(a0.x, a0.y, a1.x, a1.y);
            *(float4*)(o + 4) = make_float4(a2.x, a2.y, a3.x, a3.y);
        }
    }
}

// ---------------- 1x1 conv -> d_out in (B,D,N) ----------------
#define C1_SMEM ((128*128 + 32*132) * 4)

__global__ __launch_bounds__(256) void conv1x1(const float* __restrict__ ow,
                                               const float* __restrict__ ob,
                                               float* __restrict__ out) {
    extern __shared__ float sm[];
    float* ws = sm;             // [128][128]
    float* as = sm + 16384;     // [32][132]
    const int b = blockIdx.y, n0 = blockIdx.x * 32, t = threadIdx.x;

    for (int f = t; f < 4096; f += 256) ((float4*)ws)[f] = ((const float4*)ow)[f];
    for (int f = t; f < 1024; f += 256) {
        int r = f >> 5, c = f & 31;
        *(float4*)(as + r*132 + c*4) =
            *(const float4*)(g_a + (size_t)(b*N_ + n0 + r)*D_ + c*4);
    }
    __syncthreads();

    const int rg = t >> 4, cg = t & 15;
    const int o0 = rg*8, nA = cg*2;
    float acc[8][2];
#pragma unroll
    for (int u = 0; u < 8; u++) { acc[u][0] = 0.f; acc[u][1] = 0.f; }

    for (int i4 = 0; i4 < 32; i4++) {
        float4 a0 = *(const float4*)(as + nA*132 + i4*4);
        float4 a1 = *(const float4*)(as + (nA+1)*132 + i4*4);
#pragma unroll
        for (int rr = 0; rr < 8; rr++) {
            float4 w = *(const float4*)(ws + (o0+rr)*128 + i4*4);
            acc[rr][0] = fmaf(w.x, a0.x, acc[rr][0]);
            acc[rr][0] = fmaf(w.y, a0.y, acc[rr][0]);
            acc[rr][0] = fmaf(w.z, a0.z, acc[rr][0]);
            acc[rr][0] = fmaf(w.w, a0.w, acc[rr][0]);
            acc[rr][1] = fmaf(w.x, a1.x, acc[rr][1]);
            acc[rr][1] = fmaf(w.y, a1.y, acc[rr][1]);
            acc[rr][1] = fmaf(w.z, a1.z, acc[rr][1]);
            acc[rr][1] = fmaf(w.w, a1.w, acc[rr][1]);
        }
    }
#pragma unroll
    for (int rr = 0; rr < 8; rr++) {
        float bo = ob[o0 + rr];
        float* p = out + (size_t)(b*D_ + o0 + rr)*N_ + n0 + nA;
        p[0] = acc[rr][0] + bo;
        p[1] = acc[rr][1] + bo;
    }
}

// ---------------- BatchNorm ----------------
__global__ void bn_stats(const float* __restrict__ y, const float* __restrict__ gamma,
                         const float* __restrict__ beta) {
    int d = blockIdx.x, t = threadIdx.x;
    double s = 0.0, s2 = 0.0;
    for (int b = 0; b < B_; b++) {
        const float* p = y + (size_t)(b*D_ + d) * N_;
        for (int n = t; n < N_; n += 256) { double v = p[n]; s += v; s2 += v*v; }
    }
    __shared__ double sh[512];
    sh[t] = s; sh[256 + t] = s2;
    __syncthreads();
    for (int o = 128; o > 0; o >>= 1) {
        if (t < o) { sh[t] += sh[t+o]; sh[256+t] += sh[256+t+o]; }
        __syncthreads();
    }
    if (t == 0) {
        double cnt = (double)B_ * (double)N_;
        double m = sh[0] / cnt;
        double var = sh[256] / cnt - m*m;
        double rs = rsqrt(var + 1e-5);
        double sc = rs * (double)gamma[d];
        g_scale[d] = (float)sc;
        g_shift[d] = (float)((double)beta[d] - m*sc);
    }
}

__global__ void bn_apply(float* __restrict__ y) {
    int i = (blockIdx.x * 256 + threadIdx.x) * 4;
    int d = (i >> 13) & 127;
    float sc = g_scale[d], sh = g_shift[d];
    float4 v = *(float4*)(y + i);
    v.x = v.x*sc + sh; v.y = v.y*sc + sh; v.z = v.z*sc + sh; v.w = v.w*sc + sh;
    *(float4*)(y + i) = v;
}

// ---------------- launch ----------------
extern "C" void kernel_launch(void* const* d_in, const int* in_sizes, int n_in,
                              void* d_out, int out_size) {
    const float* x  = (const float*)d_in[0];
    const float* qw = (const float*)d_in[1];
    const float* qb = (const float*)d_in[2];
    const float* kw = (const float*)d_in[3];
    const float* kb = (const float*)d_in[4];
    const float* vw = (const float*)d_in[5];
    const float* vb = (const float*)d_in[6];
    const float* ow = (const float*)d_in[7];
    const float* ob = (const float*)d_in[8];
    const float* gamma = (const float*)d_in[9];
    const float* beta  = (const float*)d_in[10];
    float* out = (float*)d_out;

    cudaFuncSetAttribute(qkv_conv, cudaFuncAttributeMaxDynamicSharedMemorySize, QKV_SMEM);
    cudaFuncSetAttribute(attn_kernel, cudaFuncAttributeMaxDynamicSharedMemorySize, ATTN_SMEM);
    cudaFuncSetAttribute(conv1x1, cudaFuncAttributeMaxDynamicSharedMemorySize, C1_SMEM);

    prep_weights<<<(D_*5*D_ + 255) / 256, 256>>>(qw, kw, vw);
    prep_trig<<<(N_*64) / 256, 256>>>();
    qkv_conv<<<dim3(N_/QT, B_), 256, QKV_SMEM>>>(x, qb, kb, vb);
    attn_kernel<<<dim3(NW_, B_), 256, ATTN_SMEM>>>();
    conv1x1<<<dim3(N_/32, B_), 256, C1_SMEM>>>(ow, ob, out);
    bn_stats<<<D_, 256>>>(out, gamma, beta);
    bn_apply<<<(B_*D_*N_) / 1024, 256>>>(out);
}

// round 5
// speedup vs baseline: 1.5675x; 1.4083x over previous
#include <cuda_runtime.h>
#include <cuda_bf16.h>
#include <math.h>

#define B_ 16
#define D_ 128
#define N_ 8192
#define NW_ 64

typedef unsigned long long ull;
typedef unsigned int u32;

// ---------------- device scratch ----------------
// split weights: [conv 3][ichunk 8][plane 2][tap 5][o 128][ii 16] bf16
__device__ __align__(16) __nv_bfloat16 g_wsp[3*8*2*5*128*16];
__device__ float g_cs[N_*64];
__device__ float g_sn[N_*64];
__device__ float g_q[B_*N_*D_];  // (B,N,D) rotary+scaled
__device__ float g_k[B_*N_*D_];
__device__ float g_v[B_*N_*D_];
__device__ float g_a[B_*N_*D_];
__device__ float g_scale[D_];
__device__ float g_shift[D_];

// ---------------- f32x2 helpers (attn) ----------------
__device__ __forceinline__ void fma2(ull& acc, ull a, ull b) {
    asm("fma.rn.f32x2 %0, %1, %2, %0;" : "+l"(acc) : "l"(a), "l"(b));
}
__device__ __forceinline__ ull bcast2(float v) {
    ull r; asm("mov.b64 %0, {%1, %1};" : "=l"(r) : "f"(v)); return r;
}
__device__ __forceinline__ float2 unpack2(ull p) {
    float2 r; asm("mov.b64 {%0, %1}, %2;" : "=f"(r.x), "=f"(r.y) : "l"(p)); return r;
}

// ---------------- mma helpers ----------------
__device__ __forceinline__ void mma16816(float* c, const u32* a, u32 b0, u32 b1) {
    asm("mma.sync.aligned.m16n8k16.row.col.f32.bf16.bf16.f32 "
        "{%0,%1,%2,%3}, {%4,%5,%6,%7}, {%8,%9}, {%0,%1,%2,%3};"
        : "+f"(c[0]), "+f"(c[1]), "+f"(c[2]), "+f"(c[3])
        : "r"(a[0]), "r"(a[1]), "r"(a[2]), "r"(a[3]), "r"(b0), "r"(b1));
}
__device__ __forceinline__ void ldmat4(u32* r, u32 addr) {
    asm volatile("ldmatrix.sync.aligned.m8n8.x4.shared.b16 {%0,%1,%2,%3}, [%4];"
                 : "=r"(r[0]), "=r"(r[1]), "=r"(r[2]), "=r"(r[3]) : "r"(addr));
}

// ---------------- prep: split weights to bf16 hi/lo ----------------
__global__ void prep_wsplit(const float* __restrict__ qw, const float* __restrict__ kw,
                            const float* __restrict__ vw) {
    int e = blockIdx.x * blockDim.x + threadIdx.x;
    if (e >= 3*8*5*128*16) return;
    int ii = e % 16;
    int o  = (e / 16) % 128;
    int t  = (e / 2048) % 5;
    int ch = (e / 10240) % 8;
    int c  = e / 81920;
    const float* w = (c == 0) ? qw : (c == 1) ? kw : vw;
    float v = w[o*640 + (ch*16 + ii)*5 + t];
    __nv_bfloat16 hi = __float2bfloat16(v);
    __nv_bfloat16 lo = __float2bfloat16(v - __bfloat162float(hi));
    int base = (c*8 + ch) * 20480;                   // per (c,ch) block
    int off  = t*2048 + o*16 + ii;
    g_wsp[base + off]         = hi;                  // plane 0
    g_wsp[base + 10240 + off] = lo;                  // plane 1
}

__global__ void prep_trig() {
    __shared__ float invf_s[64];
    int t = threadIdx.x;
    if (t < 64) invf_s[t] = (float)pow(10000.0, -((double)(2*t)) / 128.0);
    __syncthreads();
    int e = blockIdx.x * 256 + t;
    int n = e >> 6, f = e & 63;
    float ang = (float)n * invf_s[f];     // match JAX fp32 angle rounding
    double s, c;
    sincos((double)ang, &s, &c);
    g_cs[e] = (float)c;
    g_sn[e] = (float)s;
}

// ---------- tensor-core fused QKV conv + bias + rotary + scale ----------
// smem layout (bytes):
#define XH_OFF 0            // [132 rows][136 cols] bf16 = 35904
#define XL_OFF 35904
#define W_OFF  71808        // 2 planes x 20480 B = 40960
#define KSM_OFF 112768      // [128][132] fp32 = 67584
#define QKV_TC_SMEM 180352  // total
// qsm overlays XH/XL region ([128][132] fp32 = 67584 <= 71808)
#define XSTR 136

__global__ __launch_bounds__(256) void qkv_tc(const float* __restrict__ x,
                                              const float* __restrict__ qb,
                                              const float* __restrict__ kb,
                                              const float* __restrict__ vb) {
    extern __shared__ char smem[];
    __nv_bfloat16* xh = (__nv_bfloat16*)(smem + XH_OFF);
    __nv_bfloat16* xl = (__nv_bfloat16*)(smem + XL_OFF);
    float* ksm = (float*)(smem + KSM_OFF);
    float* qsm = (float*)(smem + XH_OFF);

    const int b = blockIdx.y, n0 = blockIdx.x * 128;
    const int t = threadIdx.x;
    const int lane = t & 31, wid = t >> 5;
    const int warpM = wid >> 2, warpN = wid & 3;     // 2 x 4 warps
    const int mbase = warpM * 64, nbase = warpN * 32;

    // ---- load x tile transposed + split ----
    for (int idx = t; idx < 128*132; idx += 256) {
        int i = idx / 132, c = idx % 132;
        int n = n0 - 4 + c;
        float v = (n >= 0) ? x[(size_t)(b*D_ + i)*N_ + n] : 0.0f;
        __nv_bfloat16 hi = __float2bfloat16(v);
        xh[c*XSTR + i] = hi;
        xl[c*XSTR + i] = __float2bfloat16(v - __bfloat162float(hi));
    }
    __syncthreads();

    const u32 xh_s = (u32)__cvta_generic_to_shared(xh);
    const u32 xl_s = (u32)__cvta_generic_to_shared(xl);
    const int rl = lane & 15, cl8 = (lane >> 4) * 8;

    // conv order: v(2), k(1), q(0)
#pragma unroll 1
    for (int cl = 0; cl < 3; cl++) {
        const int c = (cl == 0) ? 2 : (cl == 1) ? 1 : 0;
        float acc[4][4][4];
#pragma unroll
        for (int mt = 0; mt < 4; mt++)
#pragma unroll
            for (int nt = 0; nt < 4; nt++)
#pragma unroll
                for (int u = 0; u < 4; u++) acc[mt][nt][u] = 0.0f;

#pragma unroll 1
        for (int ch = 0; ch < 8; ch++) {
            __syncthreads();
            {   // load W chunk (both planes, contiguous 40960 B)
                const float4* src = (const float4*)(g_wsp + (size_t)(c*8 + ch) * 20480);
                float4* dst = (float4*)(smem + W_OFF);
#pragma unroll
                for (int k2 = 0; k2 < 10; k2++) dst[t + k2*256] = src[t + k2*256];
            }
            __syncthreads();

#pragma unroll 1
            for (int tap = 0; tap < 5; tap++) {
                u32 ah[4][4], al[4][4];
#pragma unroll
                for (int mt = 0; mt < 4; mt++) {
                    int row = mbase + mt*16 + rl + tap;
                    int col = ch*16 + cl8;
                    u32 off = (u32)(row*XSTR + col) * 2;
                    ldmat4(ah[mt], xh_s + off);
                    ldmat4(al[mt], xl_s + off);
                }
#pragma unroll
                for (int prod = 0; prod < 3; prod++) {
                    const u32 (*asel)[4] = (prod == 2) ? al : ah;
                    int pl = (prod == 1) ? 1 : 0;
                    const char* wb = smem + W_OFF + pl*20480 + tap*4096;
#pragma unroll
                    for (int nt = 0; nt < 4; nt++) {
                        int o = nbase + nt*8 + (lane >> 2);
                        int k0 = (lane & 3) * 2;
                        const char* bp = wb + (o*16 + k0) * 2;
                        u32 b0 = *(const u32*)bp;
                        u32 b1 = *(const u32*)(bp + 16);
#pragma unroll
                        for (int mt = 0; mt < 4; mt++)
                            mma16816(acc[mt][nt], asel[mt], b0, b1);
                    }
                }
            }
        }

        // ---- epilogue per conv ----
        if (cl == 0) {            // v: direct to global with bias
#pragma unroll
            for (int mt = 0; mt < 4; mt++)
#pragma unroll
                for (int nt = 0; nt < 4; nt++) {
                    int row = mbase + mt*16 + (lane >> 2);
                    int col = nbase + nt*8 + (lane & 3)*2;
                    float b0 = vb[col], b1 = vb[col+1];
                    float* p0 = g_v + (size_t)(b*N_ + n0 + row)*D_ + col;
                    float* p1 = g_v + (size_t)(b*N_ + n0 + row + 8)*D_ + col;
                    *(float2*)p0 = make_float2(acc[mt][nt][0] + b0, acc[mt][nt][1] + b1);
                    *(float2*)p1 = make_float2(acc[mt][nt][2] + b0, acc[mt][nt][3] + b1);
                }
        } else if (cl == 1) {     // k -> ksm with bias
#pragma unroll
            for (int mt = 0; mt < 4; mt++)
#pragma unroll
                for (int nt = 0; nt < 4; nt++) {
                    int row = mbase + mt*16 + (lane >> 2);
                    int col = nbase + nt*8 + (lane & 3)*2;
                    float b0 = kb[col], b1 = kb[col+1];
                    ksm[row*132 + col]       = acc[mt][nt][0] + b0;
                    ksm[row*132 + col + 1]   = acc[mt][nt][1] + b1;
                    ksm[(row+8)*132 + col]   = acc[mt][nt][2] + b0;
                    ksm[(row+8)*132 + col+1] = acc[mt][nt][3] + b1;
                }
        } else {                  // q -> qsm (overlays x; sync first)
            __syncthreads();
#pragma unroll
            for (int mt = 0; mt < 4; mt++)
#pragma unroll
                for (int nt = 0; nt < 4; nt++) {
                    int row = mbase + mt*16 + (lane >> 2);
                    int col = nbase + nt*8 + (lane & 3)*2;
                    float b0 = qb[col], b1 = qb[col+1];
                    qsm[row*132 + col]       = acc[mt][nt][0] + b0;
                    qsm[row*132 + col + 1]   = acc[mt][nt][1] + b1;
                    qsm[(row+8)*132 + col]   = acc[mt][nt][2] + b0;
                    qsm[(row+8)*132 + col+1] = acc[mt][nt][3] + b1;
                }
        }
    }
    __syncthreads();

    // ---- rotary + scale -> g_q, g_k ----
    const float scl = 0.08838834764831845f;   // 128^-0.5
    const int d = t & 127, h = t >> 7;
    const int dp = (d + 64) & 127;
    const float sg = (d < 64) ? -1.0f : 1.0f;
    const int f = d & 63;
    for (int j = h; j < 128; j += 2) {
        int n = n0 + j;
        float cc = g_cs[n*64 + f], ss = g_sn[n*64 + f];
        float qv = qsm[j*132 + d], qh2 = sg * qsm[j*132 + dp];
        float kv = ksm[j*132 + d], kh2 = sg * ksm[j*132 + dp];
        size_t o = (size_t)(b*N_ + n)*128 + d;
        g_q[o] = (qv*cc + qh2*ss) * scl;
        g_k[o] = kv*cc + kh2*ss;
    }
}

// ---------------- windowed causal attention (R3, kept) ----------------
#define SS 260
#define ATTN_SMEM ((16384 + 128*SS + 8192) * 4)

__global__ __launch_bounds__(256) void attn_kernel() {
    extern __shared__ float sm[];
    float* qs = sm;                  // [128][128]
    float* S  = sm + 16384;          // [128][260]
    float* kb = S + 128*SS;          // k chunk [64][128] swizzled / v chunk [32][128]

    const int wi = blockIdx.x, b = blockIdx.y;
    const int n0 = wi * 128, t = threadIdx.x;

    for (int fI = t; fI < 4096; fI += 256) {
        int r = fI >> 5, c4 = fI & 31;
        *(float4*)(qs + r*128 + c4*4) =
            *(const float4*)(g_q + (size_t)(b*N_ + n0 + r)*D_ + c4*4);
    }

    {
        const int rg = t >> 4, cg = t & 15;
        const int r0 = rg * 8;
        for (int ch = 0; ch < 4; ch++) {
            __syncthreads();
            for (int fI = t; fI < 2048; fI += 256) {
                int r = fI >> 5, c4 = fI & 31;
                int nk = n0 - 128 + ch*64 + r;
                float4 v = make_float4(0.f, 0.f, 0.f, 0.f);
                if (nk >= 0) v = *(const float4*)(g_k + (size_t)(b*N_ + nk)*D_ + c4*4);
                *(float4*)(kb + r*128 + ((c4 ^ (r & 7)) * 4)) = v;
            }
            __syncthreads();

            ull acc[8][4];
#pragma unroll
            for (int u0 = 0; u0 < 8; u0++)
#pragma unroll
                for (int u1 = 0; u1 < 4; u1++) acc[u0][u1] = 0ULL;

            for (int d4 = 0; d4 < 32; d4++) {
                ulonglong2 q2[8];
#pragma unroll
                for (int rr = 0; rr < 8; rr++)
                    q2[rr] = *(const ulonglong2*)(qs + (r0+rr)*128 + d4*4);
#pragma unroll
                for (int u = 0; u < 4; u++) {
                    int kr = cg + 16*u;
                    ulonglong2 k2 = *(const ulonglong2*)(kb + kr*128 + ((d4 ^ (kr & 7)) * 4));
#pragma unroll
                    for (int rr = 0; rr < 8; rr++) {
                        fma2(acc[rr][u], q2[rr].x, k2.x);
                        fma2(acc[rr][u], q2[rr].y, k2.y);
                    }
                }
            }
#pragma unroll
            for (int rr = 0; rr < 8; rr++)
#pragma unroll
                for (int u = 0; u < 4; u++) {
                    float2 p = unpack2(acc[rr][u]);
                    S[(r0+rr)*SS + ch*64 + cg + 16*u] = p.x + p.y;
                }
        }
    }
    __syncthreads();

    if (t < 128) {
        float* row = S + t*SS;
        int jstart = (wi == 0) ? 128 : 0;
        int jend = 128 + t + 1;
        float m = -3.402823466e38f;
        for (int j = jstart; j < jend; j++) m = fmaxf(m, row[j]);
        float s = 0.f;
        for (int j = jstart; j < jend; j++) { float e = __expf(row[j] - m); row[j] = e; s += e; }
        float inv = 1.0f / s;
        for (int j = 0; j < jstart; j++) row[j] = 0.f;
        for (int j = jstart; j < jend; j++) row[j] *= inv;
        for (int j = jend; j < 256; j++) row[j] = 0.f;
    }

    {
        const int rg = t >> 4, cg = t & 15;
        const int r0 = rg*8, c0 = cg*8;
        ull acc[8][4];
#pragma unroll
        for (int u0 = 0; u0 < 8; u0++)
#pragma unroll
            for (int u1 = 0; u1 < 4; u1++) acc[u0][u1] = 0ULL;

        for (int ch = 0; ch < 8; ch++) {
            __syncthreads();
            for (int fI = t; fI < 1024; fI += 256) {
                int r = fI >> 5, c4 = fI & 31;
                int nk = n0 - 128 + ch*32 + r;
                float4 v = make_float4(0.f, 0.f, 0.f, 0.f);
                if (nk >= 0) v = *(const float4*)(g_v + (size_t)(b*N_ + nk)*D_ + c4*4);
                *(float4*)(kb + r*128 + c4*4) = v;
            }
            __syncthreads();
            for (int k4 = 0; k4 < 8; k4++) {
                float4 p4[8];
#pragma unroll
                for (int rr = 0; rr < 8; rr++)
                    p4[rr] = *(const float4*)(S + (r0+rr)*SS + ch*32 + k4*4);
#pragma unroll
                for (int j = 0; j < 4; j++) {
                    ulonglong2 va  = *(const ulonglong2*)(kb + (k4*4+j)*128 + c0);
                    ulonglong2 vb2 = *(const ulonglong2*)(kb + (k4*4+j)*128 + c0 + 4);
#pragma unroll
                    for (int rr = 0; rr < 8; rr++) {
                        float pv = (j==0)?p4[rr].x:(j==1)?p4[rr].y:(j==2)?p4[rr].z:p4[rr].w;
                        ull pb = bcast2(pv);
                        fma2(acc[rr][0], pb, va.x);
                        fma2(acc[rr][1], pb, va.y);
                        fma2(acc[rr][2], pb, vb2.x);
                        fma2(acc[rr][3], pb, vb2.y);
                    }
                }
            }
        }
#pragma unroll
        for (int rr = 0; rr < 8; rr++) {
            float2 a0 = unpack2(acc[rr][0]), a1 = unpack2(acc[rr][1]);
            float2 a2 = unpack2(acc[rr][2]), a3 = unpack2(acc[rr][3]);
            float* o = g_a + (size_t)(b*N_ + n0 + r0 + rr)*D_ + c0;
            *(float4*)(o)     = make_float4(a0.x, a0.y, a1.x, a1.y);
            *(float4*)(o + 4) = make_float4(a2.x, a2.y, a3.x, a3.y);
        }
    }
}

// ---------------- 1x1 conv -> d_out in (B,D,N) ----------------
#define C1_SMEM ((128*128 + 32*132) * 4)

__global__ __launch_bounds__(256) void conv1x1(const float* __restrict__ ow,
                                               const float* __restrict__ ob,
                                               float* __restrict__ out) {
    extern __shared__ float sm[];
    float* ws = sm;             // [128][128]
    float* as = sm + 16384;     // [32][132]
    const int b = blockIdx.y, n0 = blockIdx.x * 32, t = threadIdx.x;

    for (int f = t; f < 4096; f += 256) ((float4*)ws)[f] = ((const float4*)ow)[f];
    for (int f = t; f < 1024; f += 256) {
        int r = f >> 5, c = f & 31;
        *(float4*)(as + r*132 + c*4) =
            *(const float4*)(g_a + (size_t)(b*N_ + n0 + r)*D_ + c*4);
    }
    __syncthreads();

    const int rg = t >> 4, cg = t & 15;
    const int o0 = rg*8, nA = cg*2;
    float acc[8][2];
#pragma unroll
    for (int u = 0; u < 8; u++) { acc[u][0] = 0.f; acc[u][1] = 0.f; }

    for (int i4 = 0; i4 < 32; i4++) {
        float4 a0 = *(const float4*)(as + nA*132 + i4*4);
        float4 a1 = *(const float4*)(as + (nA+1)*132 + i4*4);
#pragma unroll
        for (int rr = 0; rr < 8; rr++) {
            float4 w = *(const float4*)(ws + (o0+rr)*128 + i4*4);
            acc[rr][0] = fmaf(w.x, a0.x, acc[rr][0]);
            acc[rr][0] = fmaf(w.y, a0.y, acc[rr][0]);
            acc[rr][0] = fmaf(w.z, a0.z, acc[rr][0]);
            acc[rr][0] = fmaf(w.w, a0.w, acc[rr][0]);
            acc[rr][1] = fmaf(w.x, a1.x, acc[rr][1]);
            acc[rr][1] = fmaf(w.y, a1.y, acc[rr][1]);
            acc[rr][1] = fmaf(w.z, a1.z, acc[rr][1]);
            acc[rr][1] = fmaf(w.w, a1.w, acc[rr][1]);
        }
    }
#pragma unroll
    for (int rr = 0; rr < 8; rr++) {
        float bo = ob[o0 + rr];
        float* p = out + (size_t)(b*D_ + o0 + rr)*N_ + n0 + nA;
        p[0] = acc[rr][0] + bo;
        p[1] = acc[rr][1] + bo;
    }
}

// ---------------- BatchNorm ----------------
__global__ void bn_stats(const float* __restrict__ y, const float* __restrict__ gamma,
                         const float* __restrict__ beta) {
    int d = blockIdx.x, t = threadIdx.x;
    double s = 0.0, s2 = 0.0;
    for (int b = 0; b < B_; b++) {
        const float* p = y + (size_t)(b*D_ + d) * N_;
        for (int n = t; n < N_; n += 256) { double v = p[n]; s += v; s2 += v*v; }
    }
    __shared__ double sh[512];
    sh[t] = s; sh[256 + t] = s2;
    __syncthreads();
    for (int o = 128; o > 0; o >>= 1) {
        if (t < o) { sh[t] += sh[t+o]; sh[256+t] += sh[256+t+o]; }
        __syncthreads();
    }
    if (t == 0) {
        double cnt = (double)B_ * (double)N_;
        double m = sh[0] / cnt;
        double var = sh[256] / cnt - m*m;
        double rs = rsqrt(var + 1e-5);
        double sc = rs * (double)gamma[d];
        g_scale[d] = (float)sc;
        g_shift[d] = (float)((double)beta[d] - m*sc);
    }
}

__global__ void bn_apply(float* __restrict__ y) {
    int i = (blockIdx.x * 256 + threadIdx.x) * 4;
    int d = (i >> 13) & 127;
    float sc = g_scale[d], sh = g_shift[d];
    float4 v = *(float4*)(y + i);
    v.x = v.x*sc + sh; v.y = v.y*sc + sh; v.z = v.z*sc + sh; v.w = v.w*sc + sh;
    *(float4*)(y + i) = v;
}

// ---------------- launch ----------------
extern "C" void kernel_launch(void* const* d_in, const int* in_sizes, int n_in,
                              void* d_out, int out_size) {
    const float* x  = (const float*)d_in[0];
    const float* qw = (const float*)d_in[1];
    const float* qb = (const float*)d_in[2];
    const float* kw = (const float*)d_in[3];
    const float* kb = (const float*)d_in[4];
    const float* vw = (const float*)d_in[5];
    const float* vb = (const float*)d_in[6];
    const float* ow = (const float*)d_in[7];
    const float* ob = (const float*)d_in[8];
    const float* gamma = (const float*)d_in[9];
    const float* beta  = (const float*)d_in[10];
    float* out = (float*)d_out;

    cudaFuncSetAttribute(qkv_tc, cudaFuncAttributeMaxDynamicSharedMemorySize, QKV_TC_SMEM);
    cudaFuncSetAttribute(attn_kernel, cudaFuncAttributeMaxDynamicSharedMemorySize, ATTN_SMEM);
    cudaFuncSetAttribute(conv1x1, cudaFuncAttributeMaxDynamicSharedMemorySize, C1_SMEM);

    prep_wsplit<<<(3*8*5*128*16 + 255) / 256, 256>>>(qw, kw, vw);
    prep_trig<<<(N_*64) / 256, 256>>>();
    qkv_tc<<<dim3(N_/128, B_), 256, QKV_TC_SMEM>>>(x, qb, kb, vb);
    attn_kernel<<<dim3(NW_, B_), 256, ATTN_SMEM>>>();
    conv1x1<<<dim3(N_/32, B_), 256, C1_SMEM>>>(ow, ob, out);
    bn_stats<<<D_, 256>>>(out, gamma, beta);
    bn_apply<<<(B_*D_*N_) / 1024, 256>>>(out);
}

// round 6
// speedup vs baseline: 1.8053x; 1.1517x over previous
#include <cuda_runtime.h>
#include <cuda_bf16.h>
#include <math.h>

#define B_ 16
#define D_ 128
#define N_ 8192
#define NW_ 64

typedef unsigned long long ull;
typedef unsigned int u32;
typedef unsigned short u16;

// ---------------- device scratch ----------------
// split weights: [conv 3][ichunk 8][plane 2][tap 5][o 128][ii 16] bf16
__device__ __align__(16) __nv_bfloat16 g_wsp[3*8*2*5*128*16];
__device__ float g_cs[N_*64];
__device__ float g_sn[N_*64];
__device__ __align__(16) __nv_bfloat16 g_qh[B_*N_*D_];   // rotary+scaled, split
__device__ __align__(16) __nv_bfloat16 g_ql[B_*N_*D_];
__device__ __align__(16) __nv_bfloat16 g_kh[B_*N_*D_];   // rotary, split
__device__ __align__(16) __nv_bfloat16 g_kl[B_*N_*D_];
__device__ __align__(16) __nv_bfloat16 g_vh[B_*N_*D_];   // +bias, split
__device__ __align__(16) __nv_bfloat16 g_vl[B_*N_*D_];
__device__ float g_a[B_*N_*D_];
__device__ float g_scale[D_];
__device__ float g_shift[D_];

// ---------------- mma helpers (validated in R5) ----------------
__device__ __forceinline__ void mma16816(float* c, const u32* a, u32 b0, u32 b1) {
    asm("mma.sync.aligned.m16n8k16.row.col.f32.bf16.bf16.f32 "
        "{%0,%1,%2,%3}, {%4,%5,%6,%7}, {%8,%9}, {%0,%1,%2,%3};"
        : "+f"(c[0]), "+f"(c[1]), "+f"(c[2]), "+f"(c[3])
        : "r"(a[0]), "r"(a[1]), "r"(a[2]), "r"(a[3]), "r"(b0), "r"(b1));
}
__device__ __forceinline__ void ldmat4(u32* r, u32 addr) {
    asm volatile("ldmatrix.sync.aligned.m8n8.x4.shared.b16 {%0,%1,%2,%3}, [%4];"
                 : "=r"(r[0]), "=r"(r[1]), "=r"(r[2]), "=r"(r[3]) : "r"(addr));
}
__device__ __forceinline__ u32 packbf(float a, float b) {
    __nv_bfloat162 t = __floats2bfloat162_rn(a, b);
    return *(u32*)&t;
}

// ---------------- prep: split weights to bf16 hi/lo ----------------
__global__ void prep_wsplit(const float* __restrict__ qw, const float* __restrict__ kw,
                            const float* __restrict__ vw) {
    int e = blockIdx.x * blockDim.x + threadIdx.x;
    if (e >= 3*8*5*128*16) return;
    int ii = e % 16;
    int o  = (e / 16) % 128;
    int t  = (e / 2048) % 5;
    int ch = (e / 10240) % 8;
    int c  = e / 81920;
    const float* w = (c == 0) ? qw : (c == 1) ? kw : vw;
    float v = w[o*640 + (ch*16 + ii)*5 + t];
    __nv_bfloat16 hi = __float2bfloat16(v);
    __nv_bfloat16 lo = __float2bfloat16(v - __bfloat162float(hi));
    int base = (c*8 + ch) * 20480;
    int off  = t*2048 + o*16 + ii;
    g_wsp[base + off]         = hi;
    g_wsp[base + 10240 + off] = lo;
}

__global__ void prep_trig() {
    __shared__ float invf_s[64];
    int t = threadIdx.x;
    if (t < 64) invf_s[t] = (float)pow(10000.0, -((double)(2*t)) / 128.0);
    __syncthreads();
    int e = blockIdx.x * 256 + t;
    int n = e >> 6, f = e & 63;
    float ang = (float)n * invf_s[f];
    double s, c;
    sincos((double)ang, &s, &c);
    g_cs[e] = (float)c;
    g_sn[e] = (float)s;
}

// ---------- tensor-core fused QKV conv + bias + rotary + scale + split ----------
#define XH_OFF 0
#define XL_OFF 35904
#define W_OFF  71808
#define KSM_OFF 112768
#define QKV_TC_SMEM 180352
#define XSTR 136

__global__ __launch_bounds__(256) void qkv_tc(const float* __restrict__ x,
                                              const float* __restrict__ qb,
                                              const float* __restrict__ kb,
                                              const float* __restrict__ vb) {
    extern __shared__ char smem[];
    __nv_bfloat16* xh = (__nv_bfloat16*)(smem + XH_OFF);
    __nv_bfloat16* xl = (__nv_bfloat16*)(smem + XL_OFF);
    float* ksm = (float*)(smem + KSM_OFF);
    float* qsm = (float*)(smem + XH_OFF);

    const int b = blockIdx.y, n0 = blockIdx.x * 128;
    const int t = threadIdx.x;
    const int lane = t & 31, wid = t >> 5;
    const int warpM = wid >> 2, warpN = wid & 3;
    const int mbase = warpM * 64, nbase = warpN * 32;

    for (int idx = t; idx < 128*132; idx += 256) {
        int i = idx / 132, c = idx % 132;
        int n = n0 - 4 + c;
        float v = (n >= 0) ? x[(size_t)(b*D_ + i)*N_ + n] : 0.0f;
        __nv_bfloat16 hi = __float2bfloat16(v);
        xh[c*XSTR + i] = hi;
        xl[c*XSTR + i] = __float2bfloat16(v - __bfloat162float(hi));
    }
    __syncthreads();

    const u32 xh_s = (u32)__cvta_generic_to_shared(xh);
    const u32 xl_s = (u32)__cvta_generic_to_shared(xl);
    const int rl = lane & 15, cl8 = (lane >> 4) * 8;

#pragma unroll 1
    for (int cl = 0; cl < 3; cl++) {
        const int c = (cl == 0) ? 2 : (cl == 1) ? 1 : 0;
        float acc[4][4][4];
#pragma unroll
        for (int mt = 0; mt < 4; mt++)
#pragma unroll
            for (int nt = 0; nt < 4; nt++)
#pragma unroll
                for (int u = 0; u < 4; u++) acc[mt][nt][u] = 0.0f;

#pragma unroll 1
        for (int ch = 0; ch < 8; ch++) {
            __syncthreads();
            {
                const float4* src = (const float4*)(g_wsp + (size_t)(c*8 + ch) * 20480);
                float4* dst = (float4*)(smem + W_OFF);
#pragma unroll
                for (int k2 = 0; k2 < 10; k2++) dst[t + k2*256] = src[t + k2*256];
            }
            __syncthreads();

#pragma unroll 1
            for (int tap = 0; tap < 5; tap++) {
                u32 ah[4][4], al[4][4];
#pragma unroll
                for (int mt = 0; mt < 4; mt++) {
                    int row = mbase + mt*16 + rl + tap;
                    int col = ch*16 + cl8;
                    u32 off = (u32)(row*XSTR + col) * 2;
                    ldmat4(ah[mt], xh_s + off);
                    ldmat4(al[mt], xl_s + off);
                }
#pragma unroll
                for (int prod = 0; prod < 3; prod++) {
                    const u32 (*asel)[4] = (prod == 2) ? al : ah;
                    int pl = (prod == 1) ? 1 : 0;
                    const char* wb = smem + W_OFF + pl*20480 + tap*4096;
#pragma unroll
                    for (int nt = 0; nt < 4; nt++) {
                        int o = nbase + nt*8 + (lane >> 2);
                        int k0 = (lane & 3) * 2;
                        const char* bp = wb + (o*16 + k0) * 2;
                        u32 b0 = *(const u32*)bp;
                        u32 b1 = *(const u32*)(bp + 16);
#pragma unroll
                        for (int mt = 0; mt < 4; mt++)
                            mma16816(acc[mt][nt], asel[mt], b0, b1);
                    }
                }
            }
        }

        if (cl == 0) {            // v: split bf16 direct to global with bias
#pragma unroll
            for (int mt = 0; mt < 4; mt++)
#pragma unroll
                for (int nt = 0; nt < 4; nt++) {
                    int row = mbase + mt*16 + (lane >> 2);
                    int col = nbase + nt*8 + (lane & 3)*2;
                    float b0 = vb[col], b1 = vb[col+1];
#pragma unroll
                    for (int half = 0; half < 2; half++) {
                        float v0 = acc[mt][nt][half*2]   + b0;
                        float v1 = acc[mt][nt][half*2+1] + b1;
                        __nv_bfloat16 h0 = __float2bfloat16(v0);
                        __nv_bfloat16 h1 = __float2bfloat16(v1);
                        size_t off = (size_t)(b*N_ + n0 + row + half*8)*D_ + col;
                        *(u32*)(g_vh + off) = packbf(__bfloat162float(h0), __bfloat162float(h1));
                        *(u32*)(g_vl + off) = packbf(v0 - __bfloat162float(h0),
                                                     v1 - __bfloat162float(h1));
                    }
                }
        } else if (cl == 1) {     // k -> ksm fp32 with bias
#pragma unroll
            for (int mt = 0; mt < 4; mt++)
#pragma unroll
                for (int nt = 0; nt < 4; nt++) {
                    int row = mbase + mt*16 + (lane >> 2);
                    int col = nbase + nt*8 + (lane & 3)*2;
                    float b0 = kb[col], b1 = kb[col+1];
                    ksm[row*132 + col]       = acc[mt][nt][0] + b0;
                    ksm[row*132 + col + 1]   = acc[mt][nt][1] + b1;
                    ksm[(row+8)*132 + col]   = acc[mt][nt][2] + b0;
                    ksm[(row+8)*132 + col+1] = acc[mt][nt][3] + b1;
                }
        } else {                  // q -> qsm (overlays x; sync first)
            __syncthreads();
#pragma unroll
            for (int mt = 0; mt < 4; mt++)
#pragma unroll
                for (int nt = 0; nt < 4; nt++) {
                    int row = mbase + mt*16 + (lane >> 2);
                    int col = nbase + nt*8 + (lane & 3)*2;
                    float b0 = qb[col], b1 = qb[col+1];
                    qsm[row*132 + col]       = acc[mt][nt][0] + b0;
                    qsm[row*132 + col + 1]   = acc[mt][nt][1] + b1;
                    qsm[(row+8)*132 + col]   = acc[mt][nt][2] + b0;
                    qsm[(row+8)*132 + col+1] = acc[mt][nt][3] + b1;
                }
        }
    }
    __syncthreads();

    // ---- rotary + scale -> split bf16 globals ----
    const float scl = 0.08838834764831845f;
    const int d = t & 127, h = t >> 7;
    const int dp = (d + 64) & 127;
    const float sg = (d < 64) ? -1.0f : 1.0f;
    const int f = d & 63;
    for (int j = h; j < 128; j += 2) {
        int n = n0 + j;
        float cc = g_cs[n*64 + f], ss = g_sn[n*64 + f];
        float qv = qsm[j*132 + d], qh2 = sg * qsm[j*132 + dp];
        float kv = ksm[j*132 + d], kh2 = sg * ksm[j*132 + dp];
        float qf = (qv*cc + qh2*ss) * scl;
        float kf = kv*cc + kh2*ss;
        size_t o = (size_t)(b*N_ + n)*128 + d;
        __nv_bfloat16 qhi = __float2bfloat16(qf);
        __nv_bfloat16 khi = __float2bfloat16(kf);
        g_qh[o] = qhi; g_ql[o] = __float2bfloat16(qf - __bfloat162float(qhi));
        g_kh[o] = khi; g_kl[o] = __float2bfloat16(kf - __bfloat162float(khi));
    }
}

// ---------------- tensor-core windowed causal attention ----------------
// smem byte offsets
#define AT_QH 0          // [128][136] bf16 = 34816
#define AT_S  34816      // [128][256] fp32 = 131072
#define AT_QL 165888     // [128][136] bf16 (QK phase only)
#define AT_KH 200704     // [32][132] bf16 = 8448
#define AT_KL 209152
#define AT_VH 165888     // PV phase (overlays QL)
#define AT_VL 174336
#define AT_PH 182784     // [128][40] bf16 = 10240
#define AT_PL 193024
#define AT_M  217600     // float[128]
#define AT_I  218112     // float[128]
#define AT_SMEM 218624

__global__ __launch_bounds__(256) void attn_tc() {
    extern __shared__ char sm8[];
    __nv_bfloat16* qhs = (__nv_bfloat16*)(sm8 + AT_QH);
    float*         S   = (float*)(sm8 + AT_S);
    __nv_bfloat16* qls = (__nv_bfloat16*)(sm8 + AT_QL);
    __nv_bfloat16* khs = (__nv_bfloat16*)(sm8 + AT_KH);
    __nv_bfloat16* kls = (__nv_bfloat16*)(sm8 + AT_KL);
    __nv_bfloat16* vhs = (__nv_bfloat16*)(sm8 + AT_VH);
    __nv_bfloat16* vls = (__nv_bfloat16*)(sm8 + AT_VL);
    __nv_bfloat16* phs = (__nv_bfloat16*)(sm8 + AT_PH);
    __nv_bfloat16* pls = (__nv_bfloat16*)(sm8 + AT_PL);
    float* mrow = (float*)(sm8 + AT_M);
    float* irow = (float*)(sm8 + AT_I);

    const int wi = blockIdx.x, b = blockIdx.y;
    const int n0 = wi * 128, t = threadIdx.x;
    const int lane = t & 31, wid = t >> 5;
    const int warpM = wid >> 2, warpN = wid & 3;
    const int mbase = warpM * 64;
    const int rl = lane & 15, cl8 = (lane >> 4) * 8;
    const int g = lane >> 2, tg = lane & 3;
    const int jstart = (wi == 0) ? 128 : 0;

    const u32 qh_s = (u32)__cvta_generic_to_shared(qhs);
    const u32 ql_s = (u32)__cvta_generic_to_shared(qls);
    const u32 ph_s = (u32)__cvta_generic_to_shared(phs);
    const u32 pl_s = (u32)__cvta_generic_to_shared(pls);

    // ---- load q split (u32 = 2 bf16) ----
    for (int idx = t; idx < 4096; idx += 256) {
        int r = idx >> 5, c2 = idx & 31;           // 32 u64? no: 64 u32/row -> use 2 per iter
        // do 2 u32 per iteration: cols [c2*2, c2*2+1]
        const u32* sh = (const u32*)(g_qh + (size_t)(b*N_ + n0 + r)*D_);
        const u32* sl = (const u32*)(g_ql + (size_t)(b*N_ + n0 + r)*D_);
        u32* dh = (u32*)qhs + r*68;
        u32* dl = (u32*)qls + r*68;
        dh[c2*2]   = sh[c2*2];   dh[c2*2+1] = sh[c2*2+1];
        dl[c2*2]   = sl[c2*2];   dl[c2*2+1] = sl[c2*2+1];
    }

    // ==== phase 1: S = q @ k^T, 8 chunks of 32 keys ====
#pragma unroll 1
    for (int ch = 0; ch < 8; ch++) {
        __syncthreads();
        for (int idx = t; idx < 2048; idx += 256) {
            int r = idx >> 6, c2 = idx & 63;
            int nk = n0 - 128 + ch*32 + r;
            u32 hv = 0, lv = 0;
            if (nk >= 0) {
                hv = *(const u32*)(g_kh + (size_t)(b*N_ + nk)*D_ + c2*2);
                lv = *(const u32*)(g_kl + (size_t)(b*N_ + nk)*D_ + c2*2);
            }
            ((u32*)khs)[r*66 + c2] = hv;
            ((u32*)kls)[r*66 + c2] = lv;
        }
        __syncthreads();

        float acc[4][4];
#pragma unroll
        for (int mt = 0; mt < 4; mt++)
#pragma unroll
            for (int u = 0; u < 4; u++) acc[mt][u] = 0.0f;

#pragma unroll 1
        for (int kt = 0; kt < 8; kt++) {
            u32 ah[4][4], al[4][4];
#pragma unroll
            for (int mt = 0; mt < 4; mt++) {
                u32 off = (u32)((mbase + mt*16 + rl)*136 + kt*16 + cl8) * 2;
                ldmat4(ah[mt], qh_s + off);
                ldmat4(al[mt], ql_s + off);
            }
            int n = warpN*8 + g;
            int k0 = kt*16 + tg*2;
            u32 bh0 = *(const u32*)((const char*)khs + (n*132 + k0)*2);
            u32 bh1 = *(const u32*)((const char*)khs + (n*132 + k0 + 8)*2);
            u32 bl0 = *(const u32*)((const char*)kls + (n*132 + k0)*2);
            u32 bl1 = *(const u32*)((const char*)kls + (n*132 + k0 + 8)*2);
#pragma unroll
            for (int mt = 0; mt < 4; mt++) {
                mma16816(acc[mt], ah[mt], bh0, bh1);
                mma16816(acc[mt], al[mt], bh0, bh1);
                mma16816(acc[mt], ah[mt], bl0, bl1);
            }
        }
#pragma unroll
        for (int mt = 0; mt < 4; mt++) {
            int row = mbase + mt*16 + g;
            int col = ch*32 + warpN*8 + tg*2;
            *(float2*)(S + row*256 + col)       = make_float2(acc[mt][0], acc[mt][1]);
            *(float2*)(S + (row+8)*256 + col)   = make_float2(acc[mt][2], acc[mt][3]);
        }
    }
    __syncthreads();

    // ==== phase 2: softmax stats (m, 1/sum) per row; 2 threads/row ====
    {
        int r = t >> 1, half = t & 1;
        int jend = 128 + r + 1;
        float m = -3.402823466e38f;
        for (int c4 = (jstart >> 2) + half; c4*4 < jend; c4 += 2) {
            float4 v = *(const float4*)(S + r*256 + c4*4);
            int c = c4*4;
            if (c   < jend) m = fmaxf(m, v.x);
            if (c+1 < jend) m = fmaxf(m, v.y);
            if (c+2 < jend) m = fmaxf(m, v.z);
            if (c+3 < jend) m = fmaxf(m, v.w);
        }
        m = fmaxf(m, __shfl_xor_sync(0xFFFFFFFF, m, 1));
        float s = 0.0f;
        for (int c4 = (jstart >> 2) + half; c4*4 < jend; c4 += 2) {
            float4 v = *(const float4*)(S + r*256 + c4*4);
            int c = c4*4;
            if (c   < jend) s += __expf(v.x - m);
            if (c+1 < jend) s += __expf(v.y - m);
            if (c+2 < jend) s += __expf(v.z - m);
            if (c+3 < jend) s += __expf(v.w - m);
        }
        s += __shfl_xor_sync(0xFFFFFFFF, s, 1);
        if (half == 0) { mrow[r] = m; irow[r] = 1.0f / s; }
    }

    // ==== phase 3: OUT = P @ V, 8 chunks, accumulate in regs ====
    float accP[4][4][4];
#pragma unroll
    for (int mt = 0; mt < 4; mt++)
#pragma unroll
        for (int nt = 0; nt < 4; nt++)
#pragma unroll
            for (int u = 0; u < 4; u++) accP[mt][nt][u] = 0.0f;

#pragma unroll 1
    for (int ch = 0; ch < 8; ch++) {
        __syncthreads();   // first iter: stats done + last QK reads of ql done
        // load v chunk split
        for (int idx = t; idx < 2048; idx += 256) {
            int r = idx >> 6, c2 = idx & 63;
            int nk = n0 - 128 + ch*32 + r;
            u32 hv = 0, lv = 0;
            if (nk >= 0) {
                hv = *(const u32*)(g_vh + (size_t)(b*N_ + nk)*D_ + c2*2);
                lv = *(const u32*)(g_vl + (size_t)(b*N_ + nk)*D_ + c2*2);
            }
            ((u32*)vhs)[r*66 + c2] = hv;
            ((u32*)vls)[r*66 + c2] = lv;
        }
        // convert P chunk: rows r, 16 cols per thread
        {
            int r = t >> 1, c0l = (t & 1) * 16;
            float mm = mrow[r], ii = irow[r];
            int jend = 128 + r + 1;
#pragma unroll
            for (int i4 = 0; i4 < 4; i4++) {
                float4 s4 = *(const float4*)(S + r*256 + ch*32 + c0l + i4*4);
                float p[4];
                int cg = ch*32 + c0l + i4*4;
                p[0] = (cg   >= jstart && cg   < jend) ? __expf(s4.x - mm) * ii : 0.0f;
                p[1] = (cg+1 >= jstart && cg+1 < jend) ? __expf(s4.y - mm) * ii : 0.0f;
                p[2] = (cg+2 >= jstart && cg+2 < jend) ? __expf(s4.z - mm) * ii : 0.0f;
                p[3] = (cg+3 >= jstart && cg+3 < jend) ? __expf(s4.w - mm) * ii : 0.0f;
                u32 h01, h23, l01, l23;
                {
                    __nv_bfloat16 h0 = __float2bfloat16(p[0]);
                    __nv_bfloat16 h1 = __float2bfloat16(p[1]);
                    __nv_bfloat16 h2 = __float2bfloat16(p[2]);
                    __nv_bfloat16 h3 = __float2bfloat16(p[3]);
                    h01 = packbf(__bfloat162float(h0), __bfloat162float(h1));
                    h23 = packbf(__bfloat162float(h2), __bfloat162float(h3));
                    l01 = packbf(p[0] - __bfloat162float(h0), p[1] - __bfloat162float(h1));
                    l23 = packbf(p[2] - __bfloat162float(h2), p[3] - __bfloat162float(h3));
                }
                int di = (r*40 + c0l + i4*4) >> 1;   // u32 index (even cols)
                ((u32*)phs)[di]   = h01;
                ((u32*)phs)[di+1] = h23;
                ((u32*)pls)[di]   = l01;
                ((u32*)pls)[di+1] = l23;
            }
        }
        __syncthreads();

#pragma unroll
        for (int kt = 0; kt < 2; kt++) {
            u32 pa[4][4], pb[4][4];
#pragma unroll
            for (int mt = 0; mt < 4; mt++) {
                u32 off = (u32)((mbase + mt*16 + rl)*40 + kt*16 + cl8) * 2;
                ldmat4(pa[mt], ph_s + off);
                ldmat4(pb[mt], pl_s + off);
            }
#pragma unroll
            for (int nt = 0; nt < 4; nt++) {
                int n = warpN*32 + nt*8 + g;
                int k0 = kt*16 + tg*2;
                const u16* vhp = (const u16*)vhs;
                const u16* vlp = (const u16*)vls;
                u32 bh0 = vhp[k0*132 + n]     | ((u32)vhp[(k0+1)*132 + n] << 16);
                u32 bh1 = vhp[(k0+8)*132 + n] | ((u32)vhp[(k0+9)*132 + n] << 16);
                u32 bl0 = vlp[k0*132 + n]     | ((u32)vlp[(k0+1)*132 + n] << 16);
                u32 bl1 = vlp[(k0+8)*132 + n] | ((u32)vlp[(k0+9)*132 + n] << 16);
#pragma unroll
                for (int mt = 0; mt < 4; mt++) {
                    mma16816(accP[mt][nt], pa[mt], bh0, bh1);
                    mma16816(accP[mt][nt], pb[mt], bh0, bh1);
                    mma16816(accP[mt][nt], pa[mt], bl0, bl1);
                }
            }
        }
    }

    // ---- epilogue: write g_a fp32 ----
#pragma unroll
    for (int mt = 0; mt < 4; mt++)
#pragma unroll
        for (int nt = 0; nt < 4; nt++) {
            int row = mbase + mt*16 + g;
            int col = warpN*32 + nt*8 + tg*2;
            float* o0 = g_a + (size_t)(b*N_ + n0 + row)*D_ + col;
            float* o1 = g_a + (size_t)(b*N_ + n0 + row + 8)*D_ + col;
            *(float2*)o0 = make_float2(accP[mt][nt][0], accP[mt][nt][1]);
            *(float2*)o1 = make_float2(accP[mt][nt][2], accP[mt][nt][3]);
        }
}

// ---------------- 1x1 conv -> d_out in (B,D,N) ----------------
#define C1_SMEM ((128*128 + 32*132) * 4)

__global__ __launch_bounds__(256) void conv1x1(const float* __restrict__ ow,
                                               const float* __restrict__ ob,
                                               float* __restrict__ out) {
    extern __shared__ float sm[];
    float* ws = sm;
    float* as = sm + 16384;
    const int b = blockIdx.y, n0 = blockIdx.x * 32, t = threadIdx.x;

    for (int f = t; f < 4096; f += 256) ((float4*)ws)[f] = ((const float4*)ow)[f];
    for (int f = t; f < 1024; f += 256) {
        int r = f >> 5, c = f & 31;
        *(float4*)(as + r*132 + c*4) =
            *(const float4*)(g_a + (size_t)(b*N_ + n0 + r)*D_ + c*4);
    }
    __syncthreads();

    const int rg = t >> 4, cg = t & 15;
    const int o0 = rg*8, nA = cg*2;
    float acc[8][2];
#pragma unroll
    for (int u = 0; u < 8; u++) { acc[u][0] = 0.f; acc[u][1] = 0.f; }

    for (int i4 = 0; i4 < 32; i4++) {
        float4 a0 = *(const float4*)(as + nA*132 + i4*4);
        float4 a1 = *(const float4*)(as + (nA+1)*132 + i4*4);
#pragma unroll
        for (int rr = 0; rr < 8; rr++) {
            float4 w = *(const float4*)(ws + (o0+rr)*128 + i4*4);
            acc[rr][0] = fmaf(w.x, a0.x, acc[rr][0]);
            acc[rr][0] = fmaf(w.y, a0.y, acc[rr][0]);
            acc[rr][0] = fmaf(w.z, a0.z, acc[rr][0]);
            acc[rr][0] = fmaf(w.w, a0.w, acc[rr][0]);
            acc[rr][1] = fmaf(w.x, a1.x, acc[rr][1]);
            acc[rr][1] = fmaf(w.y, a1.y, acc[rr][1]);
            acc[rr][1] = fmaf(w.z, a1.z, acc[rr][1]);
            acc[rr][1] = fmaf(w.w, a1.w, acc[rr][1]);
        }
    }
#pragma unroll
    for (int rr = 0; rr < 8; rr++) {
        float bo = ob[o0 + rr];
        float* p = out + (size_t)(b*D_ + o0 + rr)*N_ + n0 + nA;
        p[0] = acc[rr][0] + bo;
        p[1] = acc[rr][1] + bo;
    }
}

// ---------------- BatchNorm ----------------
__global__ void bn_stats(const float* __restrict__ y, const float* __restrict__ gamma,
                         const float* __restrict__ beta) {
    int d = blockIdx.x, t = threadIdx.x;
    double s = 0.0, s2 = 0.0;
    for (int b = 0; b < B_; b++) {
        const float* p = y + (size_t)(b*D_ + d) * N_;
        for (int n = t; n < N_; n += 256) { double v = p[n]; s += v; s2 += v*v; }
    }
    __shared__ double sh[512];
    sh[t] = s; sh[256 + t] = s2;
    __syncthreads();
    for (int o = 128; o > 0; o >>= 1) {
        if (t < o) { sh[t] += sh[t+o]; sh[256+t] += sh[256+t+o]; }
        __syncthreads();
    }
    if (t == 0) {
        double cnt = (double)B_ * (double)N_;
        double m = sh[0] / cnt;
        double var = sh[256] / cnt - m*m;
        double rs = rsqrt(var + 1e-5);
        double sc = rs * (double)gamma[d];
        g_scale[d] = (float)sc;
        g_shift[d] = (float)((double)beta[d] - m*sc);
    }
}

__global__ void bn_apply(float* __restrict__ y) {
    int i = (blockIdx.x * 256 + threadIdx.x) * 4;
    int d = (i >> 13) & 127;
    float sc = g_scale[d], sh = g_shift[d];
    float4 v = *(float4*)(y + i);
    v.x = v.x*sc + sh; v.y = v.y*sc + sh; v.z = v.z*sc + sh; v.w = v.w*sc + sh;
    *(float4*)(y + i) = v;
}

// ---------------- launch ----------------
extern "C" void kernel_launch(void* const* d_in, const int* in_sizes, int n_in,
                              void* d_out, int out_size) {
    const float* x  = (const float*)d_in[0];
    const float* qw = (const float*)d_in[1];
    const float* qb = (const float*)d_in[2];
    const float* kw = (const float*)d_in[3];
    const float* kb = (const float*)d_in[4];
    const float* vw = (const float*)d_in[5];
    const float* vb = (const float*)d_in[6];
    const float* ow = (const float*)d_in[7];
    const float* ob = (const float*)d_in[8];
    const float* gamma = (const float*)d_in[9];
    const float* beta  = (const float*)d_in[10];
    float* out = (float*)d_out;

    cudaFuncSetAttribute(qkv_tc, cudaFuncAttributeMaxDynamicSharedMemorySize, QKV_TC_SMEM);
    cudaFuncSetAttribute(attn_tc, cudaFuncAttributeMaxDynamicSharedMemorySize, AT_SMEM);
    cudaFuncSetAttribute(conv1x1, cudaFuncAttributeMaxDynamicSharedMemorySize, C1_SMEM);

    prep_wsplit<<<(3*8*5*128*16 + 255) / 256, 256>>>(qw, kw, vw);
    prep_trig<<<(N_*64) / 256, 256>>>();
    qkv_tc<<<dim3(N_/128, B_), 256, QKV_TC_SMEM>>>(x, qb, kb, vb);
    attn_tc<<<dim3(NW_, B_), 256, AT_SMEM>>>();
    conv1x1<<<dim3(N_/32, B_), 256, C1_SMEM>>>(ow, ob, out);
    bn_stats<<<D_, 256>>>(out, gamma, beta);
    bn_apply<<<(B_*D_*N_) / 1024, 256>>>(out);
}

// round 7
// speedup vs baseline: 1.8616x; 1.0312x over previous
#include <cuda_runtime.h>
#include <cuda_bf16.h>
#include <math.h>

#define B_ 16
#define D_ 128
#define N_ 8192
#define NW_ 64

typedef unsigned long long ull;
typedef unsigned int u32;
typedef unsigned short u16;

// ---------------- device scratch ----------------
__device__ __align__(16) __nv_bfloat16 g_wsp[3*8*2*5*128*16];
__device__ float g_cs[N_*64];
__device__ float g_sn[N_*64];
__device__ __align__(16) __nv_bfloat16 g_qh[B_*N_*D_];   // (B,N,D) rotary+scaled
__device__ __align__(16) __nv_bfloat16 g_ql[B_*N_*D_];
__device__ __align__(16) __nv_bfloat16 g_kh[B_*N_*D_];   // (B,N,D) rotary
__device__ __align__(16) __nv_bfloat16 g_kl[B_*N_*D_];
__device__ __align__(16) __nv_bfloat16 g_vh[B_*D_*N_];   // (B,D,N) TRANSPOSED
__device__ __align__(16) __nv_bfloat16 g_vl[B_*D_*N_];
__device__ float g_a[B_*N_*D_];
__device__ float g_scale[D_];
__device__ float g_shift[D_];

// ---------------- mma helpers ----------------
__device__ __forceinline__ void mma16816(float* c, const u32* a, u32 b0, u32 b1) {
    asm("mma.sync.aligned.m16n8k16.row.col.f32.bf16.bf16.f32 "
        "{%0,%1,%2,%3}, {%4,%5,%6,%7}, {%8,%9}, {%0,%1,%2,%3};"
        : "+f"(c[0]), "+f"(c[1]), "+f"(c[2]), "+f"(c[3])
        : "r"(a[0]), "r"(a[1]), "r"(a[2]), "r"(a[3]), "r"(b0), "r"(b1));
}
__device__ __forceinline__ void ldmat4(u32* r, u32 addr) {
    asm volatile("ldmatrix.sync.aligned.m8n8.x4.shared.b16 {%0,%1,%2,%3}, [%4];"
                 : "=r"(r[0]), "=r"(r[1]), "=r"(r[2]), "=r"(r[3]) : "r"(addr));
}
__device__ __forceinline__ void ldmat2(u32* r, u32 addr) {
    asm volatile("ldmatrix.sync.aligned.m8n8.x2.shared.b16 {%0,%1}, [%2];"
                 : "=r"(r[0]), "=r"(r[1]) : "r"(addr));
}
__device__ __forceinline__ u32 packbf(float a, float b) {
    __nv_bfloat162 t = __floats2bfloat162_rn(a, b);
    return *(u32*)&t;
}

// ---------------- prep ----------------
__global__ void prep_wsplit(const float* __restrict__ qw, const float* __restrict__ kw,
                            const float* __restrict__ vw) {
    int e = blockIdx.x * blockDim.x + threadIdx.x;
    if (e >= 3*8*5*128*16) return;
    int ii = e % 16;
    int o  = (e / 16) % 128;
    int t  = (e / 2048) % 5;
    int ch = (e / 10240) % 8;
    int c  = e / 81920;
    const float* w = (c == 0) ? qw : (c == 1) ? kw : vw;
    float v = w[o*640 + (ch*16 + ii)*5 + t];
    __nv_bfloat16 hi = __float2bfloat16(v);
    __nv_bfloat16 lo = __float2bfloat16(v - __bfloat162float(hi));
    int base = (c*8 + ch) * 20480;
    int off  = t*2048 + o*16 + ii;
    g_wsp[base + off]         = hi;
    g_wsp[base + 10240 + off] = lo;
}

__global__ void prep_trig() {
    __shared__ float invf_s[64];
    int t = threadIdx.x;
    if (t < 64) invf_s[t] = (float)pow(10000.0, -((double)(2*t)) / 128.0);
    __syncthreads();
    int e = blockIdx.x * 256 + t;
    int n = e >> 6, f = e & 63;
    float ang = (float)n * invf_s[f];
    double s, c;
    sincos((double)ang, &s, &c);
    g_cs[e] = (float)c;
    g_sn[e] = (float)s;
}

// ---------- tensor-core fused QKV conv (512 threads) ----------
#define XH_OFF 0
#define XL_OFF 35904
#define W_OFF  71808
#define KSM_OFF 112768
#define QKV_TC_SMEM 180352
#define XSTR 136

__global__ __launch_bounds__(512) void qkv_tc(const float* __restrict__ x,
                                              const float* __restrict__ qb,
                                              const float* __restrict__ kb,
                                              const float* __restrict__ vb) {
    extern __shared__ char smem[];
    __nv_bfloat16* xh = (__nv_bfloat16*)(smem + XH_OFF);
    __nv_bfloat16* xl = (__nv_bfloat16*)(smem + XL_OFF);
    float* ksm = (float*)(smem + KSM_OFF);
    float* qsm = (float*)(smem + XH_OFF);

    const int b = blockIdx.y, n0 = blockIdx.x * 128;
    const int t = threadIdx.x;
    const int lane = t & 31, wid = t >> 5;
    const int warpM = wid >> 2, warpN = wid & 3;   // 4 x 4 warps
    const int mbase = warpM * 32, nbase = warpN * 32;

    for (int idx = t; idx < 128*132; idx += 512) {
        int i = idx / 132, c = idx % 132;
        int n = n0 - 4 + c;
        float v = (n >= 0) ? x[(size_t)(b*D_ + i)*N_ + n] : 0.0f;
        __nv_bfloat16 hi = __float2bfloat16(v);
        xh[c*XSTR + i] = hi;
        xl[c*XSTR + i] = __float2bfloat16(v - __bfloat162float(hi));
    }
    __syncthreads();

    const u32 xh_s = (u32)__cvta_generic_to_shared(xh);
    const u32 xl_s = (u32)__cvta_generic_to_shared(xl);
    const int rl = lane & 15, cl8 = (lane >> 4) * 8;

#pragma unroll 1
    for (int cl = 0; cl < 3; cl++) {
        const int c = (cl == 0) ? 2 : (cl == 1) ? 1 : 0;
        float acc[2][4][4];
#pragma unroll
        for (int mt = 0; mt < 2; mt++)
#pragma unroll
            for (int nt = 0; nt < 4; nt++)
#pragma unroll
                for (int u = 0; u < 4; u++) acc[mt][nt][u] = 0.0f;

#pragma unroll 1
        for (int ch = 0; ch < 8; ch++) {
            __syncthreads();
            {
                const float4* src = (const float4*)(g_wsp + (size_t)(c*8 + ch) * 20480);
                float4* dst = (float4*)(smem + W_OFF);
#pragma unroll
                for (int k2 = 0; k2 < 5; k2++) dst[t + k2*512] = src[t + k2*512];
            }
            __syncthreads();

#pragma unroll 1
            for (int tap = 0; tap < 5; tap++) {
                u32 ah[2][4], al[2][4];
#pragma unroll
                for (int mt = 0; mt < 2; mt++) {
                    int row = mbase + mt*16 + rl + tap;
                    int col = ch*16 + cl8;
                    u32 off = (u32)(row*XSTR + col) * 2;
                    ldmat4(ah[mt], xh_s + off);
                    ldmat4(al[mt], xl_s + off);
                }
#pragma unroll
                for (int prod = 0; prod < 3; prod++) {
                    const u32 (*asel)[4] = (prod == 2) ? al : ah;
                    int pl = (prod == 1) ? 1 : 0;
                    const char* wb = smem + W_OFF + pl*20480 + tap*4096;
#pragma unroll
                    for (int nt = 0; nt < 4; nt++) {
                        int o = nbase + nt*8 + (lane >> 2);
                        int k0 = (lane & 3) * 2;
                        const char* bp = wb + (o*16 + k0) * 2;
                        u32 b0 = *(const u32*)bp;
                        u32 b1 = *(const u32*)(bp + 16);
#pragma unroll
                        for (int mt = 0; mt < 2; mt++)
                            mma16816(acc[mt][nt], asel[mt], b0, b1);
                    }
                }
            }
        }

        if (cl == 0) {            // v: split bf16 -> TRANSPOSED global (B,D,N)
#pragma unroll
            for (int mt = 0; mt < 2; mt++)
#pragma unroll
                for (int nt = 0; nt < 4; nt++) {
                    int row = mbase + mt*16 + (lane >> 2);
                    int col = nbase + nt*8 + (lane & 3)*2;
#pragma unroll
                    for (int u = 0; u < 4; u++) {
                        int dd  = col + (u & 1);
                        int tok = n0 + row + (u >> 1)*8;
                        float vv = acc[mt][nt][u] + vb[dd];
                        __nv_bfloat16 h = __float2bfloat16(vv);
                        size_t off = (size_t)(b*D_ + dd)*N_ + tok;
                        g_vh[off] = h;
                        g_vl[off] = __float2bfloat16(vv - __bfloat162float(h));
                    }
                }
        } else if (cl == 1) {     // k -> ksm fp32 with bias
#pragma unroll
            for (int mt = 0; mt < 2; mt++)
#pragma unroll
                for (int nt = 0; nt < 4; nt++) {
                    int row = mbase + mt*16 + (lane >> 2);
                    int col = nbase + nt*8 + (lane & 3)*2;
                    float b0 = kb[col], b1 = kb[col+1];
                    ksm[row*132 + col]       = acc[mt][nt][0] + b0;
                    ksm[row*132 + col + 1]   = acc[mt][nt][1] + b1;
                    ksm[(row+8)*132 + col]   = acc[mt][nt][2] + b0;
                    ksm[(row+8)*132 + col+1] = acc[mt][nt][3] + b1;
                }
        } else {                  // q -> qsm (overlays x)
            __syncthreads();
#pragma unroll
            for (int mt = 0; mt < 2; mt++)
#pragma unroll
                for (int nt = 0; nt < 4; nt++) {
                    int row = mbase + mt*16 + (lane >> 2);
                    int col = nbase + nt*8 + (lane & 3)*2;
                    float b0 = qb[col], b1 = qb[col+1];
                    qsm[row*132 + col]       = acc[mt][nt][0] + b0;
                    qsm[row*132 + col + 1]   = acc[mt][nt][1] + b1;
                    qsm[(row+8)*132 + col]   = acc[mt][nt][2] + b0;
                    qsm[(row+8)*132 + col+1] = acc[mt][nt][3] + b1;
                }
        }
    }
    __syncthreads();

    // ---- rotary + scale -> split bf16 globals ----
    const float scl = 0.08838834764831845f;
    const int d = t & 127, h = t >> 7;
    const int dp = (d + 64) & 127;
    const float sg = (d < 64) ? -1.0f : 1.0f;
    const int f = d & 63;
    for (int j = h; j < 128; j += 4) {
        int n = n0 + j;
        float cc = g_cs[n*64 + f], ss = g_sn[n*64 + f];
        float qv = qsm[j*132 + d], qh2 = sg * qsm[j*132 + dp];
        float kv = ksm[j*132 + d], kh2 = sg * ksm[j*132 + dp];
        float qf = (qv*cc + qh2*ss) * scl;
        float kf = kv*cc + kh2*ss;
        size_t o = (size_t)(b*N_ + n)*128 + d;
        __nv_bfloat16 qhi = __float2bfloat16(qf);
        __nv_bfloat16 khi = __float2bfloat16(kf);
        g_qh[o] = qhi; g_ql[o] = __float2bfloat16(qf - __bfloat162float(qhi));
        g_kh[o] = khi; g_kl[o] = __float2bfloat16(kf - __bfloat162float(khi));
    }
}

// ---------------- tensor-core windowed attention (512 threads) ----------------
#define AT_QH 0          // [128][136] bf16 = 34816
#define AT_S  34816      // [128][256] fp32 -> ends 165888
#define AT_QL 165888     // [128][136] bf16 (QK phase)
#define AT_KH 200704     // [32][136] bf16 = 8704
#define AT_KL 209408     // ends 218112
#define AT_VH 165888     // PV: [128][40] bf16 = 10240 (overlays QL)
#define AT_VL 176128
#define AT_PH 186368     // [128][40]
#define AT_PL 196608     // ends 206848 (overlays KH, dead)
#define AT_M  218112
#define AT_I  218624
#define AT_SMEM 219136

__global__ __launch_bounds__(512) void attn_tc() {
    extern __shared__ char sm8[];
    __nv_bfloat16* qhs = (__nv_bfloat16*)(sm8 + AT_QH);
    float*         S   = (float*)(sm8 + AT_S);
    __nv_bfloat16* qls = (__nv_bfloat16*)(sm8 + AT_QL);
    __nv_bfloat16* khs = (__nv_bfloat16*)(sm8 + AT_KH);
    __nv_bfloat16* kls = (__nv_bfloat16*)(sm8 + AT_KL);
    __nv_bfloat16* vhs = (__nv_bfloat16*)(sm8 + AT_VH);
    __nv_bfloat16* vls = (__nv_bfloat16*)(sm8 + AT_VL);
    __nv_bfloat16* phs = (__nv_bfloat16*)(sm8 + AT_PH);
    __nv_bfloat16* pls = (__nv_bfloat16*)(sm8 + AT_PL);
    float* mrow = (float*)(sm8 + AT_M);
    float* irow = (float*)(sm8 + AT_I);

    const int wi = blockIdx.x, b = blockIdx.y;
    const int n0 = wi * 128, t = threadIdx.x;
    const int lane = t & 31, wid = t >> 5;
    const int warpM = wid >> 2, warpN = wid & 3;    // 4 x 4
    const int mbase = warpM * 32;
    const int rl = lane & 15, cl8 = (lane >> 4) * 8;
    const int g = lane >> 2, tg = lane & 3;
    const int l7 = lane & 7, l8 = (lane >> 3) & 1;
    const int jstart = (wi == 0) ? 128 : 0;

    const u32 qh_s = (u32)__cvta_generic_to_shared(qhs);
    const u32 ql_s = (u32)__cvta_generic_to_shared(qls);
    const u32 kh_s = (u32)__cvta_generic_to_shared(khs);
    const u32 kl_s = (u32)__cvta_generic_to_shared(kls);
    const u32 vh_s = (u32)__cvta_generic_to_shared(vhs);
    const u32 vl_s = (u32)__cvta_generic_to_shared(vls);
    const u32 ph_s = (u32)__cvta_generic_to_shared(phs);
    const u32 pl_s = (u32)__cvta_generic_to_shared(pls);

    // ---- load q split ----
    for (int idx = t; idx < 8192; idx += 512) {
        int r = idx >> 6, c = idx & 63;
        ((u32*)qhs)[r*68 + c] = ((const u32*)(g_qh + (size_t)(b*N_ + n0 + r)*D_))[c];
        ((u32*)qls)[r*68 + c] = ((const u32*)(g_ql + (size_t)(b*N_ + n0 + r)*D_))[c];
    }

    // ==== phase 1: S = q @ k^T, 8 chunks of 32 keys ====
#pragma unroll 1
    for (int ch = 0; ch < 8; ch++) {
        __syncthreads();
        for (int idx = t; idx < 2048; idx += 512) {
            int r = idx >> 6, c2 = idx & 63;
            int nk = n0 - 128 + ch*32 + r;
            u32 hv = 0, lv = 0;
            if (nk >= 0) {
                hv = *(const u32*)(g_kh + (size_t)(b*N_ + nk)*D_ + c2*2);
                lv = *(const u32*)(g_kl + (size_t)(b*N_ + nk)*D_ + c2*2);
            }
            ((u32*)khs)[r*68 + c2] = hv;
            ((u32*)kls)[r*68 + c2] = lv;
        }
        __syncthreads();

        float acc[2][4];
#pragma unroll
        for (int mt = 0; mt < 2; mt++)
#pragma unroll
            for (int u = 0; u < 4; u++) acc[mt][u] = 0.0f;

#pragma unroll 1
        for (int kt = 0; kt < 8; kt++) {
            u32 ah[2][4], al[2][4];
#pragma unroll
            for (int mt = 0; mt < 2; mt++) {
                u32 off = (u32)((mbase + mt*16 + rl)*136 + kt*16 + cl8) * 2;
                ldmat4(ah[mt], qh_s + off);
                ldmat4(al[mt], ql_s + off);
            }
            u32 boff = (u32)((warpN*8 + l7)*136 + kt*16 + l8*8) * 2;
            u32 bh[2], bl[2];
            ldmat2(bh, kh_s + boff);
            ldmat2(bl, kl_s + boff);
#pragma unroll
            for (int mt = 0; mt < 2; mt++) {
                mma16816(acc[mt], ah[mt], bh[0], bh[1]);
                mma16816(acc[mt], al[mt], bh[0], bh[1]);
                mma16816(acc[mt], ah[mt], bl[0], bl[1]);
            }
        }
#pragma unroll
        for (int mt = 0; mt < 2; mt++) {
            int row = mbase + mt*16 + g;
            int col = ch*32 + warpN*8 + tg*2;
            *(float2*)(S + row*256 + col)     = make_float2(acc[mt][0], acc[mt][1]);
            *(float2*)(S + (row+8)*256 + col) = make_float2(acc[mt][2], acc[mt][3]);
        }
    }
    __syncthreads();

    // ==== phase 2: softmax stats, 4 threads/row ====
    {
        int r = t >> 2, q4 = t & 3;
        int jend = 128 + r + 1;
        float m = -3.402823466e38f;
        for (int c4 = (jstart >> 2) + q4; c4*4 < jend; c4 += 4) {
            float4 v = *(const float4*)(S + r*256 + c4*4);
            int c = c4*4;
            if (c   < jend) m = fmaxf(m, v.x);
            if (c+1 < jend) m = fmaxf(m, v.y);
            if (c+2 < jend) m = fmaxf(m, v.z);
            if (c+3 < jend) m = fmaxf(m, v.w);
        }
        m = fmaxf(m, __shfl_xor_sync(0xFFFFFFFF, m, 1));
        m = fmaxf(m, __shfl_xor_sync(0xFFFFFFFF, m, 2));
        float s = 0.0f;
        for (int c4 = (jstart >> 2) + q4; c4*4 < jend; c4 += 4) {
            float4 v = *(const float4*)(S + r*256 + c4*4);
            int c = c4*4;
            if (c   < jend) s += __expf(v.x - m);
            if (c+1 < jend) s += __expf(v.y - m);
            if (c+2 < jend) s += __expf(v.z - m);
            if (c+3 < jend) s += __expf(v.w - m);
        }
        s += __shfl_xor_sync(0xFFFFFFFF, s, 1);
        s += __shfl_xor_sync(0xFFFFFFFF, s, 2);
        if (q4 == 0) { mrow[r] = m; irow[r] = 1.0f / s; }
    }

    // ==== phase 3: OUT = P @ V ====
    float accP[2][4][4];
#pragma unroll
    for (int mt = 0; mt < 2; mt++)
#pragma unroll
        for (int nt = 0; nt < 4; nt++)
#pragma unroll
            for (int u = 0; u < 4; u++) accP[mt][nt][u] = 0.0f;

#pragma unroll 1
    for (int ch = 0; ch < 8; ch++) {
        __syncthreads();
        const int nk0 = n0 - 128 + ch*32;
        // load v chunk transposed-global -> [128 d][40 k]
        for (int idx = t; idx < 2048; idx += 512) {
            int dd = idx >> 4, c = idx & 15;
            int tok = nk0 + c*2;
            u32 hv = 0, lv = 0;
            if (tok >= 0) {
                hv = *(const u32*)(g_vh + (size_t)(b*D_ + dd)*N_ + tok);
                lv = *(const u32*)(g_vl + (size_t)(b*D_ + dd)*N_ + tok);
            }
            *(u32*)((u16*)vhs + dd*40 + c*2) = hv;
            *(u32*)((u16*)vls + dd*40 + c*2) = lv;
        }
        // convert P chunk: r = t>>2, 8 cols each
        {
            int r = t >> 2, c0l = (t & 3) * 8;
            float mm = mrow[r], ii = irow[r];
            int jend = 128 + r + 1;
#pragma unroll
            for (int i4 = 0; i4 < 2; i4++) {
                int cg = ch*32 + c0l + i4*4;
                float4 s4 = *(const float4*)(S + r*256 + cg);
                float p[4];
                p[0] = (cg   >= jstart && cg   < jend) ? __expf(s4.x - mm) * ii : 0.0f;
                p[1] = (cg+1 >= jstart && cg+1 < jend) ? __expf(s4.y - mm) * ii : 0.0f;
                p[2] = (cg+2 >= jstart && cg+2 < jend) ? __expf(s4.z - mm) * ii : 0.0f;
                p[3] = (cg+3 >= jstart && cg+3 < jend) ? __expf(s4.w - mm) * ii : 0.0f;
                __nv_bfloat16 h0 = __float2bfloat16(p[0]);
                __nv_bfloat16 h1 = __float2bfloat16(p[1]);
                __nv_bfloat16 h2 = __float2bfloat16(p[2]);
                __nv_bfloat16 h3 = __float2bfloat16(p[3]);
                int di = (r*40 + c0l + i4*4) >> 1;
                ((u32*)phs)[di]   = packbf(__bfloat162float(h0), __bfloat162float(h1));
                ((u32*)phs)[di+1] = packbf(__bfloat162float(h2), __bfloat162float(h3));
                ((u32*)pls)[di]   = packbf(p[0] - __bfloat162float(h0), p[1] - __bfloat162float(h1));
                ((u32*)pls)[di+1] = packbf(p[2] - __bfloat162float(h2), p[3] - __bfloat162float(h3));
            }
        }
        __syncthreads();

#pragma unroll
        for (int kt = 0; kt < 2; kt++) {
            u32 pa[2][4], pb[2][4];
#pragma unroll
            for (int mt = 0; mt < 2; mt++) {
                u32 off = (u32)((mbase + mt*16 + rl)*40 + kt*16 + cl8) * 2;
                ldmat4(pa[mt], ph_s + off);
                ldmat4(pb[mt], pl_s + off);
            }
#pragma unroll
            for (int nt = 0; nt < 4; nt++) {
                u32 boff = (u32)((warpN*32 + nt*8 + l7)*40 + kt*16 + l8*8) * 2;
                u32 vh2[2], vl2[2];
                ldmat2(vh2, vh_s + boff);
                ldmat2(vl2, vl_s + boff);
#pragma unroll
                for (int mt = 0; mt < 2; mt++) {
                    mma16816(accP[mt][nt], pa[mt], vh2[0], vh2[1]);
                    mma16816(accP[mt][nt], pb[mt], vh2[0], vh2[1]);
                    mma16816(accP[mt][nt], pa[mt], vl2[0], vl2[1]);
                }
            }
        }
    }

    // ---- epilogue: g_a fp32 ----
#pragma unroll
    for (int mt = 0; mt < 2; mt++)
#pragma unroll
        for (int nt = 0; nt < 4; nt++) {
            int row = mbase + mt*16 + g;
            int col = warpN*32 + nt*8 + tg*2;
            float* o0 = g_a + (size_t)(b*N_ + n0 + row)*D_ + col;
            float* o1 = g_a + (size_t)(b*N_ + n0 + row + 8)*D_ + col;
            *(float2*)o0 = make_float2(accP[mt][nt][0], accP[mt][nt][1]);
            *(float2*)o1 = make_float2(accP[mt][nt][2], accP[mt][nt][3]);
        }
}

// ---------------- 1x1 conv -> d_out (B,D,N) ----------------
#define C1_SMEM ((128*128 + 32*132) * 4)

__global__ __launch_bounds__(256) void conv1x1(const float* __restrict__ ow,
                                               const float* __restrict__ ob,
                                               float* __restrict__ out) {
    extern __shared__ float sm[];
    float* ws = sm;
    float* as = sm + 16384;
    const int b = blockIdx.y, n0 = blockIdx.x * 32, t = threadIdx.x;

    for (int f = t; f < 4096; f += 256) ((float4*)ws)[f] = ((const float4*)ow)[f];
    for (int f = t; f < 1024; f += 256) {
        int r = f >> 5, c = f & 31;
        *(float4*)(as + r*132 + c*4) =
            *(const float4*)(g_a + (size_t)(b*N_ + n0 + r)*D_ + c*4);
    }
    __syncthreads();

    const int rg = t >> 4, cg = t & 15;
    const int o0 = rg*8, nA = cg*2;
    float acc[8][2];
#pragma unroll
    for (int u = 0; u < 8; u++) { acc[u][0] = 0.f; acc[u][1] = 0.f; }

    for (int i4 = 0; i4 < 32; i4++) {
        float4 a0 = *(const float4*)(as + nA*132 + i4*4);
        float4 a1 = *(const float4*)(as + (nA+1)*132 + i4*4);
#pragma unroll
        for (int rr = 0; rr < 8; rr++) {
            float4 w = *(const float4*)(ws + (o0+rr)*128 + i4*4);
            acc[rr][0] = fmaf(w.x, a0.x, acc[rr][0]);
            acc[rr][0] = fmaf(w.y, a0.y, acc[rr][0]);
            acc[rr][0] = fmaf(w.z, a0.z, acc[rr][0]);
            acc[rr][0] = fmaf(w.w, a0.w, acc[rr][0]);
            acc[rr][1] = fmaf(w.x, a1.x, acc[rr][1]);
            acc[rr][1] = fmaf(w.y, a1.y, acc[rr][1]);
            acc[rr][1] = fmaf(w.z, a1.z, acc[rr][1]);
            acc[rr][1] = fmaf(w.w, a1.w, acc[rr][1]);
        }
    }
#pragma unroll
    for (int rr = 0; rr < 8; rr++) {
        float bo = ob[o0 + rr];
        float* p = out + (size_t)(b*D_ + o0 + rr)*N_ + n0 + nA;
        p[0] = acc[rr][0] + bo;
        p[1] = acc[rr][1] + bo;
    }
}

// ---------------- BatchNorm ----------------
__global__ void bn_stats(const float* __restrict__ y, const float* __restrict__ gamma,
                         const float* __restrict__ beta) {
    int d = blockIdx.x, t = threadIdx.x;
    double s = 0.0, s2 = 0.0;
    for (int b = 0; b < B_; b++) {
        const float* p = y + (size_t)(b*D_ + d) * N_;
        for (int n = t; n < N_; n += 256) { double v = p[n]; s += v; s2 += v*v; }
    }
    __shared__ double sh[512];
    sh[t] = s; sh[256 + t] = s2;
    __syncthreads();
    for (int o = 128; o > 0; o >>= 1) {
        if (t < o) { sh[t] += sh[t+o]; sh[256+t] += sh[256+t+o]; }
        __syncthreads();
    }
    if (t == 0) {
        double cnt = (double)B_ * (double)N_;
        double m = sh[0] / cnt;
        double var = sh[256] / cnt - m*m;
        double rs = rsqrt(var + 1e-5);
        double sc = rs * (double)gamma[d];
        g_scale[d] = (float)sc;
        g_shift[d] = (float)((double)beta[d] - m*sc);
    }
}

__global__ void bn_apply(float* __restrict__ y) {
    int i = (blockIdx.x * 256 + threadIdx.x) * 4;
    int d = (i >> 13) & 127;
    float sc = g_scale[d], sh = g_shift[d];
    float4 v = *(float4*)(y + i);
    v.x = v.x*sc + sh; v.y = v.y*sc + sh; v.z = v.z*sc + sh; v.w = v.w*sc + sh;
    *(float4*)(y + i) = v;
}

// ---------------- launch ----------------
extern "C" void kernel_launch(void* const* d_in, const int* in_sizes, int n_in,
                              void* d_out, int out_size) {
    const float* x  = (const float*)d_in[0];
    const float* qw = (const float*)d_in[1];
    const float* qb = (const float*)d_in[2];
    const float* kw = (const float*)d_in[3];
    const float* kb = (const float*)d_in[4];
    const float* vw = (const float*)d_in[5];
    const float* vb = (const float*)d_in[6];
    const float* ow = (const float*)d_in[7];
    const float* ob = (const float*)d_in[8];
    const float* gamma = (const float*)d_in[9];
    const float* beta  = (const float*)d_in[10];
    float* out = (float*)d_out;

    cudaFuncSetAttribute(qkv_tc, cudaFuncAttributeMaxDynamicSharedMemorySize, QKV_TC_SMEM);
    cudaFuncSetAttribute(attn_tc, cudaFuncAttributeMaxDynamicSharedMemorySize, AT_SMEM);
    cudaFuncSetAttribute(conv1x1, cudaFuncAttributeMaxDynamicSharedMemorySize, C1_SMEM);

    prep_wsplit<<<(3*8*5*128*16 + 255) / 256, 256>>>(qw, kw, vw);
    prep_trig<<<(N_*64) / 256, 256>>>();
    qkv_tc<<<dim3(N_/128, B_), 512, QKV_TC_SMEM>>>(x, qb, kb, vb);
    attn_tc<<<dim3(NW_, B_), 512, AT_SMEM>>>();
    conv1x1<<<dim3(N_/32, B_), 256, C1_SMEM>>>(ow, ob, out);
    bn_stats<<<D_, 256>>>(out, gamma, beta);
    bn_apply<<<(B_*D_*N_) / 1024, 256>>>(out);
}

// round 8
// speedup vs baseline: 2.2137x; 1.1891x over previous
#include <cuda_runtime.h>
#include <cuda_bf16.h>
#include <math.h>

#define B_ 16
#define D_ 128
#define N_ 8192
#define NW_ 64

typedef unsigned long long ull;
typedef unsigned int u32;
typedef unsigned short u16;

// ---------------- device scratch ----------------
__device__ __align__(16) __nv_bfloat16 g_wsp[3*8*2*5*128*16];
__device__ float g_cs[N_*64];
__device__ float g_sn[N_*64];
__device__ __align__(16) __nv_bfloat16 g_qh[B_*N_*D_];   // (B,N,D) rotary+scaled
__device__ __align__(16) __nv_bfloat16 g_ql[B_*N_*D_];
__device__ __align__(16) __nv_bfloat16 g_kh[B_*N_*D_];   // (B,N,D) rotary
__device__ __align__(16) __nv_bfloat16 g_kl[B_*N_*D_];
__device__ __align__(16) __nv_bfloat16 g_vh[B_*D_*N_];   // (B,D,N) transposed
__device__ __align__(16) __nv_bfloat16 g_vl[B_*D_*N_];
__device__ __align__(16) __nv_bfloat16 g_ah[B_*N_*D_];   // attention out, split
__device__ __align__(16) __nv_bfloat16 g_al[B_*N_*D_];
__device__ __align__(16) __nv_bfloat16 g_owh[D_*D_];     // 1x1 weights split
__device__ __align__(16) __nv_bfloat16 g_owl[D_*D_];
__device__ float g_scale[D_];
__device__ float g_shift[D_];

// ---------------- mma helpers ----------------
__device__ __forceinline__ void mma16816(float* c, const u32* a, u32 b0, u32 b1) {
    asm("mma.sync.aligned.m16n8k16.row.col.f32.bf16.bf16.f32 "
        "{%0,%1,%2,%3}, {%4,%5,%6,%7}, {%8,%9}, {%0,%1,%2,%3};"
        : "+f"(c[0]), "+f"(c[1]), "+f"(c[2]), "+f"(c[3])
        : "r"(a[0]), "r"(a[1]), "r"(a[2]), "r"(a[3]), "r"(b0), "r"(b1));
}
__device__ __forceinline__ void ldmat4(u32* r, u32 addr) {
    asm volatile("ldmatrix.sync.aligned.m8n8.x4.shared.b16 {%0,%1,%2,%3}, [%4];"
                 : "=r"(r[0]), "=r"(r[1]), "=r"(r[2]), "=r"(r[3]) : "r"(addr));
}
__device__ __forceinline__ void ldmat2(u32* r, u32 addr) {
    asm volatile("ldmatrix.sync.aligned.m8n8.x2.shared.b16 {%0,%1}, [%2];"
                 : "=r"(r[0]), "=r"(r[1]) : "r"(addr));
}
__device__ __forceinline__ u32 packbf(float a, float b) {
    __nv_bfloat162 t = __floats2bfloat162_rn(a, b);
    return *(u32*)&t;
}

// ---------------- prep ----------------
__global__ void prep_wsplit(const float* __restrict__ qw, const float* __restrict__ kw,
                            const float* __restrict__ vw) {
    int e = blockIdx.x * blockDim.x + threadIdx.x;
    if (e >= 3*8*5*128*16) return;
    int ii = e % 16;
    int o  = (e / 16) % 128;
    int t  = (e / 2048) % 5;
    int ch = (e / 10240) % 8;
    int c  = e / 81920;
    const float* w = (c == 0) ? qw : (c == 1) ? kw : vw;
    float v = w[o*640 + (ch*16 + ii)*5 + t];
    __nv_bfloat16 hi = __float2bfloat16(v);
    __nv_bfloat16 lo = __float2bfloat16(v - __bfloat162float(hi));
    int base = (c*8 + ch) * 20480;
    int off  = t*2048 + o*16 + ii;
    g_wsp[base + off]         = hi;
    g_wsp[base + 10240 + off] = lo;
}

__global__ void prep_owsplit(const float* __restrict__ ow) {
    int e = blockIdx.x * blockDim.x + threadIdx.x;
    if (e >= D_*D_) return;
    float v = ow[e];
    __nv_bfloat16 hi = __float2bfloat16(v);
    g_owh[e] = hi;
    g_owl[e] = __float2bfloat16(v - __bfloat162float(hi));
}

__global__ void prep_trig() {
    __shared__ float invf_s[64];
    int t = threadIdx.x;
    if (t < 64) invf_s[t] = (float)pow(10000.0, -((double)(2*t)) / 128.0);
    __syncthreads();
    int e = blockIdx.x * 256 + t;
    int n = e >> 6, f = e & 63;
    float ang = (float)n * invf_s[f];
    double s, c;
    sincos((double)ang, &s, &c);
    g_cs[e] = (float)c;
    g_sn[e] = (float)s;
}

// ---------- tensor-core fused QKV conv (512 threads, W prefetch) ----------
#define XH_OFF 0
#define XL_OFF 35904
#define W_OFF  71808
#define KSM_OFF 112768
#define QKV_TC_SMEM 180352
#define XSTR 136

__global__ __launch_bounds__(512) void qkv_tc(const float* __restrict__ x,
                                              const float* __restrict__ qb,
                                              const float* __restrict__ kb,
                                              const float* __restrict__ vb) {
    extern __shared__ char smem[];
    __nv_bfloat16* xh = (__nv_bfloat16*)(smem + XH_OFF);
    __nv_bfloat16* xl = (__nv_bfloat16*)(smem + XL_OFF);
    float* ksm = (float*)(smem + KSM_OFF);
    float* qsm = (float*)(smem + XH_OFF);

    const int b = blockIdx.y, n0 = blockIdx.x * 128;
    const int t = threadIdx.x;
    const int lane = t & 31, wid = t >> 5;
    const int warpM = wid >> 2, warpN = wid & 3;
    const int mbase = warpM * 32, nbase = warpN * 32;

    for (int idx = t; idx < 128*132; idx += 512) {
        int i = idx / 132, c = idx % 132;
        int n = n0 - 4 + c;
        float v = (n >= 0) ? x[(size_t)(b*D_ + i)*N_ + n] : 0.0f;
        __nv_bfloat16 hi = __float2bfloat16(v);
        xh[c*XSTR + i] = hi;
        xl[c*XSTR + i] = __float2bfloat16(v - __bfloat162float(hi));
    }

    const u32 xh_s = (u32)__cvta_generic_to_shared(xh);
    const u32 xl_s = (u32)__cvta_generic_to_shared(xl);
    const int rl = lane & 15, cl8 = (lane >> 4) * 8;

    // prefetch first W chunk (c=2, ch=0)
    float4 wR[5];
#pragma unroll
    for (int k2 = 0; k2 < 5; k2++)
        wR[k2] = ((const float4*)(g_wsp + (size_t)(2*8 + 0) * 20480))[t + k2*512];

#pragma unroll 1
    for (int cl = 0; cl < 3; cl++) {
        float acc[2][4][4];
#pragma unroll
        for (int mt = 0; mt < 2; mt++)
#pragma unroll
            for (int nt = 0; nt < 4; nt++)
#pragma unroll
                for (int u = 0; u < 4; u++) acc[mt][nt][u] = 0.0f;

#pragma unroll 1
        for (int ch = 0; ch < 8; ch++) {
            __syncthreads();
            {   // commit prefetched W to smem
                float4* dst = (float4*)(smem + W_OFF);
#pragma unroll
                for (int k2 = 0; k2 < 5; k2++) dst[t + k2*512] = wR[k2];
            }
            // prefetch next chunk
            int nidx = cl*8 + ch + 1;
            if (nidx < 24) {
                int cl2 = nidx >> 3, ch2 = nidx & 7;
                int c2 = (cl2 == 0) ? 2 : (cl2 == 1) ? 1 : 0;
                const float4* src = (const float4*)(g_wsp + (size_t)(c2*8 + ch2) * 20480);
#pragma unroll
                for (int k2 = 0; k2 < 5; k2++) wR[k2] = src[t + k2*512];
            }
            __syncthreads();

#pragma unroll 1
            for (int tap = 0; tap < 5; tap++) {
                u32 ah[2][4], al[2][4];
#pragma unroll
                for (int mt = 0; mt < 2; mt++) {
                    int row = mbase + mt*16 + rl + tap;
                    int col = ch*16 + cl8;
                    u32 off = (u32)(row*XSTR + col) * 2;
                    ldmat4(ah[mt], xh_s + off);
                    ldmat4(al[mt], xl_s + off);
                }
#pragma unroll
                for (int prod = 0; prod < 3; prod++) {
                    const u32 (*asel)[4] = (prod == 2) ? al : ah;
                    int pl = (prod == 1) ? 1 : 0;
                    const char* wb = smem + W_OFF + pl*20480 + tap*4096;
#pragma unroll
                    for (int nt = 0; nt < 4; nt++) {
                        int o = nbase + nt*8 + (lane >> 2);
                        int k0 = (lane & 3) * 2;
                        const char* bp = wb + (o*16 + k0) * 2;
                        u32 b0 = *(const u32*)bp;
                        u32 b1 = *(const u32*)(bp + 16);
#pragma unroll
                        for (int mt = 0; mt < 2; mt++)
                            mma16816(acc[mt][nt], asel[mt], b0, b1);
                    }
                }
            }
        }

        if (cl == 0) {            // v -> transposed global split
#pragma unroll
            for (int mt = 0; mt < 2; mt++)
#pragma unroll
                for (int nt = 0; nt < 4; nt++) {
                    int row = mbase + mt*16 + (lane >> 2);
                    int col = nbase + nt*8 + (lane & 3)*2;
#pragma unroll
                    for (int u = 0; u < 4; u++) {
                        int dd  = col + (u & 1);
                        int tok = n0 + row + (u >> 1)*8;
                        float vv = acc[mt][nt][u] + vb[dd];
                        __nv_bfloat16 h = __float2bfloat16(vv);
                        size_t off = (size_t)(b*D_ + dd)*N_ + tok;
                        g_vh[off] = h;
                        g_vl[off] = __float2bfloat16(vv - __bfloat162float(h));
                    }
                }
        } else if (cl == 1) {     // k -> ksm fp32 + bias
#pragma unroll
            for (int mt = 0; mt < 2; mt++)
#pragma unroll
                for (int nt = 0; nt < 4; nt++) {
                    int row = mbase + mt*16 + (lane >> 2);
                    int col = nbase + nt*8 + (lane & 3)*2;
                    float b0 = kb[col], b1 = kb[col+1];
                    ksm[row*132 + col]       = acc[mt][nt][0] + b0;
                    ksm[row*132 + col + 1]   = acc[mt][nt][1] + b1;
                    ksm[(row+8)*132 + col]   = acc[mt][nt][2] + b0;
                    ksm[(row+8)*132 + col+1] = acc[mt][nt][3] + b1;
                }
        } else {                  // q -> qsm (overlays x)
            __syncthreads();
#pragma unroll
            for (int mt = 0; mt < 2; mt++)
#pragma unroll
                for (int nt = 0; nt < 4; nt++) {
                    int row = mbase + mt*16 + (lane >> 2);
                    int col = nbase + nt*8 + (lane & 3)*2;
                    float b0 = qb[col], b1 = qb[col+1];
                    qsm[row*132 + col]       = acc[mt][nt][0] + b0;
                    qsm[row*132 + col + 1]   = acc[mt][nt][1] + b1;
                    qsm[(row+8)*132 + col]   = acc[mt][nt][2] + b0;
                    qsm[(row+8)*132 + col+1] = acc[mt][nt][3] + b1;
                }
        }
    }
    __syncthreads();

    // ---- rotary + scale -> split bf16 globals ----
    const float scl = 0.08838834764831845f;
    const int d = t & 127, h = t >> 7;
    const int dp = (d + 64) & 127;
    const float sg = (d < 64) ? -1.0f : 1.0f;
    const int f = d & 63;
    for (int j = h; j < 128; j += 4) {
        int n = n0 + j;
        float cc = g_cs[n*64 + f], ss = g_sn[n*64 + f];
        float qv = qsm[j*132 + d], qh2 = sg * qsm[j*132 + dp];
        float kv = ksm[j*132 + d], kh2 = sg * ksm[j*132 + dp];
        float qf = (qv*cc + qh2*ss) * scl;
        float kf = kv*cc + kh2*ss;
        size_t o = (size_t)(b*N_ + n)*128 + d;
        __nv_bfloat16 qhi = __float2bfloat16(qf);
        __nv_bfloat16 khi = __float2bfloat16(kf);
        g_qh[o] = qhi; g_ql[o] = __float2bfloat16(qf - __bfloat162float(qhi));
        g_kh[o] = khi; g_kl[o] = __float2bfloat16(kf - __bfloat162float(khi));
    }
}

// ---------------- tensor-core windowed attention (512 threads, prefetch) ----------------
#define AT_QH 0
#define AT_S  34816
#define AT_QL 165888
#define AT_KH 200704
#define AT_KL 209408
#define AT_VH 165888
#define AT_VL 176128
#define AT_PH 186368
#define AT_PL 196608
#define AT_M  218112
#define AT_I  218624
#define AT_SMEM 219136

__global__ __launch_bounds__(512) void attn_tc() {
    extern __shared__ char sm8[];
    __nv_bfloat16* qhs = (__nv_bfloat16*)(sm8 + AT_QH);
    float*         S   = (float*)(sm8 + AT_S);
    __nv_bfloat16* qls = (__nv_bfloat16*)(sm8 + AT_QL);
    __nv_bfloat16* khs = (__nv_bfloat16*)(sm8 + AT_KH);
    __nv_bfloat16* kls = (__nv_bfloat16*)(sm8 + AT_KL);
    __nv_bfloat16* vhs = (__nv_bfloat16*)(sm8 + AT_VH);
    __nv_bfloat16* vls = (__nv_bfloat16*)(sm8 + AT_VL);
    __nv_bfloat16* phs = (__nv_bfloat16*)(sm8 + AT_PH);
    __nv_bfloat16* pls = (__nv_bfloat16*)(sm8 + AT_PL);
    float* mrow = (float*)(sm8 + AT_M);
    float* irow = (float*)(sm8 + AT_I);

    const int wi = blockIdx.x, b = blockIdx.y;
    const int n0 = wi * 128, t = threadIdx.x;
    const int lane = t & 31, wid = t >> 5;
    const int warpM = wid >> 2, warpN = wid & 3;
    const int mbase = warpM * 32;
    const int rl = lane & 15, cl8 = (lane >> 4) * 8;
    const int g = lane >> 2, tg = lane & 3;
    const int l7 = lane & 7, l8 = (lane >> 3) & 1;
    const int jstart = (wi == 0) ? 128 : 0;

    const u32 qh_s = (u32)__cvta_generic_to_shared(qhs);
    const u32 ql_s = (u32)__cvta_generic_to_shared(qls);
    const u32 kh_s = (u32)__cvta_generic_to_shared(khs);
    const u32 kl_s = (u32)__cvta_generic_to_shared(kls);
    const u32 vh_s = (u32)__cvta_generic_to_shared(vhs);
    const u32 vl_s = (u32)__cvta_generic_to_shared(vls);
    const u32 ph_s = (u32)__cvta_generic_to_shared(phs);
    const u32 pl_s = (u32)__cvta_generic_to_shared(pls);

    // ---- load q split ----
    for (int idx = t; idx < 8192; idx += 512) {
        int r = idx >> 6, c = idx & 63;
        ((u32*)qhs)[r*68 + c] = ((const u32*)(g_qh + (size_t)(b*N_ + n0 + r)*D_))[c];
        ((u32*)qls)[r*68 + c] = ((const u32*)(g_ql + (size_t)(b*N_ + n0 + r)*D_))[c];
    }

    u32 hR[4], lR[4];
    // prefetch k chunk 0
    {
        int nk0 = n0 - 128;
#pragma unroll
        for (int i = 0; i < 4; i++) {
            int idx = t + i*512;
            int r = idx >> 6, c2 = idx & 63;
            int nk = nk0 + r;
            hR[i] = 0; lR[i] = 0;
            if (nk >= 0) {
                hR[i] = *(const u32*)(g_kh + (size_t)(b*N_ + nk)*D_ + c2*2);
                lR[i] = *(const u32*)(g_kl + (size_t)(b*N_ + nk)*D_ + c2*2);
            }
        }
    }

    // ==== phase 1: S = q @ k^T, 8 chunks of 32 keys, reg-prefetched ====
#pragma unroll 1
    for (int ch = 0; ch < 8; ch++) {
        __syncthreads();
#pragma unroll
        for (int i = 0; i < 4; i++) {
            int idx = t + i*512;
            int r = idx >> 6, c2 = idx & 63;
            ((u32*)khs)[r*68 + c2] = hR[i];
            ((u32*)kls)[r*68 + c2] = lR[i];
        }
        if (ch < 7) {
            int nk0 = n0 - 128 + (ch+1)*32;
#pragma unroll
            for (int i = 0; i < 4; i++) {
                int idx = t + i*512;
                int r = idx >> 6, c2 = idx & 63;
                int nk = nk0 + r;
                hR[i] = 0; lR[i] = 0;
                if (nk >= 0) {
                    hR[i] = *(const u32*)(g_kh + (size_t)(b*N_ + nk)*D_ + c2*2);
                    lR[i] = *(const u32*)(g_kl + (size_t)(b*N_ + nk)*D_ + c2*2);
                }
            }
        }
        __syncthreads();

        float acc[2][4];
#pragma unroll
        for (int mt = 0; mt < 2; mt++)
#pragma unroll
            for (int u = 0; u < 4; u++) acc[mt][u] = 0.0f;

#pragma unroll 1
        for (int kt = 0; kt < 8; kt++) {
            u32 ah[2][4], al[2][4];
#pragma unroll
            for (int mt = 0; mt < 2; mt++) {
                u32 off = (u32)((mbase + mt*16 + rl)*136 + kt*16 + cl8) * 2;
                ldmat4(ah[mt], qh_s + off);
                ldmat4(al[mt], ql_s + off);
            }
            u32 boff = (u32)((warpN*8 + l7)*136 + kt*16 + l8*8) * 2;
            u32 bh[2], bl[2];
            ldmat2(bh, kh_s + boff);
            ldmat2(bl, kl_s + boff);
#pragma unroll
            for (int mt = 0; mt < 2; mt++) {
                mma16816(acc[mt], ah[mt], bh[0], bh[1]);
                mma16816(acc[mt], al[mt], bh[0], bh[1]);
                mma16816(acc[mt], ah[mt], bl[0], bl[1]);
            }
        }
#pragma unroll
        for (int mt = 0; mt < 2; mt++) {
            int row = mbase + mt*16 + g;
            int col = ch*32 + warpN*8 + tg*2;
            *(float2*)(S + row*256 + col)     = make_float2(acc[mt][0], acc[mt][1]);
            *(float2*)(S + (row+8)*256 + col) = make_float2(acc[mt][2], acc[mt][3]);
        }
    }

    // prefetch v chunk 0 (transposed layout) — overlaps stats
    {
        int nk0 = n0 - 128;
#pragma unroll
        for (int i = 0; i < 4; i++) {
            int idx = t + i*512;
            int dd = idx >> 4, c = idx & 15;
            int tok = nk0 + c*2;
            hR[i] = 0; lR[i] = 0;
            if (tok >= 0) {
                hR[i] = *(const u32*)(g_vh + (size_t)(b*D_ + dd)*N_ + tok);
                lR[i] = *(const u32*)(g_vl + (size_t)(b*D_ + dd)*N_ + tok);
            }
        }
    }
    __syncthreads();

    // ==== phase 2: softmax stats ====
    {
        int r = t >> 2, q4 = t & 3;
        int jend = 128 + r + 1;
        float m = -3.402823466e38f;
        for (int c4 = (jstart >> 2) + q4; c4*4 < jend; c4 += 4) {
            float4 v = *(const float4*)(S + r*256 + c4*4);
            int c = c4*4;
            if (c   < jend) m = fmaxf(m, v.x);
            if (c+1 < jend) m = fmaxf(m, v.y);
            if (c+2 < jend) m = fmaxf(m, v.z);
            if (c+3 < jend) m = fmaxf(m, v.w);
        }
        m = fmaxf(m, __shfl_xor_sync(0xFFFFFFFF, m, 1));
        m = fmaxf(m, __shfl_xor_sync(0xFFFFFFFF, m, 2));
        float s = 0.0f;
        for (int c4 = (jstart >> 2) + q4; c4*4 < jend; c4 += 4) {
            float4 v = *(const float4*)(S + r*256 + c4*4);
            int c = c4*4;
            if (c   < jend) s += __expf(v.x - m);
            if (c+1 < jend) s += __expf(v.y - m);
            if (c+2 < jend) s += __expf(v.z - m);
            if (c+3 < jend) s += __expf(v.w - m);
        }
        s += __shfl_xor_sync(0xFFFFFFFF, s, 1);
        s += __shfl_xor_sync(0xFFFFFFFF, s, 2);
        if (q4 == 0) { mrow[r] = m; irow[r] = 1.0f / s; }
    }

    // ==== phase 3: OUT = P @ V, reg-prefetched v ====
    float accP[2][4][4];
#pragma unroll
    for (int mt = 0; mt < 2; mt++)
#pragma unroll
        for (int nt = 0; nt < 4; nt++)
#pragma unroll
            for (int u = 0; u < 4; u++) accP[mt][nt][u] = 0.0f;

#pragma unroll 1
    for (int ch = 0; ch < 8; ch++) {
        __syncthreads();      // covers stats (first iter) + prev mma reads
#pragma unroll
        for (int i = 0; i < 4; i++) {
            int idx = t + i*512;
            int dd = idx >> 4, c = idx & 15;
            *(u32*)((u16*)vhs + dd*40 + c*2) = hR[i];
            *(u32*)((u16*)vls + dd*40 + c*2) = lR[i];
        }
        // convert P chunk
        {
            int r = t >> 2, c0l = (t & 3) * 8;
            float mm = mrow[r], ii = irow[r];
            int jend = 128 + r + 1;
#pragma unroll
            for (int i4 = 0; i4 < 2; i4++) {
                int cg = ch*32 + c0l + i4*4;
                float4 s4 = *(const float4*)(S + r*256 + cg);
                float p[4];
                p[0] = (cg   >= jstart && cg   < jend) ? __expf(s4.x - mm) * ii : 0.0f;
                p[1] = (cg+1 >= jstart && cg+1 < jend) ? __expf(s4.y - mm) * ii : 0.0f;
                p[2] = (cg+2 >= jstart && cg+2 < jend) ? __expf(s4.z - mm) * ii : 0.0f;
                p[3] = (cg+3 >= jstart && cg+3 < jend) ? __expf(s4.w - mm) * ii : 0.0f;
                __nv_bfloat16 h0 = __float2bfloat16(p[0]);
                __nv_bfloat16 h1 = __float2bfloat16(p[1]);
                __nv_bfloat16 h2 = __float2bfloat16(p[2]);
                __nv_bfloat16 h3 = __float2bfloat16(p[3]);
                int di = (r*40 + c0l + i4*4) >> 1;
                ((u32*)phs)[di]   = packbf(__bfloat162float(h0), __bfloat162float(h1));
                ((u32*)phs)[di+1] = packbf(__bfloat162float(h2), __bfloat162float(h3));
                ((u32*)pls)[di]   = packbf(p[0] - __bfloat162float(h0), p[1] - __bfloat162float(h1));
                ((u32*)pls)[di+1] = packbf(p[2] - __bfloat162float(h2), p[3] - __bfloat162float(h3));
            }
        }
        // prefetch next v chunk
        if (ch < 7) {
            int nk0 = n0 - 128 + (ch+1)*32;
#pragma unroll
            for (int i = 0; i < 4; i++) {
                int idx = t + i*512;
                int dd = idx >> 4, c = idx & 15;
                int tok = nk0 + c*2;
                hR[i] = 0; lR[i] = 0;
                if (tok >= 0) {
                    hR[i] = *(const u32*)(g_vh + (size_t)(b*D_ + dd)*N_ + tok);
                    lR[i] = *(const u32*)(g_vl + (size_t)(b*D_ + dd)*N_ + tok);
                }
            }
        }
        __syncthreads();

#pragma unroll
        for (int kt = 0; kt < 2; kt++) {
            u32 pa[2][4], pb[2][4];
#pragma unroll
            for (int mt = 0; mt < 2; mt++) {
                u32 off = (u32)((mbase + mt*16 + rl)*40 + kt*16 + cl8) * 2;
                ldmat4(pa[mt], ph_s + off);
                ldmat4(pb[mt], pl_s + off);
            }
#pragma unroll
            for (int nt = 0; nt < 4; nt++) {
                u32 boff = (u32)((warpN*32 + nt*8 + l7)*40 + kt*16 + l8*8) * 2;
                u32 vh2[2], vl2[2];
                ldmat2(vh2, vh_s + boff);
                ldmat2(vl2, vl_s + boff);
#pragma unroll
                for (int mt = 0; mt < 2; mt++) {
                    mma16816(accP[mt][nt], pa[mt], vh2[0], vh2[1]);
                    mma16816(accP[mt][nt], pb[mt], vh2[0], vh2[1]);
                    mma16816(accP[mt][nt], pa[mt], vl2[0], vl2[1]);
                }
            }
        }
    }

    // ---- epilogue: split bf16 attention output ----
#pragma unroll
    for (int mt = 0; mt < 2; mt++)
#pragma unroll
        for (int nt = 0; nt < 4; nt++) {
            int row = mbase + mt*16 + g;
            int col = warpN*32 + nt*8 + tg*2;
#pragma unroll
            for (int half = 0; half < 2; half++) {
                float v0 = accP[mt][nt][half*2];
                float v1 = accP[mt][nt][half*2+1];
                __nv_bfloat16 h0 = __float2bfloat16(v0);
                __nv_bfloat16 h1 = __float2bfloat16(v1);
                size_t off = (size_t)(b*N_ + n0 + row + half*8)*D_ + col;
                *(u32*)(g_ah + off) = packbf(__bfloat162float(h0), __bfloat162float(h1));
                *(u32*)(g_al + off) = packbf(v0 - __bfloat162float(h0), v1 - __bfloat162float(h1));
            }
        }
}

// ---------------- tensor-core 1x1 conv -> d_out (B,D,N) ----------------
#define C1_AH 0
#define C1_AL 34816
#define C1_WH 69632
#define C1_WL 104448
#define C1T_SMEM 139264

__global__ __launch_bounds__(512) void conv1x1_tc(const float* __restrict__ ob_,
                                                  float* __restrict__ out) {
    extern __shared__ char sm8[];
    __nv_bfloat16* ahs = (__nv_bfloat16*)(sm8 + C1_AH);
    __nv_bfloat16* als = (__nv_bfloat16*)(sm8 + C1_AL);
    __nv_bfloat16* whs = (__nv_bfloat16*)(sm8 + C1_WH);
    __nv_bfloat16* wls = (__nv_bfloat16*)(sm8 + C1_WL);

    const int b = blockIdx.y, n0 = blockIdx.x * 128;
    const int t = threadIdx.x;
    const int lane = t & 31, wid = t >> 5;
    const int warpM = wid >> 2, warpN = wid & 3;
    const int mbase = warpM * 32, nbase = warpN * 32;
    const int rl = lane & 15, cl8 = (lane >> 4) * 8;
    const int g = lane >> 2, tg = lane & 3;
    const int l7 = lane & 7, l8 = (lane >> 3) & 1;

    for (int idx = t; idx < 8192; idx += 512) {
        int r = idx >> 6, c = idx & 63;
        ((u32*)ahs)[r*68 + c] = ((const u32*)(g_ah + (size_t)(b*N_ + n0 + r)*D_))[c];
        ((u32*)als)[r*68 + c] = ((const u32*)(g_al + (size_t)(b*N_ + n0 + r)*D_))[c];
        ((u32*)whs)[r*68 + c] = ((const u32*)(g_owh + (size_t)r*D_))[c];
        ((u32*)wls)[r*68 + c] = ((const u32*)(g_owl + (size_t)r*D_))[c];
    }
    __syncthreads();

    const u32 ah_s = (u32)__cvta_generic_to_shared(ahs);
    const u32 al_s = (u32)__cvta_generic_to_shared(als);
    const u32 wh_s = (u32)__cvta_generic_to_shared(whs);
    const u32 wl_s = (u32)__cvta_generic_to_shared(wls);

    float acc[2][4][4];
#pragma unroll
    for (int mt = 0; mt < 2; mt++)
#pragma unroll
        for (int nt = 0; nt < 4; nt++)
#pragma unroll
            for (int u = 0; u < 4; u++) acc[mt][nt][u] = 0.0f;

#pragma unroll 1
    for (int kt = 0; kt < 8; kt++) {
        u32 aH[2][4], aL[2][4];
#pragma unroll
        for (int mt = 0; mt < 2; mt++) {
            u32 off = (u32)((mbase + mt*16 + rl)*136 + kt*16 + cl8) * 2;
            ldmat4(aH[mt], ah_s + off);
            ldmat4(aL[mt], al_s + off);
        }
#pragma unroll
        for (int nt = 0; nt < 4; nt++) {
            u32 boff = (u32)((nbase + nt*8 + l7)*136 + kt*16 + l8*8) * 2;
            u32 wh2[2], wl2[2];
            ldmat2(wh2, wh_s + boff);
            ldmat2(wl2, wl_s + boff);
#pragma unroll
            for (int mt = 0; mt < 2; mt++) {
                mma16816(acc[mt][nt], aH[mt], wh2[0], wh2[1]);
                mma16816(acc[mt][nt], aL[mt], wh2[0], wh2[1]);
                mma16816(acc[mt][nt], aH[mt], wl2[0], wl2[1]);
            }
        }
    }

    // epilogue: transposed write (B,D,N) + bias
#pragma unroll
    for (int mt = 0; mt < 2; mt++)
#pragma unroll
        for (int nt = 0; nt < 4; nt++) {
            int row = mbase + mt*16 + g;
            int col = nbase + nt*8 + tg*2;
#pragma unroll
            for (int u = 0; u < 4; u++) {
                int dd  = col + (u & 1);
                int tok = n0 + row + (u >> 1)*8;
                out[(size_t)(b*D_ + dd)*N_ + tok] = acc[mt][nt][u] + ob_[dd];
            }
        }
}

// ---------------- BatchNorm ----------------
__global__ void bn_stats(const float* __restrict__ y, const float* __restrict__ gamma,
                         const float* __restrict__ beta) {
    int d = blockIdx.x, t = threadIdx.x;
    double s = 0.0, s2 = 0.0;
    for (int b = 0; b < B_; b++) {
        const float* p = y + (size_t)(b*D_ + d) * N_;
        for (int n = t; n < N_; n += 256) { double v = p[n]; s += v; s2 += v*v; }
    }
    __shared__ double sh[512];
    sh[t] = s; sh[256 + t] = s2;
    __syncthreads();
    for (int o = 128; o > 0; o >>= 1) {
        if (t < o) { sh[t] += sh[t+o]; sh[256+t] += sh[256+t+o]; }
        __syncthreads();
    }
    if (t == 0) {
        double cnt = (double)B_ * (double)N_;
        double m = sh[0] / cnt;
        double var = sh[256] / cnt - m*m;
        double rs = rsqrt(var + 1e-5);
        double sc = rs * (double)gamma[d];
        g_scale[d] = (float)sc;
        g_shift[d] = (float)((double)beta[d] - m*sc);
    }
}

__global__ void bn_apply(float* __restrict__ y) {
    int i = (blockIdx.x * 256 + threadIdx.x) * 4;
    int d = (i >> 13) & 127;
    float sc = g_scale[d], sh = g_shift[d];
    float4 v = *(float4*)(y + i);
    v.x = v.x*sc + sh; v.y = v.y*sc + sh; v.z = v.z*sc + sh; v.w = v.w*sc + sh;
    *(float4*)(y + i) = v;
}

// ---------------- launch ----------------
extern "C" void kernel_launch(void* const* d_in, const int* in_sizes, int n_in,
                              void* d_out, int out_size) {
    const float* x  = (const float*)d_in[0];
    const float* qw = (const float*)d_in[1];
    const float* qb = (const float*)d_in[2];
    const float* kw = (const float*)d_in[3];
    const float* kb = (const float*)d_in[4];
    const float* vw = (const float*)d_in[5];
    const float* vb = (const float*)d_in[6];
    const float* ow = (const float*)d_in[7];
    const float* ob = (const float*)d_in[8];
    const float* gamma = (const float*)d_in[9];
    const float* beta  = (const float*)d_in[10];
    float* out = (float*)d_out;

    cudaFuncSetAttribute(qkv_tc, cudaFuncAttributeMaxDynamicSharedMemorySize, QKV_TC_SMEM);
    cudaFuncSetAttribute(attn_tc, cudaFuncAttributeMaxDynamicSharedMemorySize, AT_SMEM);
    cudaFuncSetAttribute(conv1x1_tc, cudaFuncAttributeMaxDynamicSharedMemorySize, C1T_SMEM);

    prep_wsplit<<<(3*8*5*128*16 + 255) / 256, 256>>>(qw, kw, vw);
    prep_owsplit<<<(D_*D_ + 255) / 256, 256>>>(ow);
    prep_trig<<<(N_*64) / 256, 256>>>();
    qkv_tc<<<dim3(N_/128, B_), 512, QKV_TC_SMEM>>>(x, qb, kb, vb);
    attn_tc<<<dim3(NW_, B_), 512, AT_SMEM>>>();
    conv1x1_tc<<<dim3(N_/128, B_), 512, C1T_SMEM>>>(ob, out);
    bn_stats<<<D_, 256>>>(out, gamma, beta);
    bn_apply<<<(B_*D_*N_) / 1024, 256>>>(out);
}

// round 9
// speedup vs baseline: 2.2297x; 1.0072x over previous
#include <cuda_runtime.h>
#include <cuda_bf16.h>
#include <math.h>

#define B_ 16
#define D_ 128
#define N_ 8192
#define NW_ 64

typedef unsigned long long ull;
typedef unsigned int u32;
typedef unsigned short u16;

// ---------------- device scratch ----------------
__device__ __align__(16) __nv_bfloat16 g_wsp[3*8*2*5*128*16];
__device__ float g_cs[N_*64];
__device__ float g_sn[N_*64];
__device__ __align__(16) __nv_bfloat16 g_qh[B_*N_*D_];   // (B,N,D) rotary+scaled
__device__ __align__(16) __nv_bfloat16 g_ql[B_*N_*D_];
__device__ __align__(16) __nv_bfloat16 g_kh[B_*N_*D_];   // (B,N,D) rotary
__device__ __align__(16) __nv_bfloat16 g_kl[B_*N_*D_];
__device__ __align__(16) __nv_bfloat16 g_vh[B_*D_*N_];   // (B,D,N) transposed
__device__ __align__(16) __nv_bfloat16 g_vl[B_*D_*N_];
__device__ __align__(16) __nv_bfloat16 g_ah[B_*N_*D_];   // attention out, split
__device__ __align__(16) __nv_bfloat16 g_al[B_*N_*D_];
__device__ __align__(16) __nv_bfloat16 g_owh[D_*D_];     // 1x1 weights split
__device__ __align__(16) __nv_bfloat16 g_owl[D_*D_];
__device__ float g_scale[D_];
__device__ float g_shift[D_];

// ---------------- mma helpers ----------------
__device__ __forceinline__ void mma16816(float* c, const u32* a, u32 b0, u32 b1) {
    asm("mma.sync.aligned.m16n8k16.row.col.f32.bf16.bf16.f32 "
        "{%0,%1,%2,%3}, {%4,%5,%6,%7}, {%8,%9}, {%0,%1,%2,%3};"
        : "+f"(c[0]), "+f"(c[1]), "+f"(c[2]), "+f"(c[3])
        : "r"(a[0]), "r"(a[1]), "r"(a[2]), "r"(a[3]), "r"(b0), "r"(b1));
}
__device__ __forceinline__ void ldmat4(u32* r, u32 addr) {
    asm volatile("ldmatrix.sync.aligned.m8n8.x4.shared.b16 {%0,%1,%2,%3}, [%4];"
                 : "=r"(r[0]), "=r"(r[1]), "=r"(r[2]), "=r"(r[3]) : "r"(addr));
}
__device__ __forceinline__ void ldmat2(u32* r, u32 addr) {
    asm volatile("ldmatrix.sync.aligned.m8n8.x2.shared.b16 {%0,%1}, [%2];"
                 : "=r"(r[0]), "=r"(r[1]) : "r"(addr));
}
__device__ __forceinline__ u32 packbf(float a, float b) {
    __nv_bfloat162 t = __floats2bfloat162_rn(a, b);
    return *(u32*)&t;
}

// ---------------- prep ----------------
__global__ void prep_wsplit(const float* __restrict__ qw, const float* __restrict__ kw,
                            const float* __restrict__ vw) {
    int e = blockIdx.x * blockDim.x + threadIdx.x;
    if (e >= 3*8*5*128*16) return;
    int ii = e % 16;
    int o  = (e / 16) % 128;
    int t  = (e / 2048) % 5;
    int ch = (e / 10240) % 8;
    int c  = e / 81920;
    const float* w = (c == 0) ? qw : (c == 1) ? kw : vw;
    float v = w[o*640 + (ch*16 + ii)*5 + t];
    __nv_bfloat16 hi = __float2bfloat16(v);
    __nv_bfloat16 lo = __float2bfloat16(v - __bfloat162float(hi));
    int base = (c*8 + ch) * 20480;
    int off  = t*2048 + o*16 + ii;
    g_wsp[base + off]         = hi;
    g_wsp[base + 10240 + off] = lo;
}

__global__ void prep_owsplit(const float* __restrict__ ow) {
    int e = blockIdx.x * blockDim.x + threadIdx.x;
    if (e >= D_*D_) return;
    float v = ow[e];
    __nv_bfloat16 hi = __float2bfloat16(v);
    g_owh[e] = hi;
    g_owl[e] = __float2bfloat16(v - __bfloat162float(hi));
}

__global__ void prep_trig() {
    __shared__ float invf_s[64];
    int t = threadIdx.x;
    if (t < 64) invf_s[t] = (float)pow(10000.0, -((double)(2*t)) / 128.0);
    __syncthreads();
    int e = blockIdx.x * 256 + t;
    int n = e >> 6, f = e & 63;
    float ang = (float)n * invf_s[f];
    double s, c;
    sincos((double)ang, &s, &c);
    g_cs[e] = (float)c;
    g_sn[e] = (float)s;
}

// ---------- tensor-core fused QKV conv (512 threads, W prefetch, ldmatrix-B) ----------
#define XH_OFF 0
#define XL_OFF 35904
#define W_OFF  71808
#define KSM_OFF 112768
#define QKV_TC_SMEM 180352
#define XSTR 136

__global__ __launch_bounds__(512) void qkv_tc(const float* __restrict__ x,
                                              const float* __restrict__ qb,
                                              const float* __restrict__ kb,
                                              const float* __restrict__ vb) {
    extern __shared__ char smem[];
    __nv_bfloat16* xh = (__nv_bfloat16*)(smem + XH_OFF);
    __nv_bfloat16* xl = (__nv_bfloat16*)(smem + XL_OFF);
    float* ksm = (float*)(smem + KSM_OFF);
    float* qsm = (float*)(smem + XH_OFF);

    const int b = blockIdx.y, n0 = blockIdx.x * 128;
    const int t = threadIdx.x;
    const int lane = t & 31, wid = t >> 5;
    const int warpM = wid >> 2, warpN = wid & 3;
    const int mbase = warpM * 32, nbase = warpN * 32;
    const int l7 = lane & 7, l8 = (lane >> 3) & 1;

    for (int idx = t; idx < 128*132; idx += 512) {
        int i = idx / 132, c = idx % 132;
        int n = n0 - 4 + c;
        float v = (n >= 0) ? x[(size_t)(b*D_ + i)*N_ + n] : 0.0f;
        __nv_bfloat16 hi = __float2bfloat16(v);
        xh[c*XSTR + i] = hi;
        xl[c*XSTR + i] = __float2bfloat16(v - __bfloat162float(hi));
    }

    const u32 xh_s = (u32)__cvta_generic_to_shared(xh);
    const u32 xl_s = (u32)__cvta_generic_to_shared(xl);
    const u32 w_s  = (u32)__cvta_generic_to_shared(smem + W_OFF);
    const int rl = lane & 15, cl8 = (lane >> 4) * 8;

    // prefetch first W chunk (c=2, ch=0)
    float4 wR[5];
#pragma unroll
    for (int k2 = 0; k2 < 5; k2++)
        wR[k2] = ((const float4*)(g_wsp + (size_t)(2*8 + 0) * 20480))[t + k2*512];

#pragma unroll 1
    for (int cl = 0; cl < 3; cl++) {
        float acc[2][4][4];
#pragma unroll
        for (int mt = 0; mt < 2; mt++)
#pragma unroll
            for (int nt = 0; nt < 4; nt++)
#pragma unroll
                for (int u = 0; u < 4; u++) acc[mt][nt][u] = 0.0f;

#pragma unroll 1
        for (int ch = 0; ch < 8; ch++) {
            __syncthreads();
            {   // commit prefetched W to smem
                float4* dst = (float4*)(smem + W_OFF);
#pragma unroll
                for (int k2 = 0; k2 < 5; k2++) dst[t + k2*512] = wR[k2];
            }
            // prefetch next chunk
            int nidx = cl*8 + ch + 1;
            if (nidx < 24) {
                int cl2 = nidx >> 3, ch2 = nidx & 7;
                int c2 = (cl2 == 0) ? 2 : (cl2 == 1) ? 1 : 0;
                const float4* src = (const float4*)(g_wsp + (size_t)(c2*8 + ch2) * 20480);
#pragma unroll
                for (int k2 = 0; k2 < 5; k2++) wR[k2] = src[t + k2*512];
            }
            __syncthreads();

#pragma unroll 1
            for (int tap = 0; tap < 5; tap++) {
                u32 ah[2][4], al[2][4];
#pragma unroll
                for (int mt = 0; mt < 2; mt++) {
                    int row = mbase + mt*16 + rl + tap;
                    int col = ch*16 + cl8;
                    u32 off = (u32)(row*XSTR + col) * 2;
                    ldmat4(ah[mt], xh_s + off);
                    ldmat4(al[mt], xl_s + off);
                }
                // B fragments via ldmatrix.x2 (validated pattern from attn):
                // W tile rows o at 32B stride; lanes 0-7 -> rows, lanes 8-15 -> k+8
                u32 brow = (u32)(tap*4096 + (nbase + l7)*32 + l8*16);
#pragma unroll
                for (int nt = 0; nt < 4; nt++) {
                    u32 bh[2], bl[2];
                    ldmat2(bh, w_s + brow + nt*256);
                    ldmat2(bl, w_s + 20480 + brow + nt*256);
#pragma unroll
                    for (int mt = 0; mt < 2; mt++) {
                        mma16816(acc[mt][nt], ah[mt], bh[0], bh[1]);
                        mma16816(acc[mt][nt], ah[mt], bl[0], bl[1]);
                        mma16816(acc[mt][nt], al[mt], bh[0], bh[1]);
                    }
                }
            }
        }

        if (cl == 0) {            // v -> transposed global split
#pragma unroll
            for (int mt = 0; mt < 2; mt++)
#pragma unroll
                for (int nt = 0; nt < 4; nt++) {
                    int row = mbase + mt*16 + (lane >> 2);
                    int col = nbase + nt*8 + (lane & 3)*2;
#pragma unroll
                    for (int u = 0; u < 4; u++) {
                        int dd  = col + (u & 1);
                        int tok = n0 + row + (u >> 1)*8;
                        float vv = acc[mt][nt][u] + vb[dd];
                        __nv_bfloat16 h = __float2bfloat16(vv);
                        size_t off = (size_t)(b*D_ + dd)*N_ + tok;
                        g_vh[off] = h;
                        g_vl[off] = __float2bfloat16(vv - __bfloat162float(h));
                    }
                }
        } else if (cl == 1) {     // k -> ksm fp32 + bias
#pragma unroll
            for (int mt = 0; mt < 2; mt++)
#pragma unroll
                for (int nt = 0; nt < 4; nt++) {
                    int row = mbase + mt*16 + (lane >> 2);
                    int col = nbase + nt*8 + (lane & 3)*2;
                    float b0 = kb[col], b1 = kb[col+1];
                    ksm[row*132 + col]       = acc[mt][nt][0] + b0;
                    ksm[row*132 + col + 1]   = acc[mt][nt][1] + b1;
                    ksm[(row+8)*132 + col]   = acc[mt][nt][2] + b0;
                    ksm[(row+8)*132 + col+1] = acc[mt][nt][3] + b1;
                }
        } else {                  // q -> qsm (overlays x)
            __syncthreads();
#pragma unroll
            for (int mt = 0; mt < 2; mt++)
#pragma unroll
                for (int nt = 0; nt < 4; nt++) {
                    int row = mbase + mt*16 + (lane >> 2);
                    int col = nbase + nt*8 + (lane & 3)*2;
                    float b0 = qb[col], b1 = qb[col+1];
                    qsm[row*132 + col]       = acc[mt][nt][0] + b0;
                    qsm[row*132 + col + 1]   = acc[mt][nt][1] + b1;
                    qsm[(row+8)*132 + col]   = acc[mt][nt][2] + b0;
                    qsm[(row+8)*132 + col+1] = acc[mt][nt][3] + b1;
                }
        }
    }
    __syncthreads();

    // ---- rotary + scale -> split bf16 globals ----
    const float scl = 0.08838834764831845f;
    const int d = t & 127, h = t >> 7;
    const int dp = (d + 64) & 127;
    const float sg = (d < 64) ? -1.0f : 1.0f;
    const int f = d & 63;
    for (int j = h; j < 128; j += 4) {
        int n = n0 + j;
        float cc = g_cs[n*64 + f], ss = g_sn[n*64 + f];
        float qv = qsm[j*132 + d], qh2 = sg * qsm[j*132 + dp];
        float kv = ksm[j*132 + d], kh2 = sg * ksm[j*132 + dp];
        float qf = (qv*cc + qh2*ss) * scl;
        float kf = kv*cc + kh2*ss;
        size_t o = (size_t)(b*N_ + n)*128 + d;
        __nv_bfloat16 qhi = __float2bfloat16(qf);
        __nv_bfloat16 khi = __float2bfloat16(kf);
        g_qh[o] = qhi; g_ql[o] = __float2bfloat16(qf - __bfloat162float(qhi));
        g_kh[o] = khi; g_kl[o] = __float2bfloat16(kf - __bfloat162float(khi));
    }
}

// ---------------- tensor-core windowed attention (512 threads, prefetch) ----------------
#define AT_QH 0
#define AT_S  34816
#define AT_QL 165888
#define AT_KH 200704
#define AT_KL 209408
#define AT_VH 165888
#define AT_VL 176128
#define AT_PH 186368
#define AT_PL 196608
#define AT_M  218112
#define AT_I  218624
#define AT_SMEM 219136

__global__ __launch_bounds__(512) void attn_tc() {
    extern __shared__ char sm8[];
    __nv_bfloat16* qhs = (__nv_bfloat16*)(sm8 + AT_QH);
    float*         S   = (float*)(sm8 + AT_S);
    __nv_bfloat16* qls = (__nv_bfloat16*)(sm8 + AT_QL);
    __nv_bfloat16* khs = (__nv_bfloat16*)(sm8 + AT_KH);
    __nv_bfloat16* kls = (__nv_bfloat16*)(sm8 + AT_KL);
    __nv_bfloat16* vhs = (__nv_bfloat16*)(sm8 + AT_VH);
    __nv_bfloat16* vls = (__nv_bfloat16*)(sm8 + AT_VL);
    __nv_bfloat16* phs = (__nv_bfloat16*)(sm8 + AT_PH);
    __nv_bfloat16* pls = (__nv_bfloat16*)(sm8 + AT_PL);
    float* mrow = (float*)(sm8 + AT_M);
    float* irow = (float*)(sm8 + AT_I);

    const int wi = blockIdx.x, b = blockIdx.y;
    const int n0 = wi * 128, t = threadIdx.x;
    const int lane = t & 31, wid = t >> 5;
    const int warpM = wid >> 2, warpN = wid & 3;
    const int mbase = warpM * 32;
    const int rl = lane & 15, cl8 = (lane >> 4) * 8;
    const int g = lane >> 2, tg = lane & 3;
    const int l7 = lane & 7, l8 = (lane >> 3) & 1;
    const int jstart = (wi == 0) ? 128 : 0;

    const u32 qh_s = (u32)__cvta_generic_to_shared(qhs);
    const u32 ql_s = (u32)__cvta_generic_to_shared(qls);
    const u32 kh_s = (u32)__cvta_generic_to_shared(khs);
    const u32 kl_s = (u32)__cvta_generic_to_shared(kls);
    const u32 vh_s = (u32)__cvta_generic_to_shared(vhs);
    const u32 vl_s = (u32)__cvta_generic_to_shared(vls);
    const u32 ph_s = (u32)__cvta_generic_to_shared(phs);
    const u32 pl_s = (u32)__cvta_generic_to_shared(pls);

    // ---- load q split ----
    for (int idx = t; idx < 8192; idx += 512) {
        int r = idx >> 6, c = idx & 63;
        ((u32*)qhs)[r*68 + c] = ((const u32*)(g_qh + (size_t)(b*N_ + n0 + r)*D_))[c];
        ((u32*)qls)[r*68 + c] = ((const u32*)(g_ql + (size_t)(b*N_ + n0 + r)*D_))[c];
    }

    u32 hR[4], lR[4];
    // prefetch k chunk 0
    {
        int nk0 = n0 - 128;
#pragma unroll
        for (int i = 0; i < 4; i++) {
            int idx = t + i*512;
            int r = idx >> 6, c2 = idx & 63;
            int nk = nk0 + r;
            hR[i] = 0; lR[i] = 0;
            if (nk >= 0) {
                hR[i] = *(const u32*)(g_kh + (size_t)(b*N_ + nk)*D_ + c2*2);
                lR[i] = *(const u32*)(g_kl + (size_t)(b*N_ + nk)*D_ + c2*2);
            }
        }
    }

    // ==== phase 1: S = q @ k^T ====
#pragma unroll 1
    for (int ch = 0; ch < 8; ch++) {
        __syncthreads();
#pragma unroll
        for (int i = 0; i < 4; i++) {
            int idx = t + i*512;
            int r = idx >> 6, c2 = idx & 63;
            ((u32*)khs)[r*68 + c2] = hR[i];
            ((u32*)kls)[r*68 + c2] = lR[i];
        }
        if (ch < 7) {
            int nk0 = n0 - 128 + (ch+1)*32;
#pragma unroll
            for (int i = 0; i < 4; i++) {
                int idx = t + i*512;
                int r = idx >> 6, c2 = idx & 63;
                int nk = nk0 + r;
                hR[i] = 0; lR[i] = 0;
                if (nk >= 0) {
                    hR[i] = *(const u32*)(g_kh + (size_t)(b*N_ + nk)*D_ + c2*2);
                    lR[i] = *(const u32*)(g_kl + (size_t)(b*N_ + nk)*D_ + c2*2);
                }
            }
        }
        __syncthreads();

        float acc[2][4];
#pragma unroll
        for (int mt = 0; mt < 2; mt++)
#pragma unroll
            for (int u = 0; u < 4; u++) acc[mt][u] = 0.0f;

#pragma unroll 1
        for (int kt = 0; kt < 8; kt++) {
            u32 ah[2][4], al[2][4];
#pragma unroll
            for (int mt = 0; mt < 2; mt++) {
                u32 off = (u32)((mbase + mt*16 + rl)*136 + kt*16 + cl8) * 2;
                ldmat4(ah[mt], qh_s + off);
                ldmat4(al[mt], ql_s + off);
            }
            u32 boff = (u32)((warpN*8 + l7)*136 + kt*16 + l8*8) * 2;
            u32 bh[2], bl[2];
            ldmat2(bh, kh_s + boff);
            ldmat2(bl, kl_s + boff);
#pragma unroll
            for (int mt = 0; mt < 2; mt++) {
                mma16816(acc[mt], ah[mt], bh[0], bh[1]);
                mma16816(acc[mt], al[mt], bh[0], bh[1]);
                mma16816(acc[mt], ah[mt], bl[0], bl[1]);
            }
        }
#pragma unroll
        for (int mt = 0; mt < 2; mt++) {
            int row = mbase + mt*16 + g;
            int col = ch*32 + warpN*8 + tg*2;
            *(float2*)(S + row*256 + col)     = make_float2(acc[mt][0], acc[mt][1]);
            *(float2*)(S + (row+8)*256 + col) = make_float2(acc[mt][2], acc[mt][3]);
        }
    }

    // prefetch v chunk 0
    {
        int nk0 = n0 - 128;
#pragma unroll
        for (int i = 0; i < 4; i++) {
            int idx = t + i*512;
            int dd = idx >> 4, c = idx & 15;
            int tok = nk0 + c*2;
            hR[i] = 0; lR[i] = 0;
            if (tok >= 0) {
                hR[i] = *(const u32*)(g_vh + (size_t)(b*D_ + dd)*N_ + tok);
                lR[i] = *(const u32*)(g_vl + (size_t)(b*D_ + dd)*N_ + tok);
            }
        }
    }
    __syncthreads();

    // ==== phase 2: softmax stats ====
    {
        int r = t >> 2, q4 = t & 3;
        int jend = 128 + r + 1;
        float m = -3.402823466e38f;
        for (int c4 = (jstart >> 2) + q4; c4*4 < jend; c4 += 4) {
            float4 v = *(const float4*)(S + r*256 + c4*4);
            int c = c4*4;
            if (c   < jend) m = fmaxf(m, v.x);
            if (c+1 < jend) m = fmaxf(m, v.y);
            if (c+2 < jend) m = fmaxf(m, v.z);
            if (c+3 < jend) m = fmaxf(m, v.w);
        }
        m = fmaxf(m, __shfl_xor_sync(0xFFFFFFFF, m, 1));
        m = fmaxf(m, __shfl_xor_sync(0xFFFFFFFF, m, 2));
        float s = 0.0f;
        for (int c4 = (jstart >> 2) + q4; c4*4 < jend; c4 += 4) {
            float4 v = *(const float4*)(S + r*256 + c4*4);
            int c = c4*4;
            if (c   < jend) s += __expf(v.x - m);
            if (c+1 < jend) s += __expf(v.y - m);
            if (c+2 < jend) s += __expf(v.z - m);
            if (c+3 < jend) s += __expf(v.w - m);
        }
        s += __shfl_xor_sync(0xFFFFFFFF, s, 1);
        s += __shfl_xor_sync(0xFFFFFFFF, s, 2);
        if (q4 == 0) { mrow[r] = m; irow[r] = 1.0f / s; }
    }

    // ==== phase 3: OUT = P @ V ====
    float accP[2][4][4];
#pragma unroll
    for (int mt = 0; mt < 2; mt++)
#pragma unroll
        for (int nt = 0; nt < 4; nt++)
#pragma unroll
            for (int u = 0; u < 4; u++) accP[mt][nt][u] = 0.0f;

#pragma unroll 1
    for (int ch = 0; ch < 8; ch++) {
        __syncthreads();
#pragma unroll
        for (int i = 0; i < 4; i++) {
            int idx = t + i*512;
            int dd = idx >> 4, c = idx & 15;
            *(u32*)((u16*)vhs + dd*40 + c*2) = hR[i];
            *(u32*)((u16*)vls + dd*40 + c*2) = lR[i];
        }
        // convert P chunk
        {
            int r = t >> 2, c0l = (t & 3) * 8;
            float mm = mrow[r], ii = irow[r];
            int jend = 128 + r + 1;
#pragma unroll
            for (int i4 = 0; i4 < 2; i4++) {
                int cg = ch*32 + c0l + i4*4;
                float4 s4 = *(const float4*)(S + r*256 + cg);
                float p[4];
                p[0] = (cg   >= jstart && cg   < jend) ? __expf(s4.x - mm) * ii : 0.0f;
                p[1] = (cg+1 >= jstart && cg+1 < jend) ? __expf(s4.y - mm) * ii : 0.0f;
                p[2] = (cg+2 >= jstart && cg+2 < jend) ? __expf(s4.z - mm) * ii : 0.0f;
                p[3] = (cg+3 >= jstart && cg+3 < jend) ? __expf(s4.w - mm) * ii : 0.0f;
                __nv_bfloat16 h0 = __float2bfloat16(p[0]);
                __nv_bfloat16 h1 = __float2bfloat16(p[1]);
                __nv_bfloat16 h2 = __float2bfloat16(p[2]);
                __nv_bfloat16 h3 = __float2bfloat16(p[3]);
                int di = (r*40 + c0l + i4*4) >> 1;
                ((u32*)phs)[di]   = packbf(__bfloat162float(h0), __bfloat162float(h1));
                ((u32*)phs)[di+1] = packbf(__bfloat162float(h2), __bfloat162float(h3));
                ((u32*)pls)[di]   = packbf(p[0] - __bfloat162float(h0), p[1] - __bfloat162float(h1));
                ((u32*)pls)[di+1] = packbf(p[2] - __bfloat162float(h2), p[3] - __bfloat162float(h3));
            }
        }
        // prefetch next v chunk
        if (ch < 7) {
            int nk0 = n0 - 128 + (ch+1)*32;
#pragma unroll
            for (int i = 0; i < 4; i++) {
                int idx = t + i*512;
                int dd = idx >> 4, c = idx & 15;
                int tok = nk0 + c*2;
                hR[i] = 0; lR[i] = 0;
                if (tok >= 0) {
                    hR[i] = *(const u32*)(g_vh + (size_t)(b*D_ + dd)*N_ + tok);
                    lR[i] = *(const u32*)(g_vl + (size_t)(b*D_ + dd)*N_ + tok);
                }
            }
        }
        __syncthreads();

#pragma unroll
        for (int kt = 0; kt < 2; kt++) {
            u32 pa[2][4], pb[2][4];
#pragma unroll
            for (int mt = 0; mt < 2; mt++) {
                u32 off = (u32)((mbase + mt*16 + rl)*40 + kt*16 + cl8) * 2;
                ldmat4(pa[mt], ph_s + off);
                ldmat4(pb[mt], pl_s + off);
            }
#pragma unroll
            for (int nt = 0; nt < 4; nt++) {
                u32 boff = (u32)((warpN*32 + nt*8 + l7)*40 + kt*16 + l8*8) * 2;
                u32 vh2[2], vl2[2];
                ldmat2(vh2, vh_s + boff);
                ldmat2(vl2, vl_s + boff);
#pragma unroll
                for (int mt = 0; mt < 2; mt++) {
                    mma16816(accP[mt][nt], pa[mt], vh2[0], vh2[1]);
                    mma16816(accP[mt][nt], pb[mt], vh2[0], vh2[1]);
                    mma16816(accP[mt][nt], pa[mt], vl2[0], vl2[1]);
                }
            }
        }
    }

    // ---- epilogue: split bf16 attention output ----
#pragma unroll
    for (int mt = 0; mt < 2; mt++)
#pragma unroll
        for (int nt = 0; nt < 4; nt++) {
            int row = mbase + mt*16 + g;
            int col = warpN*32 + nt*8 + tg*2;
#pragma unroll
            for (int half = 0; half < 2; half++) {
                float v0 = accP[mt][nt][half*2];
                float v1 = accP[mt][nt][half*2+1];
                __nv_bfloat16 h0 = __float2bfloat16(v0);
                __nv_bfloat16 h1 = __float2bfloat16(v1);
                size_t off = (size_t)(b*N_ + n0 + row + half*8)*D_ + col;
                *(u32*)(g_ah + off) = packbf(__bfloat162float(h0), __bfloat162float(h1));
                *(u32*)(g_al + off) = packbf(v0 - __bfloat162float(h0), v1 - __bfloat162float(h1));
            }
        }
}

// ---------------- tensor-core 1x1 conv -> d_out (B,D,N) ----------------
#define C1_AH 0
#define C1_AL 34816
#define C1_WH 69632
#define C1_WL 104448
#define C1T_SMEM 139264

__global__ __launch_bounds__(512) void conv1x1_tc(const float* __restrict__ ob_,
                                                  float* __restrict__ out) {
    extern __shared__ char sm8[];
    __nv_bfloat16* ahs = (__nv_bfloat16*)(sm8 + C1_AH);
    __nv_bfloat16* als = (__nv_bfloat16*)(sm8 + C1_AL);
    __nv_bfloat16* whs = (__nv_bfloat16*)(sm8 + C1_WH);
    __nv_bfloat16* wls = (__nv_bfloat16*)(sm8 + C1_WL);

    const int b = blockIdx.y, n0 = blockIdx.x * 128;
    const int t = threadIdx.x;
    const int lane = t & 31, wid = t >> 5;
    const int warpM = wid >> 2, warpN = wid & 3;
    const int mbase = warpM * 32, nbase = warpN * 32;
    const int rl = lane & 15, cl8 = (lane >> 4) * 8;
    const int g = lane >> 2, tg = lane & 3;
    const int l7 = lane & 7, l8 = (lane >> 3) & 1;

    for (int idx = t; idx < 8192; idx += 512) {
        int r = idx >> 6, c = idx & 63;
        ((u32*)ahs)[r*68 + c] = ((const u32*)(g_ah + (size_t)(b*N_ + n0 + r)*D_))[c];
        ((u32*)als)[r*68 + c] = ((const u32*)(g_al + (size_t)(b*N_ + n0 + r)*D_))[c];
        ((u32*)whs)[r*68 + c] = ((const u32*)(g_owh + (size_t)r*D_))[c];
        ((u32*)wls)[r*68 + c] = ((const u32*)(g_owl + (size_t)r*D_))[c];
    }
    __syncthreads();

    const u32 ah_s = (u32)__cvta_generic_to_shared(ahs);
    const u32 al_s = (u32)__cvta_generic_to_shared(als);
    const u32 wh_s = (u32)__cvta_generic_to_shared(whs);
    const u32 wl_s = (u32)__cvta_generic_to_shared(wls);

    float acc[2][4][4];
#pragma unroll
    for (int mt = 0; mt < 2; mt++)
#pragma unroll
        for (int nt = 0; nt < 4; nt++)
#pragma unroll
            for (int u = 0; u < 4; u++) acc[mt][nt][u] = 0.0f;

#pragma unroll 1
    for (int kt = 0; kt < 8; kt++) {
        u32 aH[2][4], aL[2][4];
#pragma unroll
        for (int mt = 0; mt < 2; mt++) {
            u32 off = (u32)((mbase + mt*16 + rl)*136 + kt*16 + cl8) * 2;
            ldmat4(aH[mt], ah_s + off);
            ldmat4(aL[mt], al_s + off);
        }
#pragma unroll
        for (int nt = 0; nt < 4; nt++) {
            u32 boff = (u32)((nbase + nt*8 + l7)*136 + kt*16 + l8*8) * 2;
            u32 wh2[2], wl2[2];
            ldmat2(wh2, wh_s + boff);
            ldmat2(wl2, wl_s + boff);
#pragma unroll
            for (int mt = 0; mt < 2; mt++) {
                mma16816(acc[mt][nt], aH[mt], wh2[0], wh2[1]);
                mma16816(acc[mt][nt], aL[mt], wh2[0], wh2[1]);
                mma16816(acc[mt][nt], aH[mt], wl2[0], wl2[1]);
            }
        }
    }

    // epilogue: transposed write (B,D,N) + bias
#pragma unroll
    for (int mt = 0; mt < 2; mt++)
#pragma unroll
        for (int nt = 0; nt < 4; nt++) {
            int row = mbase + mt*16 + g;
            int col = nbase + nt*8 + tg*2;
#pragma unroll
            for (int u = 0; u < 4; u++) {
                int dd  = col + (u & 1);
                int tok = n0 + row + (u >> 1)*8;
                out[(size_t)(b*D_ + dd)*N_ + tok] = acc[mt][nt][u] + ob_[dd];
            }
        }
}

// ---------------- BatchNorm ----------------
__global__ void bn_stats(const float* __restrict__ y, const float* __restrict__ gamma,
                         const float* __restrict__ beta) {
    int d = blockIdx.x, t = threadIdx.x;
    double s = 0.0, s2 = 0.0;
    for (int b = 0; b < B_; b++) {
        const float* p = y + (size_t)(b*D_ + d) * N_;
        for (int n = t; n < N_; n += 256) { double v = p[n]; s += v; s2 += v*v; }
    }
    __shared__ double sh[512];
    sh[t] = s; sh[256 + t] = s2;
    __syncthreads();
    for (int o = 128; o > 0; o >>= 1) {
        if (t < o) { sh[t] += sh[t+o]; sh[256+t] += sh[256+t+o]; }
        __syncthreads();
    }
    if (t == 0) {
        double cnt = (double)B_ * (double)N_;
        double m = sh[0] / cnt;
        double var = sh[256] / cnt - m*m;
        double rs = rsqrt(var + 1e-5);
        double sc = rs * (double)gamma[d];
        g_scale[d] = (float)sc;
        g_shift[d] = (float)((double)beta[d] - m*sc);
    }
}

__global__ void bn_apply(float* __restrict__ y) {
    int i = (blockIdx.x * 256 + threadIdx.x) * 4;
    int d = (i >> 13) & 127;
    float sc = g_scale[d], sh = g_shift[d];
    float4 v = *(float4*)(y + i);
    v.x = v.x*sc + sh; v.y = v.y*sc + sh; v.z = v.z*sc + sh; v.w = v.w*sc + sh;
    *(float4*)(y + i) = v;
}

// ---------------- launch ----------------
extern "C" void kernel_launch(void* const* d_in, const int* in_sizes, int n_in,
                              void* d_out, int out_size) {
    const float* x  = (const float*)d_in[0];
    const float* qw = (const float*)d_in[1];
    const float* qb = (const float*)d_in[2];
    const float* kw = (const float*)d_in[3];
    const float* kb = (const float*)d_in[4];
    const float* vw = (const float*)d_in[5];
    const float* vb = (const float*)d_in[6];
    const float* ow = (const float*)d_in[7];
    const float* ob = (const float*)d_in[8];
    const float* gamma = (const float*)d_in[9];
    const float* beta  = (const float*)d_in[10];
    float* out = (float*)d_out;

    cudaFuncSetAttribute(qkv_tc, cudaFuncAttributeMaxDynamicSharedMemorySize, QKV_TC_SMEM);
    cudaFuncSetAttribute(attn_tc, cudaFuncAttributeMaxDynamicSharedMemorySize, AT_SMEM);
    cudaFuncSetAttribute(conv1x1_tc, cudaFuncAttributeMaxDynamicSharedMemorySize, C1T_SMEM);

    prep_wsplit<<<(3*8*5*128*16 + 255) / 256, 256>>>(qw, kw, vw);
    prep_owsplit<<<(D_*D_ + 255) / 256, 256>>>(ow);
    prep_trig<<<(N_*64) / 256, 256>>>();
    qkv_tc<<<dim3(N_/128, B_), 512, QKV_TC_SMEM>>>(x, qb, kb, vb);
    attn_tc<<<dim3(NW_, B_), 512, AT_SMEM>>>();
    conv1x1_tc<<<dim3(N_/128, B_), 512, C1T_SMEM>>>(ob, out);
    bn_stats<<<D_, 256>>>(out, gamma, beta);
    bn_apply<<<(B_*D_*N_) / 1024, 256>>>(out);
}

// round 11
// speedup vs baseline: 2.3617x; 1.0592x over previous
#include <cuda_runtime.h>
#include <cuda_bf16.h>
#include <math.h>

#define B_ 16
#define D_ 128
#define N_ 8192
#define NW_ 64

typedef unsigned long long ull;
typedef unsigned int u32;
typedef unsigned short u16;

// ---------------- device scratch ----------------
__device__ __align__(16) __nv_bfloat16 g_wsp[3*8*2*5*128*16];
__device__ float g_cs[N_*64];
__device__ float g_sn[N_*64];
__device__ __align__(16) __nv_bfloat16 g_qh[B_*N_*D_];   // (B,N,D) rotary+scaled
__device__ __align__(16) __nv_bfloat16 g_ql[B_*N_*D_];
__device__ __align__(16) __nv_bfloat16 g_kh[B_*N_*D_];   // (B,N,D) rotary
__device__ __align__(16) __nv_bfloat16 g_kl[B_*N_*D_];
__device__ __align__(16) __nv_bfloat16 g_vh[B_*D_*N_];   // (B,D,N) transposed
__device__ __align__(16) __nv_bfloat16 g_vl[B_*D_*N_];
__device__ __align__(16) __nv_bfloat16 g_ah[B_*N_*D_];   // attention out, split
__device__ __align__(16) __nv_bfloat16 g_al[B_*N_*D_];
__device__ __align__(16) __nv_bfloat16 g_owh[D_*D_];     // 1x1 weights split
__device__ __align__(16) __nv_bfloat16 g_owl[D_*D_];
__device__ float g_scale[D_];
__device__ float g_shift[D_];

// ---------------- mma / async helpers ----------------
__device__ __forceinline__ void mma16816(float* c, const u32* a, u32 b0, u32 b1) {
    asm("mma.sync.aligned.m16n8k16.row.col.f32.bf16.bf16.f32 "
        "{%0,%1,%2,%3}, {%4,%5,%6,%7}, {%8,%9}, {%0,%1,%2,%3};"
        : "+f"(c[0]), "+f"(c[1]), "+f"(c[2]), "+f"(c[3])
        : "r"(a[0]), "r"(a[1]), "r"(a[2]), "r"(a[3]), "r"(b0), "r"(b1));
}
__device__ __forceinline__ void ldmat4(u32* r, u32 addr) {
    asm volatile("ldmatrix.sync.aligned.m8n8.x4.shared.b16 {%0,%1,%2,%3}, [%4];"
                 : "=r"(r[0]), "=r"(r[1]), "=r"(r[2]), "=r"(r[3]) : "r"(addr));
}
__device__ __forceinline__ void ldmat2(u32* r, u32 addr) {
    asm volatile("ldmatrix.sync.aligned.m8n8.x2.shared.b16 {%0,%1}, [%2];"
                 : "=r"(r[0]), "=r"(r[1]) : "r"(addr));
}
__device__ __forceinline__ u32 packbf(float a, float b) {
    __nv_bfloat162 t = __floats2bfloat162_rn(a, b);
    return *(u32*)&t;
}
#define CP_ASYNC16(dst, src) \
    asm volatile("cp.async.cg.shared.global [%0], [%1], 16;" :: "r"(dst), "l"(src))
#define CP_COMMIT() asm volatile("cp.async.commit_group;" ::: "memory")
#define CP_WAIT0()  asm volatile("cp.async.wait_group 0;" ::: "memory")

// W block byte stride: 20480 elements * 2 B = 40960 B per (conv,ch) block
#define WBLK_BYTES 40960

// ---------------- prep ----------------
// W layout per (conv,ch) block: [plane 2][tap 5][o 128][ii 16] bf16,
// with 16B XOR swizzle on (o&4) to make B-ldmatrix conflict-free.
__global__ void prep_wsplit(const float* __restrict__ qw, const float* __restrict__ kw,
                            const float* __restrict__ vw) {
    int e = blockIdx.x * blockDim.x + threadIdx.x;
    if (e >= 3*8*5*128*16) return;
    int ii = e % 16;
    int o  = (e / 16) % 128;
    int t  = (e / 2048) % 5;
    int ch = (e / 10240) % 8;
    int c  = e / 81920;
    const float* w = (c == 0) ? qw : (c == 1) ? kw : vw;
    float v = w[o*640 + (ch*16 + ii)*5 + t];
    __nv_bfloat16 hi = __float2bfloat16(v);
    __nv_bfloat16 lo = __float2bfloat16(v - __bfloat162float(hi));
    int base = (c*8 + ch) * 20480;              // elements
    int iisw = ii ^ ((o & 4) ? 8 : 0);          // 16B-granule swizzle
    int off  = t*2048 + o*16 + iisw;
    g_wsp[base + off]         = hi;
    g_wsp[base + 10240 + off] = lo;
}

__global__ void prep_owsplit(const float* __restrict__ ow) {
    int e = blockIdx.x * blockDim.x + threadIdx.x;
    if (e >= D_*D_) return;
    float v = ow[e];
    __nv_bfloat16 hi = __float2bfloat16(v);
    g_owh[e] = hi;
    g_owl[e] = __float2bfloat16(v - __bfloat162float(hi));
}

__global__ void prep_trig() {
    __shared__ float invf_s[64];
    int t = threadIdx.x;
    if (t < 64) invf_s[t] = (float)pow(10000.0, -((double)(2*t)) / 128.0);
    __syncthreads();
    int e = blockIdx.x * 256 + t;
    int n = e >> 6, f = e & 63;
    float ang = (float)n * invf_s[f];
    double s, c;
    sincos((double)ang, &s, &c);
    g_cs[e] = (float)c;
    g_sn[e] = (float)s;
}

// ---------- tensor-core fused QKV conv (512 thr, cp.async W dbl-buf, swizzled ldmat4-B) ----------
#define XH_OFF 0
#define XL_OFF 35904
#define W_OFF  71808          // two 40960B buffers
#define KSM_OFF 153728
#define QKV_TC_SMEM 221312
#define XSTR 136

__global__ __launch_bounds__(512) void qkv_tc(const float* __restrict__ x,
                                              const float* __restrict__ qb,
                                              const float* __restrict__ kb,
                                              const float* __restrict__ vb) {
    extern __shared__ char smem[];
    __nv_bfloat16* xh = (__nv_bfloat16*)(smem + XH_OFF);
    __nv_bfloat16* xl = (__nv_bfloat16*)(smem + XL_OFF);
    float* ksm = (float*)(smem + KSM_OFF);
    float* qsm = (float*)(smem + XH_OFF);

    const int b = blockIdx.y, n0 = blockIdx.x * 128;
    const int t = threadIdx.x;
    const int lane = t & 31, wid = t >> 5;
    const int warpM = wid >> 2, warpN = wid & 3;
    const int mbase = warpM * 32, nbase = warpN * 32;

    const u32 w_s  = (u32)__cvta_generic_to_shared(smem + W_OFF);

    // prologue: async-load W chunk 0 (c=2,ch=0 -> block 16) into buffer 0
    {
        const char* src = (const char*)g_wsp + (size_t)16 * WBLK_BYTES + t*16;
        u32 dst = w_s + t*16;
#pragma unroll
        for (int k2 = 0; k2 < 5; k2++)
            CP_ASYNC16(dst + k2*8192, src + k2*8192);
        CP_COMMIT();
    }

    for (int idx = t; idx < 128*132; idx += 512) {
        int i = idx / 132, c = idx % 132;
        int n = n0 - 4 + c;
        float v = (n >= 0) ? x[(size_t)(b*D_ + i)*N_ + n] : 0.0f;
        __nv_bfloat16 hi = __float2bfloat16(v);
        xh[c*XSTR + i] = hi;
        xl[c*XSTR + i] = __float2bfloat16(v - __bfloat162float(hi));
    }

    const u32 xh_s = (u32)__cvta_generic_to_shared(xh);
    const u32 xl_s = (u32)__cvta_generic_to_shared(xl);
    const int rl = lane & 15, cl8 = (lane >> 4) * 8;

    // B-ldmatrix per-lane addresses (constant across taps/chunks):
    // lanes 0-7: rows nbase..+7 k0-7; 8-15: same rows k8-15;
    // 16-23: rows nbase+8..15 k0-7; 24-31: same k8-15 (XOR-swizzled)
    const int oA = nbase + ((lane >> 4) & 1)*8 + (lane & 7);        // nt pair 0
    const u32 koffA = (u32)((((lane >> 3) & 1)*16) ^ ((oA & 4) ? 16 : 0));
    const u32 bA = (u32)(oA*32) + koffA;
    const int oB = oA + 16;                                          // nt pair 1
    const u32 koffB = (u32)((((lane >> 3) & 1)*16) ^ ((oB & 4) ? 16 : 0));
    const u32 bB = (u32)(oB*32) + koffB;

#pragma unroll 1
    for (int cl = 0; cl < 3; cl++) {
        float acc[2][4][4];
#pragma unroll
        for (int mt = 0; mt < 2; mt++)
#pragma unroll
            for (int nt = 0; nt < 4; nt++)
#pragma unroll
                for (int u = 0; u < 4; u++) acc[mt][nt][u] = 0.0f;

#pragma unroll 1
        for (int ch = 0; ch < 8; ch++) {
            const int idx = cl*8 + ch;
            CP_WAIT0();
            __syncthreads();
            // issue prefetch of chunk idx+1 into the other buffer
            int nidx = idx + 1;
            if (nidx < 24) {
                int cl2 = nidx >> 3, ch2 = nidx & 7;
                int c2 = (cl2 == 0) ? 2 : (cl2 == 1) ? 1 : 0;
                const char* src = (const char*)g_wsp + (size_t)(c2*8 + ch2)*WBLK_BYTES + t*16;
                u32 dst = w_s + (u32)(nidx & 1)*40960 + t*16;
#pragma unroll
                for (int k2 = 0; k2 < 5; k2++)
                    CP_ASYNC16(dst + k2*8192, src + k2*8192);
            }
            CP_COMMIT();

            const u32 wb = w_s + (u32)(idx & 1)*40960;

#pragma unroll 1
            for (int tap = 0; tap < 5; tap++) {
                u32 ah[2][4], al[2][4];
#pragma unroll
                for (int mt = 0; mt < 2; mt++) {
                    int row = mbase + mt*16 + rl + tap;
                    int col = ch*16 + cl8;
                    u32 off = (u32)(row*XSTR + col) * 2;
                    ldmat4(ah[mt], xh_s + off);
                    ldmat4(al[mt], xl_s + off);
                }
                const u32 tb = wb + (u32)(tap*4096);
                u32 bh0[4], bl0[4], bh1[4], bl1[4];
                ldmat4(bh0, tb + bA);
                ldmat4(bl0, tb + 20480 + bA);
                ldmat4(bh1, tb + bB);
                ldmat4(bl1, tb + 20480 + bB);
#pragma unroll
                for (int mt = 0; mt < 2; mt++) {
                    mma16816(acc[mt][0], ah[mt], bh0[0], bh0[1]);
                    mma16816(acc[mt][0], ah[mt], bl0[0], bl0[1]);
                    mma16816(acc[mt][0], al[mt], bh0[0], bh0[1]);
                    mma16816(acc[mt][1], ah[mt], bh0[2], bh0[3]);
                    mma16816(acc[mt][1], ah[mt], bl0[2], bl0[3]);
                    mma16816(acc[mt][1], al[mt], bh0[2], bh0[3]);
                    mma16816(acc[mt][2], ah[mt], bh1[0], bh1[1]);
                    mma16816(acc[mt][2], ah[mt], bl1[0], bl1[1]);
                    mma16816(acc[mt][2], al[mt], bh1[0], bh1[1]);
                    mma16816(acc[mt][3], ah[mt], bh1[2], bh1[3]);
                    mma16816(acc[mt][3], ah[mt], bl1[2], bl1[3]);
                    mma16816(acc[mt][3], al[mt], bh1[2], bh1[3]);
                }
            }
        }

        if (cl == 0) {            // v -> transposed global split
#pragma unroll
            for (int mt = 0; mt < 2; mt++)
#pragma unroll
                for (int nt = 0; nt < 4; nt++) {
                    int row = mbase + mt*16 + (lane >> 2);
                    int col = nbase + nt*8 + (lane & 3)*2;
#pragma unroll
                    for (int u = 0; u < 4; u++) {
                        int dd  = col + (u & 1);
                        int tok = n0 + row + (u >> 1)*8;
                        float vv = acc[mt][nt][u] + vb[dd];
                        __nv_bfloat16 h = __float2bfloat16(vv);
                        size_t off = (size_t)(b*D_ + dd)*N_ + tok;
                        g_vh[off] = h;
                        g_vl[off] = __float2bfloat16(vv - __bfloat162float(h));
                    }
                }
        } else if (cl == 1) {     // k -> ksm fp32 + bias
#pragma unroll
            for (int mt = 0; mt < 2; mt++)
#pragma unroll
                for (int nt = 0; nt < 4; nt++) {
                    int row = mbase + mt*16 + (lane >> 2);
                    int col = nbase + nt*8 + (lane & 3)*2;
                    float b0 = kb[col], b1 = kb[col+1];
                    ksm[row*132 + col]       = acc[mt][nt][0] + b0;
                    ksm[row*132 + col + 1]   = acc[mt][nt][1] + b1;
                    ksm[(row+8)*132 + col]   = acc[mt][nt][2] + b0;
                    ksm[(row+8)*132 + col+1] = acc[mt][nt][3] + b1;
                }
        } else {                  // q -> qsm (overlays x)
            __syncthreads();
#pragma unroll
            for (int mt = 0; mt < 2; mt++)
#pragma unroll
                for (int nt = 0; nt < 4; nt++) {
                    int row = mbase + mt*16 + (lane >> 2);
                    int col = nbase + nt*8 + (lane & 3)*2;
                    float b0 = qb[col], b1 = qb[col+1];
                    qsm[row*132 + col]       = acc[mt][nt][0] + b0;
                    qsm[row*132 + col + 1]   = acc[mt][nt][1] + b1;
                    qsm[(row+8)*132 + col]   = acc[mt][nt][2] + b0;
                    qsm[(row+8)*132 + col+1] = acc[mt][nt][3] + b1;
                }
        }
    }
    __syncthreads();

    // ---- rotary + scale -> split bf16 globals ----
    const float scl = 0.08838834764831845f;
    const int d = t & 127, h = t >> 7;
    const int dp = (d + 64) & 127;
    const float sg = (d < 64) ? -1.0f : 1.0f;
    const int f = d & 63;
    for (int j = h; j < 128; j += 4) {
        int n = n0 + j;
        float cc = g_cs[n*64 + f], ss = g_sn[n*64 + f];
        float qv = qsm[j*132 + d], qh2 = sg * qsm[j*132 + dp];
        float kv = ksm[j*132 + d], kh2 = sg * ksm[j*132 + dp];
        float qf = (qv*cc + qh2*ss) * scl;
        float kf = kv*cc + kh2*ss;
        size_t o = (size_t)(b*N_ + n)*128 + d;
        __nv_bfloat16 qhi = __float2bfloat16(qf);
        __nv_bfloat16 khi = __float2bfloat16(kf);
        g_qh[o] = qhi; g_ql[o] = __float2bfloat16(qf - __bfloat162float(qhi));
        g_kh[o] = khi; g_kl[o] = __float2bfloat16(kf - __bfloat162float(khi));
    }
}

// ---------------- tensor-core windowed attention (unchanged from R9) ----------------
#define AT_QH 0
#define AT_S  34816
#define AT_QL 165888
#define AT_KH 200704
#define AT_KL 209408
#define AT_VH 165888
#define AT_VL 176128
#define AT_PH 186368
#define AT_PL 196608
#define AT_M  218112
#define AT_I  218624
#define AT_SMEM 219136

__global__ __launch_bounds__(512) void attn_tc() {
    extern __shared__ char sm8[];
    __nv_bfloat16* qhs = (__nv_bfloat16*)(sm8 + AT_QH);
    float*         S   = (float*)(sm8 + AT_S);
    __nv_bfloat16* qls = (__nv_bfloat16*)(sm8 + AT_QL);
    __nv_bfloat16* khs = (__nv_bfloat16*)(sm8 + AT_KH);
    __nv_bfloat16* kls = (__nv_bfloat16*)(sm8 + AT_KL);
    __nv_bfloat16* vhs = (__nv_bfloat16*)(sm8 + AT_VH);
    __nv_bfloat16* vls = (__nv_bfloat16*)(sm8 + AT_VL);
    __nv_bfloat16* phs = (__nv_bfloat16*)(sm8 + AT_PH);
    __nv_bfloat16* pls = (__nv_bfloat16*)(sm8 + AT_PL);
    float* mrow = (float*)(sm8 + AT_M);
    float* irow = (float*)(sm8 + AT_I);

    const int wi = blockIdx.x, b = blockIdx.y;
    const int n0 = wi * 128, t = threadIdx.x;
    const int lane = t & 31, wid = t >> 5;
    const int warpM = wid >> 2, warpN = wid & 3;
    const int mbase = warpM * 32;
    const int rl = lane & 15, cl8 = (lane >> 4) * 8;
    const int g = lane >> 2, tg = lane & 3;
    const int l7 = lane & 7, l8 = (lane >> 3) & 1;
    const int jstart = (wi == 0) ? 128 : 0;

    const u32 qh_s = (u32)__cvta_generic_to_shared(qhs);
    const u32 ql_s = (u32)__cvta_generic_to_shared(qls);
    const u32 kh_s = (u32)__cvta_generic_to_shared(khs);
    const u32 kl_s = (u32)__cvta_generic_to_shared(kls);
    const u32 vh_s = (u32)__cvta_generic_to_shared(vhs);
    const u32 vl_s = (u32)__cvta_generic_to_shared(vls);
    const u32 ph_s = (u32)__cvta_generic_to_shared(phs);
    const u32 pl_s = (u32)__cvta_generic_to_shared(pls);

    for (int idx = t; idx < 8192; idx += 512) {
        int r = idx >> 6, c = idx & 63;
        ((u32*)qhs)[r*68 + c] = ((const u32*)(g_qh + (size_t)(b*N_ + n0 + r)*D_))[c];
        ((u32*)qls)[r*68 + c] = ((const u32*)(g_ql + (size_t)(b*N_ + n0 + r)*D_))[c];
    }

    u32 hR[4], lR[4];
    {
        int nk0 = n0 - 128;
#pragma unroll
        for (int i = 0; i < 4; i++) {
            int idx = t + i*512;
            int r = idx >> 6, c2 = idx & 63;
            int nk = nk0 + r;
            hR[i] = 0; lR[i] = 0;
            if (nk >= 0) {
                hR[i] = *(const u32*)(g_kh + (size_t)(b*N_ + nk)*D_ + c2*2);
                lR[i] = *(const u32*)(g_kl + (size_t)(b*N_ + nk)*D_ + c2*2);
            }
        }
    }

#pragma unroll 1
    for (int ch = 0; ch < 8; ch++) {
        __syncthreads();
#pragma unroll
        for (int i = 0; i < 4; i++) {
            int idx = t + i*512;
            int r = idx >> 6, c2 = idx & 63;
            ((u32*)khs)[r*68 + c2] = hR[i];
            ((u32*)kls)[r*68 + c2] = lR[i];
        }
        if (ch < 7) {
            int nk0 = n0 - 128 + (ch+1)*32;
#pragma unroll
            for (int i = 0; i < 4; i++) {
                int idx = t + i*512;
                int r = idx >> 6, c2 = idx & 63;
                int nk = nk0 + r;
                hR[i] = 0; lR[i] = 0;
                if (nk >= 0) {
                    hR[i] = *(const u32*)(g_kh + (size_t)(b*N_ + nk)*D_ + c2*2);
                    lR[i] = *(const u32*)(g_kl + (size_t)(b*N_ + nk)*D_ + c2*2);
                }
            }
        }
        __syncthreads();

        float acc[2][4];
#pragma unroll
        for (int mt = 0; mt < 2; mt++)
#pragma unroll
            for (int u = 0; u < 4; u++) acc[mt][u] = 0.0f;

#pragma unroll 1
        for (int kt = 0; kt < 8; kt++) {
            u32 ah[2][4], al[2][4];
#pragma unroll
            for (int mt = 0; mt < 2; mt++) {
                u32 off = (u32)((mbase + mt*16 + rl)*136 + kt*16 + cl8) * 2;
                ldmat4(ah[mt], qh_s + off);
                ldmat4(al[mt], ql_s + off);
            }
            u32 boff = (u32)((warpN*8 + l7)*136 + kt*16 + l8*8) * 2;
            u32 bh[2], bl[2];
            ldmat2(bh, kh_s + boff);
            ldmat2(bl, kl_s + boff);
#pragma unroll
            for (int mt = 0; mt < 2; mt++) {
                mma16816(acc[mt], ah[mt], bh[0], bh[1]);
                mma16816(acc[mt], al[mt], bh[0], bh[1]);
                mma16816(acc[mt], ah[mt], bl[0], bl[1]);
            }
        }
#pragma unroll
        for (int mt = 0; mt < 2; mt++) {
            int row = mbase + mt*16 + g;
            int col = ch*32 + warpN*8 + tg*2;
            *(float2*)(S + row*256 + col)     = make_float2(acc[mt][0], acc[mt][1]);
            *(float2*)(S + (row+8)*256 + col) = make_float2(acc[mt][2], acc[mt][3]);
        }
    }

    {
        int nk0 = n0 - 128;
#pragma unroll
        for (int i = 0; i < 4; i++) {
            int idx = t + i*512;
            int dd = idx >> 4, c = idx & 15;
            int tok = nk0 + c*2;
            hR[i] = 0; lR[i] = 0;
            if (tok >= 0) {
                hR[i] = *(const u32*)(g_vh + (size_t)(b*D_ + dd)*N_ + tok);
                lR[i] = *(const u32*)(g_vl + (size_t)(b*D_ + dd)*N_ + tok);
            }
        }
    }
    __syncthreads();

    {
        int r = t >> 2, q4 = t & 3;
        int jend = 128 + r + 1;
        float m = -3.402823466e38f;
        for (int c4 = (jstart >> 2) + q4; c4*4 < jend; c4 += 4) {
            float4 v = *(const float4*)(S + r*256 + c4*4);
            int c = c4*4;
            if (c   < jend) m = fmaxf(m, v.x);
            if (c+1 < jend) m = fmaxf(m, v.y);
            if (c+2 < jend) m = fmaxf(m, v.z);
            if (c+3 < jend) m = fmaxf(m, v.w);
        }
        m = fmaxf(m, __shfl_xor_sync(0xFFFFFFFF, m, 1));
        m = fmaxf(m, __shfl_xor_sync(0xFFFFFFFF, m, 2));
        float s = 0.0f;
        for (int c4 = (jstart >> 2) + q4; c4*4 < jend; c4 += 4) {
            float4 v = *(const float4*)(S + r*256 + c4*4);
            int c = c4*4;
            if (c   < jend) s += __expf(v.x - m);
            if (c+1 < jend) s += __expf(v.y - m);
            if (c+2 < jend) s += __expf(v.z - m);
            if (c+3 < jend) s += __expf(v.w - m);
        }
        s += __shfl_xor_sync(0xFFFFFFFF, s, 1);
        s += __shfl_xor_sync(0xFFFFFFFF, s, 2);
        if (q4 == 0) { mrow[r] = m; irow[r] = 1.0f / s; }
    }

    float accP[2][4][4];
#pragma unroll
    for (int mt = 0; mt < 2; mt++)
#pragma unroll
        for (int nt = 0; nt < 4; nt++)
#pragma unroll
            for (int u = 0; u < 4; u++) accP[mt][nt][u] = 0.0f;

#pragma unroll 1
    for (int ch = 0; ch < 8; ch++) {
        __syncthreads();
#pragma unroll
        for (int i = 0; i < 4; i++) {
            int idx = t + i*512;
            int dd = idx >> 4, c = idx & 15;
            *(u32*)((u16*)vhs + dd*40 + c*2) = hR[i];
            *(u32*)((u16*)vls + dd*40 + c*2) = lR[i];
        }
        {
            int r = t >> 2, c0l = (t & 3) * 8;
            float mm = mrow[r], ii = irow[r];
            int jend = 128 + r + 1;
#pragma unroll
            for (int i4 = 0; i4 < 2; i4++) {
                int cg = ch*32 + c0l + i4*4;
                float4 s4 = *(const float4*)(S + r*256 + cg);
                float p[4];
                p[0] = (cg   >= jstart && cg   < jend) ? __expf(s4.x - mm) * ii : 0.0f;
                p[1] = (cg+1 >= jstart && cg+1 < jend) ? __expf(s4.y - mm) * ii : 0.0f;
                p[2] = (cg+2 >= jstart && cg+2 < jend) ? __expf(s4.z - mm) * ii : 0.0f;
                p[3] = (cg+3 >= jstart && cg+3 < jend) ? __expf(s4.w - mm) * ii : 0.0f;
                __nv_bfloat16 h0 = __float2bfloat16(p[0]);
                __nv_bfloat16 h1 = __float2bfloat16(p[1]);
                __nv_bfloat16 h2 = __float2bfloat16(p[2]);
                __nv_bfloat16 h3 = __float2bfloat16(p[3]);
                int di = (r*40 + c0l + i4*4) >> 1;
                ((u32*)phs)[di]   = packbf(__bfloat162float(h0), __bfloat162float(h1));
                ((u32*)phs)[di+1] = packbf(__bfloat162float(h2), __bfloat162float(h3));
                ((u32*)pls)[di]   = packbf(p[0] - __bfloat162float(h0), p[1] - __bfloat162float(h1));
                ((u32*)pls)[di+1] = packbf(p[2] - __bfloat162float(h2), p[3] - __bfloat162float(h3));
            }
        }
        if (ch < 7) {
            int nk0 = n0 - 128 + (ch+1)*32;
#pragma unroll
            for (int i = 0; i < 4; i++) {
                int idx = t + i*512;
                int dd = idx >> 4, c = idx & 15;
                int tok = nk0 + c*2;
                hR[i] = 0; lR[i] = 0;
                if (tok >= 0) {
                    hR[i] = *(const u32*)(g_vh + (size_t)(b*D_ + dd)*N_ + tok);
                    lR[i] = *(const u32*)(g_vl + (size_t)(b*D_ + dd)*N_ + tok);
                }
            }
        }
        __syncthreads();

#pragma unroll
        for (int kt = 0; kt < 2; kt++) {
            u32 pa[2][4], pb[2][4];
#pragma unroll
            for (int mt = 0; mt < 2; mt++) {
                u32 off = (u32)((mbase + mt*16 + rl)*40 + kt*16 + cl8) * 2;
                ldmat4(pa[mt], ph_s + off);
                ldmat4(pb[mt], pl_s + off);
            }
#pragma unroll
            for (int nt = 0; nt < 4; nt++) {
                u32 boff = (u32)((warpN*32 + nt*8 + l7)*40 + kt*16 + l8*8) * 2;
                u32 vh2[2], vl2[2];
                ldmat2(vh2, vh_s + boff);
                ldmat2(vl2, vl_s + boff);
#pragma unroll
                for (int mt = 0; mt < 2; mt++) {
                    mma16816(accP[mt][nt], pa[mt], vh2[0], vh2[1]);
                    mma16816(accP[mt][nt], pb[mt], vh2[0], vh2[1]);
                    mma16816(accP[mt][nt], pa[mt], vl2[0], vl2[1]);
                }
            }
        }
    }

#pragma unroll
    for (int mt = 0; mt < 2; mt++)
#pragma unroll
        for (int nt = 0; nt < 4; nt++) {
            int row = mbase + mt*16 + g;
            int col = warpN*32 + nt*8 + tg*2;
#pragma unroll
            for (int half = 0; half < 2; half++) {
                float v0 = accP[mt][nt][half*2];
                float v1 = accP[mt][nt][half*2+1];
                __nv_bfloat16 h0 = __float2bfloat16(v0);
                __nv_bfloat16 h1 = __float2bfloat16(v1);
                size_t off = (size_t)(b*N_ + n0 + row + half*8)*D_ + col;
                *(u32*)(g_ah + off) = packbf(__bfloat162float(h0), __bfloat162float(h1));
                *(u32*)(g_al + off) = packbf(v0 - __bfloat162float(h0), v1 - __bfloat162float(h1));
            }
        }
}

// ---------------- tensor-core 1x1 conv -> d_out (B,D,N) (unchanged) ----------------
#define C1_AH 0
#define C1_AL 34816
#define C1_WH 69632
#define C1_WL 104448
#define C1T_SMEM 139264

__global__ __launch_bounds__(512) void conv1x1_tc(const float* __restrict__ ob_,
                                                  float* __restrict__ out) {
    extern __shared__ char sm8[];
    __nv_bfloat16* ahs = (__nv_bfloat16*)(sm8 + C1_AH);
    __nv_bfloat16* als = (__nv_bfloat16*)(sm8 + C1_AL);
    __nv_bfloat16* whs = (__nv_bfloat16*)(sm8 + C1_WH);
    __nv_bfloat16* wls = (__nv_bfloat16*)(sm8 + C1_WL);

    const int b = blockIdx.y, n0 = blockIdx.x * 128;
    const int t = threadIdx.x;
    const int lane = t & 31, wid = t >> 5;
    const int warpM = wid >> 2, warpN = wid & 3;
    const int mbase = warpM * 32, nbase = warpN * 32;
    const int rl = lane & 15, cl8 = (lane >> 4) * 8;
    const int g = lane >> 2, tg = lane & 3;
    const int l7 = lane & 7, l8 = (lane >> 3) & 1;

    for (int idx = t; idx < 8192; idx += 512) {
        int r = idx >> 6, c = idx & 63;
        ((u32*)ahs)[r*68 + c] = ((const u32*)(g_ah + (size_t)(b*N_ + n0 + r)*D_))[c];
        ((u32*)als)[r*68 + c] = ((const u32*)(g_al + (size_t)(b*N_ + n0 + r)*D_))[c];
        ((u32*)whs)[r*68 + c] = ((const u32*)(g_owh + (size_t)r*D_))[c];
        ((u32*)wls)[r*68 + c] = ((const u32*)(g_owl + (size_t)r*D_))[c];
    }
    __syncthreads();

    const u32 ah_s = (u32)__cvta_generic_to_shared(ahs);
    const u32 al_s = (u32)__cvta_generic_to_shared(als);
    const u32 wh_s = (u32)__cvta_generic_to_shared(whs);
    const u32 wl_s = (u32)__cvta_generic_to_shared(wls);

    float acc[2][4][4];
#pragma unroll
    for (int mt = 0; mt < 2; mt++)
#pragma unroll
        for (int nt = 0; nt < 4; nt++)
#pragma unroll
            for (int u = 0; u < 4; u++) acc[mt][nt][u] = 0.0f;

#pragma unroll 1
    for (int kt = 0; kt < 8; kt++) {
        u32 aH[2][4], aL[2][4];
#pragma unroll
        for (int mt = 0; mt < 2; mt++) {
            u32 off = (u32)((mbase + mt*16 + rl)*136 + kt*16 + cl8) * 2;
            ldmat4(aH[mt], ah_s + off);
            ldmat4(aL[mt], al_s + off);
        }
#pragma unroll
        for (int nt = 0; nt < 4; nt++) {
            u32 boff = (u32)((nbase + nt*8 + l7)*136 + kt*16 + l8*8) * 2;
            u32 wh2[2], wl2[2];
            ldmat2(wh2, wh_s + boff);
            ldmat2(wl2, wl_s + boff);
#pragma unroll
            for (int mt = 0; mt < 2; mt++) {
                mma16816(acc[mt][nt], aH[mt], wh2[0], wh2[1]);
                mma16816(acc[mt][nt], aL[mt], wh2[0], wh2[1]);
                mma16816(acc[mt][nt], aH[mt], wl2[0], wl2[1]);
            }
        }
    }

#pragma unroll
    for (int mt = 0; mt < 2; mt++)
#pragma unroll
        for (int nt = 0; nt < 4; nt++) {
            int row = mbase + mt*16 + g;
            int col = nbase + nt*8 + tg*2;
#pragma unroll
            for (int u = 0; u < 4; u++) {
                int dd  = col + (u & 1);
                int tok = n0 + row + (u >> 1)*8;
                out[(size_t)(b*D_ + dd)*N_ + tok] = acc[mt][nt][u] + ob_[dd];
            }
        }
}

// ---------------- BatchNorm ----------------
__global__ void bn_stats(const float* __restrict__ y, const float* __restrict__ gamma,
                         const float* __restrict__ beta) {
    int d = blockIdx.x, t = threadIdx.x;
    double s = 0.0, s2 = 0.0;
    for (int b = 0; b < B_; b++) {
        const float* p = y + (size_t)(b*D_ + d) * N_;
        for (int n = t; n < N_; n += 256) { double v = p[n]; s += v; s2 += v*v; }
    }
    __shared__ double sh[512];
    sh[t] = s; sh[256 + t] = s2;
    __syncthreads();
    for (int o = 128; o > 0; o >>= 1) {
        if (t < o) { sh[t] += sh[t+o]; sh[256+t] += sh[256+t+o]; }
        __syncthreads();
    }
    if (t == 0) {
        double cnt = (double)B_ * (double)N_;
        double m = sh[0] / cnt;
        double var = sh[256] / cnt - m*m;
        double rs = rsqrt(var + 1e-5);
        double sc = rs * (double)gamma[d];
        g_scale[d] = (float)sc;
        g_shift[d] = (float)((double)beta[d] - m*sc);
    }
}

__global__ void bn_apply(float* __restrict__ y) {
    int i = (blockIdx.x * 256 + threadIdx.x) * 4;
    int d = (i >> 13) & 127;
    float sc = g_scale[d], sh = g_shift[d];
    float4 v = *(float4*)(y + i);
    v.x = v.x*sc + sh; v.y = v.y*sc + sh; v.z = v.z*sc + sh; v.w = v.w*sc + sh;
    *(float4*)(y + i) = v;
}

// ---------------- launch ----------------
extern "C" void kernel_launch(void* const* d_in, const int* in_sizes, int n_in,
                              void* d_out, int out_size) {
    const float* x  = (const float*)d_in[0];
    const float* qw = (const float*)d_in[1];
    const float* qb = (const float*)d_in[2];
    const float* kw = (const float*)d_in[3];
    const float* kb = (const float*)d_in[4];
    const float* vw = (const float*)d_in[5];
    const float* vb = (const float*)d_in[6];
    const float* ow = (const float*)d_in[7];
    const float* ob = (const float*)d_in[8];
    const float* gamma = (const float*)d_in[9];
    const float* beta  = (const float*)d_in[10];
    float* out = (float*)d_out;

    cudaFuncSetAttribute(qkv_tc, cudaFuncAttributeMaxDynamicSharedMemorySize, QKV_TC_SMEM);
    cudaFuncSetAttribute(attn_tc, cudaFuncAttributeMaxDynamicSharedMemorySize, AT_SMEM);
    cudaFuncSetAttribute(conv1x1_tc, cudaFuncAttributeMaxDynamicSharedMemorySize, C1T_SMEM);

    prep_wsplit<<<(3*8*5*128*16 + 255) / 256, 256>>>(qw, kw, vw);
    prep_owsplit<<<(D_*D_ + 255) / 256, 256>>>(ow);
    prep_trig<<<(N_*64) / 256, 256>>>();
    qkv_tc<<<dim3(N_/128, B_), 512, QKV_TC_SMEM>>>(x, qb, kb, vb);
    attn_tc<<<dim3(NW_, B_), 512, AT_SMEM>>>();
    conv1x1_tc<<<dim3(N_/128, B_), 512, C1T_SMEM>>>(ob, out);
    bn_stats<<<D_, 256>>>(out, gamma, beta);
    bn_apply<<<(B_*D_*N_) / 1024, 256>>>(out);
}

// round 12
// speedup vs baseline: 2.3863x; 1.0104x over previous
#include <cuda_runtime.h>
#include <cuda_bf16.h>
#include <math.h>

#define B_ 16
#define D_ 128
#define N_ 8192
#define NW_ 64

typedef unsigned long long ull;
typedef unsigned int u32;
typedef unsigned short u16;

// ---------------- device scratch ----------------
__device__ __align__(16) __nv_bfloat16 g_wsp[3*8*2*5*128*16];
__device__ float g_cs[N_*64];
__device__ float g_sn[N_*64];
__device__ __align__(16) __nv_bfloat16 g_qh[B_*N_*D_];   // (B,N,D) rotary+scaled
__device__ __align__(16) __nv_bfloat16 g_ql[B_*N_*D_];
__device__ __align__(16) __nv_bfloat16 g_kh[B_*N_*D_];   // (B,N,D) rotary
__device__ __align__(16) __nv_bfloat16 g_kl[B_*N_*D_];
__device__ __align__(16) __nv_bfloat16 g_vh[B_*D_*N_];   // (B,D,N) transposed
__device__ __align__(16) __nv_bfloat16 g_vl[B_*D_*N_];
__device__ __align__(16) __nv_bfloat16 g_ah[B_*N_*D_];   // attention out, split
__device__ __align__(16) __nv_bfloat16 g_al[B_*N_*D_];
__device__ __align__(16) __nv_bfloat16 g_owh[D_*D_];     // 1x1 weights split
__device__ __align__(16) __nv_bfloat16 g_owl[D_*D_];
__device__ float g_scale[D_];
__device__ float g_shift[D_];

// ---------------- mma / async helpers ----------------
__device__ __forceinline__ void mma16816(float* c, const u32* a, u32 b0, u32 b1) {
    asm("mma.sync.aligned.m16n8k16.row.col.f32.bf16.bf16.f32 "
        "{%0,%1,%2,%3}, {%4,%5,%6,%7}, {%8,%9}, {%0,%1,%2,%3};"
        : "+f"(c[0]), "+f"(c[1]), "+f"(c[2]), "+f"(c[3])
        : "r"(a[0]), "r"(a[1]), "r"(a[2]), "r"(a[3]), "r"(b0), "r"(b1));
}
__device__ __forceinline__ void ldmat4(u32* r, u32 addr) {
    asm volatile("ldmatrix.sync.aligned.m8n8.x4.shared.b16 {%0,%1,%2,%3}, [%4];"
                 : "=r"(r[0]), "=r"(r[1]), "=r"(r[2]), "=r"(r[3]) : "r"(addr));
}
__device__ __forceinline__ void ldmat2(u32* r, u32 addr) {
    asm volatile("ldmatrix.sync.aligned.m8n8.x2.shared.b16 {%0,%1}, [%2];"
                 : "=r"(r[0]), "=r"(r[1]) : "r"(addr));
}
__device__ __forceinline__ u32 packbf(float a, float b) {
    __nv_bfloat162 t = __floats2bfloat162_rn(a, b);
    return *(u32*)&t;
}
// FMA-pipe exp (deg-5 Taylor of 2^f on [-0.5,0.5]; rel err ~2.4e-6).
// Replaces MUFU ex2 (rt=8/SMSP, the attn bottleneck) with ~11 fma/alu ops.
__device__ __forceinline__ float fexp(float x) {
    float y = fmaxf(x * 1.4426950408889634f, -126.0f);
    float fy = rintf(y);
    float f = y - fy;
    float p = 0.0013333558f;
    p = fmaf(p, f, 0.0096181291f);
    p = fmaf(p, f, 0.0555041087f);
    p = fmaf(p, f, 0.2402265070f);
    p = fmaf(p, f, 0.6931471806f);
    p = fmaf(p, f, 1.0f);
    int e = __float2int_rn(y);
    float s = __int_as_float((e + 127) << 23);
    return p * s;
}
#define CP_ASYNC16(dst, src) \
    asm volatile("cp.async.cg.shared.global [%0], [%1], 16;" :: "r"(dst), "l"(src))
#define CP_COMMIT() asm volatile("cp.async.commit_group;" ::: "memory")
#define CP_WAIT0()  asm volatile("cp.async.wait_group 0;" ::: "memory")

#define WBLK_BYTES 40960   // 20480 elements * 2B per (conv,ch) W block

// ---------------- prep ----------------
__global__ void prep_wsplit(const float* __restrict__ qw, const float* __restrict__ kw,
                            const float* __restrict__ vw) {
    int e = blockIdx.x * blockDim.x + threadIdx.x;
    if (e >= 3*8*5*128*16) return;
    int ii = e % 16;
    int o  = (e / 16) % 128;
    int t  = (e / 2048) % 5;
    int ch = (e / 10240) % 8;
    int c  = e / 81920;
    const float* w = (c == 0) ? qw : (c == 1) ? kw : vw;
    float v = w[o*640 + (ch*16 + ii)*5 + t];
    __nv_bfloat16 hi = __float2bfloat16(v);
    __nv_bfloat16 lo = __float2bfloat16(v - __bfloat162float(hi));
    int base = (c*8 + ch) * 20480;              // elements
    int iisw = ii ^ ((o & 4) ? 8 : 0);          // 16B-granule swizzle
    int off  = t*2048 + o*16 + iisw;
    g_wsp[base + off]         = hi;
    g_wsp[base + 10240 + off] = lo;
}

__global__ void prep_owsplit(const float* __restrict__ ow) {
    int e = blockIdx.x * blockDim.x + threadIdx.x;
    if (e >= D_*D_) return;
    float v = ow[e];
    __nv_bfloat16 hi = __float2bfloat16(v);
    g_owh[e] = hi;
    g_owl[e] = __float2bfloat16(v - __bfloat162float(hi));
}

__global__ void prep_trig() {
    __shared__ float invf_s[64];
    int t = threadIdx.x;
    if (t < 64) invf_s[t] = (float)pow(10000.0, -((double)(2*t)) / 128.0);
    __syncthreads();
    int e = blockIdx.x * 256 + t;
    int n = e >> 6, f = e & 63;
    float ang = (float)n * invf_s[f];
    double s, c;
    sincos((double)ang, &s, &c);
    g_cs[e] = (float)c;
    g_sn[e] = (float)s;
}

// ---------- tensor-core fused QKV conv (unchanged from R11) ----------
#define XH_OFF 0
#define XL_OFF 35904
#define W_OFF  71808
#define KSM_OFF 153728
#define QKV_TC_SMEM 221312
#define XSTR 136

__global__ __launch_bounds__(512) void qkv_tc(const float* __restrict__ x,
                                              const float* __restrict__ qb,
                                              const float* __restrict__ kb,
                                              const float* __restrict__ vb) {
    extern __shared__ char smem[];
    __nv_bfloat16* xh = (__nv_bfloat16*)(smem + XH_OFF);
    __nv_bfloat16* xl = (__nv_bfloat16*)(smem + XL_OFF);
    float* ksm = (float*)(smem + KSM_OFF);
    float* qsm = (float*)(smem + XH_OFF);

    const int b = blockIdx.y, n0 = blockIdx.x * 128;
    const int t = threadIdx.x;
    const int lane = t & 31, wid = t >> 5;
    const int warpM = wid >> 2, warpN = wid & 3;
    const int mbase = warpM * 32, nbase = warpN * 32;

    const u32 w_s  = (u32)__cvta_generic_to_shared(smem + W_OFF);

    {
        const char* src = (const char*)g_wsp + (size_t)16 * WBLK_BYTES + t*16;
        u32 dst = w_s + t*16;
#pragma unroll
        for (int k2 = 0; k2 < 5; k2++)
            CP_ASYNC16(dst + k2*8192, src + k2*8192);
        CP_COMMIT();
    }

    for (int idx = t; idx < 128*132; idx += 512) {
        int i = idx / 132, c = idx % 132;
        int n = n0 - 4 + c;
        float v = (n >= 0) ? x[(size_t)(b*D_ + i)*N_ + n] : 0.0f;
        __nv_bfloat16 hi = __float2bfloat16(v);
        xh[c*XSTR + i] = hi;
        xl[c*XSTR + i] = __float2bfloat16(v - __bfloat162float(hi));
    }

    const u32 xh_s = (u32)__cvta_generic_to_shared(xh);
    const u32 xl_s = (u32)__cvta_generic_to_shared(xl);
    const int rl = lane & 15, cl8 = (lane >> 4) * 8;

    const int oA = nbase + ((lane >> 4) & 1)*8 + (lane & 7);
    const u32 koffA = (u32)((((lane >> 3) & 1)*16) ^ ((oA & 4) ? 16 : 0));
    const u32 bA = (u32)(oA*32) + koffA;
    const int oB = oA + 16;
    const u32 koffB = (u32)((((lane >> 3) & 1)*16) ^ ((oB & 4) ? 16 : 0));
    const u32 bB = (u32)(oB*32) + koffB;

#pragma unroll 1
    for (int cl = 0; cl < 3; cl++) {
        float acc[2][4][4];
#pragma unroll
        for (int mt = 0; mt < 2; mt++)
#pragma unroll
            for (int nt = 0; nt < 4; nt++)
#pragma unroll
                for (int u = 0; u < 4; u++) acc[mt][nt][u] = 0.0f;

#pragma unroll 1
        for (int ch = 0; ch < 8; ch++) {
            const int idx = cl*8 + ch;
            CP_WAIT0();
            __syncthreads();
            int nidx = idx + 1;
            if (nidx < 24) {
                int cl2 = nidx >> 3, ch2 = nidx & 7;
                int c2 = (cl2 == 0) ? 2 : (cl2 == 1) ? 1 : 0;
                const char* src = (const char*)g_wsp + (size_t)(c2*8 + ch2)*WBLK_BYTES + t*16;
                u32 dst = w_s + (u32)(nidx & 1)*40960 + t*16;
#pragma unroll
                for (int k2 = 0; k2 < 5; k2++)
                    CP_ASYNC16(dst + k2*8192, src + k2*8192);
            }
            CP_COMMIT();

            const u32 wb = w_s + (u32)(idx & 1)*40960;

#pragma unroll 1
            for (int tap = 0; tap < 5; tap++) {
                u32 ah[2][4], al[2][4];
#pragma unroll
                for (int mt = 0; mt < 2; mt++) {
                    int row = mbase + mt*16 + rl + tap;
                    int col = ch*16 + cl8;
                    u32 off = (u32)(row*XSTR + col) * 2;
                    ldmat4(ah[mt], xh_s + off);
                    ldmat4(al[mt], xl_s + off);
                }
                const u32 tb = wb + (u32)(tap*4096);
                u32 bh0[4], bl0[4], bh1[4], bl1[4];
                ldmat4(bh0, tb + bA);
                ldmat4(bl0, tb + 20480 + bA);
                ldmat4(bh1, tb + bB);
                ldmat4(bl1, tb + 20480 + bB);
#pragma unroll
                for (int mt = 0; mt < 2; mt++) {
                    mma16816(acc[mt][0], ah[mt], bh0[0], bh0[1]);
                    mma16816(acc[mt][0], ah[mt], bl0[0], bl0[1]);
                    mma16816(acc[mt][0], al[mt], bh0[0], bh0[1]);
                    mma16816(acc[mt][1], ah[mt], bh0[2], bh0[3]);
                    mma16816(acc[mt][1], ah[mt], bl0[2], bl0[3]);
                    mma16816(acc[mt][1], al[mt], bh0[2], bh0[3]);
                    mma16816(acc[mt][2], ah[mt], bh1[0], bh1[1]);
                    mma16816(acc[mt][2], ah[mt], bl1[0], bl1[1]);
                    mma16816(acc[mt][2], al[mt], bh1[0], bh1[1]);
                    mma16816(acc[mt][3], ah[mt], bh1[2], bh1[3]);
                    mma16816(acc[mt][3], ah[mt], bl1[2], bl1[3]);
                    mma16816(acc[mt][3], al[mt], bh1[2], bh1[3]);
                }
            }
        }

        if (cl == 0) {
#pragma unroll
            for (int mt = 0; mt < 2; mt++)
#pragma unroll
                for (int nt = 0; nt < 4; nt++) {
                    int row = mbase + mt*16 + (lane >> 2);
                    int col = nbase + nt*8 + (lane & 3)*2;
#pragma unroll
                    for (int u = 0; u < 4; u++) {
                        int dd  = col + (u & 1);
                        int tok = n0 + row + (u >> 1)*8;
                        float vv = acc[mt][nt][u] + vb[dd];
                        __nv_bfloat16 h = __float2bfloat16(vv);
                        size_t off = (size_t)(b*D_ + dd)*N_ + tok;
                        g_vh[off] = h;
                        g_vl[off] = __float2bfloat16(vv - __bfloat162float(h));
                    }
                }
        } else if (cl == 1) {
#pragma unroll
            for (int mt = 0; mt < 2; mt++)
#pragma unroll
                for (int nt = 0; nt < 4; nt++) {
                    int row = mbase + mt*16 + (lane >> 2);
                    int col = nbase + nt*8 + (lane & 3)*2;
                    float b0 = kb[col], b1 = kb[col+1];
                    ksm[row*132 + col]       = acc[mt][nt][0] + b0;
                    ksm[row*132 + col + 1]   = acc[mt][nt][1] + b1;
                    ksm[(row+8)*132 + col]   = acc[mt][nt][2] + b0;
                    ksm[(row+8)*132 + col+1] = acc[mt][nt][3] + b1;
                }
        } else {
            __syncthreads();
#pragma unroll
            for (int mt = 0; mt < 2; mt++)
#pragma unroll
                for (int nt = 0; nt < 4; nt++) {
                    int row = mbase + mt*16 + (lane >> 2);
                    int col = nbase + nt*8 + (lane & 3)*2;
                    float b0 = qb[col], b1 = qb[col+1];
                    qsm[row*132 + col]       = acc[mt][nt][0] + b0;
                    qsm[row*132 + col + 1]   = acc[mt][nt][1] + b1;
                    qsm[(row+8)*132 + col]   = acc[mt][nt][2] + b0;
                    qsm[(row+8)*132 + col+1] = acc[mt][nt][3] + b1;
                }
        }
    }
    __syncthreads();

    const float scl = 0.08838834764831845f;
    const int d = t & 127, h = t >> 7;
    const int dp = (d + 64) & 127;
    const float sg = (d < 64) ? -1.0f : 1.0f;
    const int f = d & 63;
    for (int j = h; j < 128; j += 4) {
        int n = n0 + j;
        float cc = g_cs[n*64 + f], ss = g_sn[n*64 + f];
        float qv = qsm[j*132 + d], qh2 = sg * qsm[j*132 + dp];
        float kv = ksm[j*132 + d], kh2 = sg * ksm[j*132 + dp];
        float qf = (qv*cc + qh2*ss) * scl;
        float kf = kv*cc + kh2*ss;
        size_t o = (size_t)(b*N_ + n)*128 + d;
        __nv_bfloat16 qhi = __float2bfloat16(qf);
        __nv_bfloat16 khi = __float2bfloat16(kf);
        g_qh[o] = qhi; g_ql[o] = __float2bfloat16(qf - __bfloat162float(qhi));
        g_kh[o] = khi; g_kl[o] = __float2bfloat16(kf - __bfloat162float(khi));
    }
}

// ---------------- tensor-core windowed attention (fexp + mask-skip) ----------------
#define AT_QH 0
#define AT_S  34816
#define AT_QL 165888
#define AT_KH 200704
#define AT_KL 209408
#define AT_VH 165888
#define AT_VL 176128
#define AT_PH 186368
#define AT_PL 196608
#define AT_M  218112
#define AT_I  218624
#define AT_SMEM 219136

__global__ __launch_bounds__(512) void attn_tc() {
    extern __shared__ char sm8[];
    __nv_bfloat16* qhs = (__nv_bfloat16*)(sm8 + AT_QH);
    float*         S   = (float*)(sm8 + AT_S);
    __nv_bfloat16* qls = (__nv_bfloat16*)(sm8 + AT_QL);
    __nv_bfloat16* khs = (__nv_bfloat16*)(sm8 + AT_KH);
    __nv_bfloat16* kls = (__nv_bfloat16*)(sm8 + AT_KL);
    __nv_bfloat16* vhs = (__nv_bfloat16*)(sm8 + AT_VH);
    __nv_bfloat16* vls = (__nv_bfloat16*)(sm8 + AT_VL);
    __nv_bfloat16* phs = (__nv_bfloat16*)(sm8 + AT_PH);
    __nv_bfloat16* pls = (__nv_bfloat16*)(sm8 + AT_PL);
    float* mrow = (float*)(sm8 + AT_M);
    float* irow = (float*)(sm8 + AT_I);

    const int wi = blockIdx.x, b = blockIdx.y;
    const int n0 = wi * 128, t = threadIdx.x;
    const int lane = t & 31, wid = t >> 5;
    const int warpM = wid >> 2, warpN = wid & 3;
    const int mbase = warpM * 32;
    const int rl = lane & 15, cl8 = (lane >> 4) * 8;
    const int g = lane >> 2, tg = lane & 3;
    const int l7 = lane & 7, l8 = (lane >> 3) & 1;
    const int jstart = (wi == 0) ? 128 : 0;

    const u32 qh_s = (u32)__cvta_generic_to_shared(qhs);
    const u32 ql_s = (u32)__cvta_generic_to_shared(qls);
    const u32 kh_s = (u32)__cvta_generic_to_shared(khs);
    const u32 kl_s = (u32)__cvta_generic_to_shared(kls);
    const u32 vh_s = (u32)__cvta_generic_to_shared(vhs);
    const u32 vl_s = (u32)__cvta_generic_to_shared(vls);
    const u32 ph_s = (u32)__cvta_generic_to_shared(phs);
    const u32 pl_s = (u32)__cvta_generic_to_shared(pls);

    for (int idx = t; idx < 8192; idx += 512) {
        int r = idx >> 6, c = idx & 63;
        ((u32*)qhs)[r*68 + c] = ((const u32*)(g_qh + (size_t)(b*N_ + n0 + r)*D_))[c];
        ((u32*)qls)[r*68 + c] = ((const u32*)(g_ql + (size_t)(b*N_ + n0 + r)*D_))[c];
    }

    u32 hR[4], lR[4];
    {
        int nk0 = n0 - 128;
#pragma unroll
        for (int i = 0; i < 4; i++) {
            int idx = t + i*512;
            int r = idx >> 6, c2 = idx & 63;
            int nk = nk0 + r;
            hR[i] = 0; lR[i] = 0;
            if (nk >= 0) {
                hR[i] = *(const u32*)(g_kh + (size_t)(b*N_ + nk)*D_ + c2*2);
                lR[i] = *(const u32*)(g_kl + (size_t)(b*N_ + nk)*D_ + c2*2);
            }
        }
    }

    // ==== phase 1: S = q @ k^T ====
#pragma unroll 1
    for (int ch = 0; ch < 8; ch++) {
        __syncthreads();
#pragma unroll
        for (int i = 0; i < 4; i++) {
            int idx = t + i*512;
            int r = idx >> 6, c2 = idx & 63;
            ((u32*)khs)[r*68 + c2] = hR[i];
            ((u32*)kls)[r*68 + c2] = lR[i];
        }
        if (ch < 7) {
            int nk0 = n0 - 128 + (ch+1)*32;
#pragma unroll
            for (int i = 0; i < 4; i++) {
                int idx = t + i*512;
                int r = idx >> 6, c2 = idx & 63;
                int nk = nk0 + r;
                hR[i] = 0; lR[i] = 0;
                if (nk >= 0) {
                    hR[i] = *(const u32*)(g_kh + (size_t)(b*N_ + nk)*D_ + c2*2);
                    lR[i] = *(const u32*)(g_kl + (size_t)(b*N_ + nk)*D_ + c2*2);
                }
            }
        }
        __syncthreads();

        // mask-skip: this warp's rows [mbase, mbase+32) need j <= 128+mbase+31;
        // chunk covers j in [32ch, 32ch+31]; also skip fully-left-masked chunks.
        if (32*ch > 159 + mbase || 32*ch + 31 < jstart) continue;

        float acc[2][4];
#pragma unroll
        for (int mt = 0; mt < 2; mt++)
#pragma unroll
            for (int u = 0; u < 4; u++) acc[mt][u] = 0.0f;

#pragma unroll 1
        for (int kt = 0; kt < 8; kt++) {
            u32 ah[2][4], al[2][4];
#pragma unroll
            for (int mt = 0; mt < 2; mt++) {
                u32 off = (u32)((mbase + mt*16 + rl)*136 + kt*16 + cl8) * 2;
                ldmat4(ah[mt], qh_s + off);
                ldmat4(al[mt], ql_s + off);
            }
            u32 boff = (u32)((warpN*8 + l7)*136 + kt*16 + l8*8) * 2;
            u32 bh[2], bl[2];
            ldmat2(bh, kh_s + boff);
            ldmat2(bl, kl_s + boff);
#pragma unroll
            for (int mt = 0; mt < 2; mt++) {
                mma16816(acc[mt], ah[mt], bh[0], bh[1]);
                mma16816(acc[mt], al[mt], bh[0], bh[1]);
                mma16816(acc[mt], ah[mt], bl[0], bl[1]);
            }
        }
#pragma unroll
        for (int mt = 0; mt < 2; mt++) {
            int row = mbase + mt*16 + g;
            int col = ch*32 + warpN*8 + tg*2;
            *(float2*)(S + row*256 + col)     = make_float2(acc[mt][0], acc[mt][1]);
            *(float2*)(S + (row+8)*256 + col) = make_float2(acc[mt][2], acc[mt][3]);
        }
    }

    {
        int nk0 = n0 - 128;
#pragma unroll
        for (int i = 0; i < 4; i++) {
            int idx = t + i*512;
            int dd = idx >> 4, c = idx & 15;
            int tok = nk0 + c*2;
            hR[i] = 0; lR[i] = 0;
            if (tok >= 0) {
                hR[i] = *(const u32*)(g_vh + (size_t)(b*D_ + dd)*N_ + tok);
                lR[i] = *(const u32*)(g_vl + (size_t)(b*D_ + dd)*N_ + tok);
            }
        }
    }
    __syncthreads();

    // ==== phase 2: softmax stats; writes e=fexp(S-m) back into S ====
    {
        int r = t >> 2, q4 = t & 3;
        int jend = 128 + r + 1;
        float m = -3.402823466e38f;
        for (int c4 = (jstart >> 2) + q4; c4*4 < jend; c4 += 4) {
            float4 v = *(const float4*)(S + r*256 + c4*4);
            int c = c4*4;
            if (c   < jend) m = fmaxf(m, v.x);
            if (c+1 < jend) m = fmaxf(m, v.y);
            if (c+2 < jend) m = fmaxf(m, v.z);
            if (c+3 < jend) m = fmaxf(m, v.w);
        }
        m = fmaxf(m, __shfl_xor_sync(0xFFFFFFFF, m, 1));
        m = fmaxf(m, __shfl_xor_sync(0xFFFFFFFF, m, 2));
        float s = 0.0f;
        for (int c4 = (jstart >> 2) + q4; c4*4 < jend; c4 += 4) {
            float4 v = *(const float4*)(S + r*256 + c4*4);
            int c = c4*4;
            float e0 = (c   < jend) ? fexp(v.x - m) : 0.0f;
            float e1 = (c+1 < jend) ? fexp(v.y - m) : 0.0f;
            float e2 = (c+2 < jend) ? fexp(v.z - m) : 0.0f;
            float e3 = (c+3 < jend) ? fexp(v.w - m) : 0.0f;
            s += (e0 + e1) + (e2 + e3);
            *(float4*)(S + r*256 + c4*4) = make_float4(e0, e1, e2, e3);
        }
        s += __shfl_xor_sync(0xFFFFFFFF, s, 1);
        s += __shfl_xor_sync(0xFFFFFFFF, s, 2);
        if (q4 == 0) { irow[r] = 1.0f / s; }
    }

    // ==== phase 3: OUT = P @ V ====
    float accP[2][4][4];
#pragma unroll
    for (int mt = 0; mt < 2; mt++)
#pragma unroll
        for (int nt = 0; nt < 4; nt++)
#pragma unroll
            for (int u = 0; u < 4; u++) accP[mt][nt][u] = 0.0f;

#pragma unroll 1
    for (int ch = 0; ch < 8; ch++) {
        __syncthreads();
#pragma unroll
        for (int i = 0; i < 4; i++) {
            int idx = t + i*512;
            int dd = idx >> 4, c = idx & 15;
            *(u32*)((u16*)vhs + dd*40 + c*2) = hR[i];
            *(u32*)((u16*)vls + dd*40 + c*2) = lR[i];
        }
        // pack P chunk (S already holds e = exp(S - m); just scale + split)
        {
            int r = t >> 2, c0l = (t & 3) * 8;
            float ii = irow[r];
            int jend = 128 + r + 1;
#pragma unroll
            for (int i4 = 0; i4 < 2; i4++) {
                int cg = ch*32 + c0l + i4*4;
                float4 s4 = *(const float4*)(S + r*256 + cg);
                float p[4];
                p[0] = (cg   >= jstart && cg   < jend) ? s4.x * ii : 0.0f;
                p[1] = (cg+1 >= jstart && cg+1 < jend) ? s4.y * ii : 0.0f;
                p[2] = (cg+2 >= jstart && cg+2 < jend) ? s4.z * ii : 0.0f;
                p[3] = (cg+3 >= jstart && cg+3 < jend) ? s4.w * ii : 0.0f;
                __nv_bfloat16 h0 = __float2bfloat16(p[0]);
                __nv_bfloat16 h1 = __float2bfloat16(p[1]);
                __nv_bfloat16 h2 = __float2bfloat16(p[2]);
                __nv_bfloat16 h3 = __float2bfloat16(p[3]);
                int di = (r*40 + c0l + i4*4) >> 1;
                ((u32*)phs)[di]   = packbf(__bfloat162float(h0), __bfloat162float(h1));
                ((u32*)phs)[di+1] = packbf(__bfloat162float(h2), __bfloat162float(h3));
                ((u32*)pls)[di]   = packbf(p[0] - __bfloat162float(h0), p[1] - __bfloat162float(h1));
                ((u32*)pls)[di+1] = packbf(p[2] - __bfloat162float(h2), p[3] - __bfloat162float(h3));
            }
        }
        if (ch < 7) {
            int nk0 = n0 - 128 + (ch+1)*32;
#pragma unroll
            for (int i = 0; i < 4; i++) {
                int idx = t + i*512;
                int dd = idx >> 4, c = idx & 15;
                int tok = nk0 + c*2;
                hR[i] = 0; lR[i] = 0;
                if (tok >= 0) {
                    hR[i] = *(const u32*)(g_vh + (size_t)(b*D_ + dd)*N_ + tok);
                    lR[i] = *(const u32*)(g_vl + (size_t)(b*D_ + dd)*N_ + tok);
                }
            }
        }
        __syncthreads();

        // mask-skip (P is all-zero for this warp's rows in these chunks)
        if (32*ch > 159 + mbase || 32*ch + 31 < jstart) continue;

#pragma unroll
        for (int kt = 0; kt < 2; kt++) {
            u32 pa[2][4], pb[2][4];
#pragma unroll
            for (int mt = 0; mt < 2; mt++) {
                u32 off = (u32)((mbase + mt*16 + rl)*40 + kt*16 + cl8) * 2;
                ldmat4(pa[mt], ph_s + off);
                ldmat4(pb[mt], pl_s + off);
            }
#pragma unroll
            for (int nt = 0; nt < 4; nt++) {
                u32 boff = (u32)((warpN*32 + nt*8 + l7)*40 + kt*16 + l8*8) * 2;
                u32 vh2[2], vl2[2];
                ldmat2(vh2, vh_s + boff);
                ldmat2(vl2, vl_s + boff);
#pragma unroll
                for (int mt = 0; mt < 2; mt++) {
                    mma16816(accP[mt][nt], pa[mt], vh2[0], vh2[1]);
                    mma16816(accP[mt][nt], pb[mt], vh2[0], vh2[1]);
                    mma16816(accP[mt][nt], pa[mt], vl2[0], vl2[1]);
                }
            }
        }
    }

#pragma unroll
    for (int mt = 0; mt < 2; mt++)
#pragma unroll
        for (int nt = 0; nt < 4; nt++) {
            int row = mbase + mt*16 + g;
            int col = warpN*32 + nt*8 + tg*2;
#pragma unroll
            for (int half = 0; half < 2; half++) {
                float v0 = accP[mt][nt][half*2];
                float v1 = accP[mt][nt][half*2+1];
                __nv_bfloat16 h0 = __float2bfloat16(v0);
                __nv_bfloat16 h1 = __float2bfloat16(v1);
                size_t off = (size_t)(b*N_ + n0 + row + half*8)*D_ + col;
                *(u32*)(g_ah + off) = packbf(__bfloat162float(h0), __bfloat162float(h1));
                *(u32*)(g_al + off) = packbf(v0 - __bfloat162float(h0), v1 - __bfloat162float(h1));
            }
        }
}

// ---------------- tensor-core 1x1 conv (unchanged) ----------------
#define C1_AH 0
#define C1_AL 34816
#define C1_WH 69632
#define C1_WL 104448
#define C1T_SMEM 139264

__global__ __launch_bounds__(512) void conv1x1_tc(const float* __restrict__ ob_,
                                                  float* __restrict__ out) {
    extern __shared__ char sm8[];
    __nv_bfloat16* ahs = (__nv_bfloat16*)(sm8 + C1_AH);
    __nv_bfloat16* als = (__nv_bfloat16*)(sm8 + C1_AL);
    __nv_bfloat16* whs = (__nv_bfloat16*)(sm8 + C1_WH);
    __nv_bfloat16* wls = (__nv_bfloat16*)(sm8 + C1_WL);

    const int b = blockIdx.y, n0 = blockIdx.x * 128;
    const int t = threadIdx.x;
    const int lane = t & 31, wid = t >> 5;
    const int warpM = wid >> 2, warpN = wid & 3;
    const int mbase = warpM * 32, nbase = warpN * 32;
    const int rl = lane & 15, cl8 = (lane >> 4) * 8;
    const int g = lane >> 2, tg = lane & 3;
    const int l7 = lane & 7, l8 = (lane >> 3) & 1;

    for (int idx = t; idx < 8192; idx += 512) {
        int r = idx >> 6, c = idx & 63;
        ((u32*)ahs)[r*68 + c] = ((const u32*)(g_ah + (size_t)(b*N_ + n0 + r)*D_))[c];
        ((u32*)als)[r*68 + c] = ((const u32*)(g_al + (size_t)(b*N_ + n0 + r)*D_))[c];
        ((u32*)whs)[r*68 + c] = ((const u32*)(g_owh + (size_t)r*D_))[c];
        ((u32*)wls)[r*68 + c] = ((const u32*)(g_owl + (size_t)r*D_))[c];
    }
    __syncthreads();

    const u32 ah_s = (u32)__cvta_generic_to_shared(ahs);
    const u32 al_s = (u32)__cvta_generic_to_shared(als);
    const u32 wh_s = (u32)__cvta_generic_to_shared(whs);
    const u32 wl_s = (u32)__cvta_generic_to_shared(wls);

    float acc[2][4][4];
#pragma unroll
    for (int mt = 0; mt < 2; mt++)
#pragma unroll
        for (int nt = 0; nt < 4; nt++)
#pragma unroll
            for (int u = 0; u < 4; u++) acc[mt][nt][u] = 0.0f;

#pragma unroll 1
    for (int kt = 0; kt < 8; kt++) {
        u32 aH[2][4], aL[2][4];
#pragma unroll
        for (int mt = 0; mt < 2; mt++) {
            u32 off = (u32)((mbase + mt*16 + rl)*136 + kt*16 + cl8) * 2;
            ldmat4(aH[mt], ah_s + off);
            ldmat4(aL[mt], al_s + off);
        }
#pragma unroll
        for (int nt = 0; nt < 4; nt++) {
            u32 boff = (u32)((nbase + nt*8 + l7)*136 + kt*16 + l8*8) * 2;
            u32 wh2[2], wl2[2];
            ldmat2(wh2, wh_s + boff);
            ldmat2(wl2, wl_s + boff);
#pragma unroll
            for (int mt = 0; mt < 2; mt++) {
                mma16816(acc[mt][nt], aH[mt], wh2[0], wh2[1]);
                mma16816(acc[mt][nt], aL[mt], wh2[0], wh2[1]);
                mma16816(acc[mt][nt], aH[mt], wl2[0], wl2[1]);
            }
        }
    }

#pragma unroll
    for (int mt = 0; mt < 2; mt++)
#pragma unroll
        for (int nt = 0; nt < 4; nt++) {
            int row = mbase + mt*16 + g;
            int col = nbase + nt*8 + tg*2;
#pragma unroll
            for (int u = 0; u < 4; u++) {
                int dd  = col + (u & 1);
                int tok = n0 + row + (u >> 1)*8;
                out[(size_t)(b*D_ + dd)*N_ + tok] = acc[mt][nt][u] + ob_[dd];
            }
        }
}

// ---------------- BatchNorm ----------------
__global__ void bn_stats(const float* __restrict__ y, const float* __restrict__ gamma,
                         const float* __restrict__ beta) {
    int d = blockIdx.x, t = threadIdx.x;
    double s = 0.0, s2 = 0.0;
    for (int b = 0; b < B_; b++) {
        const float* p = y + (size_t)(b*D_ + d) * N_;
        for (int n = t; n < N_; n += 256) { double v = p[n]; s += v; s2 += v*v; }
    }
    __shared__ double sh[512];
    sh[t] = s; sh[256 + t] = s2;
    __syncthreads();
    for (int o = 128; o > 0; o >>= 1) {
        if (t < o) { sh[t] += sh[t+o]; sh[256+t] += sh[256+t+o]; }
        __syncthreads();
    }
    if (t == 0) {
        double cnt = (double)B_ * (double)N_;
        double m = sh[0] / cnt;
        double var = sh[256] / cnt - m*m;
        double rs = rsqrt(var + 1e-5);
        double sc = rs * (double)gamma[d];
        g_scale[d] = (float)sc;
        g_shift[d] = (float)((double)beta[d] - m*sc);
    }
}

__global__ void bn_apply(float* __restrict__ y) {
    int i = (blockIdx.x * 256 + threadIdx.x) * 4;
    int d = (i >> 13) & 127;
    float sc = g_scale[d], sh = g_shift[d];
    float4 v = *(float4*)(y + i);
    v.x = v.x*sc + sh; v.y = v.y*sc + sh; v.z = v.z*sc + sh; v.w = v.w*sc + sh;
    *(float4*)(y + i) = v;
}

// ---------------- launch ----------------
extern "C" void kernel_launch(void* const* d_in, const int* in_sizes, int n_in,
                              void* d_out, int out_size) {
    const float* x  = (const float*)d_in[0];
    const float* qw = (const float*)d_in[1];
    const float* qb = (const float*)d_in[2];
    const float* kw = (const float*)d_in[3];
    const float* kb = (const float*)d_in[4];
    const float* vw = (const float*)d_in[5];
    const float* vb = (const float*)d_in[6];
    const float* ow = (const float*)d_in[7];
    const float* ob = (const float*)d_in[8];
    const float* gamma = (const float*)d_in[9];
    const float* beta  = (const float*)d_in[10];
    float* out = (float*)d_out;

    cudaFuncSetAttribute(qkv_tc, cudaFuncAttributeMaxDynamicSharedMemorySize, QKV_TC_SMEM);
    cudaFuncSetAttribute(attn_tc, cudaFuncAttributeMaxDynamicSharedMemorySize, AT_SMEM);
    cudaFuncSetAttribute(conv1x1_tc, cudaFuncAttributeMaxDynamicSharedMemorySize, C1T_SMEM);

    prep_wsplit<<<(3*8*5*128*16 + 255) / 256, 256>>>(qw, kw, vw);
    prep_owsplit<<<(D_*D_ + 255) / 256, 256>>>(ow);
    prep_trig<<<(N_*64) / 256, 256>>>();
    qkv_tc<<<dim3(N_/128, B_), 512, QKV_TC_SMEM>>>(x, qb, kb, vb);
    attn_tc<<<dim3(NW_, B_), 512, AT_SMEM>>>();
    conv1x1_tc<<<dim3(N_/128, B_), 512, C1T_SMEM>>>(ob, out);
    bn_stats<<<D_, 256>>>(out, gamma, beta);
    bn_apply<<<(B_*D_*N_) / 1024, 256>>>(out);
}

// round 13
// speedup vs baseline: 2.4108x; 1.0102x over previous
#include <cuda_runtime.h>
#include <cuda_bf16.h>
#include <math.h>

#define B_ 16
#define D_ 128
#define N_ 8192
#define NW_ 64

typedef unsigned long long ull;
typedef unsigned int u32;
typedef unsigned short u16;

// ---------------- device scratch ----------------
__device__ __align__(16) __nv_bfloat16 g_wsp[3*8*2*5*128*16];
__device__ float g_cs[N_*64];
__device__ float g_sn[N_*64];
__device__ __align__(16) __nv_bfloat16 g_qh[B_*N_*D_];   // (B,N,D) rotary+scaled
__device__ __align__(16) __nv_bfloat16 g_ql[B_*N_*D_];
__device__ __align__(16) __nv_bfloat16 g_kh[B_*N_*D_];   // (B,N,D) rotary
__device__ __align__(16) __nv_bfloat16 g_kl[B_*N_*D_];
__device__ __align__(16) __nv_bfloat16 g_vh[B_*D_*N_];   // (B,D,N) transposed
__device__ __align__(16) __nv_bfloat16 g_vl[B_*D_*N_];
__device__ __align__(16) __nv_bfloat16 g_ah[B_*N_*D_];   // attention out, split
__device__ __align__(16) __nv_bfloat16 g_al[B_*N_*D_];
__device__ __align__(16) __nv_bfloat16 g_owh[D_*D_];     // 1x1 weights split
__device__ __align__(16) __nv_bfloat16 g_owl[D_*D_];
__device__ float g_scale[D_];
__device__ float g_shift[D_];

// ---------------- mma / async helpers ----------------
__device__ __forceinline__ void mma16816(float* c, const u32* a, u32 b0, u32 b1) {
    asm("mma.sync.aligned.m16n8k16.row.col.f32.bf16.bf16.f32 "
        "{%0,%1,%2,%3}, {%4,%5,%6,%7}, {%8,%9}, {%0,%1,%2,%3};"
        : "+f"(c[0]), "+f"(c[1]), "+f"(c[2]), "+f"(c[3])
        : "r"(a[0]), "r"(a[1]), "r"(a[2]), "r"(a[3]), "r"(b0), "r"(b1));
}
__device__ __forceinline__ void ldmat4(u32* r, u32 addr) {
    asm volatile("ldmatrix.sync.aligned.m8n8.x4.shared.b16 {%0,%1,%2,%3}, [%4];"
                 : "=r"(r[0]), "=r"(r[1]), "=r"(r[2]), "=r"(r[3]) : "r"(addr));
}
__device__ __forceinline__ void ldmat2(u32* r, u32 addr) {
    asm volatile("ldmatrix.sync.aligned.m8n8.x2.shared.b16 {%0,%1}, [%2];"
                 : "=r"(r[0]), "=r"(r[1]) : "r"(addr));
}
__device__ __forceinline__ u32 packbf(float a, float b) {
    __nv_bfloat162 t = __floats2bfloat162_rn(a, b);
    return *(u32*)&t;
}
__device__ __forceinline__ float fexp(float x) {
    float y = fmaxf(x * 1.4426950408889634f, -126.0f);
    float fy = rintf(y);
    float f = y - fy;
    float p = 0.0013333558f;
    p = fmaf(p, f, 0.0096181291f);
    p = fmaf(p, f, 0.0555041087f);
    p = fmaf(p, f, 0.2402265070f);
    p = fmaf(p, f, 0.6931471806f);
    p = fmaf(p, f, 1.0f);
    int e = __float2int_rn(y);
    float s = __int_as_float((e + 127) << 23);
    return p * s;
}
#define CP_ASYNC16(dst, src) \
    asm volatile("cp.async.cg.shared.global [%0], [%1], 16;" :: "r"(dst), "l"(src))
#define CP_COMMIT() asm volatile("cp.async.commit_group;" ::: "memory")
#define CP_WAIT1()  asm volatile("cp.async.wait_group 1;" ::: "memory")

#define WBLK_BYTES 40960   // 20480 bf16 elements per (conv,ch) W block

// ---------------- prep ----------------
__global__ void prep_wsplit(const float* __restrict__ qw, const float* __restrict__ kw,
                            const float* __restrict__ vw) {
    int e = blockIdx.x * blockDim.x + threadIdx.x;
    if (e >= 3*8*5*128*16) return;
    int ii = e % 16;
    int o  = (e / 16) % 128;
    int t  = (e / 2048) % 5;
    int ch = (e / 10240) % 8;
    int c  = e / 81920;
    const float* w = (c == 0) ? qw : (c == 1) ? kw : vw;
    float v = w[o*640 + (ch*16 + ii)*5 + t];
    __nv_bfloat16 hi = __float2bfloat16(v);
    __nv_bfloat16 lo = __float2bfloat16(v - __bfloat162float(hi));
    int base = (c*8 + ch) * 20480;
    int iisw = ii ^ ((o & 4) ? 8 : 0);
    int off  = t*2048 + o*16 + iisw;
    g_wsp[base + off]         = hi;
    g_wsp[base + 10240 + off] = lo;
}

__global__ void prep_owsplit(const float* __restrict__ ow) {
    int e = blockIdx.x * blockDim.x + threadIdx.x;
    if (e >= D_*D_) return;
    float v = ow[e];
    __nv_bfloat16 hi = __float2bfloat16(v);
    g_owh[e] = hi;
    g_owl[e] = __float2bfloat16(v - __bfloat162float(hi));
}

__global__ void prep_trig() {
    __shared__ float invf_s[64];
    int t = threadIdx.x;
    if (t < 64) invf_s[t] = (float)pow(10000.0, -((double)(2*t)) / 128.0);
    __syncthreads();
    int e = blockIdx.x * 256 + t;
    int n = e >> 6, f = e & 63;
    float ang = (float)n * invf_s[f];
    double s, c;
    sincos((double)ang, &s, &c);
    g_cs[e] = (float)c;
    g_sn[e] = (float)s;
}

// ---------- tensor-core fused QKV conv ----------
// 512 thr; W triple-buffered cp.async (1 barrier/chunk); column remap
// col(nt) = warpN*16 + (nt&1)*8 + (nt>>1)*64 -> rotary pairs intra-thread.
#define XH_OFF 0
#define XL_OFF 35904
#define W_OFF  71808          // three 40960B buffers
#define QKV_TC_SMEM 194688
#define XSTR 136

__global__ __launch_bounds__(512) void qkv_tc(const float* __restrict__ x,
                                              const float* __restrict__ qb,
                                              const float* __restrict__ kb,
                                              const float* __restrict__ vb) {
    extern __shared__ char smem[];
    __nv_bfloat16* xh = (__nv_bfloat16*)(smem + XH_OFF);
    __nv_bfloat16* xl = (__nv_bfloat16*)(smem + XL_OFF);

    const int b = blockIdx.y, n0 = blockIdx.x * 128;
    const int t = threadIdx.x;
    const int lane = t & 31, wid = t >> 5;
    const int warpM = wid >> 2, warpN = wid & 3;
    const int mbase = warpM * 32, cbase = warpN * 16;

    const u32 w_s = (u32)__cvta_generic_to_shared(smem + W_OFF);

    // prologue: async-load W chunks 0,1 (conv order v(2),k(1),q(0) -> blocks 16,17)
    {
        const char* s0 = (const char*)g_wsp + (size_t)16 * WBLK_BYTES + t*16;
        u32 d0 = w_s + t*16;
#pragma unroll
        for (int k2 = 0; k2 < 5; k2++) CP_ASYNC16(d0 + k2*8192, s0 + k2*8192);
        CP_COMMIT();
        const char* s1 = (const char*)g_wsp + (size_t)17 * WBLK_BYTES + t*16;
        u32 d1 = w_s + 40960 + t*16;
#pragma unroll
        for (int k2 = 0; k2 < 5; k2++) CP_ASYNC16(d1 + k2*8192, s1 + k2*8192);
        CP_COMMIT();
    }

    for (int idx = t; idx < 128*132; idx += 512) {
        int i = idx / 132, c = idx % 132;
        int n = n0 - 4 + c;
        float v = (n >= 0) ? x[(size_t)(b*D_ + i)*N_ + n] : 0.0f;
        __nv_bfloat16 hi = __float2bfloat16(v);
        xh[c*XSTR + i] = hi;
        xl[c*XSTR + i] = __float2bfloat16(v - __bfloat162float(hi));
    }

    const u32 xh_s = (u32)__cvta_generic_to_shared(xh);
    const u32 xl_s = (u32)__cvta_generic_to_shared(xl);
    const int rl = lane & 15, cl8 = (lane >> 4) * 8;

    // B-ldmatrix addresses: nt pair 0 rows cbase..+15, pair 1 rows cbase+64..+79
    const int oA = cbase + ((lane >> 4) & 1)*8 + (lane & 7);
    const u32 koffA = (u32)((((lane >> 3) & 1)*16) ^ ((oA & 4) ? 16 : 0));
    const u32 bA = (u32)(oA*32) + koffA;
    const int oB = oA + 64;
    const u32 koffB = (u32)((((lane >> 3) & 1)*16) ^ ((oB & 4) ? 16 : 0));
    const u32 bB = (u32)(oB*32) + koffB;

    const float scl = 0.08838834764831845f;

#pragma unroll 1
    for (int cl = 0; cl < 3; cl++) {
        float acc[2][4][4];
#pragma unroll
        for (int mt = 0; mt < 2; mt++)
#pragma unroll
            for (int nt = 0; nt < 4; nt++)
#pragma unroll
                for (int u = 0; u < 4; u++) acc[mt][nt][u] = 0.0f;

#pragma unroll 1
        for (int ch = 0; ch < 8; ch++) {
            const int idx = cl*8 + ch;
            CP_WAIT1();             // load idx complete (per-thread)
            __syncthreads();        // visibility + all warps done with buf (idx-1)%3
            int nidx = idx + 2;
            if (nidx < 24) {
                int cl2 = nidx >> 3, ch2 = nidx & 7;
                int c2 = (cl2 == 0) ? 2 : (cl2 == 1) ? 1 : 0;
                const char* src = (const char*)g_wsp + (size_t)(c2*8 + ch2)*WBLK_BYTES + t*16;
                u32 dst = w_s + (u32)(nidx % 3)*40960 + t*16;
#pragma unroll
                for (int k2 = 0; k2 < 5; k2++)
                    CP_ASYNC16(dst + k2*8192, src + k2*8192);
            }
            CP_COMMIT();

            const u32 wb = w_s + (u32)(idx % 3)*40960;

#pragma unroll 1
            for (int tap = 0; tap < 5; tap++) {
                u32 ah[2][4], al[2][4];
#pragma unroll
                for (int mt = 0; mt < 2; mt++) {
                    int row = mbase + mt*16 + rl + tap;
                    int col = ch*16 + cl8;
                    u32 off = (u32)(row*XSTR + col) * 2;
                    ldmat4(ah[mt], xh_s + off);
                    ldmat4(al[mt], xl_s + off);
                }
                const u32 tb = wb + (u32)(tap*4096);
                u32 bh0[4], bl0[4], bh1[4], bl1[4];
                ldmat4(bh0, tb + bA);
                ldmat4(bl0, tb + 20480 + bA);
                ldmat4(bh1, tb + bB);
                ldmat4(bl1, tb + 20480 + bB);
#pragma unroll
                for (int mt = 0; mt < 2; mt++) {
                    mma16816(acc[mt][0], ah[mt], bh0[0], bh0[1]);
                    mma16816(acc[mt][0], ah[mt], bl0[0], bl0[1]);
                    mma16816(acc[mt][0], al[mt], bh0[0], bh0[1]);
                    mma16816(acc[mt][1], ah[mt], bh0[2], bh0[3]);
                    mma16816(acc[mt][1], ah[mt], bl0[2], bl0[3]);
                    mma16816(acc[mt][1], al[mt], bh0[2], bh0[3]);
                    mma16816(acc[mt][2], ah[mt], bh1[0], bh1[1]);
                    mma16816(acc[mt][2], ah[mt], bl1[0], bl1[1]);
                    mma16816(acc[mt][2], al[mt], bh1[0], bh1[1]);
                    mma16816(acc[mt][3], ah[mt], bh1[2], bh1[3]);
                    mma16816(acc[mt][3], ah[mt], bl1[2], bl1[3]);
                    mma16816(acc[mt][3], al[mt], bh1[2], bh1[3]);
                }
            }
        }

        if (cl == 0) {            // v -> transposed global split
#pragma unroll
            for (int mt = 0; mt < 2; mt++)
#pragma unroll
                for (int nt = 0; nt < 4; nt++) {
                    int row = mbase + mt*16 + (lane >> 2);
                    int col = cbase + (nt & 1)*8 + (nt >> 1)*64 + (lane & 3)*2;
#pragma unroll
                    for (int u = 0; u < 4; u++) {
                        int dd  = col + (u & 1);
                        int tok = n0 + row + (u >> 1)*8;
                        float vv = acc[mt][nt][u] + vb[dd];
                        __nv_bfloat16 h = __float2bfloat16(vv);
                        size_t off = (size_t)(b*D_ + dd)*N_ + tok;
                        g_vh[off] = h;
                        g_vl[off] = __float2bfloat16(vv - __bfloat162float(h));
                    }
                }
        } else {                  // k (cl==1) or q (cl==2): rotary in registers
            const float* bias = (cl == 1) ? kb : qb;
            const bool isq = (cl == 2);
            __nv_bfloat16* gh = isq ? g_qh : g_kh;
            __nv_bfloat16* gl = isq ? g_ql : g_kl;
#pragma unroll
            for (int mt = 0; mt < 2; mt++)
#pragma unroll
                for (int p = 0; p < 2; p++) {
                    int c0 = cbase + p*8 + (lane & 3)*2;   // < 64
                    float bl0 = bias[c0],    bl1 = bias[c0+1];
                    float bh0 = bias[c0+64], bh1 = bias[c0+65];
#pragma unroll
                    for (int rh = 0; rh < 2; rh++) {
                        int row = mbase + mt*16 + (lane >> 2) + rh*8;
                        int n = n0 + row;
                        float2 cs = *(const float2*)(g_cs + n*64 + c0);
                        float2 sn = *(const float2*)(g_sn + n*64 + c0);
                        float lo0 = acc[mt][p][rh*2+0]   + bl0;
                        float lo1 = acc[mt][p][rh*2+1]   + bl1;
                        float hi0 = acc[mt][p+2][rh*2+0] + bh0;
                        float hi1 = acc[mt][p+2][rh*2+1] + bh1;
                        float o0 = lo0*cs.x - hi0*sn.x;   // d = c0   (<64)
                        float o1 = lo1*cs.y - hi1*sn.y;   // d = c0+1
                        float o2 = hi0*cs.x + lo0*sn.x;   // d = c0+64
                        float o3 = hi1*cs.y + lo1*sn.y;   // d = c0+65
                        if (isq) { o0 *= scl; o1 *= scl; o2 *= scl; o3 *= scl; }
                        __nv_bfloat16 h0 = __float2bfloat16(o0);
                        __nv_bfloat16 h1 = __float2bfloat16(o1);
                        __nv_bfloat16 h2 = __float2bfloat16(o2);
                        __nv_bfloat16 h3 = __float2bfloat16(o3);
                        size_t off = (size_t)(b*N_ + n)*128 + c0;
                        *(u32*)(gh + off)      = packbf(__bfloat162float(h0), __bfloat162float(h1));
                        *(u32*)(gl + off)      = packbf(o0 - __bfloat162float(h0), o1 - __bfloat162float(h1));
                        *(u32*)(gh + off + 64) = packbf(__bfloat162float(h2), __bfloat162float(h3));
                        *(u32*)(gl + off + 64) = packbf(o2 - __bfloat162float(h2), o3 - __bfloat162float(h3));
                    }
                }
        }
    }
}

// ---------------- tensor-core windowed attention (unchanged from R12) ----------------
#define AT_QH 0
#define AT_S  34816
#define AT_QL 165888
#define AT_KH 200704
#define AT_KL 209408
#define AT_VH 165888
#define AT_VL 176128
#define AT_PH 186368
#define AT_PL 196608
#define AT_M  218112
#define AT_I  218624
#define AT_SMEM 219136

__global__ __launch_bounds__(512) void attn_tc() {
    extern __shared__ char sm8[];
    __nv_bfloat16* qhs = (__nv_bfloat16*)(sm8 + AT_QH);
    float*         S   = (float*)(sm8 + AT_S);
    __nv_bfloat16* qls = (__nv_bfloat16*)(sm8 + AT_QL);
    __nv_bfloat16* khs = (__nv_bfloat16*)(sm8 + AT_KH);
    __nv_bfloat16* kls = (__nv_bfloat16*)(sm8 + AT_KL);
    __nv_bfloat16* vhs = (__nv_bfloat16*)(sm8 + AT_VH);
    __nv_bfloat16* vls = (__nv_bfloat16*)(sm8 + AT_VL);
    __nv_bfloat16* phs = (__nv_bfloat16*)(sm8 + AT_PH);
    __nv_bfloat16* pls = (__nv_bfloat16*)(sm8 + AT_PL);
    float* irow = (float*)(sm8 + AT_I);

    const int wi = blockIdx.x, b = blockIdx.y;
    const int n0 = wi * 128, t = threadIdx.x;
    const int lane = t & 31, wid = t >> 5;
    const int warpM = wid >> 2, warpN = wid & 3;
    const int mbase = warpM * 32;
    const int rl = lane & 15, cl8 = (lane >> 4) * 8;
    const int g = lane >> 2, tg = lane & 3;
    const int l7 = lane & 7, l8 = (lane >> 3) & 1;
    const int jstart = (wi == 0) ? 128 : 0;

    const u32 qh_s = (u32)__cvta_generic_to_shared(qhs);
    const u32 ql_s = (u32)__cvta_generic_to_shared(qls);
    const u32 kh_s = (u32)__cvta_generic_to_shared(khs);
    const u32 kl_s = (u32)__cvta_generic_to_shared(kls);
    const u32 vh_s = (u32)__cvta_generic_to_shared(vhs);
    const u32 vl_s = (u32)__cvta_generic_to_shared(vls);
    const u32 ph_s = (u32)__cvta_generic_to_shared(phs);
    const u32 pl_s = (u32)__cvta_generic_to_shared(pls);

    for (int idx = t; idx < 8192; idx += 512) {
        int r = idx >> 6, c = idx & 63;
        ((u32*)qhs)[r*68 + c] = ((const u32*)(g_qh + (size_t)(b*N_ + n0 + r)*D_))[c];
        ((u32*)qls)[r*68 + c] = ((const u32*)(g_ql + (size_t)(b*N_ + n0 + r)*D_))[c];
    }

    u32 hR[4], lR[4];
    {
        int nk0 = n0 - 128;
#pragma unroll
        for (int i = 0; i < 4; i++) {
            int idx = t + i*512;
            int r = idx >> 6, c2 = idx & 63;
            int nk = nk0 + r;
            hR[i] = 0; lR[i] = 0;
            if (nk >= 0) {
                hR[i] = *(const u32*)(g_kh + (size_t)(b*N_ + nk)*D_ + c2*2);
                lR[i] = *(const u32*)(g_kl + (size_t)(b*N_ + nk)*D_ + c2*2);
            }
        }
    }

#pragma unroll 1
    for (int ch = 0; ch < 8; ch++) {
        __syncthreads();
#pragma unroll
        for (int i = 0; i < 4; i++) {
            int idx = t + i*512;
            int r = idx >> 6, c2 = idx & 63;
            ((u32*)khs)[r*68 + c2] = hR[i];
            ((u32*)kls)[r*68 + c2] = lR[i];
        }
        if (ch < 7) {
            int nk0 = n0 - 128 + (ch+1)*32;
#pragma unroll
            for (int i = 0; i < 4; i++) {
                int idx = t + i*512;
                int r = idx >> 6, c2 = idx & 63;
                int nk = nk0 + r;
                hR[i] = 0; lR[i] = 0;
                if (nk >= 0) {
                    hR[i] = *(const u32*)(g_kh + (size_t)(b*N_ + nk)*D_ + c2*2);
                    lR[i] = *(const u32*)(g_kl + (size_t)(b*N_ + nk)*D_ + c2*2);
                }
            }
        }
        __syncthreads();

        if (32*ch > 159 + mbase || 32*ch + 31 < jstart) continue;

        float acc[2][4];
#pragma unroll
        for (int mt = 0; mt < 2; mt++)
#pragma unroll
            for (int u = 0; u < 4; u++) acc[mt][u] = 0.0f;

#pragma unroll 1
        for (int kt = 0; kt < 8; kt++) {
            u32 ah[2][4], al[2][4];
#pragma unroll
            for (int mt = 0; mt < 2; mt++) {
                u32 off = (u32)((mbase + mt*16 + rl)*136 + kt*16 + cl8) * 2;
                ldmat4(ah[mt], qh_s + off);
                ldmat4(al[mt], ql_s + off);
            }
            u32 boff = (u32)((warpN*8 + l7)*136 + kt*16 + l8*8) * 2;
            u32 bh[2], bl[2];
            ldmat2(bh, kh_s + boff);
            ldmat2(bl, kl_s + boff);
#pragma unroll
            for (int mt = 0; mt < 2; mt++) {
                mma16816(acc[mt], ah[mt], bh[0], bh[1]);
                mma16816(acc[mt], al[mt], bh[0], bh[1]);
                mma16816(acc[mt], ah[mt], bl[0], bl[1]);
            }
        }
#pragma unroll
        for (int mt = 0; mt < 2; mt++) {
            int row = mbase + mt*16 + g;
            int col = ch*32 + warpN*8 + tg*2;
            *(float2*)(S + row*256 + col)     = make_float2(acc[mt][0], acc[mt][1]);
            *(float2*)(S + (row+8)*256 + col) = make_float2(acc[mt][2], acc[mt][3]);
        }
    }

    {
        int nk0 = n0 - 128;
#pragma unroll
        for (int i = 0; i < 4; i++) {
            int idx = t + i*512;
            int dd = idx >> 4, c = idx & 15;
            int tok = nk0 + c*2;
            hR[i] = 0; lR[i] = 0;
            if (tok >= 0) {
                hR[i] = *(const u32*)(g_vh + (size_t)(b*D_ + dd)*N_ + tok);
                lR[i] = *(const u32*)(g_vl + (size_t)(b*D_ + dd)*N_ + tok);
            }
        }
    }
    __syncthreads();

    {
        int r = t >> 2, q4 = t & 3;
        int jend = 128 + r + 1;
        float m = -3.402823466e38f;
        for (int c4 = (jstart >> 2) + q4; c4*4 < jend; c4 += 4) {
            float4 v = *(const float4*)(S + r*256 + c4*4);
            int c = c4*4;
            if (c   < jend) m = fmaxf(m, v.x);
            if (c+1 < jend) m = fmaxf(m, v.y);
            if (c+2 < jend) m = fmaxf(m, v.z);
            if (c+3 < jend) m = fmaxf(m, v.w);
        }
        m = fmaxf(m, __shfl_xor_sync(0xFFFFFFFF, m, 1));
        m = fmaxf(m, __shfl_xor_sync(0xFFFFFFFF, m, 2));
        float s = 0.0f;
        for (int c4 = (jstart >> 2) + q4; c4*4 < jend; c4 += 4) {
            float4 v = *(const float4*)(S + r*256 + c4*4);
            int c = c4*4;
            float e0 = (c   < jend) ? fexp(v.x - m) : 0.0f;
            float e1 = (c+1 < jend) ? fexp(v.y - m) : 0.0f;
            float e2 = (c+2 < jend) ? fexp(v.z - m) : 0.0f;
            float e3 = (c+3 < jend) ? fexp(v.w - m) : 0.0f;
            s += (e0 + e1) + (e2 + e3);
            *(float4*)(S + r*256 + c4*4) = make_float4(e0, e1, e2, e3);
        }
        s += __shfl_xor_sync(0xFFFFFFFF, s, 1);
        s += __shfl_xor_sync(0xFFFFFFFF, s, 2);
        if (q4 == 0) { irow[r] = 1.0f / s; }
    }

    float accP[2][4][4];
#pragma unroll
    for (int mt = 0; mt < 2; mt++)
#pragma unroll
        for (int nt = 0; nt < 4; nt++)
#pragma unroll
            for (int u = 0; u < 4; u++) accP[mt][nt][u] = 0.0f;

#pragma unroll 1
    for (int ch = 0; ch < 8; ch++) {
        __syncthreads();
#pragma unroll
        for (int i = 0; i < 4; i++) {
            int idx = t + i*512;
            int dd = idx >> 4, c = idx & 15;
            *(u32*)((u16*)vhs + dd*40 + c*2) = hR[i];
            *(u32*)((u16*)vls + dd*40 + c*2) = lR[i];
        }
        {
            int r = t >> 2, c0l = (t & 3) * 8;
            float ii = irow[r];
            int jend = 128 + r + 1;
#pragma unroll
            for (int i4 = 0; i4 < 2; i4++) {
                int cg = ch*32 + c0l + i4*4;
                float4 s4 = *(const float4*)(S + r*256 + cg);
                float p[4];
                p[0] = (cg   >= jstart && cg   < jend) ? s4.x * ii : 0.0f;
                p[1] = (cg+1 >= jstart && cg+1 < jend) ? s4.y * ii : 0.0f;
                p[2] = (cg+2 >= jstart && cg+2 < jend) ? s4.z * ii : 0.0f;
                p[3] = (cg+3 >= jstart && cg+3 < jend) ? s4.w * ii : 0.0f;
                __nv_bfloat16 h0 = __float2bfloat16(p[0]);
                __nv_bfloat16 h1 = __float2bfloat16(p[1]);
                __nv_bfloat16 h2 = __float2bfloat16(p[2]);
                __nv_bfloat16 h3 = __float2bfloat16(p[3]);
                int di = (r*40 + c0l + i4*4) >> 1;
                ((u32*)phs)[di]   = packbf(__bfloat162float(h0), __bfloat162float(h1));
                ((u32*)phs)[di+1] = packbf(__bfloat162float(h2), __bfloat162float(h3));
                ((u32*)pls)[di]   = packbf(p[0] - __bfloat162float(h0), p[1] - __bfloat162float(h1));
                ((u32*)pls)[di+1] = packbf(p[2] - __bfloat162float(h2), p[3] - __bfloat162float(h3));
            }
        }
        if (ch < 7) {
            int nk0 = n0 - 128 + (ch+1)*32;
#pragma unroll
            for (int i = 0; i < 4; i++) {
                int idx = t + i*512;
                int dd = idx >> 4, c = idx & 15;
                int tok = nk0 + c*2;
                hR[i] = 0; lR[i] = 0;
                if (tok >= 0) {
                    hR[i] = *(const u32*)(g_vh + (size_t)(b*D_ + dd)*N_ + tok);
                    lR[i] = *(const u32*)(g_vl + (size_t)(b*D_ + dd)*N_ + tok);
                }
            }
        }
        __syncthreads();

        if (32*ch > 159 + mbase || 32*ch + 31 < jstart) continue;

#pragma unroll
        for (int kt = 0; kt < 2; kt++) {
            u32 pa[2][4], pb[2][4];
#pragma unroll
            for (int mt = 0; mt < 2; mt++) {
                u32 off = (u32)((mbase + mt*16 + rl)*40 + kt*16 + cl8) * 2;
                ldmat4(pa[mt], ph_s + off);
                ldmat4(pb[mt], pl_s + off);
            }
#pragma unroll
            for (int nt = 0; nt < 4; nt++) {
                u32 boff = (u32)((warpN*32 + nt*8 + l7)*40 + kt*16 + l8*8) * 2;
                u32 vh2[2], vl2[2];
                ldmat2(vh2, vh_s + boff);
                ldmat2(vl2, vl_s + boff);
#pragma unroll
                for (int mt = 0; mt < 2; mt++) {
                    mma16816(accP[mt][nt], pa[mt], vh2[0], vh2[1]);
                    mma16816(accP[mt][nt], pb[mt], vh2[0], vh2[1]);
                    mma16816(accP[mt][nt], pa[mt], vl2[0], vl2[1]);
                }
            }
        }
    }

#pragma unroll
    for (int mt = 0; mt < 2; mt++)
#pragma unroll
        for (int nt = 0; nt < 4; nt++) {
            int row = mbase + mt*16 + g;
            int col = warpN*32 + nt*8 + tg*2;
#pragma unroll
            for (int half = 0; half < 2; half++) {
                float v0 = accP[mt][nt][half*2];
                float v1 = accP[mt][nt][half*2+1];
                __nv_bfloat16 h0 = __float2bfloat16(v0);
                __nv_bfloat16 h1 = __float2bfloat16(v1);
                size_t off = (size_t)(b*N_ + n0 + row + half*8)*D_ + col;
                *(u32*)(g_ah + off) = packbf(__bfloat162float(h0), __bfloat162float(h1));
                *(u32*)(g_al + off) = packbf(v0 - __bfloat162float(h0), v1 - __bfloat162float(h1));
            }
        }
}

// ---------------- tensor-core 1x1 conv (unchanged) ----------------
#define C1_AH 0
#define C1_AL 34816
#define C1_WH 69632
#define C1_WL 104448
#define C1T_SMEM 139264

__global__ __launch_bounds__(512) void conv1x1_tc(const float* __restrict__ ob_,
                                                  float* __restrict__ out) {
    extern __shared__ char sm8[];
    __nv_bfloat16* ahs = (__nv_bfloat16*)(sm8 + C1_AH);
    __nv_bfloat16* als = (__nv_bfloat16*)(sm8 + C1_AL);
    __nv_bfloat16* whs = (__nv_bfloat16*)(sm8 + C1_WH);
    __nv_bfloat16* wls = (__nv_bfloat16*)(sm8 + C1_WL);

    const int b = blockIdx.y, n0 = blockIdx.x * 128;
    const int t = threadIdx.x;
    const int lane = t & 31, wid = t >> 5;
    const int warpM = wid >> 2, warpN = wid & 3;
    const int mbase = warpM * 32, nbase = warpN * 32;
    const int rl = lane & 15, cl8 = (lane >> 4) * 8;
    const int g = lane >> 2, tg = lane & 3;
    const int l7 = lane & 7, l8 = (lane >> 3) & 1;

    for (int idx = t; idx < 8192; idx += 512) {
        int r = idx >> 6, c = idx & 63;
        ((u32*)ahs)[r*68 + c] = ((const u32*)(g_ah + (size_t)(b*N_ + n0 + r)*D_))[c];
        ((u32*)als)[r*68 + c] = ((const u32*)(g_al + (size_t)(b*N_ + n0 + r)*D_))[c];
        ((u32*)whs)[r*68 + c] = ((const u32*)(g_owh + (size_t)r*D_))[c];
        ((u32*)wls)[r*68 + c] = ((const u32*)(g_owl + (size_t)r*D_))[c];
    }
    __syncthreads();

    const u32 ah_s = (u32)__cvta_generic_to_shared(ahs);
    const u32 al_s = (u32)__cvta_generic_to_shared(als);
    const u32 wh_s = (u32)__cvta_generic_to_shared(whs);
    const u32 wl_s = (u32)__cvta_generic_to_shared(wls);

    float acc[2][4][4];
#pragma unroll
    for (int mt = 0; mt < 2; mt++)
#pragma unroll
        for (int nt = 0; nt < 4; nt++)
#pragma unroll
            for (int u = 0; u < 4; u++) acc[mt][nt][u] = 0.0f;

#pragma unroll 1
    for (int kt = 0; kt < 8; kt++) {
        u32 aH[2][4], aL[2][4];
#pragma unroll
        for (int mt = 0; mt < 2; mt++) {
            u32 off = (u32)((mbase + mt*16 + rl)*136 + kt*16 + cl8) * 2;
            ldmat4(aH[mt], ah_s + off);
            ldmat4(aL[mt], al_s + off);
        }
#pragma unroll
        for (int nt = 0; nt < 4; nt++) {
            u32 boff = (u32)((nbase + nt*8 + l7)*136 + kt*16 + l8*8) * 2;
            u32 wh2[2], wl2[2];
            ldmat2(wh2, wh_s + boff);
            ldmat2(wl2, wl_s + boff);
#pragma unroll
            for (int mt = 0; mt < 2; mt++) {
                mma16816(acc[mt][nt], aH[mt], wh2[0], wh2[1]);
                mma16816(acc[mt][nt], aL[mt], wh2[0], wh2[1]);
                mma16816(acc[mt][nt], aH[mt], wl2[0], wl2[1]);
            }
        }
    }

#pragma unroll
    for (int mt = 0; mt < 2; mt++)
#pragma unroll
        for (int nt = 0; nt < 4; nt++) {
            int row = mbase + mt*16 + g;
            int col = nbase + nt*8 + tg*2;
#pragma unroll
            for (int u = 0; u < 4; u++) {
                int dd  = col + (u & 1);
                int tok = n0 + row + (u >> 1)*8;
                out[(size_t)(b*D_ + dd)*N_ + tok] = acc[mt][nt][u] + ob_[dd];
            }
        }
}

// ---------------- BatchNorm ----------------
__global__ void bn_stats(const float* __restrict__ y, const float* __restrict__ gamma,
                         const float* __restrict__ beta) {
    int d = blockIdx.x, t = threadIdx.x;
    double s = 0.0, s2 = 0.0;
    for (int b = 0; b < B_; b++) {
        const float* p = y + (size_t)(b*D_ + d) * N_;
        for (int n = t; n < N_; n += 256) { double v = p[n]; s += v; s2 += v*v; }
    }
    __shared__ double sh[512];
    sh[t] = s; sh[256 + t] = s2;
    __syncthreads();
    for (int o = 128; o > 0; o >>= 1) {
        if (t < o) { sh[t] += sh[t+o]; sh[256+t] += sh[256+t+o]; }
        __syncthreads();
    }
    if (t == 0) {
        double cnt = (double)B_ * (double)N_;
        double m = sh[0] / cnt;
        double var = sh[256] / cnt - m*m;
        double rs = rsqrt(var + 1e-5);
        double sc = rs * (double)gamma[d];
        g_scale[d] = (float)sc;
        g_shift[d] = (float)((double)beta[d] - m*sc);
    }
}

__global__ void bn_apply(float* __restrict__ y) {
    int i = (blockIdx.x * 256 + threadIdx.x) * 4;
    int d = (i >> 13) & 127;
    float sc = g_scale[d], sh = g_shift[d];
    float4 v = *(float4*)(y + i);
    v.x = v.x*sc + sh; v.y = v.y*sc + sh; v.z = v.z*sc + sh; v.w = v.w*sc + sh;
    *(float4*)(y + i) = v;
}

// ---------------- launch ----------------
extern "C" void kernel_launch(void* const* d_in, const int* in_sizes, int n_in,
                              void* d_out, int out_size) {
    const float* x  = (const float*)d_in[0];
    const float* qw = (const float*)d_in[1];
    const float* qb = (const float*)d_in[2];
    const float* kw = (const float*)d_in[3];
    const float* kb = (const float*)d_in[4];
    const float* vw = (const float*)d_in[5];
    const float* vb = (const float*)d_in[6];
    const float* ow = (const float*)d_in[7];
    const float* ob = (const float*)d_in[8];
    const float* gamma = (const float*)d_in[9];
    const float* beta  = (const float*)d_in[10];
    float* out = (float*)d_out;

    cudaFuncSetAttribute(qkv_tc, cudaFuncAttributeMaxDynamicSharedMemorySize, QKV_TC_SMEM);
    cudaFuncSetAttribute(attn_tc, cudaFuncAttributeMaxDynamicSharedMemorySize, AT_SMEM);
    cudaFuncSetAttribute(conv1x1_tc, cudaFuncAttributeMaxDynamicSharedMemorySize, C1T_SMEM);

    prep_wsplit<<<(3*8*5*128*16 + 255) / 256, 256>>>(qw, kw, vw);
    prep_owsplit<<<(D_*D_ + 255) / 256, 256>>>(ow);
    prep_trig<<<(N_*64) / 256, 256>>>();
    qkv_tc<<<dim3(N_/128, B_), 512, QKV_TC_SMEM>>>(x, qb, kb, vb);
    attn_tc<<<dim3(NW_, B_), 512, AT_SMEM>>>();
    conv1x1_tc<<<dim3(N_/128, B_), 512, C1T_SMEM>>>(ob, out);
    bn_stats<<<D_, 256>>>(out, gamma, beta);
    bn_apply<<<(B_*D_*N_) / 1024, 256>>>(out);
}

// round 14
// speedup vs baseline: 2.5341x; 1.0512x over previous
#include <cuda_runtime.h>
#include <cuda_bf16.h>
#include <math.h>

#define B_ 16
#define D_ 128
#define N_ 8192
#define NW_ 64

typedef unsigned long long ull;
typedef unsigned int u32;
typedef unsigned short u16;

// ---------------- device scratch ----------------
__device__ __align__(16) __nv_bfloat16 g_wsp[3*8*2*5*128*16];
__device__ float g_cs[N_*64];
__device__ float g_sn[N_*64];
__device__ __align__(16) __nv_bfloat16 g_qh[B_*N_*D_];   // (B,N,D) rotary+scaled
__device__ __align__(16) __nv_bfloat16 g_ql[B_*N_*D_];
__device__ __align__(16) __nv_bfloat16 g_kh[B_*N_*D_];   // (B,N,D) rotary
__device__ __align__(16) __nv_bfloat16 g_kl[B_*N_*D_];
__device__ __align__(16) __nv_bfloat16 g_vh[B_*D_*N_];   // (B,D,N) transposed
__device__ __align__(16) __nv_bfloat16 g_vl[B_*D_*N_];
__device__ __align__(16) __nv_bfloat16 g_owh[D_*D_];     // 1x1 weights split
__device__ __align__(16) __nv_bfloat16 g_owl[D_*D_];
__device__ float g_scale[D_];
__device__ float g_shift[D_];

// ---------------- mma / async helpers ----------------
__device__ __forceinline__ void mma16816(float* c, const u32* a, u32 b0, u32 b1) {
    asm("mma.sync.aligned.m16n8k16.row.col.f32.bf16.bf16.f32 "
        "{%0,%1,%2,%3}, {%4,%5,%6,%7}, {%8,%9}, {%0,%1,%2,%3};"
        : "+f"(c[0]), "+f"(c[1]), "+f"(c[2]), "+f"(c[3])
        : "r"(a[0]), "r"(a[1]), "r"(a[2]), "r"(a[3]), "r"(b0), "r"(b1));
}
__device__ __forceinline__ void ldmat4(u32* r, u32 addr) {
    asm volatile("ldmatrix.sync.aligned.m8n8.x4.shared.b16 {%0,%1,%2,%3}, [%4];"
                 : "=r"(r[0]), "=r"(r[1]), "=r"(r[2]), "=r"(r[3]) : "r"(addr));
}
__device__ __forceinline__ void ldmat2(u32* r, u32 addr) {
    asm volatile("ldmatrix.sync.aligned.m8n8.x2.shared.b16 {%0,%1}, [%2];"
                 : "=r"(r[0]), "=r"(r[1]) : "r"(addr));
}
__device__ __forceinline__ u32 packbf(float a, float b) {
    __nv_bfloat162 t = __floats2bfloat162_rn(a, b);
    return *(u32*)&t;
}
__device__ __forceinline__ float fexp(float x) {
    float y = fmaxf(x * 1.4426950408889634f, -126.0f);
    float fy = rintf(y);
    float f = y - fy;
    float p = 0.0013333558f;
    p = fmaf(p, f, 0.0096181291f);
    p = fmaf(p, f, 0.0555041087f);
    p = fmaf(p, f, 0.2402265070f);
    p = fmaf(p, f, 0.6931471806f);
    p = fmaf(p, f, 1.0f);
    int e = __float2int_rn(y);
    float s = __int_as_float((e + 127) << 23);
    return p * s;
}
#define CP_ASYNC16(dst, src) \
    asm volatile("cp.async.cg.shared.global [%0], [%1], 16;" :: "r"(dst), "l"(src))
#define CP_COMMIT() asm volatile("cp.async.commit_group;" ::: "memory")
#define CP_WAIT1()  asm volatile("cp.async.wait_group 1;" ::: "memory")

#define WBLK_BYTES 40960

// ---------------- prep ----------------
__global__ void prep_wsplit(const float* __restrict__ qw, const float* __restrict__ kw,
                            const float* __restrict__ vw) {
    int e = blockIdx.x * blockDim.x + threadIdx.x;
    if (e >= 3*8*5*128*16) return;
    int ii = e % 16;
    int o  = (e / 16) % 128;
    int t  = (e / 2048) % 5;
    int ch = (e / 10240) % 8;
    int c  = e / 81920;
    const float* w = (c == 0) ? qw : (c == 1) ? kw : vw;
    float v = w[o*640 + (ch*16 + ii)*5 + t];
    __nv_bfloat16 hi = __float2bfloat16(v);
    __nv_bfloat16 lo = __float2bfloat16(v - __bfloat162float(hi));
    int base = (c*8 + ch) * 20480;
    int iisw = ii ^ ((o & 4) ? 8 : 0);
    int off  = t*2048 + o*16 + iisw;
    g_wsp[base + off]         = hi;
    g_wsp[base + 10240 + off] = lo;
}

__global__ void prep_owsplit(const float* __restrict__ ow) {
    int e = blockIdx.x * blockDim.x + threadIdx.x;
    if (e >= D_*D_) return;
    float v = ow[e];
    __nv_bfloat16 hi = __float2bfloat16(v);
    g_owh[e] = hi;
    g_owl[e] = __float2bfloat16(v - __bfloat162float(hi));
}

__global__ void prep_trig() {
    __shared__ float invf_s[64];
    int t = threadIdx.x;
    if (t < 64) invf_s[t] = (float)pow(10000.0, -((double)(2*t)) / 128.0);
    __syncthreads();
    int e = blockIdx.x * 256 + t;
    int n = e >> 6, f = e & 63;
    float ang = (float)n * invf_s[f];
    double s, c;
    sincos((double)ang, &s, &c);
    g_cs[e] = (float)c;
    g_sn[e] = (float)s;
}

// ---------- tensor-core fused QKV conv (unchanged from R13) ----------
#define XH_OFF 0
#define XL_OFF 35904
#define W_OFF  71808
#define QKV_TC_SMEM 194688
#define XSTR 136

__global__ __launch_bounds__(512) void qkv_tc(const float* __restrict__ x,
                                              const float* __restrict__ qb,
                                              const float* __restrict__ kb,
                                              const float* __restrict__ vb) {
    extern __shared__ char smem[];
    __nv_bfloat16* xh = (__nv_bfloat16*)(smem + XH_OFF);
    __nv_bfloat16* xl = (__nv_bfloat16*)(smem + XL_OFF);

    const int b = blockIdx.y, n0 = blockIdx.x * 128;
    const int t = threadIdx.x;
    const int lane = t & 31, wid = t >> 5;
    const int warpM = wid >> 2, warpN = wid & 3;
    const int mbase = warpM * 32, cbase = warpN * 16;

    const u32 w_s = (u32)__cvta_generic_to_shared(smem + W_OFF);

    {
        const char* s0 = (const char*)g_wsp + (size_t)16 * WBLK_BYTES + t*16;
        u32 d0 = w_s + t*16;
#pragma unroll
        for (int k2 = 0; k2 < 5; k2++) CP_ASYNC16(d0 + k2*8192, s0 + k2*8192);
        CP_COMMIT();
        const char* s1 = (const char*)g_wsp + (size_t)17 * WBLK_BYTES + t*16;
        u32 d1 = w_s + 40960 + t*16;
#pragma unroll
        for (int k2 = 0; k2 < 5; k2++) CP_ASYNC16(d1 + k2*8192, s1 + k2*8192);
        CP_COMMIT();
    }

    for (int idx = t; idx < 128*132; idx += 512) {
        int i = idx / 132, c = idx % 132;
        int n = n0 - 4 + c;
        float v = (n >= 0) ? x[(size_t)(b*D_ + i)*N_ + n] : 0.0f;
        __nv_bfloat16 hi = __float2bfloat16(v);
        xh[c*XSTR + i] = hi;
        xl[c*XSTR + i] = __float2bfloat16(v - __bfloat162float(hi));
    }

    const u32 xh_s = (u32)__cvta_generic_to_shared(xh);
    const u32 xl_s = (u32)__cvta_generic_to_shared(xl);
    const int rl = lane & 15, cl8 = (lane >> 4) * 8;

    const int oA = cbase + ((lane >> 4) & 1)*8 + (lane & 7);
    const u32 koffA = (u32)((((lane >> 3) & 1)*16) ^ ((oA & 4) ? 16 : 0));
    const u32 bA = (u32)(oA*32) + koffA;
    const int oB = oA + 64;
    const u32 koffB = (u32)((((lane >> 3) & 1)*16) ^ ((oB & 4) ? 16 : 0));
    const u32 bB = (u32)(oB*32) + koffB;

    const float scl = 0.08838834764831845f;

#pragma unroll 1
    for (int cl = 0; cl < 3; cl++) {
        float acc[2][4][4];
#pragma unroll
        for (int mt = 0; mt < 2; mt++)
#pragma unroll
            for (int nt = 0; nt < 4; nt++)
#pragma unroll
                for (int u = 0; u < 4; u++) acc[mt][nt][u] = 0.0f;

#pragma unroll 1
        for (int ch = 0; ch < 8; ch++) {
            const int idx = cl*8 + ch;
            CP_WAIT1();
            __syncthreads();
            int nidx = idx + 2;
            if (nidx < 24) {
                int cl2 = nidx >> 3, ch2 = nidx & 7;
                int c2 = (cl2 == 0) ? 2 : (cl2 == 1) ? 1 : 0;
                const char* src = (const char*)g_wsp + (size_t)(c2*8 + ch2)*WBLK_BYTES + t*16;
                u32 dst = w_s + (u32)(nidx % 3)*40960 + t*16;
#pragma unroll
                for (int k2 = 0; k2 < 5; k2++)
                    CP_ASYNC16(dst + k2*8192, src + k2*8192);
            }
            CP_COMMIT();

            const u32 wb = w_s + (u32)(idx % 3)*40960;

#pragma unroll 1
            for (int tap = 0; tap < 5; tap++) {
                u32 ah[2][4], al[2][4];
#pragma unroll
                for (int mt = 0; mt < 2; mt++) {
                    int row = mbase + mt*16 + rl + tap;
                    int col = ch*16 + cl8;
                    u32 off = (u32)(row*XSTR + col) * 2;
                    ldmat4(ah[mt], xh_s + off);
                    ldmat4(al[mt], xl_s + off);
                }
                const u32 tb = wb + (u32)(tap*4096);
                u32 bh0[4], bl0[4], bh1[4], bl1[4];
                ldmat4(bh0, tb + bA);
                ldmat4(bl0, tb + 20480 + bA);
                ldmat4(bh1, tb + bB);
                ldmat4(bl1, tb + 20480 + bB);
#pragma unroll
                for (int mt = 0; mt < 2; mt++) {
                    mma16816(acc[mt][0], ah[mt], bh0[0], bh0[1]);
                    mma16816(acc[mt][0], ah[mt], bl0[0], bl0[1]);
                    mma16816(acc[mt][0], al[mt], bh0[0], bh0[1]);
                    mma16816(acc[mt][1], ah[mt], bh0[2], bh0[3]);
                    mma16816(acc[mt][1], ah[mt], bl0[2], bl0[3]);
                    mma16816(acc[mt][1], al[mt], bh0[2], bh0[3]);
                    mma16816(acc[mt][2], ah[mt], bh1[0], bh1[1]);
                    mma16816(acc[mt][2], ah[mt], bl1[0], bl1[1]);
                    mma16816(acc[mt][2], al[mt], bh1[0], bh1[1]);
                    mma16816(acc[mt][3], ah[mt], bh1[2], bh1[3]);
                    mma16816(acc[mt][3], ah[mt], bl1[2], bl1[3]);
                    mma16816(acc[mt][3], al[mt], bh1[2], bh1[3]);
                }
            }
        }

        if (cl == 0) {
#pragma unroll
            for (int mt = 0; mt < 2; mt++)
#pragma unroll
                for (int nt = 0; nt < 4; nt++) {
                    int row = mbase + mt*16 + (lane >> 2);
                    int col = cbase + (nt & 1)*8 + (nt >> 1)*64 + (lane & 3)*2;
#pragma unroll
                    for (int u = 0; u < 4; u++) {
                        int dd  = col + (u & 1);
                        int tok = n0 + row + (u >> 1)*8;
                        float vv = acc[mt][nt][u] + vb[dd];
                        __nv_bfloat16 h = __float2bfloat16(vv);
                        size_t off = (size_t)(b*D_ + dd)*N_ + tok;
                        g_vh[off] = h;
                        g_vl[off] = __float2bfloat16(vv - __bfloat162float(h));
                    }
                }
        } else {
            const float* bias = (cl == 1) ? kb : qb;
            const bool isq = (cl == 2);
            __nv_bfloat16* gh = isq ? g_qh : g_kh;
            __nv_bfloat16* gl = isq ? g_ql : g_kl;
#pragma unroll
            for (int mt = 0; mt < 2; mt++)
#pragma unroll
                for (int p = 0; p < 2; p++) {
                    int c0 = cbase + p*8 + (lane & 3)*2;
                    float bl0 = bias[c0],    bl1 = bias[c0+1];
                    float bh0 = bias[c0+64], bh1 = bias[c0+65];
#pragma unroll
                    for (int rh = 0; rh < 2; rh++) {
                        int row = mbase + mt*16 + (lane >> 2) + rh*8;
                        int n = n0 + row;
                        float2 cs = *(const float2*)(g_cs + n*64 + c0);
                        float2 sn = *(const float2*)(g_sn + n*64 + c0);
                        float lo0 = acc[mt][p][rh*2+0]   + bl0;
                        float lo1 = acc[mt][p][rh*2+1]   + bl1;
                        float hi0 = acc[mt][p+2][rh*2+0] + bh0;
                        float hi1 = acc[mt][p+2][rh*2+1] + bh1;
                        float o0 = lo0*cs.x - hi0*sn.x;
                        float o1 = lo1*cs.y - hi1*sn.y;
                        float o2 = hi0*cs.x + lo0*sn.x;
                        float o3 = hi1*cs.y + lo1*sn.y;
                        if (isq) { o0 *= scl; o1 *= scl; o2 *= scl; o3 *= scl; }
                        __nv_bfloat16 h0 = __float2bfloat16(o0);
                        __nv_bfloat16 h1 = __float2bfloat16(o1);
                        __nv_bfloat16 h2 = __float2bfloat16(o2);
                        __nv_bfloat16 h3 = __float2bfloat16(o3);
                        size_t off = (size_t)(b*N_ + n)*128 + c0;
                        *(u32*)(gh + off)      = packbf(__bfloat162float(h0), __bfloat162float(h1));
                        *(u32*)(gl + off)      = packbf(o0 - __bfloat162float(h0), o1 - __bfloat162float(h1));
                        *(u32*)(gh + off + 64) = packbf(__bfloat162float(h2), __bfloat162float(h3));
                        *(u32*)(gl + off + 64) = packbf(o2 - __bfloat162float(h2), o3 - __bfloat162float(h3));
                    }
                }
        }
    }
}

// -------- tensor-core windowed attention + FUSED 1x1 conv --------
#define AT_QH 0
#define AT_S  34816
#define AT_QL 165888
#define AT_KH 200704
#define AT_KL 209408
#define AT_VH 165888
#define AT_VL 176128
#define AT_PH 186368
#define AT_PL 196608
#define AT_I  218624
#define AT_SMEM 219136
// fused conv overlays (all regions dead after PV):
#define FC_AH 0          // [128][136] bf16 (qhs region)
#define FC_WH 34816      // [128][136] bf16 (S region)
#define FC_WL 69632      // [128][136] bf16 (S region)
#define FC_AL 104448     // [128][136] bf16 (S region)

__global__ __launch_bounds__(512) void attn_tc(const float* __restrict__ ob_,
                                               float* __restrict__ out) {
    extern __shared__ char sm8[];
    __nv_bfloat16* qhs = (__nv_bfloat16*)(sm8 + AT_QH);
    float*         S   = (float*)(sm8 + AT_S);
    __nv_bfloat16* qls = (__nv_bfloat16*)(sm8 + AT_QL);
    __nv_bfloat16* khs = (__nv_bfloat16*)(sm8 + AT_KH);
    __nv_bfloat16* kls = (__nv_bfloat16*)(sm8 + AT_KL);
    __nv_bfloat16* vhs = (__nv_bfloat16*)(sm8 + AT_VH);
    __nv_bfloat16* vls = (__nv_bfloat16*)(sm8 + AT_VL);
    __nv_bfloat16* phs = (__nv_bfloat16*)(sm8 + AT_PH);
    __nv_bfloat16* pls = (__nv_bfloat16*)(sm8 + AT_PL);
    float* irow = (float*)(sm8 + AT_I);

    const int wi = blockIdx.x, b = blockIdx.y;
    const int n0 = wi * 128, t = threadIdx.x;
    const int lane = t & 31, wid = t >> 5;
    const int warpM = wid >> 2, warpN = wid & 3;
    const int mbase = warpM * 32;
    const int rl = lane & 15, cl8 = (lane >> 4) * 8;
    const int g = lane >> 2, tg = lane & 3;
    const int l7 = lane & 7, l8 = (lane >> 3) & 1;
    const int jstart = (wi == 0) ? 128 : 0;

    const u32 qh_s = (u32)__cvta_generic_to_shared(qhs);
    const u32 ql_s = (u32)__cvta_generic_to_shared(qls);
    const u32 kh_s = (u32)__cvta_generic_to_shared(khs);
    const u32 kl_s = (u32)__cvta_generic_to_shared(kls);
    const u32 vh_s = (u32)__cvta_generic_to_shared(vhs);
    const u32 vl_s = (u32)__cvta_generic_to_shared(vls);
    const u32 ph_s = (u32)__cvta_generic_to_shared(phs);
    const u32 pl_s = (u32)__cvta_generic_to_shared(pls);

    for (int idx = t; idx < 8192; idx += 512) {
        int r = idx >> 6, c = idx & 63;
        ((u32*)qhs)[r*68 + c] = ((const u32*)(g_qh + (size_t)(b*N_ + n0 + r)*D_))[c];
        ((u32*)qls)[r*68 + c] = ((const u32*)(g_ql + (size_t)(b*N_ + n0 + r)*D_))[c];
    }

    u32 hR[4], lR[4];
    {
        int nk0 = n0 - 128;
#pragma unroll
        for (int i = 0; i < 4; i++) {
            int idx = t + i*512;
            int r = idx >> 6, c2 = idx & 63;
            int nk = nk0 + r;
            hR[i] = 0; lR[i] = 0;
            if (nk >= 0) {
                hR[i] = *(const u32*)(g_kh + (size_t)(b*N_ + nk)*D_ + c2*2);
                lR[i] = *(const u32*)(g_kl + (size_t)(b*N_ + nk)*D_ + c2*2);
            }
        }
    }

    // ==== phase 1: S = q @ k^T ====
#pragma unroll 1
    for (int ch = 0; ch < 8; ch++) {
        __syncthreads();
#pragma unroll
        for (int i = 0; i < 4; i++) {
            int idx = t + i*512;
            int r = idx >> 6, c2 = idx & 63;
            ((u32*)khs)[r*68 + c2] = hR[i];
            ((u32*)kls)[r*68 + c2] = lR[i];
        }
        if (ch < 7) {
            int nk0 = n0 - 128 + (ch+1)*32;
#pragma unroll
            for (int i = 0; i < 4; i++) {
                int idx = t + i*512;
                int r = idx >> 6, c2 = idx & 63;
                int nk = nk0 + r;
                hR[i] = 0; lR[i] = 0;
                if (nk >= 0) {
                    hR[i] = *(const u32*)(g_kh + (size_t)(b*N_ + nk)*D_ + c2*2);
                    lR[i] = *(const u32*)(g_kl + (size_t)(b*N_ + nk)*D_ + c2*2);
                }
            }
        }
        __syncthreads();

        if (32*ch > 159 + mbase || 32*ch + 31 < jstart) continue;

        float acc[2][4];
#pragma unroll
        for (int mt = 0; mt < 2; mt++)
#pragma unroll
            for (int u = 0; u < 4; u++) acc[mt][u] = 0.0f;

#pragma unroll 1
        for (int kt = 0; kt < 8; kt++) {
            u32 ah[2][4], al[2][4];
#pragma unroll
            for (int mt = 0; mt < 2; mt++) {
                u32 off = (u32)((mbase + mt*16 + rl)*136 + kt*16 + cl8) * 2;
                ldmat4(ah[mt], qh_s + off);
                ldmat4(al[mt], ql_s + off);
            }
            u32 boff = (u32)((warpN*8 + l7)*136 + kt*16 + l8*8) * 2;
            u32 bh[2], bl[2];
            ldmat2(bh, kh_s + boff);
            ldmat2(bl, kl_s + boff);
#pragma unroll
            for (int mt = 0; mt < 2; mt++) {
                mma16816(acc[mt], ah[mt], bh[0], bh[1]);
                mma16816(acc[mt], al[mt], bh[0], bh[1]);
                mma16816(acc[mt], ah[mt], bl[0], bl[1]);
            }
        }
#pragma unroll
        for (int mt = 0; mt < 2; mt++) {
            int row = mbase + mt*16 + g;
            int col = ch*32 + warpN*8 + tg*2;
            *(float2*)(S + row*256 + col)     = make_float2(acc[mt][0], acc[mt][1]);
            *(float2*)(S + (row+8)*256 + col) = make_float2(acc[mt][2], acc[mt][3]);
        }
    }

    {
        int nk0 = n0 - 128;
#pragma unroll
        for (int i = 0; i < 4; i++) {
            int idx = t + i*512;
            int dd = idx >> 4, c = idx & 15;
            int tok = nk0 + c*2;
            hR[i] = 0; lR[i] = 0;
            if (tok >= 0) {
                hR[i] = *(const u32*)(g_vh + (size_t)(b*D_ + dd)*N_ + tok);
                lR[i] = *(const u32*)(g_vl + (size_t)(b*D_ + dd)*N_ + tok);
            }
        }
    }
    __syncthreads();

    // ==== phase 2: softmax stats; writes e back into S ====
    {
        int r = t >> 2, q4 = t & 3;
        int jend = 128 + r + 1;
        float m = -3.402823466e38f;
        for (int c4 = (jstart >> 2) + q4; c4*4 < jend; c4 += 4) {
            float4 v = *(const float4*)(S + r*256 + c4*4);
            int c = c4*4;
            if (c   < jend) m = fmaxf(m, v.x);
            if (c+1 < jend) m = fmaxf(m, v.y);
            if (c+2 < jend) m = fmaxf(m, v.z);
            if (c+3 < jend) m = fmaxf(m, v.w);
        }
        m = fmaxf(m, __shfl_xor_sync(0xFFFFFFFF, m, 1));
        m = fmaxf(m, __shfl_xor_sync(0xFFFFFFFF, m, 2));
        float s = 0.0f;
        for (int c4 = (jstart >> 2) + q4; c4*4 < jend; c4 += 4) {
            float4 v = *(const float4*)(S + r*256 + c4*4);
            int c = c4*4;
            float e0 = (c   < jend) ? fexp(v.x - m) : 0.0f;
            float e1 = (c+1 < jend) ? fexp(v.y - m) : 0.0f;
            float e2 = (c+2 < jend) ? fexp(v.z - m) : 0.0f;
            float e3 = (c+3 < jend) ? fexp(v.w - m) : 0.0f;
            s += (e0 + e1) + (e2 + e3);
            *(float4*)(S + r*256 + c4*4) = make_float4(e0, e1, e2, e3);
        }
        s += __shfl_xor_sync(0xFFFFFFFF, s, 1);
        s += __shfl_xor_sync(0xFFFFFFFF, s, 2);
        if (q4 == 0) { irow[r] = 1.0f / s; }
    }

    // ==== phase 3: OUT = P @ V ====
    float accP[2][4][4];
#pragma unroll
    for (int mt = 0; mt < 2; mt++)
#pragma unroll
        for (int nt = 0; nt < 4; nt++)
#pragma unroll
            for (int u = 0; u < 4; u++) accP[mt][nt][u] = 0.0f;

#pragma unroll 1
    for (int ch = 0; ch < 8; ch++) {
        __syncthreads();
#pragma unroll
        for (int i = 0; i < 4; i++) {
            int idx = t + i*512;
            int dd = idx >> 4, c = idx & 15;
            *(u32*)((u16*)vhs + dd*40 + c*2) = hR[i];
            *(u32*)((u16*)vls + dd*40 + c*2) = lR[i];
        }
        {
            int r = t >> 2, c0l = (t & 3) * 8;
            float ii = irow[r];
            int jend = 128 + r + 1;
#pragma unroll
            for (int i4 = 0; i4 < 2; i4++) {
                int cg = ch*32 + c0l + i4*4;
                float4 s4 = *(const float4*)(S + r*256 + cg);
                float p[4];
                p[0] = (cg   >= jstart && cg   < jend) ? s4.x * ii : 0.0f;
                p[1] = (cg+1 >= jstart && cg+1 < jend) ? s4.y * ii : 0.0f;
                p[2] = (cg+2 >= jstart && cg+2 < jend) ? s4.z * ii : 0.0f;
                p[3] = (cg+3 >= jstart && cg+3 < jend) ? s4.w * ii : 0.0f;
                __nv_bfloat16 h0 = __float2bfloat16(p[0]);
                __nv_bfloat16 h1 = __float2bfloat16(p[1]);
                __nv_bfloat16 h2 = __float2bfloat16(p[2]);
                __nv_bfloat16 h3 = __float2bfloat16(p[3]);
                int di = (r*40 + c0l + i4*4) >> 1;
                ((u32*)phs)[di]   = packbf(__bfloat162float(h0), __bfloat162float(h1));
                ((u32*)phs)[di+1] = packbf(__bfloat162float(h2), __bfloat162float(h3));
                ((u32*)pls)[di]   = packbf(p[0] - __bfloat162float(h0), p[1] - __bfloat162float(h1));
                ((u32*)pls)[di+1] = packbf(p[2] - __bfloat162float(h2), p[3] - __bfloat162float(h3));
            }
        }
        if (ch < 7) {
            int nk0 = n0 - 128 + (ch+1)*32;
#pragma unroll
            for (int i = 0; i < 4; i++) {
                int idx = t + i*512;
                int dd = idx >> 4, c = idx & 15;
                int tok = nk0 + c*2;
                hR[i] = 0; lR[i] = 0;
                if (tok >= 0) {
                    hR[i] = *(const u32*)(g_vh + (size_t)(b*D_ + dd)*N_ + tok);
                    lR[i] = *(const u32*)(g_vl + (size_t)(b*D_ + dd)*N_ + tok);
                }
            }
        }
        __syncthreads();

        if (32*ch > 159 + mbase || 32*ch + 31 < jstart) continue;

#pragma unroll
        for (int kt = 0; kt < 2; kt++) {
            u32 pa[2][4], pb[2][4];
#pragma unroll
            for (int mt = 0; mt < 2; mt++) {
                u32 off = (u32)((mbase + mt*16 + rl)*40 + kt*16 + cl8) * 2;
                ldmat4(pa[mt], ph_s + off);
                ldmat4(pb[mt], pl_s + off);
            }
#pragma unroll
            for (int nt = 0; nt < 4; nt++) {
                u32 boff = (u32)((warpN*32 + nt*8 + l7)*40 + kt*16 + l8*8) * 2;
                u32 vh2[2], vl2[2];
                ldmat2(vh2, vh_s + boff);
                ldmat2(vl2, vl_s + boff);
#pragma unroll
                for (int mt = 0; mt < 2; mt++) {
                    mma16816(accP[mt][nt], pa[mt], vh2[0], vh2[1]);
                    mma16816(accP[mt][nt], pb[mt], vh2[0], vh2[1]);
                    mma16816(accP[mt][nt], pa[mt], vl2[0], vl2[1]);
                }
            }
        }
    }

    // ==== fused 1x1 conv ====
    // All prior smem regions dead: stage attention tile + ow weights.
    __nv_bfloat16* ahs = (__nv_bfloat16*)(sm8 + FC_AH);
    __nv_bfloat16* als = (__nv_bfloat16*)(sm8 + FC_AL);
    __nv_bfloat16* whs = (__nv_bfloat16*)(sm8 + FC_WH);
    __nv_bfloat16* wls = (__nv_bfloat16*)(sm8 + FC_WL);

    // load ow split (L2-resident)
    for (int idx = t; idx < 8192; idx += 512) {
        int r = idx >> 6, c = idx & 63;
        ((u32*)whs)[r*68 + c] = ((const u32*)(g_owh + (size_t)r*D_))[c];
        ((u32*)wls)[r*68 + c] = ((const u32*)(g_owl + (size_t)r*D_))[c];
    }
    // write attention fragments as split bf16
#pragma unroll
    for (int mt = 0; mt < 2; mt++)
#pragma unroll
        for (int nt = 0; nt < 4; nt++) {
            int row = mbase + mt*16 + g;
            int col = warpN*32 + nt*8 + tg*2;
#pragma unroll
            for (int half = 0; half < 2; half++) {
                float v0 = accP[mt][nt][half*2];
                float v1 = accP[mt][nt][half*2+1];
                __nv_bfloat16 h0 = __float2bfloat16(v0);
                __nv_bfloat16 h1 = __float2bfloat16(v1);
                int r2 = row + half*8;
                *(u32*)(ahs + r2*136 + col) = packbf(__bfloat162float(h0), __bfloat162float(h1));
                *(u32*)(als + r2*136 + col) = packbf(v0 - __bfloat162float(h0), v1 - __bfloat162float(h1));
            }
        }
    __syncthreads();

    const u32 ah_s = (u32)__cvta_generic_to_shared(ahs);
    const u32 al_s = (u32)__cvta_generic_to_shared(als);
    const u32 wh_s = (u32)__cvta_generic_to_shared(whs);
    const u32 wl_s = (u32)__cvta_generic_to_shared(wls);
    const int nbase = warpN * 32;

    float accC[2][4][4];
#pragma unroll
    for (int mt = 0; mt < 2; mt++)
#pragma unroll
        for (int nt = 0; nt < 4; nt++)
#pragma unroll
            for (int u = 0; u < 4; u++) accC[mt][nt][u] = 0.0f;

#pragma unroll 1
    for (int kt = 0; kt < 8; kt++) {
        u32 aH[2][4], aL[2][4];
#pragma unroll
        for (int mt = 0; mt < 2; mt++) {
            u32 off = (u32)((mbase + mt*16 + rl)*136 + kt*16 + cl8) * 2;
            ldmat4(aH[mt], ah_s + off);
            ldmat4(aL[mt], al_s + off);
        }
#pragma unroll
        for (int nt = 0; nt < 4; nt++) {
            u32 boff = (u32)((nbase + nt*8 + l7)*136 + kt*16 + l8*8) * 2;
            u32 wh2[2], wl2[2];
            ldmat2(wh2, wh_s + boff);
            ldmat2(wl2, wl_s + boff);
#pragma unroll
            for (int mt = 0; mt < 2; mt++) {
                mma16816(accC[mt][nt], aH[mt], wh2[0], wh2[1]);
                mma16816(accC[mt][nt], aL[mt], wh2[0], wh2[1]);
                mma16816(accC[mt][nt], aH[mt], wl2[0], wl2[1]);
            }
        }
    }

    // transposed write (B,D,N) + bias
#pragma unroll
    for (int mt = 0; mt < 2; mt++)
#pragma unroll
        for (int nt = 0; nt < 4; nt++) {
            int row = mbase + mt*16 + g;
            int col = nbase + nt*8 + tg*2;
#pragma unroll
            for (int u = 0; u < 4; u++) {
                int dd  = col + (u & 1);
                int tok = n0 + row + (u >> 1)*8;
                out[(size_t)(b*D_ + dd)*N_ + tok] = accC[mt][nt][u] + ob_[dd];
            }
        }
}

// ---------------- BatchNorm ----------------
__global__ void bn_stats(const float* __restrict__ y, const float* __restrict__ gamma,
                         const float* __restrict__ beta) {
    int d = blockIdx.x, t = threadIdx.x;
    double s = 0.0, s2 = 0.0;
    for (int b = 0; b < B_; b++) {
        const float* p = y + (size_t)(b*D_ + d) * N_;
        for (int n = t; n < N_; n += 256) { double v = p[n]; s += v; s2 += v*v; }
    }
    __shared__ double sh[512];
    sh[t] = s; sh[256 + t] = s2;
    __syncthreads();
    for (int o = 128; o > 0; o >>= 1) {
        if (t < o) { sh[t] += sh[t+o]; sh[256+t] += sh[256+t+o]; }
        __syncthreads();
    }
    if (t == 0) {
        double cnt = (double)B_ * (double)N_;
        double m = sh[0] / cnt;
        double var = sh[256] / cnt - m*m;
        double rs = rsqrt(var + 1e-5);
        double sc = rs * (double)gamma[d];
        g_scale[d] = (float)sc;
        g_shift[d] = (float)((double)beta[d] - m*sc);
    }
}

__global__ void bn_apply(float* __restrict__ y) {
    int i = (blockIdx.x * 256 + threadIdx.x) * 4;
    int d = (i >> 13) & 127;
    float sc = g_scale[d], sh = g_shift[d];
    float4 v = *(float4*)(y + i);
    v.x = v.x*sc + sh; v.y = v.y*sc + sh; v.z = v.z*sc + sh; v.w = v.w*sc + sh;
    *(float4*)(y + i) = v;
}

// ---------------- launch ----------------
extern "C" void kernel_launch(void* const* d_in, const int* in_sizes, int n_in,
                              void* d_out, int out_size) {
    const float* x  = (const float*)d_in[0];
    const float* qw = (const float*)d_in[1];
    const float* qb = (const float*)d_in[2];
    const float* kw = (const float*)d_in[3];
    const float* kb = (const float*)d_in[4];
    const float* vw = (const float*)d_in[5];
    const float* vb = (const float*)d_in[6];
    const float* ow = (const float*)d_in[7];
    const float* ob = (const float*)d_in[8];
    const float* gamma = (const float*)d_in[9];
    const float* beta  = (const float*)d_in[10];
    float* out = (float*)d_out;

    cudaFuncSetAttribute(qkv_tc, cudaFuncAttributeMaxDynamicSharedMemorySize, QKV_TC_SMEM);
    cudaFuncSetAttribute(attn_tc, cudaFuncAttributeMaxDynamicSharedMemorySize, AT_SMEM);

    prep_wsplit<<<(3*8*5*128*16 + 255) / 256, 256>>>(qw, kw, vw);
    prep_owsplit<<<(D_*D_ + 255) / 256, 256>>>(ow);
    prep_trig<<<(N_*64) / 256, 256>>>();
    qkv_tc<<<dim3(N_/128, B_), 512, QKV_TC_SMEM>>>(x, qb, kb, vb);
    attn_tc<<<dim3(NW_, B_), 512, AT_SMEM>>>(ob, out);
    bn_stats<<<D_, 256>>>(out, gamma, beta);
    bn_apply<<<(B_*D_*N_) / 1024, 256>>>(out);
}

// round 15
// speedup vs baseline: 2.5420x; 1.0031x over previous
#include <cuda_runtime.h>
#include <cuda_bf16.h>
#include <math.h>

#define B_ 16
#define D_ 128
#define N_ 8192
#define NW_ 64

typedef unsigned long long ull;
typedef unsigned int u32;
typedef unsigned short u16;

// ---------------- device scratch ----------------
__device__ __align__(16) __nv_bfloat16 g_wsp[3*8*2*5*128*16];
__device__ float g_cs[N_*64];
__device__ float g_sn[N_*64];
__device__ __align__(16) __nv_bfloat16 g_qh[B_*N_*D_];
__device__ __align__(16) __nv_bfloat16 g_ql[B_*N_*D_];
__device__ __align__(16) __nv_bfloat16 g_kh[B_*N_*D_];
__device__ __align__(16) __nv_bfloat16 g_kl[B_*N_*D_];
__device__ __align__(16) __nv_bfloat16 g_vh[B_*D_*N_];
__device__ __align__(16) __nv_bfloat16 g_vl[B_*D_*N_];
__device__ __align__(16) __nv_bfloat16 g_owh[D_*D_];
__device__ __align__(16) __nv_bfloat16 g_owl[D_*D_];
__device__ float g_scale[D_];
__device__ float g_shift[D_];

// ---------------- mma / async helpers ----------------
__device__ __forceinline__ void mma16816(float* c, const u32* a, u32 b0, u32 b1) {
    asm("mma.sync.aligned.m16n8k16.row.col.f32.bf16.bf16.f32 "
        "{%0,%1,%2,%3}, {%4,%5,%6,%7}, {%8,%9}, {%0,%1,%2,%3};"
        : "+f"(c[0]), "+f"(c[1]), "+f"(c[2]), "+f"(c[3])
        : "r"(a[0]), "r"(a[1]), "r"(a[2]), "r"(a[3]), "r"(b0), "r"(b1));
}
__device__ __forceinline__ void ldmat4(u32* r, u32 addr) {
    asm volatile("ldmatrix.sync.aligned.m8n8.x4.shared.b16 {%0,%1,%2,%3}, [%4];"
                 : "=r"(r[0]), "=r"(r[1]), "=r"(r[2]), "=r"(r[3]) : "r"(addr));
}
__device__ __forceinline__ void ldmat2(u32* r, u32 addr) {
    asm volatile("ldmatrix.sync.aligned.m8n8.x2.shared.b16 {%0,%1}, [%2];"
                 : "=r"(r[0]), "=r"(r[1]) : "r"(addr));
}
__device__ __forceinline__ u32 packbf(float a, float b) {
    __nv_bfloat162 t = __floats2bfloat162_rn(a, b);
    return *(u32*)&t;
}
__device__ __forceinline__ float fexp(float x) {
    float y = fmaxf(x * 1.4426950408889634f, -126.0f);
    float fy = rintf(y);
    float f = y - fy;
    float p = 0.0013333558f;
    p = fmaf(p, f, 0.0096181291f);
    p = fmaf(p, f, 0.0555041087f);
    p = fmaf(p, f, 0.2402265070f);
    p = fmaf(p, f, 0.6931471806f);
    p = fmaf(p, f, 1.0f);
    int e = __float2int_rn(y);
    float s = __int_as_float((e + 127) << 23);
    return p * s;
}
#define CP_ASYNC16(dst, src) \
    asm volatile("cp.async.cg.shared.global [%0], [%1], 16;" :: "r"(dst), "l"(src))
#define CP_COMMIT() asm volatile("cp.async.commit_group;" ::: "memory")
#define CP_WAIT1()  asm volatile("cp.async.wait_group 1;" ::: "memory")

#define WBLK_BYTES 40960

// ---------------- prep ----------------
__global__ void prep_wsplit(const float* __restrict__ qw, const float* __restrict__ kw,
                            const float* __restrict__ vw) {
    int e = blockIdx.x * blockDim.x + threadIdx.x;
    if (e >= 3*8*5*128*16) return;
    int ii = e % 16;
    int o  = (e / 16) % 128;
    int t  = (e / 2048) % 5;
    int ch = (e / 10240) % 8;
    int c  = e / 81920;
    const float* w = (c == 0) ? qw : (c == 1) ? kw : vw;
    float v = w[o*640 + (ch*16 + ii)*5 + t];
    __nv_bfloat16 hi = __float2bfloat16(v);
    __nv_bfloat16 lo = __float2bfloat16(v - __bfloat162float(hi));
    int base = (c*8 + ch) * 20480;
    int iisw = ii ^ ((o & 4) ? 8 : 0);
    int off  = t*2048 + o*16 + iisw;
    g_wsp[base + off]         = hi;
    g_wsp[base + 10240 + off] = lo;
}

__global__ void prep_owsplit(const float* __restrict__ ow) {
    int e = blockIdx.x * blockDim.x + threadIdx.x;
    if (e >= D_*D_) return;
    float v = ow[e];
    __nv_bfloat16 hi = __float2bfloat16(v);
    g_owh[e] = hi;
    g_owl[e] = __float2bfloat16(v - __bfloat162float(hi));
}

__global__ void prep_trig() {
    __shared__ float invf_s[64];
    int t = threadIdx.x;
    if (t < 64) invf_s[t] = (float)pow(10000.0, -((double)(2*t)) / 128.0);
    __syncthreads();
    int e = blockIdx.x * 256 + t;
    int n = e >> 6, f = e & 63;
    float ang = (float)n * invf_s[f];
    double s, c;
    sincos((double)ang, &s, &c);
    g_cs[e] = (float)c;
    g_sn[e] = (float)s;
}

// ---------- tensor-core fused QKV conv (prod-major MMA order) ----------
#define XH_OFF 0
#define XL_OFF 35904
#define W_OFF  71808
#define QKV_TC_SMEM 194688
#define XSTR 136

__global__ __launch_bounds__(512) void qkv_tc(const float* __restrict__ x,
                                              const float* __restrict__ qb,
                                              const float* __restrict__ kb,
                                              const float* __restrict__ vb) {
    extern __shared__ char smem[];
    __nv_bfloat16* xh = (__nv_bfloat16*)(smem + XH_OFF);
    __nv_bfloat16* xl = (__nv_bfloat16*)(smem + XL_OFF);

    const int b = blockIdx.y, n0 = blockIdx.x * 128;
    const int t = threadIdx.x;
    const int lane = t & 31, wid = t >> 5;
    const int warpM = wid >> 2, warpN = wid & 3;
    const int mbase = warpM * 32, cbase = warpN * 16;

    const u32 w_s = (u32)__cvta_generic_to_shared(smem + W_OFF);

    {
        const char* s0 = (const char*)g_wsp + (size_t)16 * WBLK_BYTES + t*16;
        u32 d0 = w_s + t*16;
#pragma unroll
        for (int k2 = 0; k2 < 5; k2++) CP_ASYNC16(d0 + k2*8192, s0 + k2*8192);
        CP_COMMIT();
        const char* s1 = (const char*)g_wsp + (size_t)17 * WBLK_BYTES + t*16;
        u32 d1 = w_s + 40960 + t*16;
#pragma unroll
        for (int k2 = 0; k2 < 5; k2++) CP_ASYNC16(d1 + k2*8192, s1 + k2*8192);
        CP_COMMIT();
    }

    for (int idx = t; idx < 128*132; idx += 512) {
        int i = idx / 132, c = idx % 132;
        int n = n0 - 4 + c;
        float v = (n >= 0) ? x[(size_t)(b*D_ + i)*N_ + n] : 0.0f;
        __nv_bfloat16 hi = __float2bfloat16(v);
        xh[c*XSTR + i] = hi;
        xl[c*XSTR + i] = __float2bfloat16(v - __bfloat162float(hi));
    }

    const u32 xh_s = (u32)__cvta_generic_to_shared(xh);
    const u32 xl_s = (u32)__cvta_generic_to_shared(xl);
    const int rl = lane & 15, cl8 = (lane >> 4) * 8;

    const int oA = cbase + ((lane >> 4) & 1)*8 + (lane & 7);
    const u32 koffA = (u32)((((lane >> 3) & 1)*16) ^ ((oA & 4) ? 16 : 0));
    const u32 bA = (u32)(oA*32) + koffA;
    const int oB = oA + 64;
    const u32 koffB = (u32)((((lane >> 3) & 1)*16) ^ ((oB & 4) ? 16 : 0));
    const u32 bB = (u32)(oB*32) + koffB;

    const float scl = 0.08838834764831845f;

#pragma unroll 1
    for (int cl = 0; cl < 3; cl++) {
        float acc[2][4][4];
#pragma unroll
        for (int mt = 0; mt < 2; mt++)
#pragma unroll
            for (int nt = 0; nt < 4; nt++)
#pragma unroll
                for (int u = 0; u < 4; u++) acc[mt][nt][u] = 0.0f;

#pragma unroll 1
        for (int ch = 0; ch < 8; ch++) {
            const int idx = cl*8 + ch;
            CP_WAIT1();
            __syncthreads();
            int nidx = idx + 2;
            if (nidx < 24) {
                int cl2 = nidx >> 3, ch2 = nidx & 7;
                int c2 = (cl2 == 0) ? 2 : (cl2 == 1) ? 1 : 0;
                const char* src = (const char*)g_wsp + (size_t)(c2*8 + ch2)*WBLK_BYTES + t*16;
                u32 dst = w_s + (u32)(nidx % 3)*40960 + t*16;
#pragma unroll
                for (int k2 = 0; k2 < 5; k2++)
                    CP_ASYNC16(dst + k2*8192, src + k2*8192);
            }
            CP_COMMIT();

            const u32 wb = w_s + (u32)(idx % 3)*40960;

#pragma unroll 1
            for (int tap = 0; tap < 5; tap++) {
                u32 ah[2][4], al[2][4];
#pragma unroll
                for (int mt = 0; mt < 2; mt++) {
                    int row = mbase + mt*16 + rl + tap;
                    int col = ch*16 + cl8;
                    u32 off = (u32)(row*XSTR + col) * 2;
                    ldmat4(ah[mt], xh_s + off);
                    ldmat4(al[mt], xl_s + off);
                }
                const u32 tb = wb + (u32)(tap*4096);
                u32 bh0[4], bl0[4], bh1[4], bl1[4];
                ldmat4(bh0, tb + bA);
                ldmat4(bl0, tb + 20480 + bA);
                ldmat4(bh1, tb + bB);
                ldmat4(bl1, tb + 20480 + bB);
                // prod-major issue: same-acc reuse distance = 8 MMAs
#pragma unroll
                for (int mt = 0; mt < 2; mt++) {
                    mma16816(acc[mt][0], ah[mt], bh0[0], bh0[1]);
                    mma16816(acc[mt][1], ah[mt], bh0[2], bh0[3]);
                    mma16816(acc[mt][2], ah[mt], bh1[0], bh1[1]);
                    mma16816(acc[mt][3], ah[mt], bh1[2], bh1[3]);
                }
#pragma unroll
                for (int mt = 0; mt < 2; mt++) {
                    mma16816(acc[mt][0], al[mt], bh0[0], bh0[1]);
                    mma16816(acc[mt][1], al[mt], bh0[2], bh0[3]);
                    mma16816(acc[mt][2], al[mt], bh1[0], bh1[1]);
                    mma16816(acc[mt][3], al[mt], bh1[2], bh1[3]);
                }
#pragma unroll
                for (int mt = 0; mt < 2; mt++) {
                    mma16816(acc[mt][0], ah[mt], bl0[0], bl0[1]);
                    mma16816(acc[mt][1], ah[mt], bl0[2], bl0[3]);
                    mma16816(acc[mt][2], ah[mt], bl1[0], bl1[1]);
                    mma16816(acc[mt][3], ah[mt], bl1[2], bl1[3]);
                }
            }
        }

        if (cl == 0) {
#pragma unroll
            for (int mt = 0; mt < 2; mt++)
#pragma unroll
                for (int nt = 0; nt < 4; nt++) {
                    int row = mbase + mt*16 + (lane >> 2);
                    int col = cbase + (nt & 1)*8 + (nt >> 1)*64 + (lane & 3)*2;
#pragma unroll
                    for (int u = 0; u < 4; u++) {
                        int dd  = col + (u & 1);
                        int tok = n0 + row + (u >> 1)*8;
                        float vv = acc[mt][nt][u] + vb[dd];
                        __nv_bfloat16 h = __float2bfloat16(vv);
                        size_t off = (size_t)(b*D_ + dd)*N_ + tok;
                        g_vh[off] = h;
                        g_vl[off] = __float2bfloat16(vv - __bfloat162float(h));
                    }
                }
        } else {
            const float* bias = (cl == 1) ? kb : qb;
            const bool isq = (cl == 2);
            __nv_bfloat16* gh = isq ? g_qh : g_kh;
            __nv_bfloat16* gl = isq ? g_ql : g_kl;
#pragma unroll
            for (int mt = 0; mt < 2; mt++)
#pragma unroll
                for (int p = 0; p < 2; p++) {
                    int c0 = cbase + p*8 + (lane & 3)*2;
                    float bl0 = bias[c0],    bl1 = bias[c0+1];
                    float bh0 = bias[c0+64], bh1 = bias[c0+65];
#pragma unroll
                    for (int rh = 0; rh < 2; rh++) {
                        int row = mbase + mt*16 + (lane >> 2) + rh*8;
                        int n = n0 + row;
                        float2 cs = *(const float2*)(g_cs + n*64 + c0);
                        float2 sn = *(const float2*)(g_sn + n*64 + c0);
                        float lo0 = acc[mt][p][rh*2+0]   + bl0;
                        float lo1 = acc[mt][p][rh*2+1]   + bl1;
                        float hi0 = acc[mt][p+2][rh*2+0] + bh0;
                        float hi1 = acc[mt][p+2][rh*2+1] + bh1;
                        float o0 = lo0*cs.x - hi0*sn.x;
                        float o1 = lo1*cs.y - hi1*sn.y;
                        float o2 = hi0*cs.x + lo0*sn.x;
                        float o3 = hi1*cs.y + lo1*sn.y;
                        if (isq) { o0 *= scl; o1 *= scl; o2 *= scl; o3 *= scl; }
                        __nv_bfloat16 h0 = __float2bfloat16(o0);
                        __nv_bfloat16 h1 = __float2bfloat16(o1);
                        __nv_bfloat16 h2 = __float2bfloat16(o2);
                        __nv_bfloat16 h3 = __float2bfloat16(o3);
                        size_t off = (size_t)(b*N_ + n)*128 + c0;
                        *(u32*)(gh + off)      = packbf(__bfloat162float(h0), __bfloat162float(h1));
                        *(u32*)(gl + off)      = packbf(o0 - __bfloat162float(h0), o1 - __bfloat162float(h1));
                        *(u32*)(gh + off + 64) = packbf(__bfloat162float(h2), __bfloat162float(h3));
                        *(u32*)(gl + off + 64) = packbf(o2 - __bfloat162float(h2), o3 - __bfloat162float(h3));
                    }
                }
        }
    }
}

// -------- tensor-core windowed attention + fused 1x1 conv --------
#define AT_QH 0
#define AT_S  34816
#define AT_QL 165888
#define AT_KH 200704
#define AT_KL 209408
#define AT_VH 165888
#define AT_VL 176128
#define AT_PH 186368
#define AT_PL 196608
#define AT_I  218624
#define AT_SMEM 219136
#define FC_AH 0
#define FC_WH 34816
#define FC_WL 69632
#define FC_AL 104448

__global__ __launch_bounds__(512) void attn_tc(const float* __restrict__ ob_,
                                               float* __restrict__ out) {
    extern __shared__ char sm8[];
    __nv_bfloat16* qhs = (__nv_bfloat16*)(sm8 + AT_QH);
    float*         S   = (float*)(sm8 + AT_S);
    __nv_bfloat16* qls = (__nv_bfloat16*)(sm8 + AT_QL);
    __nv_bfloat16* khs = (__nv_bfloat16*)(sm8 + AT_KH);
    __nv_bfloat16* kls = (__nv_bfloat16*)(sm8 + AT_KL);
    __nv_bfloat16* vhs = (__nv_bfloat16*)(sm8 + AT_VH);
    __nv_bfloat16* vls = (__nv_bfloat16*)(sm8 + AT_VL);
    __nv_bfloat16* phs = (__nv_bfloat16*)(sm8 + AT_PH);
    __nv_bfloat16* pls = (__nv_bfloat16*)(sm8 + AT_PL);
    float* irow = (float*)(sm8 + AT_I);

    const int wi = blockIdx.x, b = blockIdx.y;
    const int n0 = wi * 128, t = threadIdx.x;
    const int lane = t & 31, wid = t >> 5;
    const int warpM = wid >> 2, warpN = wid & 3;
    const int mbase = warpM * 32;
    const int rl = lane & 15, cl8 = (lane >> 4) * 8;
    const int g = lane >> 2, tg = lane & 3;
    const int l7 = lane & 7, l8 = (lane >> 3) & 1;
    const int jstart = (wi == 0) ? 128 : 0;

    const u32 qh_s = (u32)__cvta_generic_to_shared(qhs);
    const u32 ql_s = (u32)__cvta_generic_to_shared(qls);
    const u32 kh_s = (u32)__cvta_generic_to_shared(khs);
    const u32 kl_s = (u32)__cvta_generic_to_shared(kls);
    const u32 vh_s = (u32)__cvta_generic_to_shared(vhs);
    const u32 vl_s = (u32)__cvta_generic_to_shared(vls);
    const u32 ph_s = (u32)__cvta_generic_to_shared(phs);
    const u32 pl_s = (u32)__cvta_generic_to_shared(pls);

    for (int idx = t; idx < 8192; idx += 512) {
        int r = idx >> 6, c = idx & 63;
        ((u32*)qhs)[r*68 + c] = ((const u32*)(g_qh + (size_t)(b*N_ + n0 + r)*D_))[c];
        ((u32*)qls)[r*68 + c] = ((const u32*)(g_ql + (size_t)(b*N_ + n0 + r)*D_))[c];
    }

    u32 hR[4], lR[4];
    {
        int nk0 = n0 - 128;
#pragma unroll
        for (int i = 0; i < 4; i++) {
            int idx = t + i*512;
            int r = idx >> 6, c2 = idx & 63;
            int nk = nk0 + r;
            hR[i] = 0; lR[i] = 0;
            if (nk >= 0) {
                hR[i] = *(const u32*)(g_kh + (size_t)(b*N_ + nk)*D_ + c2*2);
                lR[i] = *(const u32*)(g_kl + (size_t)(b*N_ + nk)*D_ + c2*2);
            }
        }
    }

    // ==== phase 1: S = q @ k^T (3 accumulator banks) ====
#pragma unroll 1
    for (int ch = 0; ch < 8; ch++) {
        __syncthreads();
#pragma unroll
        for (int i = 0; i < 4; i++) {
            int idx = t + i*512;
            int r = idx >> 6, c2 = idx & 63;
            ((u32*)khs)[r*68 + c2] = hR[i];
            ((u32*)kls)[r*68 + c2] = lR[i];
        }
        if (ch < 7) {
            int nk0 = n0 - 128 + (ch+1)*32;
#pragma unroll
            for (int i = 0; i < 4; i++) {
                int idx = t + i*512;
                int r = idx >> 6, c2 = idx & 63;
                int nk = nk0 + r;
                hR[i] = 0; lR[i] = 0;
                if (nk >= 0) {
                    hR[i] = *(const u32*)(g_kh + (size_t)(b*N_ + nk)*D_ + c2*2);
                    lR[i] = *(const u32*)(g_kl + (size_t)(b*N_ + nk)*D_ + c2*2);
                }
            }
        }
        __syncthreads();

        if (32*ch > 159 + mbase || 32*ch + 31 < jstart) continue;

        float accQ[3][2][4];
#pragma unroll
        for (int pb2 = 0; pb2 < 3; pb2++)
#pragma unroll
            for (int mt = 0; mt < 2; mt++)
#pragma unroll
                for (int u = 0; u < 4; u++) accQ[pb2][mt][u] = 0.0f;

#pragma unroll 1
        for (int kt = 0; kt < 8; kt++) {
            u32 ah[2][4], al[2][4];
#pragma unroll
            for (int mt = 0; mt < 2; mt++) {
                u32 off = (u32)((mbase + mt*16 + rl)*136 + kt*16 + cl8) * 2;
                ldmat4(ah[mt], qh_s + off);
                ldmat4(al[mt], ql_s + off);
            }
            u32 boff = (u32)((warpN*8 + l7)*136 + kt*16 + l8*8) * 2;
            u32 bh[2], bl[2];
            ldmat2(bh, kh_s + boff);
            ldmat2(bl, kl_s + boff);
            // one MMA per bank per mt: same-bank reuse distance 6
#pragma unroll
            for (int mt = 0; mt < 2; mt++) mma16816(accQ[0][mt], ah[mt], bh[0], bh[1]);
#pragma unroll
            for (int mt = 0; mt < 2; mt++) mma16816(accQ[1][mt], al[mt], bh[0], bh[1]);
#pragma unroll
            for (int mt = 0; mt < 2; mt++) mma16816(accQ[2][mt], ah[mt], bl[0], bl[1]);
        }
#pragma unroll
        for (int mt = 0; mt < 2; mt++) {
            int row = mbase + mt*16 + g;
            int col = ch*32 + warpN*8 + tg*2;
            float a0 = accQ[0][mt][0] + accQ[1][mt][0] + accQ[2][mt][0];
            float a1 = accQ[0][mt][1] + accQ[1][mt][1] + accQ[2][mt][1];
            float a2 = accQ[0][mt][2] + accQ[1][mt][2] + accQ[2][mt][2];
            float a3 = accQ[0][mt][3] + accQ[1][mt][3] + accQ[2][mt][3];
            *(float2*)(S + row*256 + col)     = make_float2(a0, a1);
            *(float2*)(S + (row+8)*256 + col) = make_float2(a2, a3);
        }
    }

    {
        int nk0 = n0 - 128;
#pragma unroll
        for (int i = 0; i < 4; i++) {
            int idx = t + i*512;
            int dd = idx >> 4, c = idx & 15;
            int tok = nk0 + c*2;
            hR[i] = 0; lR[i] = 0;
            if (tok >= 0) {
                hR[i] = *(const u32*)(g_vh + (size_t)(b*D_ + dd)*N_ + tok);
                lR[i] = *(const u32*)(g_vl + (size_t)(b*D_ + dd)*N_ + tok);
            }
        }
    }
    __syncthreads();

    // ==== phase 2: softmax stats; writes e back into S ====
    {
        int r = t >> 2, q4 = t & 3;
        int jend = 128 + r + 1;
        float m = -3.402823466e38f;
        for (int c4 = (jstart >> 2) + q4; c4*4 < jend; c4 += 4) {
            float4 v = *(const float4*)(S + r*256 + c4*4);
            int c = c4*4;
            if (c   < jend) m = fmaxf(m, v.x);
            if (c+1 < jend) m = fmaxf(m, v.y);
            if (c+2 < jend) m = fmaxf(m, v.z);
            if (c+3 < jend) m = fmaxf(m, v.w);
        }
        m = fmaxf(m, __shfl_xor_sync(0xFFFFFFFF, m, 1));
        m = fmaxf(m, __shfl_xor_sync(0xFFFFFFFF, m, 2));
        float s = 0.0f;
        for (int c4 = (jstart >> 2) + q4; c4*4 < jend; c4 += 4) {
            float4 v = *(const float4*)(S + r*256 + c4*4);
            int c = c4*4;
            float e0 = (c   < jend) ? fexp(v.x - m) : 0.0f;
            float e1 = (c+1 < jend) ? fexp(v.y - m) : 0.0f;
            float e2 = (c+2 < jend) ? fexp(v.z - m) : 0.0f;
            float e3 = (c+3 < jend) ? fexp(v.w - m) : 0.0f;
            s += (e0 + e1) + (e2 + e3);
            *(float4*)(S + r*256 + c4*4) = make_float4(e0, e1, e2, e3);
        }
        s += __shfl_xor_sync(0xFFFFFFFF, s, 1);
        s += __shfl_xor_sync(0xFFFFFFFF, s, 2);
        if (q4 == 0) { irow[r] = 1.0f / s; }
    }

    // ==== phase 3: OUT = P @ V (prod-major) ====
    float accP[2][4][4];
#pragma unroll
    for (int mt = 0; mt < 2; mt++)
#pragma unroll
        for (int nt = 0; nt < 4; nt++)
#pragma unroll
            for (int u = 0; u < 4; u++) accP[mt][nt][u] = 0.0f;

#pragma unroll 1
    for (int ch = 0; ch < 8; ch++) {
        __syncthreads();
#pragma unroll
        for (int i = 0; i < 4; i++) {
            int idx = t + i*512;
            int dd = idx >> 4, c = idx & 15;
            *(u32*)((u16*)vhs + dd*40 + c*2) = hR[i];
            *(u32*)((u16*)vls + dd*40 + c*2) = lR[i];
        }
        {
            int r = t >> 2, c0l = (t & 3) * 8;
            float ii = irow[r];
            int jend = 128 + r + 1;
#pragma unroll
            for (int i4 = 0; i4 < 2; i4++) {
                int cg = ch*32 + c0l + i4*4;
                float4 s4 = *(const float4*)(S + r*256 + cg);
                float p[4];
                p[0] = (cg   >= jstart && cg   < jend) ? s4.x * ii : 0.0f;
                p[1] = (cg+1 >= jstart && cg+1 < jend) ? s4.y * ii : 0.0f;
                p[2] = (cg+2 >= jstart && cg+2 < jend) ? s4.z * ii : 0.0f;
                p[3] = (cg+3 >= jstart && cg+3 < jend) ? s4.w * ii : 0.0f;
                __nv_bfloat16 h0 = __float2bfloat16(p[0]);
                __nv_bfloat16 h1 = __float2bfloat16(p[1]);
                __nv_bfloat16 h2 = __float2bfloat16(p[2]);
                __nv_bfloat16 h3 = __float2bfloat16(p[3]);
                int di = (r*40 + c0l + i4*4) >> 1;
                ((u32*)phs)[di]   = packbf(__bfloat162float(h0), __bfloat162float(h1));
                ((u32*)phs)[di+1] = packbf(__bfloat162float(h2), __bfloat162float(h3));
                ((u32*)pls)[di]   = packbf(p[0] - __bfloat162float(h0), p[1] - __bfloat162float(h1));
                ((u32*)pls)[di+1] = packbf(p[2] - __bfloat162float(h2), p[3] - __bfloat162float(h3));
            }
        }
        if (ch < 7) {
            int nk0 = n0 - 128 + (ch+1)*32;
#pragma unroll
            for (int i = 0; i < 4; i++) {
                int idx = t + i*512;
                int dd = idx >> 4, c = idx & 15;
                int tok = nk0 + c*2;
                hR[i] = 0; lR[i] = 0;
                if (tok >= 0) {
                    hR[i] = *(const u32*)(g_vh + (size_t)(b*D_ + dd)*N_ + tok);
                    lR[i] = *(const u32*)(g_vl + (size_t)(b*D_ + dd)*N_ + tok);
                }
            }
        }
        __syncthreads();

        if (32*ch > 159 + mbase || 32*ch + 31 < jstart) continue;

#pragma unroll
        for (int kt = 0; kt < 2; kt++) {
            u32 pa[2][4], pb[2][4];
#pragma unroll
            for (int mt = 0; mt < 2; mt++) {
                u32 off = (u32)((mbase + mt*16 + rl)*40 + kt*16 + cl8) * 2;
                ldmat4(pa[mt], ph_s + off);
                ldmat4(pb[mt], pl_s + off);
            }
            u32 vh2[4][2], vl2[4][2];
#pragma unroll
            for (int nt = 0; nt < 4; nt++) {
                u32 boff = (u32)((warpN*32 + nt*8 + l7)*40 + kt*16 + l8*8) * 2;
                ldmat2(vh2[nt], vh_s + boff);
                ldmat2(vl2[nt], vl_s + boff);
            }
            // prod-major: same-acc reuse distance = 8 MMAs
#pragma unroll
            for (int nt = 0; nt < 4; nt++)
#pragma unroll
                for (int mt = 0; mt < 2; mt++)
                    mma16816(accP[mt][nt], pa[mt], vh2[nt][0], vh2[nt][1]);
#pragma unroll
            for (int nt = 0; nt < 4; nt++)
#pragma unroll
                for (int mt = 0; mt < 2; mt++)
                    mma16816(accP[mt][nt], pb[mt], vh2[nt][0], vh2[nt][1]);
#pragma unroll
            for (int nt = 0; nt < 4; nt++)
#pragma unroll
                for (int mt = 0; mt < 2; mt++)
                    mma16816(accP[mt][nt], pa[mt], vl2[nt][0], vl2[nt][1]);
        }
    }

    // ==== fused 1x1 conv ====
    __nv_bfloat16* ahs = (__nv_bfloat16*)(sm8 + FC_AH);
    __nv_bfloat16* als = (__nv_bfloat16*)(sm8 + FC_AL);
    __nv_bfloat16* whs = (__nv_bfloat16*)(sm8 + FC_WH);
    __nv_bfloat16* wls = (__nv_bfloat16*)(sm8 + FC_WL);

    for (int idx = t; idx < 8192; idx += 512) {
        int r = idx >> 6, c = idx & 63;
        ((u32*)whs)[r*68 + c] = ((const u32*)(g_owh + (size_t)r*D_))[c];
        ((u32*)wls)[r*68 + c] = ((const u32*)(g_owl + (size_t)r*D_))[c];
    }
#pragma unroll
    for (int mt = 0; mt < 2; mt++)
#pragma unroll
        for (int nt = 0; nt < 4; nt++) {
            int row = mbase + mt*16 + g;
            int col = warpN*32 + nt*8 + tg*2;
#pragma unroll
            for (int half = 0; half < 2; half++) {
                float v0 = accP[mt][nt][half*2];
                float v1 = accP[mt][nt][half*2+1];
                __nv_bfloat16 h0 = __float2bfloat16(v0);
                __nv_bfloat16 h1 = __float2bfloat16(v1);
                int r2 = row + half*8;
                *(u32*)(ahs + r2*136 + col) = packbf(__bfloat162float(h0), __bfloat162float(h1));
                *(u32*)(als + r2*136 + col) = packbf(v0 - __bfloat162float(h0), v1 - __bfloat162float(h1));
            }
        }
    __syncthreads();

    const u32 ah_s = (u32)__cvta_generic_to_shared(ahs);
    const u32 al_s = (u32)__cvta_generic_to_shared(als);
    const u32 wh_s = (u32)__cvta_generic_to_shared(whs);
    const u32 wl_s = (u32)__cvta_generic_to_shared(wls);
    const int nbase = warpN * 32;

    float accC[2][4][4];
#pragma unroll
    for (int mt = 0; mt < 2; mt++)
#pragma unroll
        for (int nt = 0; nt < 4; nt++)
#pragma unroll
            for (int u = 0; u < 4; u++) accC[mt][nt][u] = 0.0f;

#pragma unroll 1
    for (int kt = 0; kt < 8; kt++) {
        u32 aH[2][4], aL[2][4];
#pragma unroll
        for (int mt = 0; mt < 2; mt++) {
            u32 off = (u32)((mbase + mt*16 + rl)*136 + kt*16 + cl8) * 2;
            ldmat4(aH[mt], ah_s + off);
            ldmat4(aL[mt], al_s + off);
        }
        u32 wh2[4][2], wl2[4][2];
#pragma unroll
        for (int nt = 0; nt < 4; nt++) {
            u32 boff = (u32)((nbase + nt*8 + l7)*136 + kt*16 + l8*8) * 2;
            ldmat2(wh2[nt], wh_s + boff);
            ldmat2(wl2[nt], wl_s + boff);
        }
#pragma unroll
        for (int nt = 0; nt < 4; nt++)
#pragma unroll
            for (int mt = 0; mt < 2; mt++)
                mma16816(accC[mt][nt], aH[mt], wh2[nt][0], wh2[nt][1]);
#pragma unroll
        for (int nt = 0; nt < 4; nt++)
#pragma unroll
            for (int mt = 0; mt < 2; mt++)
                mma16816(accC[mt][nt], aL[mt], wh2[nt][0], wh2[nt][1]);
#pragma unroll
        for (int nt = 0; nt < 4; nt++)
#pragma unroll
            for (int mt = 0; mt < 2; mt++)
                mma16816(accC[mt][nt], aH[mt], wl2[nt][0], wl2[nt][1]);
    }

#pragma unroll
    for (int mt = 0; mt < 2; mt++)
#pragma unroll
        for (int nt = 0; nt < 4; nt++) {
            int row = mbase + mt*16 + g;
            int col = nbase + nt*8 + tg*2;
#pragma unroll
            for (int u = 0; u < 4; u++) {
                int dd  = col + (u & 1);
                int tok = n0 + row + (u >> 1)*8;
                out[(size_t)(b*D_ + dd)*N_ + tok] = accC[mt][nt][u] + ob_[dd];
            }
        }
}

// ---------------- BatchNorm ----------------
__global__ void bn_stats(const float* __restrict__ y, const float* __restrict__ gamma,
                         const float* __restrict__ beta) {
    int d = blockIdx.x, t = threadIdx.x;
    double s = 0.0, s2 = 0.0;
    for (int b = 0; b < B_; b++) {
        const float* p = y + (size_t)(b*D_ + d) * N_;
        for (int n = t; n < N_; n += 256) { double v = p[n]; s += v; s2 += v*v; }
    }
    __shared__ double sh[512];
    sh[t] = s; sh[256 + t] = s2;
    __syncthreads();
    for (int o = 128; o > 0; o >>= 1) {
        if (t < o) { sh[t] += sh[t+o]; sh[256+t] += sh[256+t+o]; }
        __syncthreads();
    }
    if (t == 0) {
        double cnt = (double)B_ * (double)N_;
        double m = sh[0] / cnt;
        double var = sh[256] / cnt - m*m;
        double rs = rsqrt(var + 1e-5);
        double sc = rs * (double)gamma[d];
        g_scale[d] = (float)sc;
        g_shift[d] = (float)((double)beta[d] - m*sc);
    }
}

__global__ void bn_apply(float* __restrict__ y) {
    int i = (blockIdx.x * 256 + threadIdx.x) * 4;
    int d = (i >> 13) & 127;
    float sc = g_scale[d], sh = g_shift[d];
    float4 v = *(float4*)(y + i);
    v.x = v.x*sc + sh; v.y = v.y*sc + sh; v.z = v.z*sc + sh; v.w = v.w*sc + sh;
    *(float4*)(y + i) = v;
}

// ---------------- launch ----------------
extern "C" void kernel_launch(void* const* d_in, const int* in_sizes, int n_in,
                              void* d_out, int out_size) {
    const float* x  = (const float*)d_in[0];
    const float* qw = (const float*)d_in[1];
    const float* qb = (const float*)d_in[2];
    const float* kw = (const float*)d_in[3];
    const float* kb = (const float*)d_in[4];
    const float* vw = (const float*)d_in[5];
    const float* vb = (const float*)d_in[6];
    const float* ow = (const float*)d_in[7];
    const float* ob = (const float*)d_in[8];
    const float* gamma = (const float*)d_in[9];
    const float* beta  = (const float*)d_in[10];
    float* out = (float*)d_out;

    cudaFuncSetAttribute(qkv_tc, cudaFuncAttributeMaxDynamicSharedMemorySize, QKV_TC_SMEM);
    cudaFuncSetAttribute(attn_tc, cudaFuncAttributeMaxDynamicSharedMemorySize, AT_SMEM);

    prep_wsplit<<<(3*8*5*128*16 + 255) / 256, 256>>>(qw, kw, vw);
    prep_owsplit<<<(D_*D_ + 255) / 256, 256>>>(ow);
    prep_trig<<<(N_*64) / 256, 256>>>();
    qkv_tc<<<dim3(N_/128, B_), 512, QKV_TC_SMEM>>>(x, qb, kb, vb);
    attn_tc<<<dim3(NW_, B_), 512, AT_SMEM>>>(ob, out);
    bn_stats<<<D_, 256>>>(out, gamma, beta);
    bn_apply<<<(B_*D_*N_) / 1024, 256>>>(out);
}

// round 16
// speedup vs baseline: 2.5503x; 1.0033x over previous
#include <cuda_runtime.h>
#include <cuda_bf16.h>
#include <math.h>

#define B_ 16
#define D_ 128
#define N_ 8192
#define NW_ 64

typedef unsigned long long ull;
typedef unsigned int u32;
typedef unsigned short u16;

// ---------------- device scratch ----------------
__device__ __align__(16) __nv_bfloat16 g_wsp[3*8*2*5*128*16];
__device__ float g_cs[N_*64];
__device__ float g_sn[N_*64];
__device__ __align__(16) __nv_bfloat16 g_qh[B_*N_*D_];
__device__ __align__(16) __nv_bfloat16 g_ql[B_*N_*D_];
__device__ __align__(16) __nv_bfloat16 g_kh[B_*N_*D_];
__device__ __align__(16) __nv_bfloat16 g_kl[B_*N_*D_];
__device__ __align__(16) __nv_bfloat16 g_vh[B_*D_*N_];
__device__ __align__(16) __nv_bfloat16 g_vl[B_*D_*N_];
__device__ __align__(16) __nv_bfloat16 g_owh[D_*D_];
__device__ __align__(16) __nv_bfloat16 g_owl[D_*D_];
__device__ double g_bp1[B_*D_];
__device__ double g_bp2[B_*D_];
__device__ float g_scale[D_];
__device__ float g_shift[D_];

// ---------------- mma / async helpers ----------------
__device__ __forceinline__ void mma16816(float* c, const u32* a, u32 b0, u32 b1) {
    asm("mma.sync.aligned.m16n8k16.row.col.f32.bf16.bf16.f32 "
        "{%0,%1,%2,%3}, {%4,%5,%6,%7}, {%8,%9}, {%0,%1,%2,%3};"
        : "+f"(c[0]), "+f"(c[1]), "+f"(c[2]), "+f"(c[3])
        : "r"(a[0]), "r"(a[1]), "r"(a[2]), "r"(a[3]), "r"(b0), "r"(b1));
}
__device__ __forceinline__ void ldmat4(u32* r, u32 addr) {
    asm volatile("ldmatrix.sync.aligned.m8n8.x4.shared.b16 {%0,%1,%2,%3}, [%4];"
                 : "=r"(r[0]), "=r"(r[1]), "=r"(r[2]), "=r"(r[3]) : "r"(addr));
}
__device__ __forceinline__ void ldmat2(u32* r, u32 addr) {
    asm volatile("ldmatrix.sync.aligned.m8n8.x2.shared.b16 {%0,%1}, [%2];"
                 : "=r"(r[0]), "=r"(r[1]) : "r"(addr));
}
__device__ __forceinline__ u32 packbf(float a, float b) {
    __nv_bfloat162 t = __floats2bfloat162_rn(a, b);
    return *(u32*)&t;
}
__device__ __forceinline__ float fexp(float x) {
    float y = fmaxf(x * 1.4426950408889634f, -126.0f);
    float fy = rintf(y);
    float f = y - fy;
    float p = 0.0013333558f;
    p = fmaf(p, f, 0.0096181291f);
    p = fmaf(p, f, 0.0555041087f);
    p = fmaf(p, f, 0.2402265070f);
    p = fmaf(p, f, 0.6931471806f);
    p = fmaf(p, f, 1.0f);
    int e = __float2int_rn(y);
    float s = __int_as_float((e + 127) << 23);
    return p * s;
}
#define CP_ASYNC16(dst, src) \
    asm volatile("cp.async.cg.shared.global [%0], [%1], 16;" :: "r"(dst), "l"(src))
#define CP_COMMIT() asm volatile("cp.async.commit_group;" ::: "memory")
#define CP_WAIT1()  asm volatile("cp.async.wait_group 1;" ::: "memory")

#define WBLK_BYTES 40960

// ---------------- prep ----------------
__global__ void prep_wsplit(const float* __restrict__ qw, const float* __restrict__ kw,
                            const float* __restrict__ vw) {
    int e = blockIdx.x * blockDim.x + threadIdx.x;
    if (e >= 3*8*5*128*16) return;
    int ii = e % 16;
    int o  = (e / 16) % 128;
    int t  = (e / 2048) % 5;
    int ch = (e / 10240) % 8;
    int c  = e / 81920;
    const float* w = (c == 0) ? qw : (c == 1) ? kw : vw;
    float v = w[o*640 + (ch*16 + ii)*5 + t];
    __nv_bfloat16 hi = __float2bfloat16(v);
    __nv_bfloat16 lo = __float2bfloat16(v - __bfloat162float(hi));
    int base = (c*8 + ch) * 20480;
    int iisw = ii ^ ((o & 4) ? 8 : 0);
    int off  = t*2048 + o*16 + iisw;
    g_wsp[base + off]         = hi;
    g_wsp[base + 10240 + off] = lo;
}

__global__ void prep_owsplit(const float* __restrict__ ow) {
    int e = blockIdx.x * blockDim.x + threadIdx.x;
    if (e >= D_*D_) return;
    float v = ow[e];
    __nv_bfloat16 hi = __float2bfloat16(v);
    g_owh[e] = hi;
    g_owl[e] = __float2bfloat16(v - __bfloat162float(hi));
}

__global__ void prep_trig() {
    __shared__ float invf_s[64];
    int t = threadIdx.x;
    if (t < 64) invf_s[t] = (float)pow(10000.0, -((double)(2*t)) / 128.0);
    __syncthreads();
    int e = blockIdx.x * 256 + t;
    int n = e >> 6, f = e & 63;
    float ang = (float)n * invf_s[f];
    double s, c;
    sincos((double)ang, &s, &c);
    g_cs[e] = (float)c;
    g_sn[e] = (float)s;
}

// ---------- tensor-core fused QKV conv (unchanged from R15) ----------
#define XH_OFF 0
#define XL_OFF 35904
#define W_OFF  71808
#define QKV_TC_SMEM 194688
#define XSTR 136

__global__ __launch_bounds__(512) void qkv_tc(const float* __restrict__ x,
                                              const float* __restrict__ qb,
                                              const float* __restrict__ kb,
                                              const float* __restrict__ vb) {
    extern __shared__ char smem[];
    __nv_bfloat16* xh = (__nv_bfloat16*)(smem + XH_OFF);
    __nv_bfloat16* xl = (__nv_bfloat16*)(smem + XL_OFF);

    const int b = blockIdx.y, n0 = blockIdx.x * 128;
    const int t = threadIdx.x;
    const int lane = t & 31, wid = t >> 5;
    const int warpM = wid >> 2, warpN = wid & 3;
    const int mbase = warpM * 32, cbase = warpN * 16;

    const u32 w_s = (u32)__cvta_generic_to_shared(smem + W_OFF);

    {
        const char* s0 = (const char*)g_wsp + (size_t)16 * WBLK_BYTES + t*16;
        u32 d0 = w_s + t*16;
#pragma unroll
        for (int k2 = 0; k2 < 5; k2++) CP_ASYNC16(d0 + k2*8192, s0 + k2*8192);
        CP_COMMIT();
        const char* s1 = (const char*)g_wsp + (size_t)17 * WBLK_BYTES + t*16;
        u32 d1 = w_s + 40960 + t*16;
#pragma unroll
        for (int k2 = 0; k2 < 5; k2++) CP_ASYNC16(d1 + k2*8192, s1 + k2*8192);
        CP_COMMIT();
    }

    for (int idx = t; idx < 128*132; idx += 512) {
        int i = idx / 132, c = idx % 132;
        int n = n0 - 4 + c;
        float v = (n >= 0) ? x[(size_t)(b*D_ + i)*N_ + n] : 0.0f;
        __nv_bfloat16 hi = __float2bfloat16(v);
        xh[c*XSTR + i] = hi;
        xl[c*XSTR + i] = __float2bfloat16(v - __bfloat162float(hi));
    }

    const u32 xh_s = (u32)__cvta_generic_to_shared(xh);
    const u32 xl_s = (u32)__cvta_generic_to_shared(xl);
    const int rl = lane & 15, cl8 = (lane >> 4) * 8;

    const int oA = cbase + ((lane >> 4) & 1)*8 + (lane & 7);
    const u32 koffA = (u32)((((lane >> 3) & 1)*16) ^ ((oA & 4) ? 16 : 0));
    const u32 bA = (u32)(oA*32) + koffA;
    const int oB = oA + 64;
    const u32 koffB = (u32)((((lane >> 3) & 1)*16) ^ ((oB & 4) ? 16 : 0));
    const u32 bB = (u32)(oB*32) + koffB;

    const float scl = 0.08838834764831845f;

#pragma unroll 1
    for (int cl = 0; cl < 3; cl++) {
        float acc[2][4][4];
#pragma unroll
        for (int mt = 0; mt < 2; mt++)
#pragma unroll
            for (int nt = 0; nt < 4; nt++)
#pragma unroll
                for (int u = 0; u < 4; u++) acc[mt][nt][u] = 0.0f;

#pragma unroll 1
        for (int ch = 0; ch < 8; ch++) {
            const int idx = cl*8 + ch;
            CP_WAIT1();
            __syncthreads();
            int nidx = idx + 2;
            if (nidx < 24) {
                int cl2 = nidx >> 3, ch2 = nidx & 7;
                int c2 = (cl2 == 0) ? 2 : (cl2 == 1) ? 1 : 0;
                const char* src = (const char*)g_wsp + (size_t)(c2*8 + ch2)*WBLK_BYTES + t*16;
                u32 dst = w_s + (u32)(nidx % 3)*40960 + t*16;
#pragma unroll
                for (int k2 = 0; k2 < 5; k2++)
                    CP_ASYNC16(dst + k2*8192, src + k2*8192);
            }
            CP_COMMIT();

            const u32 wb = w_s + (u32)(idx % 3)*40960;

#pragma unroll 1
            for (int tap = 0; tap < 5; tap++) {
                u32 ah[2][4], al[2][4];
#pragma unroll
                for (int mt = 0; mt < 2; mt++) {
                    int row = mbase + mt*16 + rl + tap;
                    int col = ch*16 + cl8;
                    u32 off = (u32)(row*XSTR + col) * 2;
                    ldmat4(ah[mt], xh_s + off);
                    ldmat4(al[mt], xl_s + off);
                }
                const u32 tb = wb + (u32)(tap*4096);
                u32 bh0[4], bl0[4], bh1[4], bl1[4];
                ldmat4(bh0, tb + bA);
                ldmat4(bl0, tb + 20480 + bA);
                ldmat4(bh1, tb + bB);
                ldmat4(bl1, tb + 20480 + bB);
#pragma unroll
                for (int mt = 0; mt < 2; mt++) {
                    mma16816(acc[mt][0], ah[mt], bh0[0], bh0[1]);
                    mma16816(acc[mt][1], ah[mt], bh0[2], bh0[3]);
                    mma16816(acc[mt][2], ah[mt], bh1[0], bh1[1]);
                    mma16816(acc[mt][3], ah[mt], bh1[2], bh1[3]);
                }
#pragma unroll
                for (int mt = 0; mt < 2; mt++) {
                    mma16816(acc[mt][0], al[mt], bh0[0], bh0[1]);
                    mma16816(acc[mt][1], al[mt], bh0[2], bh0[3]);
                    mma16816(acc[mt][2], al[mt], bh1[0], bh1[1]);
                    mma16816(acc[mt][3], al[mt], bh1[2], bh1[3]);
                }
#pragma unroll
                for (int mt = 0; mt < 2; mt++) {
                    mma16816(acc[mt][0], ah[mt], bl0[0], bl0[1]);
                    mma16816(acc[mt][1], ah[mt], bl0[2], bl0[3]);
                    mma16816(acc[mt][2], ah[mt], bl1[0], bl1[1]);
                    mma16816(acc[mt][3], ah[mt], bl1[2], bl1[3]);
                }
            }
        }

        if (cl == 0) {
#pragma unroll
            for (int mt = 0; mt < 2; mt++)
#pragma unroll
                for (int nt = 0; nt < 4; nt++) {
                    int row = mbase + mt*16 + (lane >> 2);
                    int col = cbase + (nt & 1)*8 + (nt >> 1)*64 + (lane & 3)*2;
#pragma unroll
                    for (int u = 0; u < 4; u++) {
                        int dd  = col + (u & 1);
                        int tok = n0 + row + (u >> 1)*8;
                        float vv = acc[mt][nt][u] + vb[dd];
                        __nv_bfloat16 h = __float2bfloat16(vv);
                        size_t off = (size_t)(b*D_ + dd)*N_ + tok;
                        g_vh[off] = h;
                        g_vl[off] = __float2bfloat16(vv - __bfloat162float(h));
                    }
                }
        } else {
            const float* bias = (cl == 1) ? kb : qb;
            const bool isq = (cl == 2);
            __nv_bfloat16* gh = isq ? g_qh : g_kh;
            __nv_bfloat16* gl = isq ? g_ql : g_kl;
#pragma unroll
            for (int mt = 0; mt < 2; mt++)
#pragma unroll
                for (int p = 0; p < 2; p++) {
                    int c0 = cbase + p*8 + (lane & 3)*2;
                    float bl0 = bias[c0],    bl1 = bias[c0+1];
                    float bh0 = bias[c0+64], bh1 = bias[c0+65];
#pragma unroll
                    for (int rh = 0; rh < 2; rh++) {
                        int row = mbase + mt*16 + (lane >> 2) + rh*8;
                        int n = n0 + row;
                        float2 cs = *(const float2*)(g_cs + n*64 + c0);
                        float2 sn = *(const float2*)(g_sn + n*64 + c0);
                        float lo0 = acc[mt][p][rh*2+0]   + bl0;
                        float lo1 = acc[mt][p][rh*2+1]   + bl1;
                        float hi0 = acc[mt][p+2][rh*2+0] + bh0;
                        float hi1 = acc[mt][p+2][rh*2+1] + bh1;
                        float o0 = lo0*cs.x - hi0*sn.x;
                        float o1 = lo1*cs.y - hi1*sn.y;
                        float o2 = hi0*cs.x + lo0*sn.x;
                        float o3 = hi1*cs.y + lo1*sn.y;
                        if (isq) { o0 *= scl; o1 *= scl; o2 *= scl; o3 *= scl; }
                        __nv_bfloat16 h0 = __float2bfloat16(o0);
                        __nv_bfloat16 h1 = __float2bfloat16(o1);
                        __nv_bfloat16 h2 = __float2bfloat16(o2);
                        __nv_bfloat16 h3 = __float2bfloat16(o3);
                        size_t off = (size_t)(b*N_ + n)*128 + c0;
                        *(u32*)(gh + off)      = packbf(__bfloat162float(h0), __bfloat162float(h1));
                        *(u32*)(gl + off)      = packbf(o0 - __bfloat162float(h0), o1 - __bfloat162float(h1));
                        *(u32*)(gh + off + 64) = packbf(__bfloat162float(h2), __bfloat162float(h3));
                        *(u32*)(gl + off + 64) = packbf(o2 - __bfloat162float(h2), o3 - __bfloat162float(h3));
                    }
                }
        }
    }
}

// -------- tensor-core windowed attention + fused 1x1 conv (unchanged) --------
#define AT_QH 0
#define AT_S  34816
#define AT_QL 165888
#define AT_KH 200704
#define AT_KL 209408
#define AT_VH 165888
#define AT_VL 176128
#define AT_PH 186368
#define AT_PL 196608
#define AT_I  218624
#define AT_SMEM 219136
#define FC_AH 0
#define FC_WH 34816
#define FC_WL 69632
#define FC_AL 104448

__global__ __launch_bounds__(512) void attn_tc(const float* __restrict__ ob_,
                                               float* __restrict__ out) {
    extern __shared__ char sm8[];
    __nv_bfloat16* qhs = (__nv_bfloat16*)(sm8 + AT_QH);
    float*         S   = (float*)(sm8 + AT_S);
    __nv_bfloat16* qls = (__nv_bfloat16*)(sm8 + AT_QL);
    __nv_bfloat16* khs = (__nv_bfloat16*)(sm8 + AT_KH);
    __nv_bfloat16* kls = (__nv_bfloat16*)(sm8 + AT_KL);
    __nv_bfloat16* vhs = (__nv_bfloat16*)(sm8 + AT_VH);
    __nv_bfloat16* vls = (__nv_bfloat16*)(sm8 + AT_VL);
    __nv_bfloat16* phs = (__nv_bfloat16*)(sm8 + AT_PH);
    __nv_bfloat16* pls = (__nv_bfloat16*)(sm8 + AT_PL);
    float* irow = (float*)(sm8 + AT_I);

    const int wi = blockIdx.x, b = blockIdx.y;
    const int n0 = wi * 128, t = threadIdx.x;
    const int lane = t & 31, wid = t >> 5;
    const int warpM = wid >> 2, warpN = wid & 3;
    const int mbase = warpM * 32;
    const int rl = lane & 15, cl8 = (lane >> 4) * 8;
    const int g = lane >> 2, tg = lane & 3;
    const int l7 = lane & 7, l8 = (lane >> 3) & 1;
    const int jstart = (wi == 0) ? 128 : 0;

    const u32 qh_s = (u32)__cvta_generic_to_shared(qhs);
    const u32 ql_s = (u32)__cvta_generic_to_shared(qls);
    const u32 kh_s = (u32)__cvta_generic_to_shared(khs);
    const u32 kl_s = (u32)__cvta_generic_to_shared(kls);
    const u32 vh_s = (u32)__cvta_generic_to_shared(vhs);
    const u32 vl_s = (u32)__cvta_generic_to_shared(vls);
    const u32 ph_s = (u32)__cvta_generic_to_shared(phs);
    const u32 pl_s = (u32)__cvta_generic_to_shared(pls);

    for (int idx = t; idx < 8192; idx += 512) {
        int r = idx >> 6, c = idx & 63;
        ((u32*)qhs)[r*68 + c] = ((const u32*)(g_qh + (size_t)(b*N_ + n0 + r)*D_))[c];
        ((u32*)qls)[r*68 + c] = ((const u32*)(g_ql + (size_t)(b*N_ + n0 + r)*D_))[c];
    }

    u32 hR[4], lR[4];
    {
        int nk0 = n0 - 128;
#pragma unroll
        for (int i = 0; i < 4; i++) {
            int idx = t + i*512;
            int r = idx >> 6, c2 = idx & 63;
            int nk = nk0 + r;
            hR[i] = 0; lR[i] = 0;
            if (nk >= 0) {
                hR[i] = *(const u32*)(g_kh + (size_t)(b*N_ + nk)*D_ + c2*2);
                lR[i] = *(const u32*)(g_kl + (size_t)(b*N_ + nk)*D_ + c2*2);
            }
        }
    }

#pragma unroll 1
    for (int ch = 0; ch < 8; ch++) {
        __syncthreads();
#pragma unroll
        for (int i = 0; i < 4; i++) {
            int idx = t + i*512;
            int r = idx >> 6, c2 = idx & 63;
            ((u32*)khs)[r*68 + c2] = hR[i];
            ((u32*)kls)[r*68 + c2] = lR[i];
        }
        if (ch < 7) {
            int nk0 = n0 - 128 + (ch+1)*32;
#pragma unroll
            for (int i = 0; i < 4; i++) {
                int idx = t + i*512;
                int r = idx >> 6, c2 = idx & 63;
                int nk = nk0 + r;
                hR[i] = 0; lR[i] = 0;
                if (nk >= 0) {
                    hR[i] = *(const u32*)(g_kh + (size_t)(b*N_ + nk)*D_ + c2*2);
                    lR[i] = *(const u32*)(g_kl + (size_t)(b*N_ + nk)*D_ + c2*2);
                }
            }
        }
        __syncthreads();

        if (32*ch > 159 + mbase || 32*ch + 31 < jstart) continue;

        float accQ[3][2][4];
#pragma unroll
        for (int pb2 = 0; pb2 < 3; pb2++)
#pragma unroll
            for (int mt = 0; mt < 2; mt++)
#pragma unroll
                for (int u = 0; u < 4; u++) accQ[pb2][mt][u] = 0.0f;

#pragma unroll 1
        for (int kt = 0; kt < 8; kt++) {
            u32 ah[2][4], al[2][4];
#pragma unroll
            for (int mt = 0; mt < 2; mt++) {
                u32 off = (u32)((mbase + mt*16 + rl)*136 + kt*16 + cl8) * 2;
                ldmat4(ah[mt], qh_s + off);
                ldmat4(al[mt], ql_s + off);
            }
            u32 boff = (u32)((warpN*8 + l7)*136 + kt*16 + l8*8) * 2;
            u32 bh[2], bl[2];
            ldmat2(bh, kh_s + boff);
            ldmat2(bl, kl_s + boff);
#pragma unroll
            for (int mt = 0; mt < 2; mt++) mma16816(accQ[0][mt], ah[mt], bh[0], bh[1]);
#pragma unroll
            for (int mt = 0; mt < 2; mt++) mma16816(accQ[1][mt], al[mt], bh[0], bh[1]);
#pragma unroll
            for (int mt = 0; mt < 2; mt++) mma16816(accQ[2][mt], ah[mt], bl[0], bl[1]);
        }
#pragma unroll
        for (int mt = 0; mt < 2; mt++) {
            int row = mbase + mt*16 + g;
            int col = ch*32 + warpN*8 + tg*2;
            float a0 = accQ[0][mt][0] + accQ[1][mt][0] + accQ[2][mt][0];
            float a1 = accQ[0][mt][1] + accQ[1][mt][1] + accQ[2][mt][1];
            float a2 = accQ[0][mt][2] + accQ[1][mt][2] + accQ[2][mt][2];
            float a3 = accQ[0][mt][3] + accQ[1][mt][3] + accQ[2][mt][3];
            *(float2*)(S + row*256 + col)     = make_float2(a0, a1);
            *(float2*)(S + (row+8)*256 + col) = make_float2(a2, a3);
        }
    }

    {
        int nk0 = n0 - 128;
#pragma unroll
        for (int i = 0; i < 4; i++) {
            int idx = t + i*512;
            int dd = idx >> 4, c = idx & 15;
            int tok = nk0 + c*2;
            hR[i] = 0; lR[i] = 0;
            if (tok >= 0) {
                hR[i] = *(const u32*)(g_vh + (size_t)(b*D_ + dd)*N_ + tok);
                lR[i] = *(const u32*)(g_vl + (size_t)(b*D_ + dd)*N_ + tok);
            }
        }
    }
    __syncthreads();

    {
        int r = t >> 2, q4 = t & 3;
        int jend = 128 + r + 1;
        float m = -3.402823466e38f;
        for (int c4 = (jstart >> 2) + q4; c4*4 < jend; c4 += 4) {
            float4 v = *(const float4*)(S + r*256 + c4*4);
            int c = c4*4;
            if (c   < jend) m = fmaxf(m, v.x);
            if (c+1 < jend) m = fmaxf(m, v.y);
            if (c+2 < jend) m = fmaxf(m, v.z);
            if (c+3 < jend) m = fmaxf(m, v.w);
        }
        m = fmaxf(m, __shfl_xor_sync(0xFFFFFFFF, m, 1));
        m = fmaxf(m, __shfl_xor_sync(0xFFFFFFFF, m, 2));
        float s = 0.0f;
        for (int c4 = (jstart >> 2) + q4; c4*4 < jend; c4 += 4) {
            float4 v = *(const float4*)(S + r*256 + c4*4);
            int c = c4*4;
            float e0 = (c   < jend) ? fexp(v.x - m) : 0.0f;
            float e1 = (c+1 < jend) ? fexp(v.y - m) : 0.0f;
            float e2 = (c+2 < jend) ? fexp(v.z - m) : 0.0f;
            float e3 = (c+3 < jend) ? fexp(v.w - m) : 0.0f;
            s += (e0 + e1) + (e2 + e3);
            *(float4*)(S + r*256 + c4*4) = make_float4(e0, e1, e2, e3);
        }
        s += __shfl_xor_sync(0xFFFFFFFF, s, 1);
        s += __shfl_xor_sync(0xFFFFFFFF, s, 2);
        if (q4 == 0) { irow[r] = 1.0f / s; }
    }

    float accP[2][4][4];
#pragma unroll
    for (int mt = 0; mt < 2; mt++)
#pragma unroll
        for (int nt = 0; nt < 4; nt++)
#pragma unroll
            for (int u = 0; u < 4; u++) accP[mt][nt][u] = 0.0f;

#pragma unroll 1
    for (int ch = 0; ch < 8; ch++) {
        __syncthreads();
#pragma unroll
        for (int i = 0; i < 4; i++) {
            int idx = t + i*512;
            int dd = idx >> 4, c = idx & 15;
            *(u32*)((u16*)vhs + dd*40 + c*2) = hR[i];
            *(u32*)((u16*)vls + dd*40 + c*2) = lR[i];
        }
        {
            int r = t >> 2, c0l = (t & 3) * 8;
            float ii = irow[r];
            int jend = 128 + r + 1;
#pragma unroll
            for (int i4 = 0; i4 < 2; i4++) {
                int cg = ch*32 + c0l + i4*4;
                float4 s4 = *(const float4*)(S + r*256 + cg);
                float p[4];
                p[0] = (cg   >= jstart && cg   < jend) ? s4.x * ii : 0.0f;
                p[1] = (cg+1 >= jstart && cg+1 < jend) ? s4.y * ii : 0.0f;
                p[2] = (cg+2 >= jstart && cg+2 < jend) ? s4.z * ii : 0.0f;
                p[3] = (cg+3 >= jstart && cg+3 < jend) ? s4.w * ii : 0.0f;
                __nv_bfloat16 h0 = __float2bfloat16(p[0]);
                __nv_bfloat16 h1 = __float2bfloat16(p[1]);
                __nv_bfloat16 h2 = __float2bfloat16(p[2]);
                __nv_bfloat16 h3 = __float2bfloat16(p[3]);
                int di = (r*40 + c0l + i4*4) >> 1;
                ((u32*)phs)[di]   = packbf(__bfloat162float(h0), __bfloat162float(h1));
                ((u32*)phs)[di+1] = packbf(__bfloat162float(h2), __bfloat162float(h3));
                ((u32*)pls)[di]   = packbf(p[0] - __bfloat162float(h0), p[1] - __bfloat162float(h1));
                ((u32*)pls)[di+1] = packbf(p[2] - __bfloat162float(h2), p[3] - __bfloat162float(h3));
            }
        }
        if (ch < 7) {
            int nk0 = n0 - 128 + (ch+1)*32;
#pragma unroll
            for (int i = 0; i < 4; i++) {
                int idx = t + i*512;
                int dd = idx >> 4, c = idx & 15;
                int tok = nk0 + c*2;
                hR[i] = 0; lR[i] = 0;
                if (tok >= 0) {
                    hR[i] = *(const u32*)(g_vh + (size_t)(b*D_ + dd)*N_ + tok);
                    lR[i] = *(const u32*)(g_vl + (size_t)(b*D_ + dd)*N_ + tok);
                }
            }
        }
        __syncthreads();

        if (32*ch > 159 + mbase || 32*ch + 31 < jstart) continue;

#pragma unroll
        for (int kt = 0; kt < 2; kt++) {
            u32 pa[2][4], pb[2][4];
#pragma unroll
            for (int mt = 0; mt < 2; mt++) {
                u32 off = (u32)((mbase + mt*16 + rl)*40 + kt*16 + cl8) * 2;
                ldmat4(pa[mt], ph_s + off);
                ldmat4(pb[mt], pl_s + off);
            }
            u32 vh2[4][2], vl2[4][2];
#pragma unroll
            for (int nt = 0; nt < 4; nt++) {
                u32 boff = (u32)((warpN*32 + nt*8 + l7)*40 + kt*16 + l8*8) * 2;
                ldmat2(vh2[nt], vh_s + boff);
                ldmat2(vl2[nt], vl_s + boff);
            }
#pragma unroll
            for (int nt = 0; nt < 4; nt++)
#pragma unroll
                for (int mt = 0; mt < 2; mt++)
                    mma16816(accP[mt][nt], pa[mt], vh2[nt][0], vh2[nt][1]);
#pragma unroll
            for (int nt = 0; nt < 4; nt++)
#pragma unroll
                for (int mt = 0; mt < 2; mt++)
                    mma16816(accP[mt][nt], pb[mt], vh2[nt][0], vh2[nt][1]);
#pragma unroll
            for (int nt = 0; nt < 4; nt++)
#pragma unroll
                for (int mt = 0; mt < 2; mt++)
                    mma16816(accP[mt][nt], pa[mt], vl2[nt][0], vl2[nt][1]);
        }
    }

    // ==== fused 1x1 conv ====
    __nv_bfloat16* ahs = (__nv_bfloat16*)(sm8 + FC_AH);
    __nv_bfloat16* als = (__nv_bfloat16*)(sm8 + FC_AL);
    __nv_bfloat16* whs = (__nv_bfloat16*)(sm8 + FC_WH);
    __nv_bfloat16* wls = (__nv_bfloat16*)(sm8 + FC_WL);

    for (int idx = t; idx < 8192; idx += 512) {
        int r = idx >> 6, c = idx & 63;
        ((u32*)whs)[r*68 + c] = ((const u32*)(g_owh + (size_t)r*D_))[c];
        ((u32*)wls)[r*68 + c] = ((const u32*)(g_owl + (size_t)r*D_))[c];
    }
#pragma unroll
    for (int mt = 0; mt < 2; mt++)
#pragma unroll
        for (int nt = 0; nt < 4; nt++) {
            int row = mbase + mt*16 + g;
            int col = warpN*32 + nt*8 + tg*2;
#pragma unroll
            for (int half = 0; half < 2; half++) {
                float v0 = accP[mt][nt][half*2];
                float v1 = accP[mt][nt][half*2+1];
                __nv_bfloat16 h0 = __float2bfloat16(v0);
                __nv_bfloat16 h1 = __float2bfloat16(v1);
                int r2 = row + half*8;
                *(u32*)(ahs + r2*136 + col) = packbf(__bfloat162float(h0), __bfloat162float(h1));
                *(u32*)(als + r2*136 + col) = packbf(v0 - __bfloat162float(h0), v1 - __bfloat162float(h1));
            }
        }
    __syncthreads();

    const u32 ah_s = (u32)__cvta_generic_to_shared(ahs);
    const u32 al_s = (u32)__cvta_generic_to_shared(als);
    const u32 wh_s = (u32)__cvta_generic_to_shared(whs);
    const u32 wl_s = (u32)__cvta_generic_to_shared(wls);
    const int nbase = warpN * 32;

    float accC[2][4][4];
#pragma unroll
    for (int mt = 0; mt < 2; mt++)
#pragma unroll
        for (int nt = 0; nt < 4; nt++)
#pragma unroll
            for (int u = 0; u < 4; u++) accC[mt][nt][u] = 0.0f;

#pragma unroll 1
    for (int kt = 0; kt < 8; kt++) {
        u32 aH[2][4], aL[2][4];
#pragma unroll
        for (int mt = 0; mt < 2; mt++) {
            u32 off = (u32)((mbase + mt*16 + rl)*136 + kt*16 + cl8) * 2;
            ldmat4(aH[mt], ah_s + off);
            ldmat4(aL[mt], al_s + off);
        }
        u32 wh2[4][2], wl2[4][2];
#pragma unroll
        for (int nt = 0; nt < 4; nt++) {
            u32 boff = (u32)((nbase + nt*8 + l7)*136 + kt*16 + l8*8) * 2;
            ldmat2(wh2[nt], wh_s + boff);
            ldmat2(wl2[nt], wl_s + boff);
        }
#pragma unroll
        for (int nt = 0; nt < 4; nt++)
#pragma unroll
            for (int mt = 0; mt < 2; mt++)
                mma16816(accC[mt][nt], aH[mt], wh2[nt][0], wh2[nt][1]);
#pragma unroll
        for (int nt = 0; nt < 4; nt++)
#pragma unroll
            for (int mt = 0; mt < 2; mt++)
                mma16816(accC[mt][nt], aL[mt], wh2[nt][0], wh2[nt][1]);
#pragma unroll
        for (int nt = 0; nt < 4; nt++)
#pragma unroll
            for (int mt = 0; mt < 2; mt++)
                mma16816(accC[mt][nt], aH[mt], wl2[nt][0], wl2[nt][1]);
    }

#pragma unroll
    for (int mt = 0; mt < 2; mt++)
#pragma unroll
        for (int nt = 0; nt < 4; nt++) {
            int row = mbase + mt*16 + g;
            int col = nbase + nt*8 + tg*2;
#pragma unroll
            for (int u = 0; u < 4; u++) {
                int dd  = col + (u & 1);
                int tok = n0 + row + (u >> 1)*8;
                out[(size_t)(b*D_ + dd)*N_ + tok] = accC[mt][nt][u] + ob_[dd];
            }
        }
}

// ---------------- BatchNorm: two-stage deterministic stats ----------------
__global__ void bn_stats1(const float* __restrict__ y) {
    int d = blockIdx.x, b = blockIdx.y, t = threadIdx.x;
    const float* p = y + (size_t)(b*D_ + d) * N_;
    double s = 0.0, s2 = 0.0;
    for (int n = t; n < N_; n += 256) { double v = p[n]; s += v; s2 += v*v; }
    __shared__ double sh[512];
    sh[t] = s; sh[256 + t] = s2;
    __syncthreads();
    for (int o = 128; o > 0; o >>= 1) {
        if (t < o) { sh[t] += sh[t+o]; sh[256+t] += sh[256+t+o]; }
        __syncthreads();
    }
    if (t == 0) {
        g_bp1[b*D_ + d] = sh[0];
        g_bp2[b*D_ + d] = sh[256];
    }
}

__global__ void bn_stats2(const float* __restrict__ gamma, const float* __restrict__ beta) {
    int d = blockIdx.x, t = threadIdx.x;   // 16 threads
    __shared__ double sh[32];
    sh[t]      = g_bp1[t*D_ + d];
    sh[16 + t] = g_bp2[t*D_ + d];
    __syncthreads();
    if (t == 0) {
        double s = 0.0, s2 = 0.0;
        for (int i = 0; i < 16; i++) { s += sh[i]; s2 += sh[16+i]; }
        double cnt = (double)B_ * (double)N_;
        double m = s / cnt;
        double var = s2 / cnt - m*m;
        double rs = rsqrt(var + 1e-5);
        double sc = rs * (double)gamma[d];
        g_scale[d] = (float)sc;
        g_shift[d] = (float)((double)beta[d] - m*sc);
    }
}

__global__ void bn_apply(float* __restrict__ y) {
    int i = (blockIdx.x * 256 + threadIdx.x) * 4;
    int d = (i >> 13) & 127;
    float sc = g_scale[d], sh = g_shift[d];
    float4 v = *(float4*)(y + i);
    v.x = v.x*sc + sh; v.y = v.y*sc + sh; v.z = v.z*sc + sh; v.w = v.w*sc + sh;
    *(float4*)(y + i) = v;
}

// ---------------- launch ----------------
extern "C" void kernel_launch(void* const* d_in, const int* in_sizes, int n_in,
                              void* d_out, int out_size) {
    const float* x  = (const float*)d_in[0];
    const float* qw = (const float*)d_in[1];
    const float* qb = (const float*)d_in[2];
    const float* kw = (const float*)d_in[3];
    const float* kb = (const float*)d_in[4];
    const float* vw = (const float*)d_in[5];
    const float* vb = (const float*)d_in[6];
    const float* ow = (const float*)d_in[7];
    const float* ob = (const float*)d_in[8];
    const float* gamma = (const float*)d_in[9];
    const float* beta  = (const float*)d_in[10];
    float* out = (float*)d_out;

    cudaFuncSetAttribute(qkv_tc, cudaFuncAttributeMaxDynamicSharedMemorySize, QKV_TC_SMEM);
    cudaFuncSetAttribute(attn_tc, cudaFuncAttributeMaxDynamicSharedMemorySize, AT_SMEM);

    prep_wsplit<<<(3*8*5*128*16 + 255) / 256, 256>>>(qw, kw, vw);
    prep_owsplit<<<(D_*D_ + 255) / 256, 256>>>(ow);
    prep_trig<<<(N_*64) / 256, 256>>>();
    qkv_tc<<<dim3(N_/128, B_), 512, QKV_TC_SMEM>>>(x, qb, kb, vb);
    attn_tc<<<dim3(NW_, B_), 512, AT_SMEM>>>(ob, out);
    bn_stats1<<<dim3(D_, B_), 256>>>(out);
    bn_stats2<<<D_, 16>>>(gamma, beta);
    bn_apply<<<(B_*D_*N_) / 1024, 256>>>(out);
}

// round 17
// speedup vs baseline: 2.8375x; 1.1126x over previous
#include <cuda_runtime.h>
#include <cuda_bf16.h>
#include <math.h>

#define B_ 16
#define D_ 128
#define N_ 8192
#define NW_ 64

typedef unsigned long long ull;
typedef unsigned int u32;
typedef unsigned short u16;

// ---------------- device scratch ----------------
__device__ __align__(16) __nv_bfloat16 g_wsp[3*8*2*5*128*16];
__device__ float g_cs[N_*64];
__device__ float g_sn[N_*64];
__device__ __align__(16) __nv_bfloat16 g_qh[B_*N_*D_];
__device__ __align__(16) __nv_bfloat16 g_ql[B_*N_*D_];
__device__ __align__(16) __nv_bfloat16 g_kh[B_*N_*D_];
__device__ __align__(16) __nv_bfloat16 g_kl[B_*N_*D_];
__device__ __align__(16) __nv_bfloat16 g_vh[B_*D_*N_];
__device__ __align__(16) __nv_bfloat16 g_vl[B_*D_*N_];
__device__ __align__(16) __nv_bfloat16 g_owh[D_*D_];
__device__ __align__(16) __nv_bfloat16 g_owl[D_*D_];
__device__ float g_bps[1024*128];   // per-CTA BN partial sums
__device__ float g_bpq[1024*128];   // per-CTA BN partial sum-squares
__device__ float g_scale[D_];
__device__ float g_shift[D_];

// ---------------- mma / async helpers ----------------
__device__ __forceinline__ void mma16816(float* c, const u32* a, u32 b0, u32 b1) {
    asm("mma.sync.aligned.m16n8k16.row.col.f32.bf16.bf16.f32 "
        "{%0,%1,%2,%3}, {%4,%5,%6,%7}, {%8,%9}, {%0,%1,%2,%3};"
        : "+f"(c[0]), "+f"(c[1]), "+f"(c[2]), "+f"(c[3])
        : "r"(a[0]), "r"(a[1]), "r"(a[2]), "r"(a[3]), "r"(b0), "r"(b1));
}
__device__ __forceinline__ void ldmat4(u32* r, u32 addr) {
    asm volatile("ldmatrix.sync.aligned.m8n8.x4.shared.b16 {%0,%1,%2,%3}, [%4];"
                 : "=r"(r[0]), "=r"(r[1]), "=r"(r[2]), "=r"(r[3]) : "r"(addr));
}
__device__ __forceinline__ void ldmat2(u32* r, u32 addr) {
    asm volatile("ldmatrix.sync.aligned.m8n8.x2.shared.b16 {%0,%1}, [%2];"
                 : "=r"(r[0]), "=r"(r[1]) : "r"(addr));
}
__device__ __forceinline__ u32 packbf(float a, float b) {
    __nv_bfloat162 t = __floats2bfloat162_rn(a, b);
    return *(u32*)&t;
}
__device__ __forceinline__ float fexp(float x) {
    float y = fmaxf(x * 1.4426950408889634f, -126.0f);
    float fy = rintf(y);
    float f = y - fy;
    float p = 0.0013333558f;
    p = fmaf(p, f, 0.0096181291f);
    p = fmaf(p, f, 0.0555041087f);
    p = fmaf(p, f, 0.2402265070f);
    p = fmaf(p, f, 0.6931471806f);
    p = fmaf(p, f, 1.0f);
    int e = __float2int_rn(y);
    float s = __int_as_float((e + 127) << 23);
    return p * s;
}
#define CP_ASYNC16(dst, src) \
    asm volatile("cp.async.cg.shared.global [%0], [%1], 16;" :: "r"(dst), "l"(src))
#define CP_COMMIT() asm volatile("cp.async.commit_group;" ::: "memory")
#define CP_WAIT1()  asm volatile("cp.async.wait_group 1;" ::: "memory")

#define WBLK_BYTES 40960

// ---------------- merged prep: wsplit | owsplit | trig ----------------
__global__ void prep_all(const float* __restrict__ qw, const float* __restrict__ kw,
                         const float* __restrict__ vw, const float* __restrict__ ow) {
    int blk = blockIdx.x;
    if (blk < 960) {
        int e = blk*256 + threadIdx.x;            // < 245760
        int ii = e % 16;
        int o  = (e / 16) % 128;
        int t  = (e / 2048) % 5;
        int ch = (e / 10240) % 8;
        int c  = e / 81920;
        const float* w = (c == 0) ? qw : (c == 1) ? kw : vw;
        float v = w[o*640 + (ch*16 + ii)*5 + t];
        __nv_bfloat16 hi = __float2bfloat16(v);
        __nv_bfloat16 lo = __float2bfloat16(v - __bfloat162float(hi));
        int base = (c*8 + ch) * 20480;
        int iisw = ii ^ ((o & 4) ? 8 : 0);
        int off  = t*2048 + o*16 + iisw;
        g_wsp[base + off]         = hi;
        g_wsp[base + 10240 + off] = lo;
    } else if (blk < 1024) {
        int e = (blk - 960)*256 + threadIdx.x;    // < 16384
        float v = ow[e];
        __nv_bfloat16 hi = __float2bfloat16(v);
        g_owh[e] = hi;
        g_owl[e] = __float2bfloat16(v - __bfloat162float(hi));
    } else {
        __shared__ float invf_s[64];
        int t = threadIdx.x;
        if (t < 64) invf_s[t] = (float)pow(10000.0, -((double)(2*t)) / 128.0);
        __syncthreads();
        int e = (blk - 1024)*256 + t;             // < 524288
        int n = e >> 6, f = e & 63;
        float ang = (float)n * invf_s[f];
        double s, c;
        sincos((double)ang, &s, &c);
        g_cs[e] = (float)c;
        g_sn[e] = (float)s;
    }
}

// ---------- tensor-core fused QKV conv (unchanged from R16) ----------
#define XH_OFF 0
#define XL_OFF 35904
#define W_OFF  71808
#define QKV_TC_SMEM 194688
#define XSTR 136

__global__ __launch_bounds__(512) void qkv_tc(const float* __restrict__ x,
                                              const float* __restrict__ qb,
                                              const float* __restrict__ kb,
                                              const float* __restrict__ vb) {
    extern __shared__ char smem[];
    __nv_bfloat16* xh = (__nv_bfloat16*)(smem + XH_OFF);
    __nv_bfloat16* xl = (__nv_bfloat16*)(smem + XL_OFF);

    const int b = blockIdx.y, n0 = blockIdx.x * 128;
    const int t = threadIdx.x;
    const int lane = t & 31, wid = t >> 5;
    const int warpM = wid >> 2, warpN = wid & 3;
    const int mbase = warpM * 32, cbase = warpN * 16;

    const u32 w_s = (u32)__cvta_generic_to_shared(smem + W_OFF);

    {
        const char* s0 = (const char*)g_wsp + (size_t)16 * WBLK_BYTES + t*16;
        u32 d0 = w_s + t*16;
#pragma unroll
        for (int k2 = 0; k2 < 5; k2++) CP_ASYNC16(d0 + k2*8192, s0 + k2*8192);
        CP_COMMIT();
        const char* s1 = (const char*)g_wsp + (size_t)17 * WBLK_BYTES + t*16;
        u32 d1 = w_s + 40960 + t*16;
#pragma unroll
        for (int k2 = 0; k2 < 5; k2++) CP_ASYNC16(d1 + k2*8192, s1 + k2*8192);
        CP_COMMIT();
    }

    for (int idx = t; idx < 128*132; idx += 512) {
        int i = idx / 132, c = idx % 132;
        int n = n0 - 4 + c;
        float v = (n >= 0) ? x[(size_t)(b*D_ + i)*N_ + n] : 0.0f;
        __nv_bfloat16 hi = __float2bfloat16(v);
        xh[c*XSTR + i] = hi;
        xl[c*XSTR + i] = __float2bfloat16(v - __bfloat162float(hi));
    }

    const u32 xh_s = (u32)__cvta_generic_to_shared(xh);
    const u32 xl_s = (u32)__cvta_generic_to_shared(xl);
    const int rl = lane & 15, cl8 = (lane >> 4) * 8;

    const int oA = cbase + ((lane >> 4) & 1)*8 + (lane & 7);
    const u32 koffA = (u32)((((lane >> 3) & 1)*16) ^ ((oA & 4) ? 16 : 0));
    const u32 bA = (u32)(oA*32) + koffA;
    const int oB = oA + 64;
    const u32 koffB = (u32)((((lane >> 3) & 1)*16) ^ ((oB & 4) ? 16 : 0));
    const u32 bB = (u32)(oB*32) + koffB;

    const float scl = 0.08838834764831845f;

#pragma unroll 1
    for (int cl = 0; cl < 3; cl++) {
        float acc[2][4][4];
#pragma unroll
        for (int mt = 0; mt < 2; mt++)
#pragma unroll
            for (int nt = 0; nt < 4; nt++)
#pragma unroll
                for (int u = 0; u < 4; u++) acc[mt][nt][u] = 0.0f;

#pragma unroll 1
        for (int ch = 0; ch < 8; ch++) {
            const int idx = cl*8 + ch;
            CP_WAIT1();
            __syncthreads();
            int nidx = idx + 2;
            if (nidx < 24) {
                int cl2 = nidx >> 3, ch2 = nidx & 7;
                int c2 = (cl2 == 0) ? 2 : (cl2 == 1) ? 1 : 0;
                const char* src = (const char*)g_wsp + (size_t)(c2*8 + ch2)*WBLK_BYTES + t*16;
                u32 dst = w_s + (u32)(nidx % 3)*40960 + t*16;
#pragma unroll
                for (int k2 = 0; k2 < 5; k2++)
                    CP_ASYNC16(dst + k2*8192, src + k2*8192);
            }
            CP_COMMIT();

            const u32 wb = w_s + (u32)(idx % 3)*40960;

#pragma unroll 1
            for (int tap = 0; tap < 5; tap++) {
                u32 ah[2][4], al[2][4];
#pragma unroll
                for (int mt = 0; mt < 2; mt++) {
                    int row = mbase + mt*16 + rl + tap;
                    int col = ch*16 + cl8;
                    u32 off = (u32)(row*XSTR + col) * 2;
                    ldmat4(ah[mt], xh_s + off);
                    ldmat4(al[mt], xl_s + off);
                }
                const u32 tb = wb + (u32)(tap*4096);
                u32 bh0[4], bl0[4], bh1[4], bl1[4];
                ldmat4(bh0, tb + bA);
                ldmat4(bl0, tb + 20480 + bA);
                ldmat4(bh1, tb + bB);
                ldmat4(bl1, tb + 20480 + bB);
#pragma unroll
                for (int mt = 0; mt < 2; mt++) {
                    mma16816(acc[mt][0], ah[mt], bh0[0], bh0[1]);
                    mma16816(acc[mt][1], ah[mt], bh0[2], bh0[3]);
                    mma16816(acc[mt][2], ah[mt], bh1[0], bh1[1]);
                    mma16816(acc[mt][3], ah[mt], bh1[2], bh1[3]);
                }
#pragma unroll
                for (int mt = 0; mt < 2; mt++) {
                    mma16816(acc[mt][0], al[mt], bh0[0], bh0[1]);
                    mma16816(acc[mt][1], al[mt], bh0[2], bh0[3]);
                    mma16816(acc[mt][2], al[mt], bh1[0], bh1[1]);
                    mma16816(acc[mt][3], al[mt], bh1[2], bh1[3]);
                }
#pragma unroll
                for (int mt = 0; mt < 2; mt++) {
                    mma16816(acc[mt][0], ah[mt], bl0[0], bl0[1]);
                    mma16816(acc[mt][1], ah[mt], bl0[2], bl0[3]);
                    mma16816(acc[mt][2], ah[mt], bl1[0], bl1[1]);
                    mma16816(acc[mt][3], ah[mt], bl1[2], bl1[3]);
                }
            }
        }

        if (cl == 0) {
#pragma unroll
            for (int mt = 0; mt < 2; mt++)
#pragma unroll
                for (int nt = 0; nt < 4; nt++) {
                    int row = mbase + mt*16 + (lane >> 2);
                    int col = cbase + (nt & 1)*8 + (nt >> 1)*64 + (lane & 3)*2;
#pragma unroll
                    for (int u = 0; u < 4; u++) {
                        int dd  = col + (u & 1);
                        int tok = n0 + row + (u >> 1)*8;
                        float vv = acc[mt][nt][u] + vb[dd];
                        __nv_bfloat16 h = __float2bfloat16(vv);
                        size_t off = (size_t)(b*D_ + dd)*N_ + tok;
                        g_vh[off] = h;
                        g_vl[off] = __float2bfloat16(vv - __bfloat162float(h));
                    }
                }
        } else {
            const float* bias = (cl == 1) ? kb : qb;
            const bool isq = (cl == 2);
            __nv_bfloat16* gh = isq ? g_qh : g_kh;
            __nv_bfloat16* gl = isq ? g_ql : g_kl;
#pragma unroll
            for (int mt = 0; mt < 2; mt++)
#pragma unroll
                for (int p = 0; p < 2; p++) {
                    int c0 = cbase + p*8 + (lane & 3)*2;
                    float bl0 = bias[c0],    bl1 = bias[c0+1];
                    float bh0 = bias[c0+64], bh1 = bias[c0+65];
#pragma unroll
                    for (int rh = 0; rh < 2; rh++) {
                        int row = mbase + mt*16 + (lane >> 2) + rh*8;
                        int n = n0 + row;
                        float2 cs = *(const float2*)(g_cs + n*64 + c0);
                        float2 sn = *(const float2*)(g_sn + n*64 + c0);
                        float lo0 = acc[mt][p][rh*2+0]   + bl0;
                        float lo1 = acc[mt][p][rh*2+1]   + bl1;
                        float hi0 = acc[mt][p+2][rh*2+0] + bh0;
                        float hi1 = acc[mt][p+2][rh*2+1] + bh1;
                        float o0 = lo0*cs.x - hi0*sn.x;
                        float o1 = lo1*cs.y - hi1*sn.y;
                        float o2 = hi0*cs.x + lo0*sn.x;
                        float o3 = hi1*cs.y + lo1*sn.y;
                        if (isq) { o0 *= scl; o1 *= scl; o2 *= scl; o3 *= scl; }
                        __nv_bfloat16 h0 = __float2bfloat16(o0);
                        __nv_bfloat16 h1 = __float2bfloat16(o1);
                        __nv_bfloat16 h2 = __float2bfloat16(o2);
                        __nv_bfloat16 h3 = __float2bfloat16(o3);
                        size_t off = (size_t)(b*N_ + n)*128 + c0;
                        *(u32*)(gh + off)      = packbf(__bfloat162float(h0), __bfloat162float(h1));
                        *(u32*)(gl + off)      = packbf(o0 - __bfloat162float(h0), o1 - __bfloat162float(h1));
                        *(u32*)(gh + off + 64) = packbf(__bfloat162float(h2), __bfloat162float(h3));
                        *(u32*)(gl + off + 64) = packbf(o2 - __bfloat162float(h2), o3 - __bfloat162float(h3));
                    }
                }
        }
    }
}

// -------- tensor-core windowed attention + fused 1x1 conv + BN partials --------
#define AT_QH 0
#define AT_S  34816
#define AT_QL 165888
#define AT_KH 200704
#define AT_KL 209408
#define AT_VH 165888
#define AT_VL 176128
#define AT_PH 186368
#define AT_PL 196608
#define AT_I  218624
#define AT_SMEM 219136
#define FC_AH 0
#define FC_WH 34816
#define FC_WL 69632
#define FC_AL 104448
#define FC_BNS 139264          // float[4][128]
#define FC_BNQ 141312          // float[4][128]

__global__ __launch_bounds__(512) void attn_tc(const float* __restrict__ ob_,
                                               float* __restrict__ out) {
    extern __shared__ char sm8[];
    __nv_bfloat16* qhs = (__nv_bfloat16*)(sm8 + AT_QH);
    float*         S   = (float*)(sm8 + AT_S);
    __nv_bfloat16* qls = (__nv_bfloat16*)(sm8 + AT_QL);
    __nv_bfloat16* khs = (__nv_bfloat16*)(sm8 + AT_KH);
    __nv_bfloat16* kls = (__nv_bfloat16*)(sm8 + AT_KL);
    __nv_bfloat16* vhs = (__nv_bfloat16*)(sm8 + AT_VH);
    __nv_bfloat16* vls = (__nv_bfloat16*)(sm8 + AT_VL);
    __nv_bfloat16* phs = (__nv_bfloat16*)(sm8 + AT_PH);
    __nv_bfloat16* pls = (__nv_bfloat16*)(sm8 + AT_PL);
    float* irow = (float*)(sm8 + AT_I);

    const int wi = blockIdx.x, b = blockIdx.y;
    const int n0 = wi * 128, t = threadIdx.x;
    const int lane = t & 31, wid = t >> 5;
    const int warpM = wid >> 2, warpN = wid & 3;
    const int mbase = warpM * 32;
    const int rl = lane & 15, cl8 = (lane >> 4) * 8;
    const int g = lane >> 2, tg = lane & 3;
    const int l7 = lane & 7, l8 = (lane >> 3) & 1;
    const int jstart = (wi == 0) ? 128 : 0;

    const u32 qh_s = (u32)__cvta_generic_to_shared(qhs);
    const u32 ql_s = (u32)__cvta_generic_to_shared(qls);
    const u32 kh_s = (u32)__cvta_generic_to_shared(khs);
    const u32 kl_s = (u32)__cvta_generic_to_shared(kls);
    const u32 vh_s = (u32)__cvta_generic_to_shared(vhs);
    const u32 vl_s = (u32)__cvta_generic_to_shared(vls);
    const u32 ph_s = (u32)__cvta_generic_to_shared(phs);
    const u32 pl_s = (u32)__cvta_generic_to_shared(pls);

    for (int idx = t; idx < 8192; idx += 512) {
        int r = idx >> 6, c = idx & 63;
        ((u32*)qhs)[r*68 + c] = ((const u32*)(g_qh + (size_t)(b*N_ + n0 + r)*D_))[c];
        ((u32*)qls)[r*68 + c] = ((const u32*)(g_ql + (size_t)(b*N_ + n0 + r)*D_))[c];
    }

    u32 hR[4], lR[4];
    {
        int nk0 = n0 - 128;
#pragma unroll
        for (int i = 0; i < 4; i++) {
            int idx = t + i*512;
            int r = idx >> 6, c2 = idx & 63;
            int nk = nk0 + r;
            hR[i] = 0; lR[i] = 0;
            if (nk >= 0) {
                hR[i] = *(const u32*)(g_kh + (size_t)(b*N_ + nk)*D_ + c2*2);
                lR[i] = *(const u32*)(g_kl + (size_t)(b*N_ + nk)*D_ + c2*2);
            }
        }
    }

    // ==== phase 1: S = q @ k^T ====
#pragma unroll 1
    for (int ch = 0; ch < 8; ch++) {
        __syncthreads();
#pragma unroll
        for (int i = 0; i < 4; i++) {
            int idx = t + i*512;
            int r = idx >> 6, c2 = idx & 63;
            ((u32*)khs)[r*68 + c2] = hR[i];
            ((u32*)kls)[r*68 + c2] = lR[i];
        }
        if (ch < 7) {
            int nk0 = n0 - 128 + (ch+1)*32;
#pragma unroll
            for (int i = 0; i < 4; i++) {
                int idx = t + i*512;
                int r = idx >> 6, c2 = idx & 63;
                int nk = nk0 + r;
                hR[i] = 0; lR[i] = 0;
                if (nk >= 0) {
                    hR[i] = *(const u32*)(g_kh + (size_t)(b*N_ + nk)*D_ + c2*2);
                    lR[i] = *(const u32*)(g_kl + (size_t)(b*N_ + nk)*D_ + c2*2);
                }
            }
        }
        __syncthreads();

        if (32*ch > 159 + mbase || 32*ch + 31 < jstart) continue;

        float accQ[3][2][4];
#pragma unroll
        for (int pb2 = 0; pb2 < 3; pb2++)
#pragma unroll
            for (int mt = 0; mt < 2; mt++)
#pragma unroll
                for (int u = 0; u < 4; u++) accQ[pb2][mt][u] = 0.0f;

#pragma unroll 1
        for (int kt = 0; kt < 8; kt++) {
            u32 ah[2][4], al[2][4];
#pragma unroll
            for (int mt = 0; mt < 2; mt++) {
                u32 off = (u32)((mbase + mt*16 + rl)*136 + kt*16 + cl8) * 2;
                ldmat4(ah[mt], qh_s + off);
                ldmat4(al[mt], ql_s + off);
            }
            u32 boff = (u32)((warpN*8 + l7)*136 + kt*16 + l8*8) * 2;
            u32 bh[2], bl[2];
            ldmat2(bh, kh_s + boff);
            ldmat2(bl, kl_s + boff);
#pragma unroll
            for (int mt = 0; mt < 2; mt++) mma16816(accQ[0][mt], ah[mt], bh[0], bh[1]);
#pragma unroll
            for (int mt = 0; mt < 2; mt++) mma16816(accQ[1][mt], al[mt], bh[0], bh[1]);
#pragma unroll
            for (int mt = 0; mt < 2; mt++) mma16816(accQ[2][mt], ah[mt], bl[0], bl[1]);
        }
#pragma unroll
        for (int mt = 0; mt < 2; mt++) {
            int row = mbase + mt*16 + g;
            int col = ch*32 + warpN*8 + tg*2;
            float a0 = accQ[0][mt][0] + accQ[1][mt][0] + accQ[2][mt][0];
            float a1 = accQ[0][mt][1] + accQ[1][mt][1] + accQ[2][mt][1];
            float a2 = accQ[0][mt][2] + accQ[1][mt][2] + accQ[2][mt][2];
            float a3 = accQ[0][mt][3] + accQ[1][mt][3] + accQ[2][mt][3];
            *(float2*)(S + row*256 + col)     = make_float2(a0, a1);
            *(float2*)(S + (row+8)*256 + col) = make_float2(a2, a3);
        }
    }

    {
        int nk0 = n0 - 128;
#pragma unroll
        for (int i = 0; i < 4; i++) {
            int idx = t + i*512;
            int dd = idx >> 4, c = idx & 15;
            int tok = nk0 + c*2;
            hR[i] = 0; lR[i] = 0;
            if (tok >= 0) {
                hR[i] = *(const u32*)(g_vh + (size_t)(b*D_ + dd)*N_ + tok);
                lR[i] = *(const u32*)(g_vl + (size_t)(b*D_ + dd)*N_ + tok);
            }
        }
    }
    __syncthreads();

    // ==== phase 2: softmax stats; writes e back into S ====
    {
        int r = t >> 2, q4 = t & 3;
        int jend = 128 + r + 1;
        float m = -3.402823466e38f;
        for (int c4 = (jstart >> 2) + q4; c4*4 < jend; c4 += 4) {
            float4 v = *(const float4*)(S + r*256 + c4*4);
            int c = c4*4;
            if (c   < jend) m = fmaxf(m, v.x);
            if (c+1 < jend) m = fmaxf(m, v.y);
            if (c+2 < jend) m = fmaxf(m, v.z);
            if (c+3 < jend) m = fmaxf(m, v.w);
        }
        m = fmaxf(m, __shfl_xor_sync(0xFFFFFFFF, m, 1));
        m = fmaxf(m, __shfl_xor_sync(0xFFFFFFFF, m, 2));
        float s = 0.0f;
        for (int c4 = (jstart >> 2) + q4; c4*4 < jend; c4 += 4) {
            float4 v = *(const float4*)(S + r*256 + c4*4);
            int c = c4*4;
            float e0 = (c   < jend) ? fexp(v.x - m) : 0.0f;
            float e1 = (c+1 < jend) ? fexp(v.y - m) : 0.0f;
            float e2 = (c+2 < jend) ? fexp(v.z - m) : 0.0f;
            float e3 = (c+3 < jend) ? fexp(v.w - m) : 0.0f;
            s += (e0 + e1) + (e2 + e3);
            *(float4*)(S + r*256 + c4*4) = make_float4(e0, e1, e2, e3);
        }
        s += __shfl_xor_sync(0xFFFFFFFF, s, 1);
        s += __shfl_xor_sync(0xFFFFFFFF, s, 2);
        if (q4 == 0) { irow[r] = 1.0f / s; }
    }

    // ==== phase 3: OUT = P @ V ====
    float accP[2][4][4];
#pragma unroll
    for (int mt = 0; mt < 2; mt++)
#pragma unroll
        for (int nt = 0; nt < 4; nt++)
#pragma unroll
            for (int u = 0; u < 4; u++) accP[mt][nt][u] = 0.0f;

#pragma unroll 1
    for (int ch = 0; ch < 8; ch++) {
        __syncthreads();
#pragma unroll
        for (int i = 0; i < 4; i++) {
            int idx = t + i*512;
            int dd = idx >> 4, c = idx & 15;
            *(u32*)((u16*)vhs + dd*40 + c*2) = hR[i];
            *(u32*)((u16*)vls + dd*40 + c*2) = lR[i];
        }
        {
            int r = t >> 2, c0l = (t & 3) * 8;
            float ii = irow[r];
            int jend = 128 + r + 1;
#pragma unroll
            for (int i4 = 0; i4 < 2; i4++) {
                int cg = ch*32 + c0l + i4*4;
                float4 s4 = *(const float4*)(S + r*256 + cg);
                float p[4];
                p[0] = (cg   >= jstart && cg   < jend) ? s4.x * ii : 0.0f;
                p[1] = (cg+1 >= jstart && cg+1 < jend) ? s4.y * ii : 0.0f;
                p[2] = (cg+2 >= jstart && cg+2 < jend) ? s4.z * ii : 0.0f;
                p[3] = (cg+3 >= jstart && cg+3 < jend) ? s4.w * ii : 0.0f;
                __nv_bfloat16 h0 = __float2bfloat16(p[0]);
                __nv_bfloat16 h1 = __float2bfloat16(p[1]);
                __nv_bfloat16 h2 = __float2bfloat16(p[2]);
                __nv_bfloat16 h3 = __float2bfloat16(p[3]);
                int di = (r*40 + c0l + i4*4) >> 1;
                ((u32*)phs)[di]   = packbf(__bfloat162float(h0), __bfloat162float(h1));
                ((u32*)phs)[di+1] = packbf(__bfloat162float(h2), __bfloat162float(h3));
                ((u32*)pls)[di]   = packbf(p[0] - __bfloat162float(h0), p[1] - __bfloat162float(h1));
                ((u32*)pls)[di+1] = packbf(p[2] - __bfloat162float(h2), p[3] - __bfloat162float(h3));
            }
        }
        if (ch < 7) {
            int nk0 = n0 - 128 + (ch+1)*32;
#pragma unroll
            for (int i = 0; i < 4; i++) {
                int idx = t + i*512;
                int dd = idx >> 4, c = idx & 15;
                int tok = nk0 + c*2;
                hR[i] = 0; lR[i] = 0;
                if (tok >= 0) {
                    hR[i] = *(const u32*)(g_vh + (size_t)(b*D_ + dd)*N_ + tok);
                    lR[i] = *(const u32*)(g_vl + (size_t)(b*D_ + dd)*N_ + tok);
                }
            }
        }
        __syncthreads();

        if (32*ch > 159 + mbase || 32*ch + 31 < jstart) continue;

#pragma unroll
        for (int kt = 0; kt < 2; kt++) {
            u32 pa[2][4], pb[2][4];
#pragma unroll
            for (int mt = 0; mt < 2; mt++) {
                u32 off = (u32)((mbase + mt*16 + rl)*40 + kt*16 + cl8) * 2;
                ldmat4(pa[mt], ph_s + off);
                ldmat4(pb[mt], pl_s + off);
            }
            u32 vh2[4][2], vl2[4][2];
#pragma unroll
            for (int nt = 0; nt < 4; nt++) {
                u32 boff = (u32)((warpN*32 + nt*8 + l7)*40 + kt*16 + l8*8) * 2;
                ldmat2(vh2[nt], vh_s + boff);
                ldmat2(vl2[nt], vl_s + boff);
            }
#pragma unroll
            for (int nt = 0; nt < 4; nt++)
#pragma unroll
                for (int mt = 0; mt < 2; mt++)
                    mma16816(accP[mt][nt], pa[mt], vh2[nt][0], vh2[nt][1]);
#pragma unroll
            for (int nt = 0; nt < 4; nt++)
#pragma unroll
                for (int mt = 0; mt < 2; mt++)
                    mma16816(accP[mt][nt], pb[mt], vh2[nt][0], vh2[nt][1]);
#pragma unroll
            for (int nt = 0; nt < 4; nt++)
#pragma unroll
                for (int mt = 0; mt < 2; mt++)
                    mma16816(accP[mt][nt], pa[mt], vl2[nt][0], vl2[nt][1]);
        }
    }

    // ==== fused 1x1 conv ====
    __nv_bfloat16* ahs = (__nv_bfloat16*)(sm8 + FC_AH);
    __nv_bfloat16* als = (__nv_bfloat16*)(sm8 + FC_AL);
    __nv_bfloat16* whs = (__nv_bfloat16*)(sm8 + FC_WH);
    __nv_bfloat16* wls = (__nv_bfloat16*)(sm8 + FC_WL);

    for (int idx = t; idx < 8192; idx += 512) {
        int r = idx >> 6, c = idx & 63;
        ((u32*)whs)[r*68 + c] = ((const u32*)(g_owh + (size_t)r*D_))[c];
        ((u32*)wls)[r*68 + c] = ((const u32*)(g_owl + (size_t)r*D_))[c];
    }
#pragma unroll
    for (int mt = 0; mt < 2; mt++)
#pragma unroll
        for (int nt = 0; nt < 4; nt++) {
            int row = mbase + mt*16 + g;
            int col = warpN*32 + nt*8 + tg*2;
#pragma unroll
            for (int half = 0; half < 2; half++) {
                float v0 = accP[mt][nt][half*2];
                float v1 = accP[mt][nt][half*2+1];
                __nv_bfloat16 h0 = __float2bfloat16(v0);
                __nv_bfloat16 h1 = __float2bfloat16(v1);
                int r2 = row + half*8;
                *(u32*)(ahs + r2*136 + col) = packbf(__bfloat162float(h0), __bfloat162float(h1));
                *(u32*)(als + r2*136 + col) = packbf(v0 - __bfloat162float(h0), v1 - __bfloat162float(h1));
            }
        }
    __syncthreads();

    const u32 ah_s = (u32)__cvta_generic_to_shared(ahs);
    const u32 al_s = (u32)__cvta_generic_to_shared(als);
    const u32 wh_s = (u32)__cvta_generic_to_shared(whs);
    const u32 wl_s = (u32)__cvta_generic_to_shared(wls);
    const int nbase = warpN * 32;

    float accC[2][4][4];
#pragma unroll
    for (int mt = 0; mt < 2; mt++)
#pragma unroll
        for (int nt = 0; nt < 4; nt++)
#pragma unroll
            for (int u = 0; u < 4; u++) accC[mt][nt][u] = 0.0f;

#pragma unroll 1
    for (int kt = 0; kt < 8; kt++) {
        u32 aH[2][4], aL[2][4];
#pragma unroll
        for (int mt = 0; mt < 2; mt++) {
            u32 off = (u32)((mbase + mt*16 + rl)*136 + kt*16 + cl8) * 2;
            ldmat4(aH[mt], ah_s + off);
            ldmat4(aL[mt], al_s + off);
        }
        u32 wh2[4][2], wl2[4][2];
#pragma unroll
        for (int nt = 0; nt < 4; nt++) {
            u32 boff = (u32)((nbase + nt*8 + l7)*136 + kt*16 + l8*8) * 2;
            ldmat2(wh2[nt], wh_s + boff);
            ldmat2(wl2[nt], wl_s + boff);
        }
#pragma unroll
        for (int nt = 0; nt < 4; nt++)
#pragma unroll
            for (int mt = 0; mt < 2; mt++)
                mma16816(accC[mt][nt], aH[mt], wh2[nt][0], wh2[nt][1]);
#pragma unroll
        for (int nt = 0; nt < 4; nt++)
#pragma unroll
            for (int mt = 0; mt < 2; mt++)
                mma16816(accC[mt][nt], aL[mt], wh2[nt][0], wh2[nt][1]);
#pragma unroll
        for (int nt = 0; nt < 4; nt++)
#pragma unroll
            for (int mt = 0; mt < 2; mt++)
                mma16816(accC[mt][nt], aH[mt], wl2[nt][0], wl2[nt][1]);
    }

    // ---- write out (transposed, + bias) ----
#pragma unroll
    for (int mt = 0; mt < 2; mt++)
#pragma unroll
        for (int nt = 0; nt < 4; nt++) {
            int row = mbase + mt*16 + g;
            int col = nbase + nt*8 + tg*2;
#pragma unroll
            for (int u = 0; u < 4; u++) {
                int dd  = col + (u & 1);
                int tok = n0 + row + (u >> 1)*8;
                out[(size_t)(b*D_ + dd)*N_ + tok] = accC[mt][nt][u] + ob_[dd];
            }
        }

    // ---- fused BN partials (deterministic) ----
    {
        float* bnS = (float*)(sm8 + FC_BNS);   // [4 warpM][128 ch]
        float* bnQ = (float*)(sm8 + FC_BNQ);
        float ps[8], pq[8];
#pragma unroll
        for (int nt = 0; nt < 4; nt++)
#pragma unroll
            for (int b2 = 0; b2 < 2; b2++) {
                int i8 = nt*2 + b2;
                int dd = nbase + nt*8 + tg*2 + b2;
                float bias = ob_[dd];
                float v0 = accC[0][nt][b2]     + bias;
                float v1 = accC[0][nt][2 + b2] + bias;
                float v2 = accC[1][nt][b2]     + bias;
                float v3 = accC[1][nt][2 + b2] + bias;
                ps[i8] = (v0 + v1) + (v2 + v3);
                pq[i8] = (v0*v0 + v1*v1) + (v2*v2 + v3*v3);
            }
        // reduce over g (lane bits 2..4), tg preserved
#pragma unroll
        for (int off = 4; off <= 16; off <<= 1)
#pragma unroll
            for (int i8 = 0; i8 < 8; i8++) {
                ps[i8] += __shfl_xor_sync(0xFFFFFFFF, ps[i8], off);
                pq[i8] += __shfl_xor_sync(0xFFFFFFFF, pq[i8], off);
            }
        if (lane < 4) {
#pragma unroll
            for (int nt = 0; nt < 4; nt++)
#pragma unroll
                for (int b2 = 0; b2 < 2; b2++) {
                    int dd = nbase + nt*8 + lane*2 + b2;
                    bnS[warpM*128 + dd] = ps[nt*2 + b2];
                    bnQ[warpM*128 + dd] = pq[nt*2 + b2];
                }
        }
        __syncthreads();
        if (t < 128) {
            float s = ((bnS[t] + bnS[128 + t]) + (bnS[256 + t] + bnS[384 + t]));
            float q = ((bnQ[t] + bnQ[128 + t]) + (bnQ[256 + t] + bnQ[384 + t]));
            int slot = b*64 + wi;
            g_bps[(size_t)slot*128 + t] = s;
            g_bpq[(size_t)slot*128 + t] = q;
        }
    }
}

// ---------------- BN: stage-2 reduce + apply ----------------
__global__ void bn_stats2(const float* __restrict__ gamma, const float* __restrict__ beta) {
    int d = blockIdx.x, t = threadIdx.x;   // 256 threads
    double s = 0.0, q = 0.0;
    for (int i = t; i < 1024; i += 256) {
        s += (double)g_bps[(size_t)i*128 + d];
        q += (double)g_bpq[(size_t)i*128 + d];
    }
    __shared__ double sh[512];
    sh[t] = s; sh[256 + t] = q;
    __syncthreads();
    for (int o = 128; o > 0; o >>= 1) {
        if (t < o) { sh[t] += sh[t+o]; sh[256+t] += sh[256+t+o]; }
        __syncthreads();
    }
    if (t == 0) {
        double cnt = (double)B_ * (double)N_;
        double m = sh[0] / cnt;
        double var = sh[256] / cnt - m*m;
        double rs = rsqrt(var + 1e-5);
        double sc = rs * (double)gamma[d];
        g_scale[d] = (float)sc;
        g_shift[d] = (float)((double)beta[d] - m*sc);
    }
}

__global__ void bn_apply(float* __restrict__ y) {
    int i = (blockIdx.x * 256 + threadIdx.x) * 4;
    int d = (i >> 13) & 127;
    float sc = g_scale[d], sh = g_shift[d];
    float4 v = *(float4*)(y + i);
    v.x = v.x*sc + sh; v.y = v.y*sc + sh; v.z = v.z*sc + sh; v.w = v.w*sc + sh;
    *(float4*)(y + i) = v;
}

// ---------------- launch ----------------
extern "C" void kernel_launch(void* const* d_in, const int* in_sizes, int n_in,
                              void* d_out, int out_size) {
    const float* x  = (const float*)d_in[0];
    const float* qw = (const float*)d_in[1];
    const float* qb = (const float*)d_in[2];
    const float* kw = (const float*)d_in[3];
    const float* kb = (const float*)d_in[4];
    const float* vw = (const float*)d_in[5];
    const float* vb = (const float*)d_in[6];
    const float* ow = (const float*)d_in[7];
    const float* ob = (const float*)d_in[8];
    const float* gamma = (const float*)d_in[9];
    const float* beta  = (const float*)d_in[10];
    float* out = (float*)d_out;

    cudaFuncSetAttribute(qkv_tc, cudaFuncAttributeMaxDynamicSharedMemorySize, QKV_TC_SMEM);
    cudaFuncSetAttribute(attn_tc, cudaFuncAttributeMaxDynamicSharedMemorySize, AT_SMEM);

    prep_all<<<3072, 256>>>(qw, kw, vw, ow);
    qkv_tc<<<dim3(N_/128, B_), 512, QKV_TC_SMEM>>>(x, qb, kb, vb);
    attn_tc<<<dim3(NW_, B_), 512, AT_SMEM>>>(ob, out);
    bn_stats2<<<D_, 256>>>(gamma, beta);
    bn_apply<<<(B_*D_*N_) / 1024, 256>>>(out);
}